// round 1
// baseline (speedup 1.0000x reference)
#include <cuda_runtime.h>
#include <math.h>

// ---------------- problem constants ----------------
#define BB 2
#define TT 1024
#define CC 1024
#define HH 16
#define VD 32
#define NOPE_ 32
#define RP 32      // rope pairs (ROPE_D/2)
#define RD 64
#define DQK 96
#define KEEP_ 256
#define QL 96
#define KVL 32

#define LOG1E4_OVER_32 0.28782313662425572f   // ln(10000)/32
#define ATTN_SCALE 0.10206207261596577f       // 1/sqrt(96)

// ---------------- scratch (single __device__ array, offsets in floats) ----------------
constexpr int OFF_NQ     = 0;
constexpr int OFF_CKV    = OFF_NQ     + BB*TT*QL;
constexpr int OFF_QNOPE  = OFF_CKV    + BB*TT*KVL;
constexpr int OFF_QROPE  = OFF_QNOPE  + BB*TT*512;
constexpr int OFF_KNOPE  = OFF_QROPE  + BB*TT*1024;
constexpr int OFF_V1RAW  = OFF_KNOPE  + BB*TT*512;
constexpr int OFF_KROPE  = OFF_V1RAW  + BB*TT*512;
constexpr int OFF_KWRAW  = OFF_KROPE  + BB*TT*RD;
constexpr int OFF_VWRAW  = OFF_KWRAW  + BB*TT*1536;
constexpr int OFF_SELX   = OFF_VWRAW  + BB*TT*512;
constexpr int OFF_KSRAW  = OFF_SELX   + BB*KEEP_*CC;
constexpr int OFF_VSRAW  = OFF_KSRAW  + BB*KEEP_*1536;
constexpr int OFF_XMEAN  = OFF_VSRAW  + BB*KEEP_*512;
constexpr int OFF_GATE   = OFF_XMEAN  + BB*CC;
constexpr int OFF_SCORES = OFF_GATE   + 8;
constexpr int OFF_IDX    = OFF_SCORES + BB*TT;
constexpr int OFF_Q      = OFF_IDX    + BB*KEEP_;
constexpr int OFF_K1     = OFF_Q      + BB*HH*TT*DQK;
constexpr int OFF_V1     = OFF_K1     + BB*HH*TT*DQK;
constexpr int OFF_KW     = OFF_V1     + BB*HH*TT*VD;
constexpr int OFF_VW     = OFF_KW     + BB*HH*TT*DQK;
constexpr int OFF_KS     = OFF_VW     + BB*HH*TT*VD;
constexpr int OFF_VS     = OFF_KS     + BB*HH*KEEP_*DQK;
constexpr int OFF_ATTN   = OFF_VS     + BB*HH*KEEP_*VD;
constexpr int SCRATCH_TOTAL = OFF_ATTN + BB*TT*HH*VD;

__device__ float g_scratch[SCRATCH_TOTAL];

// ---------------- generic fp32 GEMM: C[M,N] = A[M,K] @ B[K,N] ----------------
// 64x64 tile, BK=16, 256 threads, 4x4 per thread.
// Requirements used here: M % 64 == 0, K % 16 == 0, N % 32 == 0.
__global__ void gemm64(const float* __restrict__ A, const float* __restrict__ B,
                       float* __restrict__ C, int M, int N, int K) {
    __shared__ float As[16][64];
    __shared__ float Bs[16][64];
    int tid = threadIdx.x;
    int tx = tid & 15, ty = tid >> 4;
    int col0 = blockIdx.x * 64, row0 = blockIdx.y * 64;

    float acc[4][4];
#pragma unroll
    for (int r = 0; r < 4; r++)
#pragma unroll
        for (int c = 0; c < 4; c++) acc[r][c] = 0.f;

    for (int k0 = 0; k0 < K; k0 += 16) {
        {   // A tile: 64 rows x 16 k, each thread 4 consecutive k
            int i = tid * 4;
            int m = i >> 4;
            int kk = i & 15;
            const float* ap = A + (row0 + m) * K + k0 + kk;
            float4 av = *(const float4*)ap;
            As[kk + 0][m] = av.x; As[kk + 1][m] = av.y;
            As[kk + 2][m] = av.z; As[kk + 3][m] = av.w;
        }
        {   // B tile: 16 k x 64 cols
            int i = tid * 4;
            int kk = i >> 6;
            int n = i & 63;
            int gc = col0 + n;
            float4 bv = make_float4(0.f, 0.f, 0.f, 0.f);
            if (gc < N) bv = *(const float4*)(B + (k0 + kk) * N + gc);
            *(float4*)&Bs[kk][n] = bv;
        }
        __syncthreads();
#pragma unroll
        for (int kk = 0; kk < 16; kk++) {
            float4 a4 = *(const float4*)&As[kk][ty * 4];
            float4 b4 = *(const float4*)&Bs[kk][tx * 4];
            float av[4] = {a4.x, a4.y, a4.z, a4.w};
            float bv[4] = {b4.x, b4.y, b4.z, b4.w};
#pragma unroll
            for (int r = 0; r < 4; r++)
#pragma unroll
                for (int c = 0; c < 4; c++) acc[r][c] += av[r] * bv[c];
        }
        __syncthreads();
    }
#pragma unroll
    for (int r = 0; r < 4; r++) {
        int gr = row0 + ty * 4 + r;
#pragma unroll
        for (int c = 0; c < 4; c++) {
            int gc = col0 + tx * 4 + c;
            if (gc < N) C[gr * N + gc] = acc[r][c];
        }
    }
}

// ---------------- RMS norm (in place), one block per row, 128 threads ----------------
__global__ void rms_kernel(float* __restrict__ data, const float* __restrict__ g, int N) {
    int row = blockIdx.x, tid = threadIdx.x;
    __shared__ float s4[4];
    float v = (tid < N) ? data[row * N + tid] : 0.f;
    float sq = v * v;
#pragma unroll
    for (int o = 16; o > 0; o >>= 1) sq += __shfl_xor_sync(0xffffffffu, sq, o);
    if ((tid & 31) == 0) s4[tid >> 5] = sq;
    __syncthreads();
    float tot = s4[0] + s4[1] + s4[2] + s4[3];
    float sc = rsqrtf(tot / (float)N + 1e-6f);
    if (tid < N) data[row * N + tid] = v * sc * g[tid];
}

// ---------------- xmean over T ----------------
__global__ void xmean_kernel(const float* __restrict__ x, float* __restrict__ xmean) {
    int c = blockIdx.x * 256 + threadIdx.x;
    int b = blockIdx.y;
    float s = 0.f;
    for (int t = 0; t < TT; t++) s += x[(b * TT + t) * CC + c];
    xmean[b * CC + c] = s * (1.f / (float)TT);
}

// ---------------- gate = softmax(xmean @ w_gate) ----------------
__global__ void gate_kernel(const float* __restrict__ xmean, const float* __restrict__ wg,
                            float* __restrict__ gate) {
    int b = blockIdx.x, tid = threadIdx.x;
    __shared__ float sg[3];
    if (tid < 3) {
        float s = 0.f;
        for (int c = 0; c < CC; c++) s += xmean[b * CC + c] * wg[c * 3 + tid];
        sg[tid] = s;
    }
    __syncthreads();
    if (tid == 0) {
        float m = fmaxf(sg[0], fmaxf(sg[1], sg[2]));
        float e0 = expf(sg[0] - m), e1 = expf(sg[1] - m), e2 = expf(sg[2] - m);
        float inv = 1.f / (e0 + e1 + e2);
        gate[b * 4 + 0] = e0 * inv;
        gate[b * 4 + 1] = e1 * inv;
        gate[b * 4 + 2] = e2 * inv;
    }
}

// ---------------- importance scores = x @ w_imp ----------------
__global__ void scores_kernel(const float* __restrict__ x, const float* __restrict__ w,
                              float* __restrict__ out) {
    int row = blockIdx.x, tid = threadIdx.x;  // 256 threads
    __shared__ float s8[8];
    float s = 0.f;
    for (int c = tid; c < CC; c += 256) s += x[row * CC + c] * w[c];
#pragma unroll
    for (int o = 16; o > 0; o >>= 1) s += __shfl_xor_sync(0xffffffffu, s, o);
    if ((tid & 31) == 0) s8[tid >> 5] = s;
    __syncthreads();
    if (tid == 0) {
        float t = 0.f;
#pragma unroll
        for (int i = 0; i < 8; i++) t += s8[i];
        out[row] = t;
    }
}

// ---------------- top-k(256) of 1024 per batch + ascending index sort ----------------
__global__ void topk_kernel(const float* __restrict__ scores, int* __restrict__ idxout) {
    __shared__ float sv[1024];
    __shared__ int si[1024];
    __shared__ int ti[256];
    int b = blockIdx.x, tid = threadIdx.x;
    sv[tid] = scores[b * TT + tid];
    si[tid] = tid;
    __syncthreads();
    // bitonic sort, descending by (value, then smaller index wins)
    for (int k = 2; k <= 1024; k <<= 1) {
        for (int j = k >> 1; j > 0; j >>= 1) {
            int ixj = tid ^ j;
            if (ixj > tid) {
                bool desc = ((tid & k) == 0);
                float va = sv[tid], vb = sv[ixj];
                int ia = si[tid], ib = si[ixj];
                bool agtb = (va > vb) || (va == vb && ia < ib);
                if (desc ? !agtb : agtb) {
                    sv[tid] = vb; sv[ixj] = va;
                    si[tid] = ib; si[ixj] = ia;
                }
            }
            __syncthreads();
        }
    }
    if (tid < 256) ti[tid] = si[tid];
    __syncthreads();
    // bitonic sort of 256 indices, ascending
    for (int k = 2; k <= 256; k <<= 1) {
        for (int j = k >> 1; j > 0; j >>= 1) {
            int ixj = tid ^ j;
            if (tid < 256 && ixj > tid) {
                bool asc = ((tid & k) == 0);
                int ia = ti[tid], ib = ti[ixj];
                if (asc ? (ia > ib) : (ia < ib)) { ti[tid] = ib; ti[ixj] = ia; }
            }
            __syncthreads();
        }
    }
    if (tid < 256) idxout[b * KEEP_ + tid] = ti[tid];
}

// ---------------- gather selected rows ----------------
__global__ void gather_kernel(const float* __restrict__ x, const int* __restrict__ idx,
                              float* __restrict__ selx) {
    int row = blockIdx.x;          // 0..511
    int b = row >> 8;
    int t = idx[row];
    for (int c = threadIdx.x; c < CC; c += 256)
        selx[row * CC + c] = x[(b * TT + t) * CC + c];
}

// ---------------- assemble Q: nope + rope -> [B,H,T,96] ----------------
__global__ void assemble_q_kernel(const float* __restrict__ qnope, const float* __restrict__ qrope,
                                  float* __restrict__ Q) {
    int row = blockIdx.x;
    int b = row >> 10, t = row & 1023;
    int j = threadIdx.x;          // 512
    int h = j >> 5, d = j & 31;
    int qb = (((b * HH + h) * TT) + t) * DQK;
    Q[qb + d] = qnope[row * 512 + j];
    float x1 = qrope[row * 1024 + h * RD + d];
    float x2 = qrope[row * 1024 + h * RD + RP + d];
    float f = expf(-LOG1E4_OVER_32 * (float)d);
    float sn, cs;
    sincosf((float)t * f, &sn, &cs);
    Q[qb + NOPE_ + d] = x1 * cs - x2 * sn;
    Q[qb + NOPE_ + RP + d] = x1 * sn + x2 * cs;
}

// ---------------- assemble K1/V1 (nope + shared rope/16) ----------------
__global__ void assemble_k1v1_kernel(const float* __restrict__ knope, const float* __restrict__ v1raw,
                                     const float* __restrict__ kroperaw,
                                     float* __restrict__ K, float* __restrict__ V) {
    int row = blockIdx.x;
    int b = row >> 10, t = row & 1023;
    int j = threadIdx.x;
    int h = j >> 5, d = j & 31;
    int kb = (((b * HH + h) * TT) + t) * DQK;
    K[kb + d] = knope[row * 512 + j];
    float x1 = kroperaw[row * RD + d] * 0.0625f;
    float x2 = kroperaw[row * RD + RP + d] * 0.0625f;
    float f = expf(-LOG1E4_OVER_32 * (float)d);
    float sn, cs;
    sincosf((float)t * f, &sn, &cs);
    K[kb + NOPE_ + d] = x1 * cs - x2 * sn;
    K[kb + NOPE_ + RP + d] = x1 * sn + x2 * cs;
    V[(((b * HH + h) * TT) + t) * VD + d] = v1raw[row * 512 + j];
}

// ---------------- assemble selected/window K,V (raw cols h*96+r / h*32+d) ----------------
__global__ void assemble_kv_kernel(const float* __restrict__ kraw, const float* __restrict__ vraw,
                                   float* __restrict__ K, float* __restrict__ V, int S) {
    int row = blockIdx.x;
    int b = row / S, pos = row % S;
    int j = threadIdx.x;
    int h = j >> 5, d = j & 31;
    float nope = kraw[row * 1536 + h * DQK + d];
    float x1 = kraw[row * 1536 + h * DQK + NOPE_ + d];
    float x2 = kraw[row * 1536 + h * DQK + NOPE_ + RP + d];
    float f = expf(-LOG1E4_OVER_32 * (float)d);
    float sn, cs;
    sincosf((float)pos * f, &sn, &cs);
    int kb = (((b * HH + h) * S) + pos) * DQK;
    K[kb + d] = nope;
    K[kb + NOPE_ + d] = x1 * cs - x2 * sn;
    K[kb + NOPE_ + RP + d] = x1 * sn + x2 * cs;
    V[(((b * HH + h) * S) + pos) * VD + d] = vraw[row * 512 + h * VD + d];
}

// ---------------- fused 3-branch attention + gate, 1 block per (b,h,t), 128 thr ----------
__device__ __forceinline__ float blockMax128(float v, float* s4, int tid) {
#pragma unroll
    for (int o = 16; o > 0; o >>= 1) v = fmaxf(v, __shfl_xor_sync(0xffffffffu, v, o));
    if ((tid & 31) == 0) s4[tid >> 5] = v;
    __syncthreads();
    v = fmaxf(fmaxf(s4[0], s4[1]), fmaxf(s4[2], s4[3]));
    __syncthreads();
    return v;
}
__device__ __forceinline__ float blockSum128(float v, float* s4, int tid) {
#pragma unroll
    for (int o = 16; o > 0; o >>= 1) v += __shfl_xor_sync(0xffffffffu, v, o);
    if ((tid & 31) == 0) s4[tid >> 5] = v;
    __syncthreads();
    v = s4[0] + s4[1] + s4[2] + s4[3];
    __syncthreads();
    return v;
}

__global__ void attn_kernel(const float* __restrict__ Q,
                            const float* __restrict__ K1, const float* __restrict__ V1,
                            const float* __restrict__ KS, const float* __restrict__ VS,
                            const float* __restrict__ KW, const float* __restrict__ VW,
                            const float* __restrict__ gate, float* __restrict__ outp) {
    int t = blockIdx.x, h = blockIdx.y, b = blockIdx.z;
    int tid = threadIdx.x;  // 128
    __shared__ float sq[DQK];
    __shared__ float sp[128];
    __shared__ float sred[4];
    __shared__ float sacc[128];

    const float* qp = Q + ((b * HH + h) * TT + t) * DQK;
    if (tid < DQK) sq[tid] = qp[tid];
    __syncthreads();

    float fout = 0.f;  // valid on tid<32
    int g = tid >> 5, lane = tid & 31;

    for (int br = 0; br < 3; br++) {
        const float* Kp;
        const float* Vp;
        int nk;
        if (br == 0) {
            Kp = K1 + (b * HH + h) * TT * DQK;
            Vp = V1 + (b * HH + h) * TT * VD;
            nk = t + 1;
        } else if (br == 1) {
            Kp = KS + (b * HH + h) * KEEP_ * DQK;
            Vp = VS + (b * HH + h) * KEEP_ * VD;
            nk = KEEP_;
        } else {
            Kp = KW + (b * HH + h) * TT * DQK;
            Vp = VW + (b * HH + h) * TT * VD;
            nk = t + 1;
        }
        float m = -1e30f, l = 0.f, accv = 0.f;
        for (int k0 = 0; k0 < nk; k0 += 128) {
            int key = k0 + tid;
            float s = -1e30f;
            if (key < nk) {
                const float4* kp4 = (const float4*)(Kp + key * DQK);
                const float4* sq4 = (const float4*)sq;
                float acc = 0.f;
#pragma unroll
                for (int i = 0; i < 24; i++) {
                    float4 kv = kp4[i];
                    float4 qv = sq4[i];
                    acc += kv.x * qv.x + kv.y * qv.y + kv.z * qv.z + kv.w * qv.w;
                }
                s = acc * ATTN_SCALE;
            }
            float cm = blockMax128(s, sred, tid);
            float newm = fmaxf(m, cm);
            float p = __expf(s - newm);
            sp[tid] = p;
            float csum = blockSum128(p, sred, tid);  // also orders sp writes
            float alpha = __expf(m - newm);
            l = l * alpha + csum;
            m = newm;
            accv *= alpha;
            const float* vb = Vp + (k0 + g * 32) * VD + lane;
#pragma unroll
            for (int kk = 0; kk < 32; kk++) accv += sp[g * 32 + kk] * vb[kk * VD];
            __syncthreads();  // protect sp for next chunk
        }
        sacc[tid] = accv;
        __syncthreads();
        if (tid < 32) {
            float r = (sacc[tid] + sacc[32 + tid] + sacc[64 + tid] + sacc[96 + tid]) / l;
            fout += gate[b * 4 + br] * r;
        }
        __syncthreads();
    }
    if (tid < 32) outp[(b * TT + t) * (HH * VD) + h * VD + tid] = fout;
}

// ---------------- launcher ----------------
extern "C" void kernel_launch(void* const* d_in, const int* in_sizes, int n_in,
                              void* d_out, int out_size) {
    const float* x         = (const float*)d_in[0];
    const float* w_cq      = (const float*)d_in[1];
    const float* g_qnorm   = (const float*)d_in[2];
    const float* w_dq_nope = (const float*)d_in[3];
    const float* w_dq_rope = (const float*)d_in[4];
    const float* w_ckv     = (const float*)d_in[5];
    const float* g_kvnorm  = (const float*)d_in[6];
    const float* w_dk_nope = (const float*)d_in[7];
    const float* w_dv      = (const float*)d_in[8];
    const float* w_krope   = (const float*)d_in[9];
    const float* w_imp     = (const float*)d_in[10];
    const float* w_selk    = (const float*)d_in[11];
    const float* w_selv    = (const float*)d_in[12];
    const float* w_wink    = (const float*)d_in[13];
    const float* w_winv    = (const float*)d_in[14];
    const float* w_gate    = (const float*)d_in[15];
    const float* w_proj    = (const float*)d_in[16];
    float* out = (float*)d_out;

    float* base = nullptr;
    cudaGetSymbolAddress((void**)&base, g_scratch);

    float* nq     = base + OFF_NQ;
    float* ckv    = base + OFF_CKV;
    float* qnope  = base + OFF_QNOPE;
    float* qrope  = base + OFF_QROPE;
    float* knope  = base + OFF_KNOPE;
    float* v1raw  = base + OFF_V1RAW;
    float* krope  = base + OFF_KROPE;
    float* kwraw  = base + OFF_KWRAW;
    float* vwraw  = base + OFF_VWRAW;
    float* selx   = base + OFF_SELX;
    float* ksraw  = base + OFF_KSRAW;
    float* vsraw  = base + OFF_VSRAW;
    float* xmean  = base + OFF_XMEAN;
    float* gate   = base + OFF_GATE;
    float* scores = base + OFF_SCORES;
    int*   idx    = (int*)(base + OFF_IDX);
    float* Qb     = base + OFF_Q;
    float* K1b    = base + OFF_K1;
    float* V1b    = base + OFF_V1;
    float* KWb    = base + OFF_KW;
    float* VWb    = base + OFF_VW;
    float* KSb    = base + OFF_KS;
    float* VSb    = base + OFF_VS;
    float* attnb  = base + OFF_ATTN;

    const int M = BB * TT;  // 2048

    // Q path
    gemm64<<<dim3(2, M / 64), 256>>>(x, w_cq, nq, M, QL, CC);
    rms_kernel<<<M, 128>>>(nq, g_qnorm, QL);
    gemm64<<<dim3(8, M / 64), 256>>>(nq, w_dq_nope, qnope, M, 512, QL);
    gemm64<<<dim3(16, M / 64), 256>>>(nq, w_dq_rope, qrope, M, 1024, QL);

    // KV path
    gemm64<<<dim3(1, M / 64), 256>>>(x, w_ckv, ckv, M, KVL, CC);
    rms_kernel<<<M, 128>>>(ckv, g_kvnorm, KVL);
    gemm64<<<dim3(8, M / 64), 256>>>(ckv, w_dk_nope, knope, M, 512, KVL);
    gemm64<<<dim3(8, M / 64), 256>>>(ckv, w_dv, v1raw, M, 512, KVL);
    gemm64<<<dim3(1, M / 64), 256>>>(x, w_krope, krope, M, RD, CC);

    // window K/V
    gemm64<<<dim3(24, M / 64), 256>>>(x, w_wink, kwraw, M, 1536, CC);
    gemm64<<<dim3(8, M / 64), 256>>>(x, w_winv, vwraw, M, 512, CC);

    // gate
    xmean_kernel<<<dim3(4, BB), 256>>>(x, xmean);
    gate_kernel<<<BB, 32>>>(xmean, w_gate, gate);

    // selection
    scores_kernel<<<M, 256>>>(x, w_imp, scores);
    topk_kernel<<<BB, 1024>>>(scores, idx);
    gather_kernel<<<BB * KEEP_, 256>>>(x, idx, selx);
    gemm64<<<dim3(24, (BB * KEEP_) / 64), 256>>>(selx, w_selk, ksraw, BB * KEEP_, 1536, CC);
    gemm64<<<dim3(8, (BB * KEEP_) / 64), 256>>>(selx, w_selv, vsraw, BB * KEEP_, 512, CC);

    // assemble (rope + layout)
    assemble_q_kernel<<<M, 512>>>(qnope, qrope, Qb);
    assemble_k1v1_kernel<<<M, 512>>>(knope, v1raw, krope, K1b, V1b);
    assemble_kv_kernel<<<BB * KEEP_, 512>>>(ksraw, vsraw, KSb, VSb, KEEP_);
    assemble_kv_kernel<<<M, 512>>>(kwraw, vwraw, KWb, VWb, TT);

    // fused attention (3 branches + gate)
    attn_kernel<<<dim3(TT, HH, BB), 128>>>(Qb, K1b, V1b, KSb, VSb, KWb, VWb, gate, attnb);

    // output projection
    gemm64<<<dim3(16, M / 64), 256>>>(attnb, w_proj, out, M, CC, 512);
}

// round 2
// speedup vs baseline: 2.0409x; 2.0409x over previous
#include <cuda_runtime.h>
#include <math.h>

// ---------------- problem constants ----------------
#define BB 2
#define TT 1024
#define CC 1024
#define HH 16
#define VD 32
#define NOPE_ 32
#define RP 32      // rope pairs (ROPE_D/2)
#define RD 64
#define DQK 96
#define KEEP_ 256
#define QL 96
#define KVL 32

#define LOG1E4_OVER_32 0.28782313662425572f   // ln(10000)/32
#define ATTN_SCALE 0.10206207261596577f       // 1/sqrt(96)

// ---------------- scratch ----------------
constexpr int OFF_NQ     = 0;
constexpr int OFF_CKV    = OFF_NQ     + BB*TT*QL;
constexpr int OFF_QNOPE  = OFF_CKV    + BB*TT*KVL;
constexpr int OFF_QROPE  = OFF_QNOPE  + BB*TT*512;
constexpr int OFF_KNOPE  = OFF_QROPE  + BB*TT*1024;
constexpr int OFF_V1RAW  = OFF_KNOPE  + BB*TT*512;
constexpr int OFF_KROPE  = OFF_V1RAW  + BB*TT*512;
constexpr int OFF_KWRAW  = OFF_KROPE  + BB*TT*RD;
constexpr int OFF_VWRAW  = OFF_KWRAW  + BB*TT*1536;
constexpr int OFF_SELX   = OFF_VWRAW  + BB*TT*512;
constexpr int OFF_KSRAW  = OFF_SELX   + BB*KEEP_*CC;
constexpr int OFF_VSRAW  = OFF_KSRAW  + BB*KEEP_*1536;
constexpr int OFF_XMEAN  = OFF_VSRAW  + BB*KEEP_*512;
constexpr int OFF_GATE   = OFF_XMEAN  + BB*CC;
constexpr int OFF_SCORES = OFF_GATE   + 8;
constexpr int OFF_IDX    = OFF_SCORES + BB*TT;
constexpr int OFF_Q      = OFF_IDX    + BB*KEEP_;
constexpr int OFF_K1     = OFF_Q      + BB*HH*TT*DQK;
constexpr int OFF_V1     = OFF_K1     + BB*HH*TT*DQK;
constexpr int OFF_KW     = OFF_V1     + BB*HH*TT*VD;
constexpr int OFF_VW     = OFF_KW     + BB*HH*TT*DQK;
constexpr int OFF_KS     = OFF_VW     + BB*HH*TT*VD;
constexpr int OFF_VS     = OFF_KS     + BB*HH*KEEP_*DQK;
constexpr int OFF_ATTN   = OFF_VS     + BB*HH*KEEP_*VD;
constexpr int SCRATCH_TOTAL = OFF_ATTN + BB*TT*HH*VD;

__device__ float g_scratch[SCRATCH_TOTAL];

// ---------------- GEMM 64x64 tile (small-N cases) ----------------
__global__ void gemm64(const float* __restrict__ A, const float* __restrict__ B,
                       float* __restrict__ C, int M, int N, int K) {
    __shared__ float As[16][64];
    __shared__ float Bs[16][64];
    int tid = threadIdx.x;
    int tx = tid & 15, ty = tid >> 4;
    int col0 = blockIdx.x * 64, row0 = blockIdx.y * 64;

    float acc[4][4];
#pragma unroll
    for (int r = 0; r < 4; r++)
#pragma unroll
        for (int c = 0; c < 4; c++) acc[r][c] = 0.f;

    for (int k0 = 0; k0 < K; k0 += 16) {
        {
            int i = tid * 4;
            int m = i >> 4;
            int kk = i & 15;
            float4 av = *(const float4*)(A + (row0 + m) * K + k0 + kk);
            As[kk + 0][m] = av.x; As[kk + 1][m] = av.y;
            As[kk + 2][m] = av.z; As[kk + 3][m] = av.w;
        }
        {
            int i = tid * 4;
            int kk = i >> 6;
            int n = i & 63;
            int gc = col0 + n;
            float4 bv = make_float4(0.f, 0.f, 0.f, 0.f);
            if (gc < N) bv = *(const float4*)(B + (k0 + kk) * N + gc);
            *(float4*)&Bs[kk][n] = bv;
        }
        __syncthreads();
#pragma unroll
        for (int kk = 0; kk < 16; kk++) {
            float4 a4 = *(const float4*)&As[kk][ty * 4];
            float4 b4 = *(const float4*)&Bs[kk][tx * 4];
            float av[4] = {a4.x, a4.y, a4.z, a4.w};
            float bv[4] = {b4.x, b4.y, b4.z, b4.w};
#pragma unroll
            for (int r = 0; r < 4; r++)
#pragma unroll
                for (int c = 0; c < 4; c++) acc[r][c] += av[r] * bv[c];
        }
        __syncthreads();
    }
#pragma unroll
    for (int r = 0; r < 4; r++) {
        int gr = row0 + ty * 4 + r;
#pragma unroll
        for (int c = 0; c < 4; c++) {
            int gc = col0 + tx * 4 + c;
            if (gc < N) C[gr * N + gc] = acc[r][c];
        }
    }
}

// ---------------- GEMM 128x64 tile, 8x4 per thread (requires M%128==0, N%64==0, K%16==0) ----
__global__ void gemm128(const float* __restrict__ A, const float* __restrict__ B,
                        float* __restrict__ C, int M, int N, int K) {
    __shared__ float As[16][128];
    __shared__ float Bs[16][64];
    int tid = threadIdx.x;
    int tx = tid & 15, ty = tid >> 4;
    int col0 = blockIdx.x * 64, row0 = blockIdx.y * 128;

    float acc[8][4];
#pragma unroll
    for (int r = 0; r < 8; r++)
#pragma unroll
        for (int c = 0; c < 4; c++) acc[r][c] = 0.f;

    for (int k0 = 0; k0 < K; k0 += 16) {
#pragma unroll
        for (int half = 0; half < 2; half++) {
            int i = tid * 4 + half * 1024;
            int m = i >> 4;
            int kk = i & 15;
            float4 av = *(const float4*)(A + (row0 + m) * K + k0 + kk);
            As[kk + 0][m] = av.x; As[kk + 1][m] = av.y;
            As[kk + 2][m] = av.z; As[kk + 3][m] = av.w;
        }
        {
            int i = tid * 4;
            int kk = i >> 6;
            int n = i & 63;
            float4 bv = *(const float4*)(B + (k0 + kk) * N + col0 + n);
            *(float4*)&Bs[kk][n] = bv;
        }
        __syncthreads();
#pragma unroll
        for (int kk = 0; kk < 16; kk++) {
            float4 a0 = *(const float4*)&As[kk][ty * 8];
            float4 a1 = *(const float4*)&As[kk][ty * 8 + 4];
            float4 b4 = *(const float4*)&Bs[kk][tx * 4];
            float av[8] = {a0.x, a0.y, a0.z, a0.w, a1.x, a1.y, a1.z, a1.w};
            float bv[4] = {b4.x, b4.y, b4.z, b4.w};
#pragma unroll
            for (int r = 0; r < 8; r++)
#pragma unroll
                for (int c = 0; c < 4; c++) acc[r][c] += av[r] * bv[c];
        }
        __syncthreads();
    }
#pragma unroll
    for (int r = 0; r < 8; r++) {
        int gr = row0 + ty * 8 + r;
        float4 o = make_float4(acc[r][0], acc[r][1], acc[r][2], acc[r][3]);
        *(float4*)(C + gr * N + col0 + tx * 4) = o;
    }
}

// ---------------- RMS norm ----------------
__global__ void rms_kernel(float* __restrict__ data, const float* __restrict__ g, int N) {
    int row = blockIdx.x, tid = threadIdx.x;
    __shared__ float s4[4];
    float v = (tid < N) ? data[row * N + tid] : 0.f;
    float sq = v * v;
#pragma unroll
    for (int o = 16; o > 0; o >>= 1) sq += __shfl_xor_sync(0xffffffffu, sq, o);
    if ((tid & 31) == 0) s4[tid >> 5] = sq;
    __syncthreads();
    float tot = s4[0] + s4[1] + s4[2] + s4[3];
    float sc = rsqrtf(tot / (float)N + 1e-6f);
    if (tid < N) data[row * N + tid] = v * sc * g[tid];
}

// ---------------- xmean over T ----------------
__global__ void xmean_kernel(const float* __restrict__ x, float* __restrict__ xmean) {
    int c = blockIdx.x * 256 + threadIdx.x;
    int b = blockIdx.y;
    float s = 0.f;
    for (int t = 0; t < TT; t++) s += x[(b * TT + t) * CC + c];
    xmean[b * CC + c] = s * (1.f / (float)TT);
}

// ---------------- gate ----------------
__global__ void gate_kernel(const float* __restrict__ xmean, const float* __restrict__ wg,
                            float* __restrict__ gate) {
    int b = blockIdx.x, tid = threadIdx.x;
    __shared__ float sg[3];
    if (tid < 3) {
        float s = 0.f;
        for (int c = 0; c < CC; c++) s += xmean[b * CC + c] * wg[c * 3 + tid];
        sg[tid] = s;
    }
    __syncthreads();
    if (tid == 0) {
        float m = fmaxf(sg[0], fmaxf(sg[1], sg[2]));
        float e0 = expf(sg[0] - m), e1 = expf(sg[1] - m), e2 = expf(sg[2] - m);
        float inv = 1.f / (e0 + e1 + e2);
        gate[b * 4 + 0] = e0 * inv;
        gate[b * 4 + 1] = e1 * inv;
        gate[b * 4 + 2] = e2 * inv;
    }
}

// ---------------- importance scores ----------------
__global__ void scores_kernel(const float* __restrict__ x, const float* __restrict__ w,
                              float* __restrict__ out) {
    int row = blockIdx.x, tid = threadIdx.x;
    __shared__ float s8[8];
    float s = 0.f;
    for (int c = tid; c < CC; c += 256) s += x[row * CC + c] * w[c];
#pragma unroll
    for (int o = 16; o > 0; o >>= 1) s += __shfl_xor_sync(0xffffffffu, s, o);
    if ((tid & 31) == 0) s8[tid >> 5] = s;
    __syncthreads();
    if (tid == 0) {
        float t = 0.f;
#pragma unroll
        for (int i = 0; i < 8; i++) t += s8[i];
        out[row] = t;
    }
}

// ---------------- top-k(256) ----------------
__global__ void topk_kernel(const float* __restrict__ scores, int* __restrict__ idxout) {
    __shared__ float sv[1024];
    __shared__ int si[1024];
    __shared__ int ti[256];
    int b = blockIdx.x, tid = threadIdx.x;
    sv[tid] = scores[b * TT + tid];
    si[tid] = tid;
    __syncthreads();
    for (int k = 2; k <= 1024; k <<= 1) {
        for (int j = k >> 1; j > 0; j >>= 1) {
            int ixj = tid ^ j;
            if (ixj > tid) {
                bool desc = ((tid & k) == 0);
                float va = sv[tid], vb = sv[ixj];
                int ia = si[tid], ib = si[ixj];
                bool agtb = (va > vb) || (va == vb && ia < ib);
                if (desc ? !agtb : agtb) {
                    sv[tid] = vb; sv[ixj] = va;
                    si[tid] = ib; si[ixj] = ia;
                }
            }
            __syncthreads();
        }
    }
    if (tid < 256) ti[tid] = si[tid];
    __syncthreads();
    for (int k = 2; k <= 256; k <<= 1) {
        for (int j = k >> 1; j > 0; j >>= 1) {
            int ixj = tid ^ j;
            if (tid < 256 && ixj > tid) {
                bool asc = ((tid & k) == 0);
                int ia = ti[tid], ib = ti[ixj];
                if (asc ? (ia > ib) : (ia < ib)) { ti[tid] = ib; ti[ixj] = ia; }
            }
            __syncthreads();
        }
    }
    if (tid < 256) idxout[b * KEEP_ + tid] = ti[tid];
}

// ---------------- gather ----------------
__global__ void gather_kernel(const float* __restrict__ x, const int* __restrict__ idx,
                              float* __restrict__ selx) {
    int row = blockIdx.x;
    int b = row >> 8;
    int t = idx[row];
    for (int c = threadIdx.x; c < CC; c += 256)
        selx[row * CC + c] = x[(b * TT + t) * CC + c];
}

// ---------------- assembles (rope + layout) ----------------
__global__ void assemble_q_kernel(const float* __restrict__ qnope, const float* __restrict__ qrope,
                                  float* __restrict__ Q) {
    int row = blockIdx.x;
    int b = row >> 10, t = row & 1023;
    int j = threadIdx.x;
    int h = j >> 5, d = j & 31;
    int qb = (((b * HH + h) * TT) + t) * DQK;
    Q[qb + d] = qnope[row * 512 + j];
    float x1 = qrope[row * 1024 + h * RD + d];
    float x2 = qrope[row * 1024 + h * RD + RP + d];
    float f = expf(-LOG1E4_OVER_32 * (float)d);
    float sn, cs;
    sincosf((float)t * f, &sn, &cs);
    Q[qb + NOPE_ + d] = x1 * cs - x2 * sn;
    Q[qb + NOPE_ + RP + d] = x1 * sn + x2 * cs;
}

__global__ void assemble_k1v1_kernel(const float* __restrict__ knope, const float* __restrict__ v1raw,
                                     const float* __restrict__ kroperaw,
                                     float* __restrict__ K, float* __restrict__ V) {
    int row = blockIdx.x;
    int b = row >> 10, t = row & 1023;
    int j = threadIdx.x;
    int h = j >> 5, d = j & 31;
    int kb = (((b * HH + h) * TT) + t) * DQK;
    K[kb + d] = knope[row * 512 + j];
    float x1 = kroperaw[row * RD + d] * 0.0625f;
    float x2 = kroperaw[row * RD + RP + d] * 0.0625f;
    float f = expf(-LOG1E4_OVER_32 * (float)d);
    float sn, cs;
    sincosf((float)t * f, &sn, &cs);
    K[kb + NOPE_ + d] = x1 * cs - x2 * sn;
    K[kb + NOPE_ + RP + d] = x1 * sn + x2 * cs;
    V[(((b * HH + h) * TT) + t) * VD + d] = v1raw[row * 512 + j];
}

__global__ void assemble_kv_kernel(const float* __restrict__ kraw, const float* __restrict__ vraw,
                                   float* __restrict__ K, float* __restrict__ V, int S) {
    int row = blockIdx.x;
    int b = row / S, pos = row % S;
    int j = threadIdx.x;
    int h = j >> 5, d = j & 31;
    float nope = kraw[row * 1536 + h * DQK + d];
    float x1 = kraw[row * 1536 + h * DQK + NOPE_ + d];
    float x2 = kraw[row * 1536 + h * DQK + NOPE_ + RP + d];
    float f = expf(-LOG1E4_OVER_32 * (float)d);
    float sn, cs;
    sincosf((float)pos * f, &sn, &cs);
    int kb = (((b * HH + h) * S) + pos) * DQK;
    K[kb + d] = nope;
    K[kb + NOPE_ + d] = x1 * cs - x2 * sn;
    K[kb + NOPE_ + RP + d] = x1 * sn + x2 * cs;
    V[(((b * HH + h) * S) + pos) * VD + d] = vraw[row * 512 + h * VD + d];
}

// ---------------- flash attention: 64 queries x 64-key chunks, 3 branches fused ----------
// threads = 256 = 16(tx) x 16(ty). ty owns 4 queries; tx owns 4 keys (S) / 2 v-dims (PV).
// Dynamic smem: Qs[96][64] | union(Ks[96][64], Ps[64][68]) | Vs[64][32]
__global__ void attn_flash(const float* __restrict__ Q,
                           const float* __restrict__ K1, const float* __restrict__ V1,
                           const float* __restrict__ KS, const float* __restrict__ VS,
                           const float* __restrict__ KW, const float* __restrict__ VW,
                           const float* __restrict__ gate, float* __restrict__ outp) {
    extern __shared__ float sm[];
    float* Qs = sm;              // [96][64]
    float* KP = sm + 96 * 64;    // Ks[96][64] or Ps[64][68]
    float* Vs = sm + 2 * 96 * 64;// [64][32], rows permuted

    int tile = 15 - blockIdx.x;            // heavy tiles first
    int h = blockIdx.y, b = blockIdx.z;
    int q0 = tile * 64;
    int tid = threadIdx.x;
    int tx = tid & 15, ty = tid >> 4;
    int bh = b * HH + h;

    // load Q tile transposed: Qs[d][q]
    const float* Qp = Q + (bh * TT + q0) * DQK;
    for (int i = tid; i < 64 * 24; i += 256) {
        int q = i / 24, dq = i % 24;
        float4 v = *(const float4*)(Qp + q * DQK + dq * 4);
        Qs[(dq * 4 + 0) * 64 + q] = v.x;
        Qs[(dq * 4 + 1) * 64 + q] = v.y;
        Qs[(dq * 4 + 2) * 64 + q] = v.z;
        Qs[(dq * 4 + 3) * 64 + q] = v.w;
    }

    float g_b[3];
    g_b[0] = gate[b * 4 + 0];
    g_b[1] = gate[b * 4 + 1];
    g_b[2] = gate[b * 4 + 2];

    float fout[4][2];
#pragma unroll
    for (int i = 0; i < 4; i++) { fout[i][0] = 0.f; fout[i][1] = 0.f; }

    for (int br = 0; br < 3; br++) {
        const float* Kp;
        const float* Vp;
        int nchunk;
        bool causal;
        if (br == 0)      { Kp = K1 + bh * TT * DQK;    Vp = V1 + bh * TT * VD;    nchunk = tile + 1; causal = true; }
        else if (br == 1) { Kp = KS + bh * KEEP_ * DQK; Vp = VS + bh * KEEP_ * VD; nchunk = 4;        causal = false; }
        else              { Kp = KW + bh * TT * DQK;    Vp = VW + bh * TT * VD;    nchunk = tile + 1; causal = true; }

        float m[4], l[4], acc[4][2];
#pragma unroll
        for (int i = 0; i < 4; i++) { m[i] = -1e30f; l[i] = 0.f; acc[i][0] = 0.f; acc[i][1] = 0.f; }

        for (int c = 0; c < nchunk; c++) {
            int k0 = c * 64;
            __syncthreads();  // prior PV reads of KP/Vs done (and Qs load on first iter)

            // load K chunk transposed: Ks[d][k]
            for (int i = tid; i < 64 * 24; i += 256) {
                int key = i / 24, dq = i % 24;
                float4 v = *(const float4*)(Kp + (k0 + key) * DQK + dq * 4);
                KP[(dq * 4 + 0) * 64 + key] = v.x;
                KP[(dq * 4 + 1) * 64 + key] = v.y;
                KP[(dq * 4 + 2) * 64 + key] = v.z;
                KP[(dq * 4 + 3) * 64 + key] = v.w;
            }
            // load V chunk, permuted rows: pr = ((key&3)<<4)|(key>>2)
            for (int i = tid; i < 64 * 8; i += 256) {
                int key = i >> 3, dq = i & 7;
                int pr = ((key & 3) << 4) | (key >> 2);
                *(float4*)&Vs[pr * 32 + dq * 4] =
                    *(const float4*)(Vp + (k0 + key) * VD + dq * 4);
            }
            __syncthreads();

            // S = Q @ K^T (4q x 4k per thread)
            float s[4][4];
#pragma unroll
            for (int i = 0; i < 4; i++)
#pragma unroll
                for (int j = 0; j < 4; j++) s[i][j] = 0.f;
#pragma unroll 8
            for (int d = 0; d < DQK; d++) {
                float4 a = *(const float4*)&Qs[d * 64 + 4 * ty];
                float4 kv = *(const float4*)&KP[d * 64 + 4 * tx];
                float av[4] = {a.x, a.y, a.z, a.w};
                float bv[4] = {kv.x, kv.y, kv.z, kv.w};
#pragma unroll
                for (int i = 0; i < 4; i++)
#pragma unroll
                    for (int j = 0; j < 4; j++) s[i][j] += av[i] * bv[j];
            }
            bool diag = causal && (c == nchunk - 1);
#pragma unroll
            for (int i = 0; i < 4; i++)
#pragma unroll
                for (int j = 0; j < 4; j++) {
                    s[i][j] *= ATTN_SCALE;
                    if (diag && (4 * tx + j > 4 * ty + i)) s[i][j] = -1e30f;
                }

            // online softmax per query row (replicated across 16 tx lanes)
            float p[4][4];
#pragma unroll
            for (int i = 0; i < 4; i++) {
                float cm = fmaxf(fmaxf(s[i][0], s[i][1]), fmaxf(s[i][2], s[i][3]));
#pragma unroll
                for (int o = 8; o > 0; o >>= 1) cm = fmaxf(cm, __shfl_xor_sync(0xffffffffu, cm, o));
                float nm = fmaxf(m[i], cm);
                float alpha = __expf(m[i] - nm);
                m[i] = nm;
                float sum = 0.f;
#pragma unroll
                for (int j = 0; j < 4; j++) { p[i][j] = __expf(s[i][j] - nm); sum += p[i][j]; }
#pragma unroll
                for (int o = 8; o > 0; o >>= 1) sum += __shfl_xor_sync(0xffffffffu, sum, o);
                l[i] = l[i] * alpha + sum;
                acc[i][0] *= alpha;
                acc[i][1] *= alpha;
            }

            __syncthreads();  // all Ks reads done before P overwrites the union
            // write P: key k=4tx+j stored at row r=16j+tx (matches Vs row perm)
#pragma unroll
            for (int j = 0; j < 4; j++) {
                float4 pv = make_float4(p[0][j], p[1][j], p[2][j], p[3][j]);
                *(float4*)&KP[(16 * j + tx) * 68 + 4 * ty] = pv;
            }
            __syncthreads();

            // PV: rows of Ps and permuted Vs line up
#pragma unroll 4
            for (int r = 0; r < 64; r++) {
                float4 pv = *(const float4*)&KP[r * 68 + 4 * ty];
                float2 vv = *(const float2*)&Vs[r * 32 + 2 * tx];
                float pa[4] = {pv.x, pv.y, pv.z, pv.w};
#pragma unroll
                for (int i = 0; i < 4; i++) {
                    acc[i][0] += pa[i] * vv.x;
                    acc[i][1] += pa[i] * vv.y;
                }
            }
        }

        float gb = g_b[br];
#pragma unroll
        for (int i = 0; i < 4; i++) {
            float inv = gb / l[i];
            fout[i][0] += acc[i][0] * inv;
            fout[i][1] += acc[i][1] * inv;
        }
    }

    // write output [b, t, h*32 + d]
#pragma unroll
    for (int i = 0; i < 4; i++) {
        int q = q0 + 4 * ty + i;
        float2 o = make_float2(fout[i][0], fout[i][1]);
        *(float2*)(outp + (b * TT + q) * (HH * VD) + h * VD + 2 * tx) = o;
    }
}

// ---------------- launcher ----------------
extern "C" void kernel_launch(void* const* d_in, const int* in_sizes, int n_in,
                              void* d_out, int out_size) {
    const float* x         = (const float*)d_in[0];
    const float* w_cq      = (const float*)d_in[1];
    const float* g_qnorm   = (const float*)d_in[2];
    const float* w_dq_nope = (const float*)d_in[3];
    const float* w_dq_rope = (const float*)d_in[4];
    const float* w_ckv     = (const float*)d_in[5];
    const float* g_kvnorm  = (const float*)d_in[6];
    const float* w_dk_nope = (const float*)d_in[7];
    const float* w_dv      = (const float*)d_in[8];
    const float* w_krope   = (const float*)d_in[9];
    const float* w_imp     = (const float*)d_in[10];
    const float* w_selk    = (const float*)d_in[11];
    const float* w_selv    = (const float*)d_in[12];
    const float* w_wink    = (const float*)d_in[13];
    const float* w_winv    = (const float*)d_in[14];
    const float* w_gate    = (const float*)d_in[15];
    const float* w_proj    = (const float*)d_in[16];
    float* out = (float*)d_out;

    float* base = nullptr;
    cudaGetSymbolAddress((void**)&base, g_scratch);

    float* nq     = base + OFF_NQ;
    float* ckv    = base + OFF_CKV;
    float* qnope  = base + OFF_QNOPE;
    float* qrope  = base + OFF_QROPE;
    float* knope  = base + OFF_KNOPE;
    float* v1raw  = base + OFF_V1RAW;
    float* krope  = base + OFF_KROPE;
    float* kwraw  = base + OFF_KWRAW;
    float* vwraw  = base + OFF_VWRAW;
    float* selx   = base + OFF_SELX;
    float* ksraw  = base + OFF_KSRAW;
    float* vsraw  = base + OFF_VSRAW;
    float* xmean  = base + OFF_XMEAN;
    float* gate   = base + OFF_GATE;
    float* scores = base + OFF_SCORES;
    int*   idx    = (int*)(base + OFF_IDX);
    float* Qb     = base + OFF_Q;
    float* K1b    = base + OFF_K1;
    float* V1b    = base + OFF_V1;
    float* KWb    = base + OFF_KW;
    float* VWb    = base + OFF_VW;
    float* KSb    = base + OFF_KS;
    float* VSb    = base + OFF_VS;
    float* attnb  = base + OFF_ATTN;

    const int M = BB * TT;  // 2048
    const int FLASH_SMEM = (96 * 64 + 96 * 64 + 64 * 32) * 4;  // 56 KB
    cudaFuncSetAttribute(attn_flash, cudaFuncAttributeMaxDynamicSharedMemorySize, FLASH_SMEM);

    // Q path
    gemm64<<<dim3(2, M / 64), 256>>>(x, w_cq, nq, M, QL, CC);
    rms_kernel<<<M, 128>>>(nq, g_qnorm, QL);
    gemm128<<<dim3(8, M / 128), 256>>>(nq, w_dq_nope, qnope, M, 512, QL);
    gemm128<<<dim3(16, M / 128), 256>>>(nq, w_dq_rope, qrope, M, 1024, QL);

    // KV path
    gemm64<<<dim3(1, M / 64), 256>>>(x, w_ckv, ckv, M, KVL, CC);
    rms_kernel<<<M, 128>>>(ckv, g_kvnorm, KVL);
    gemm128<<<dim3(8, M / 128), 256>>>(ckv, w_dk_nope, knope, M, 512, KVL);
    gemm128<<<dim3(8, M / 128), 256>>>(ckv, w_dv, v1raw, M, 512, KVL);
    gemm128<<<dim3(1, M / 128), 256>>>(x, w_krope, krope, M, RD, CC);

    // window K/V
    gemm128<<<dim3(24, M / 128), 256>>>(x, w_wink, kwraw, M, 1536, CC);
    gemm128<<<dim3(8, M / 128), 256>>>(x, w_winv, vwraw, M, 512, CC);

    // gate
    xmean_kernel<<<dim3(4, BB), 256>>>(x, xmean);
    gate_kernel<<<BB, 32>>>(xmean, w_gate, gate);

    // selection
    scores_kernel<<<M, 256>>>(x, w_imp, scores);
    topk_kernel<<<BB, 1024>>>(scores, idx);
    gather_kernel<<<BB * KEEP_, 256>>>(x, idx, selx);
    gemm128<<<dim3(24, (BB * KEEP_) / 128), 256>>>(selx, w_selk, ksraw, BB * KEEP_, 1536, CC);
    gemm128<<<dim3(8, (BB * KEEP_) / 128), 256>>>(selx, w_selv, vsraw, BB * KEEP_, 512, CC);

    // assemble (rope + layout)
    assemble_q_kernel<<<M, 512>>>(qnope, qrope, Qb);
    assemble_k1v1_kernel<<<M, 512>>>(knope, v1raw, krope, K1b, V1b);
    assemble_kv_kernel<<<BB * KEEP_, 512>>>(ksraw, vsraw, KSb, VSb, KEEP_);
    assemble_kv_kernel<<<M, 512>>>(kwraw, vwraw, KWb, VWb, TT);

    // flash attention (3 branches + gate fused)
    attn_flash<<<dim3(16, HH, BB), 256, FLASH_SMEM>>>(Qb, K1b, V1b, KSb, VSb, KWb, VWb, gate, attnb);

    // output projection
    gemm128<<<dim3(16, M / 128), 256>>>(attnb, w_proj, out, M, CC, 512);
}

// round 3
// speedup vs baseline: 2.9566x; 1.4486x over previous
#include <cuda_runtime.h>
#include <math.h>
#include <stdint.h>

// ---------------- problem constants ----------------
#define BB 2
#define TT 1024
#define CC 1024
#define HH 16
#define VD 32
#define NOPE_ 32
#define RP 32      // rope pairs (ROPE_D/2)
#define RD 64
#define DQK 96
#define KEEP_ 256
#define QL 96
#define KVL 32

#define LOG1E4_OVER_32 0.28782313662425572f   // ln(10000)/32
#define ATTN_SCALE 0.10206207261596577f       // 1/sqrt(96)

// ---------------- scratch ----------------
constexpr int OFF_NQ     = 0;
constexpr int OFF_CKV    = OFF_NQ     + BB*TT*QL;
constexpr int OFF_QNOPE  = OFF_CKV    + BB*TT*KVL;
constexpr int OFF_QROPE  = OFF_QNOPE  + BB*TT*512;
constexpr int OFF_KNOPE  = OFF_QROPE  + BB*TT*1024;
constexpr int OFF_V1RAW  = OFF_KNOPE  + BB*TT*512;
constexpr int OFF_KROPE  = OFF_V1RAW  + BB*TT*512;
constexpr int OFF_KWRAW  = OFF_KROPE  + BB*TT*RD;
constexpr int OFF_VWRAW  = OFF_KWRAW  + BB*TT*1536;
constexpr int OFF_SELX   = OFF_VWRAW  + BB*TT*512;
constexpr int OFF_KSRAW  = OFF_SELX   + BB*KEEP_*CC;
constexpr int OFF_VSRAW  = OFF_KSRAW  + BB*KEEP_*1536;
constexpr int OFF_XMEAN  = OFF_VSRAW  + BB*KEEP_*512;
constexpr int OFF_GATE   = OFF_XMEAN  + BB*CC;
constexpr int OFF_SCORES = OFF_GATE   + 8;
constexpr int OFF_IDX    = OFF_SCORES + BB*TT;
constexpr int OFF_Q      = OFF_IDX    + BB*KEEP_;
constexpr int OFF_K1     = OFF_Q      + BB*HH*TT*DQK;
constexpr int OFF_V1     = OFF_K1     + BB*HH*TT*DQK;
constexpr int OFF_KW     = OFF_V1     + BB*HH*TT*VD;
constexpr int OFF_VW     = OFF_KW     + BB*HH*TT*DQK;
constexpr int OFF_KS     = OFF_VW     + BB*HH*TT*VD;
constexpr int OFF_VS     = OFF_KS     + BB*HH*KEEP_*DQK;
constexpr int OFF_ATTN   = OFF_VS     + BB*HH*KEEP_*VD;
constexpr int SCRATCH_TOTAL = OFF_ATTN + BB*TT*HH*VD;

__device__ float g_scratch[SCRATCH_TOTAL];

// ---------------- tf32 helpers ----------------
__device__ __forceinline__ void split_tf32(float v, float& hi, float& lo) {
    uint32_t h;
    asm("cvt.rna.tf32.f32 %0, %1;" : "=r"(h) : "f"(v));
    float hf = __uint_as_float(h);
    float lf = v - hf;
    uint32_t l;
    asm("cvt.rna.tf32.f32 %0, %1;" : "=r"(l) : "f"(lf));
    hi = hf;
    lo = __uint_as_float(l);
}

__device__ __forceinline__ void mma_tf32(float* d, const uint32_t* a, const uint32_t* b) {
    asm volatile(
        "mma.sync.aligned.m16n8k8.row.col.f32.tf32.tf32.f32 "
        "{%0,%1,%2,%3}, {%4,%5,%6,%7}, {%8,%9}, {%0,%1,%2,%3};\n"
        : "+f"(d[0]), "+f"(d[1]), "+f"(d[2]), "+f"(d[3])
        : "r"(a[0]), "r"(a[1]), "r"(a[2]), "r"(a[3]), "r"(b[0]), "r"(b[1]));
}

// ---------------- tensor-core GEMM: 128x128 tile, 3-pass tf32 split ----------------
// Requirements: M%128==0, N%128==0, K%16==0.
// 256 threads = 8 warps; warp grid 2(m)x4(n); warp tile 64x32; 4x4 mma tiles per warp.
__global__ void __launch_bounds__(256, 1)
gemm_tc(const float* __restrict__ A, const float* __restrict__ B,
        float* __restrict__ C, int M, int N, int K) {
    __shared__ float Ah[128][20];
    __shared__ float Al[128][20];
    __shared__ float Bh[16][136];
    __shared__ float Bl[16][136];

    int tid = threadIdx.x;
    int warp = tid >> 5, lane = tid & 31;
    int g = lane >> 2, tg = lane & 3;
    int wm = warp >> 2;   // 0..1
    int wn = warp & 3;    // 0..3
    int row0 = blockIdx.y * 128, col0 = blockIdx.x * 128;

    float d[4][4][4];
#pragma unroll
    for (int mi = 0; mi < 4; mi++)
#pragma unroll
        for (int ni = 0; ni < 4; ni++)
#pragma unroll
            for (int r = 0; r < 4; r++) d[mi][ni][r] = 0.f;

    for (int k0 = 0; k0 < K; k0 += 16) {
        // stage A tile [128 rows][16 k] as A[m][k], hi/lo split
#pragma unroll
        for (int it = 0; it < 2; it++) {
            int i = tid + it * 256;          // 0..511
            int row = i >> 2, kc = i & 3;
            float4 v = *(const float4*)(A + (row0 + row) * K + k0 + kc * 4);
            float4 h4, l4;
            split_tf32(v.x, h4.x, l4.x);
            split_tf32(v.y, h4.y, l4.y);
            split_tf32(v.z, h4.z, l4.z);
            split_tf32(v.w, h4.w, l4.w);
            *(float4*)&Ah[row][kc * 4] = h4;
            *(float4*)&Al[row][kc * 4] = l4;
        }
        // stage B tile [16 k][128 n] as B[k][n], hi/lo split
#pragma unroll
        for (int it = 0; it < 2; it++) {
            int i = tid + it * 256;
            int kk = i >> 5, nc = i & 31;
            float4 v = *(const float4*)(B + (k0 + kk) * N + col0 + nc * 4);
            float4 h4, l4;
            split_tf32(v.x, h4.x, l4.x);
            split_tf32(v.y, h4.y, l4.y);
            split_tf32(v.z, h4.z, l4.z);
            split_tf32(v.w, h4.w, l4.w);
            *(float4*)&Bh[kk][nc * 4] = h4;
            *(float4*)&Bl[kk][nc * 4] = l4;
        }
        __syncthreads();

#pragma unroll
        for (int ks = 0; ks < 16; ks += 8) {
            uint32_t ah[4][4], al[4][4], bh[4][2], bl[4][2];
#pragma unroll
            for (int mi = 0; mi < 4; mi++) {
                int r = wm * 64 + mi * 16;
                ah[mi][0] = __float_as_uint(Ah[r + g][ks + tg]);
                ah[mi][1] = __float_as_uint(Ah[r + 8 + g][ks + tg]);
                ah[mi][2] = __float_as_uint(Ah[r + g][ks + tg + 4]);
                ah[mi][3] = __float_as_uint(Ah[r + 8 + g][ks + tg + 4]);
                al[mi][0] = __float_as_uint(Al[r + g][ks + tg]);
                al[mi][1] = __float_as_uint(Al[r + 8 + g][ks + tg]);
                al[mi][2] = __float_as_uint(Al[r + g][ks + tg + 4]);
                al[mi][3] = __float_as_uint(Al[r + 8 + g][ks + tg + 4]);
            }
#pragma unroll
            for (int ni = 0; ni < 4; ni++) {
                int c = wn * 32 + ni * 8 + g;
                bh[ni][0] = __float_as_uint(Bh[ks + tg][c]);
                bh[ni][1] = __float_as_uint(Bh[ks + tg + 4][c]);
                bl[ni][0] = __float_as_uint(Bl[ks + tg][c]);
                bl[ni][1] = __float_as_uint(Bl[ks + tg + 4][c]);
            }
            // pass 1: hi*hi
#pragma unroll
            for (int mi = 0; mi < 4; mi++)
#pragma unroll
                for (int ni = 0; ni < 4; ni++) mma_tf32(d[mi][ni], ah[mi], bh[ni]);
            // pass 2: hi*lo
#pragma unroll
            for (int mi = 0; mi < 4; mi++)
#pragma unroll
                for (int ni = 0; ni < 4; ni++) mma_tf32(d[mi][ni], ah[mi], bl[ni]);
            // pass 3: lo*hi
#pragma unroll
            for (int mi = 0; mi < 4; mi++)
#pragma unroll
                for (int ni = 0; ni < 4; ni++) mma_tf32(d[mi][ni], al[mi], bh[ni]);
        }
        __syncthreads();
    }

    // epilogue
#pragma unroll
    for (int mi = 0; mi < 4; mi++) {
#pragma unroll
        for (int ni = 0; ni < 4; ni++) {
            int r = row0 + wm * 64 + mi * 16 + g;
            int c = col0 + wn * 32 + ni * 8 + 2 * tg;
            *(float2*)(C + r * N + c) = make_float2(d[mi][ni][0], d[mi][ni][1]);
            *(float2*)(C + (r + 8) * N + c) = make_float2(d[mi][ni][2], d[mi][ni][3]);
        }
    }
}

// ---------------- GEMM 64x64 tile (small-N cases) ----------------
__global__ void gemm64(const float* __restrict__ A, const float* __restrict__ B,
                       float* __restrict__ C, int M, int N, int K) {
    __shared__ float As[16][64];
    __shared__ float Bs[16][64];
    int tid = threadIdx.x;
    int tx = tid & 15, ty = tid >> 4;
    int col0 = blockIdx.x * 64, row0 = blockIdx.y * 64;

    float acc[4][4];
#pragma unroll
    for (int r = 0; r < 4; r++)
#pragma unroll
        for (int c = 0; c < 4; c++) acc[r][c] = 0.f;

    for (int k0 = 0; k0 < K; k0 += 16) {
        {
            int i = tid * 4;
            int m = i >> 4;
            int kk = i & 15;
            float4 av = *(const float4*)(A + (row0 + m) * K + k0 + kk);
            As[kk + 0][m] = av.x; As[kk + 1][m] = av.y;
            As[kk + 2][m] = av.z; As[kk + 3][m] = av.w;
        }
        {
            int i = tid * 4;
            int kk = i >> 6;
            int n = i & 63;
            int gc = col0 + n;
            float4 bv = make_float4(0.f, 0.f, 0.f, 0.f);
            if (gc < N) bv = *(const float4*)(B + (k0 + kk) * N + gc);
            *(float4*)&Bs[kk][n] = bv;
        }
        __syncthreads();
#pragma unroll
        for (int kk = 0; kk < 16; kk++) {
            float4 a4 = *(const float4*)&As[kk][ty * 4];
            float4 b4 = *(const float4*)&Bs[kk][tx * 4];
            float av[4] = {a4.x, a4.y, a4.z, a4.w};
            float bv[4] = {b4.x, b4.y, b4.z, b4.w};
#pragma unroll
            for (int r = 0; r < 4; r++)
#pragma unroll
                for (int c = 0; c < 4; c++) acc[r][c] += av[r] * bv[c];
        }
        __syncthreads();
    }
#pragma unroll
    for (int r = 0; r < 4; r++) {
        int gr = row0 + ty * 4 + r;
#pragma unroll
        for (int c = 0; c < 4; c++) {
            int gc = col0 + tx * 4 + c;
            if (gc < N) C[gr * N + gc] = acc[r][c];
        }
    }
}

// ---------------- GEMM 128x64 tile (fp32 fallback for small GEMMs) ----------------
__global__ void gemm128(const float* __restrict__ A, const float* __restrict__ B,
                        float* __restrict__ C, int M, int N, int K) {
    __shared__ float As[16][128];
    __shared__ float Bs[16][64];
    int tid = threadIdx.x;
    int tx = tid & 15, ty = tid >> 4;
    int col0 = blockIdx.x * 64, row0 = blockIdx.y * 128;

    float acc[8][4];
#pragma unroll
    for (int r = 0; r < 8; r++)
#pragma unroll
        for (int c = 0; c < 4; c++) acc[r][c] = 0.f;

    for (int k0 = 0; k0 < K; k0 += 16) {
#pragma unroll
        for (int half = 0; half < 2; half++) {
            int i = tid * 4 + half * 1024;
            int m = i >> 4;
            int kk = i & 15;
            float4 av = *(const float4*)(A + (row0 + m) * K + k0 + kk);
            As[kk + 0][m] = av.x; As[kk + 1][m] = av.y;
            As[kk + 2][m] = av.z; As[kk + 3][m] = av.w;
        }
        {
            int i = tid * 4;
            int kk = i >> 6;
            int n = i & 63;
            float4 bv = *(const float4*)(B + (k0 + kk) * N + col0 + n);
            *(float4*)&Bs[kk][n] = bv;
        }
        __syncthreads();
#pragma unroll
        for (int kk = 0; kk < 16; kk++) {
            float4 a0 = *(const float4*)&As[kk][ty * 8];
            float4 a1 = *(const float4*)&As[kk][ty * 8 + 4];
            float4 b4 = *(const float4*)&Bs[kk][tx * 4];
            float av[8] = {a0.x, a0.y, a0.z, a0.w, a1.x, a1.y, a1.z, a1.w};
            float bv[4] = {b4.x, b4.y, b4.z, b4.w};
#pragma unroll
            for (int r = 0; r < 8; r++)
#pragma unroll
                for (int c = 0; c < 4; c++) acc[r][c] += av[r] * bv[c];
        }
        __syncthreads();
    }
#pragma unroll
    for (int r = 0; r < 8; r++) {
        int gr = row0 + ty * 8 + r;
        float4 o = make_float4(acc[r][0], acc[r][1], acc[r][2], acc[r][3]);
        *(float4*)(C + gr * N + col0 + tx * 4) = o;
    }
}

// ---------------- RMS norm ----------------
__global__ void rms_kernel(float* __restrict__ data, const float* __restrict__ g, int N) {
    int row = blockIdx.x, tid = threadIdx.x;
    __shared__ float s4[4];
    float v = (tid < N) ? data[row * N + tid] : 0.f;
    float sq = v * v;
#pragma unroll
    for (int o = 16; o > 0; o >>= 1) sq += __shfl_xor_sync(0xffffffffu, sq, o);
    if ((tid & 31) == 0) s4[tid >> 5] = sq;
    __syncthreads();
    float tot = s4[0] + s4[1] + s4[2] + s4[3];
    float sc = rsqrtf(tot / (float)N + 1e-6f);
    if (tid < N) data[row * N + tid] = v * sc * g[tid];
}

// ---------------- xmean over T ----------------
__global__ void xmean_kernel(const float* __restrict__ x, float* __restrict__ xmean) {
    int c = blockIdx.x * 256 + threadIdx.x;
    int b = blockIdx.y;
    float s = 0.f;
    for (int t = 0; t < TT; t++) s += x[(b * TT + t) * CC + c];
    xmean[b * CC + c] = s * (1.f / (float)TT);
}

// ---------------- gate ----------------
__global__ void gate_kernel(const float* __restrict__ xmean, const float* __restrict__ wg,
                            float* __restrict__ gate) {
    int b = blockIdx.x, tid = threadIdx.x;
    __shared__ float sg[3];
    if (tid < 3) {
        float s = 0.f;
        for (int c = 0; c < CC; c++) s += xmean[b * CC + c] * wg[c * 3 + tid];
        sg[tid] = s;
    }
    __syncthreads();
    if (tid == 0) {
        float m = fmaxf(sg[0], fmaxf(sg[1], sg[2]));
        float e0 = expf(sg[0] - m), e1 = expf(sg[1] - m), e2 = expf(sg[2] - m);
        float inv = 1.f / (e0 + e1 + e2);
        gate[b * 4 + 0] = e0 * inv;
        gate[b * 4 + 1] = e1 * inv;
        gate[b * 4 + 2] = e2 * inv;
    }
}

// ---------------- importance scores ----------------
__global__ void scores_kernel(const float* __restrict__ x, const float* __restrict__ w,
                              float* __restrict__ out) {
    int row = blockIdx.x, tid = threadIdx.x;
    __shared__ float s8[8];
    float s = 0.f;
    for (int c = tid; c < CC; c += 256) s += x[row * CC + c] * w[c];
#pragma unroll
    for (int o = 16; o > 0; o >>= 1) s += __shfl_xor_sync(0xffffffffu, s, o);
    if ((tid & 31) == 0) s8[tid >> 5] = s;
    __syncthreads();
    if (tid == 0) {
        float t = 0.f;
#pragma unroll
        for (int i = 0; i < 8; i++) t += s8[i];
        out[row] = t;
    }
}

// ---------------- top-k(256) ----------------
__global__ void topk_kernel(const float* __restrict__ scores, int* __restrict__ idxout) {
    __shared__ float sv[1024];
    __shared__ int si[1024];
    __shared__ int ti[256];
    int b = blockIdx.x, tid = threadIdx.x;
    sv[tid] = scores[b * TT + tid];
    si[tid] = tid;
    __syncthreads();
    for (int k = 2; k <= 1024; k <<= 1) {
        for (int j = k >> 1; j > 0; j >>= 1) {
            int ixj = tid ^ j;
            if (ixj > tid) {
                bool desc = ((tid & k) == 0);
                float va = sv[tid], vb = sv[ixj];
                int ia = si[tid], ib = si[ixj];
                bool agtb = (va > vb) || (va == vb && ia < ib);
                if (desc ? !agtb : agtb) {
                    sv[tid] = vb; sv[ixj] = va;
                    si[tid] = ib; si[ixj] = ia;
                }
            }
            __syncthreads();
        }
    }
    if (tid < 256) ti[tid] = si[tid];
    __syncthreads();
    for (int k = 2; k <= 256; k <<= 1) {
        for (int j = k >> 1; j > 0; j >>= 1) {
            int ixj = tid ^ j;
            if (tid < 256 && ixj > tid) {
                bool asc = ((tid & k) == 0);
                int ia = ti[tid], ib = ti[ixj];
                if (asc ? (ia > ib) : (ia < ib)) { ti[tid] = ib; ti[ixj] = ia; }
            }
            __syncthreads();
        }
    }
    if (tid < 256) idxout[b * KEEP_ + tid] = ti[tid];
}

// ---------------- gather ----------------
__global__ void gather_kernel(const float* __restrict__ x, const int* __restrict__ idx,
                              float* __restrict__ selx) {
    int row = blockIdx.x;
    int b = row >> 8;
    int t = idx[row];
    for (int c = threadIdx.x; c < CC; c += 256)
        selx[row * CC + c] = x[(b * TT + t) * CC + c];
}

// ---------------- assembles (rope + layout) ----------------
__global__ void assemble_q_kernel(const float* __restrict__ qnope, const float* __restrict__ qrope,
                                  float* __restrict__ Q) {
    int row = blockIdx.x;
    int b = row >> 10, t = row & 1023;
    int j = threadIdx.x;
    int h = j >> 5, d = j & 31;
    int qb = (((b * HH + h) * TT) + t) * DQK;
    Q[qb + d] = qnope[row * 512 + j];
    float x1 = qrope[row * 1024 + h * RD + d];
    float x2 = qrope[row * 1024 + h * RD + RP + d];
    float f = expf(-LOG1E4_OVER_32 * (float)d);
    float sn, cs;
    sincosf((float)t * f, &sn, &cs);
    Q[qb + NOPE_ + d] = x1 * cs - x2 * sn;
    Q[qb + NOPE_ + RP + d] = x1 * sn + x2 * cs;
}

__global__ void assemble_k1v1_kernel(const float* __restrict__ knope, const float* __restrict__ v1raw,
                                     const float* __restrict__ kroperaw,
                                     float* __restrict__ K, float* __restrict__ V) {
    int row = blockIdx.x;
    int b = row >> 10, t = row & 1023;
    int j = threadIdx.x;
    int h = j >> 5, d = j & 31;
    int kb = (((b * HH + h) * TT) + t) * DQK;
    K[kb + d] = knope[row * 512 + j];
    float x1 = kroperaw[row * RD + d] * 0.0625f;
    float x2 = kroperaw[row * RD + RP + d] * 0.0625f;
    float f = expf(-LOG1E4_OVER_32 * (float)d);
    float sn, cs;
    sincosf((float)t * f, &sn, &cs);
    K[kb + NOPE_ + d] = x1 * cs - x2 * sn;
    K[kb + NOPE_ + RP + d] = x1 * sn + x2 * cs;
    V[(((b * HH + h) * TT) + t) * VD + d] = v1raw[row * 512 + j];
}

__global__ void assemble_kv_kernel(const float* __restrict__ kraw, const float* __restrict__ vraw,
                                   float* __restrict__ K, float* __restrict__ V, int S) {
    int row = blockIdx.x;
    int b = row / S, pos = row % S;
    int j = threadIdx.x;
    int h = j >> 5, d = j & 31;
    float nope = kraw[row * 1536 + h * DQK + d];
    float x1 = kraw[row * 1536 + h * DQK + NOPE_ + d];
    float x2 = kraw[row * 1536 + h * DQK + NOPE_ + RP + d];
    float f = expf(-LOG1E4_OVER_32 * (float)d);
    float sn, cs;
    sincosf((float)pos * f, &sn, &cs);
    int kb = (((b * HH + h) * S) + pos) * DQK;
    K[kb + d] = nope;
    K[kb + NOPE_ + d] = x1 * cs - x2 * sn;
    K[kb + NOPE_ + RP + d] = x1 * sn + x2 * cs;
    V[(((b * HH + h) * S) + pos) * VD + d] = vraw[row * 512 + h * VD + d];
}

// ---------------- flash attention (unchanged from R2) ----------------
__global__ void attn_flash(const float* __restrict__ Q,
                           const float* __restrict__ K1, const float* __restrict__ V1,
                           const float* __restrict__ KS, const float* __restrict__ VS,
                           const float* __restrict__ KW, const float* __restrict__ VW,
                           const float* __restrict__ gate, float* __restrict__ outp) {
    extern __shared__ float sm[];
    float* Qs = sm;              // [96][64]
    float* KP = sm + 96 * 64;    // Ks[96][64] or Ps[64][68]
    float* Vs = sm + 2 * 96 * 64;// [64][32], rows permuted

    int tile = 15 - blockIdx.x;            // heavy tiles first
    int h = blockIdx.y, b = blockIdx.z;
    int q0 = tile * 64;
    int tid = threadIdx.x;
    int tx = tid & 15, ty = tid >> 4;
    int bh = b * HH + h;

    const float* Qp = Q + (bh * TT + q0) * DQK;
    for (int i = tid; i < 64 * 24; i += 256) {
        int q = i / 24, dq = i % 24;
        float4 v = *(const float4*)(Qp + q * DQK + dq * 4);
        Qs[(dq * 4 + 0) * 64 + q] = v.x;
        Qs[(dq * 4 + 1) * 64 + q] = v.y;
        Qs[(dq * 4 + 2) * 64 + q] = v.z;
        Qs[(dq * 4 + 3) * 64 + q] = v.w;
    }

    float g_b[3];
    g_b[0] = gate[b * 4 + 0];
    g_b[1] = gate[b * 4 + 1];
    g_b[2] = gate[b * 4 + 2];

    float fout[4][2];
#pragma unroll
    for (int i = 0; i < 4; i++) { fout[i][0] = 0.f; fout[i][1] = 0.f; }

    for (int br = 0; br < 3; br++) {
        const float* Kp;
        const float* Vp;
        int nchunk;
        bool causal;
        if (br == 0)      { Kp = K1 + bh * TT * DQK;    Vp = V1 + bh * TT * VD;    nchunk = tile + 1; causal = true; }
        else if (br == 1) { Kp = KS + bh * KEEP_ * DQK; Vp = VS + bh * KEEP_ * VD; nchunk = 4;        causal = false; }
        else              { Kp = KW + bh * TT * DQK;    Vp = VW + bh * TT * VD;    nchunk = tile + 1; causal = true; }

        float m[4], l[4], acc[4][2];
#pragma unroll
        for (int i = 0; i < 4; i++) { m[i] = -1e30f; l[i] = 0.f; acc[i][0] = 0.f; acc[i][1] = 0.f; }

        for (int c = 0; c < nchunk; c++) {
            int k0 = c * 64;
            __syncthreads();

            for (int i = tid; i < 64 * 24; i += 256) {
                int key = i / 24, dq = i % 24;
                float4 v = *(const float4*)(Kp + (k0 + key) * DQK + dq * 4);
                KP[(dq * 4 + 0) * 64 + key] = v.x;
                KP[(dq * 4 + 1) * 64 + key] = v.y;
                KP[(dq * 4 + 2) * 64 + key] = v.z;
                KP[(dq * 4 + 3) * 64 + key] = v.w;
            }
            for (int i = tid; i < 64 * 8; i += 256) {
                int key = i >> 3, dq = i & 7;
                int pr = ((key & 3) << 4) | (key >> 2);
                *(float4*)&Vs[pr * 32 + dq * 4] =
                    *(const float4*)(Vp + (k0 + key) * VD + dq * 4);
            }
            __syncthreads();

            float s[4][4];
#pragma unroll
            for (int i = 0; i < 4; i++)
#pragma unroll
                for (int j = 0; j < 4; j++) s[i][j] = 0.f;
#pragma unroll 8
            for (int d = 0; d < DQK; d++) {
                float4 a = *(const float4*)&Qs[d * 64 + 4 * ty];
                float4 kv = *(const float4*)&KP[d * 64 + 4 * tx];
                float av[4] = {a.x, a.y, a.z, a.w};
                float bv[4] = {kv.x, kv.y, kv.z, kv.w};
#pragma unroll
                for (int i = 0; i < 4; i++)
#pragma unroll
                    for (int j = 0; j < 4; j++) s[i][j] += av[i] * bv[j];
            }
            bool diag = causal && (c == nchunk - 1);
#pragma unroll
            for (int i = 0; i < 4; i++)
#pragma unroll
                for (int j = 0; j < 4; j++) {
                    s[i][j] *= ATTN_SCALE;
                    if (diag && (4 * tx + j > 4 * ty + i)) s[i][j] = -1e30f;
                }

            float p[4][4];
#pragma unroll
            for (int i = 0; i < 4; i++) {
                float cm = fmaxf(fmaxf(s[i][0], s[i][1]), fmaxf(s[i][2], s[i][3]));
#pragma unroll
                for (int o = 8; o > 0; o >>= 1) cm = fmaxf(cm, __shfl_xor_sync(0xffffffffu, cm, o));
                float nm = fmaxf(m[i], cm);
                float alpha = __expf(m[i] - nm);
                m[i] = nm;
                float sum = 0.f;
#pragma unroll
                for (int j = 0; j < 4; j++) { p[i][j] = __expf(s[i][j] - nm); sum += p[i][j]; }
#pragma unroll
                for (int o = 8; o > 0; o >>= 1) sum += __shfl_xor_sync(0xffffffffu, sum, o);
                l[i] = l[i] * alpha + sum;
                acc[i][0] *= alpha;
                acc[i][1] *= alpha;
            }

            __syncthreads();
#pragma unroll
            for (int j = 0; j < 4; j++) {
                float4 pv = make_float4(p[0][j], p[1][j], p[2][j], p[3][j]);
                *(float4*)&KP[(16 * j + tx) * 68 + 4 * ty] = pv;
            }
            __syncthreads();

#pragma unroll 4
            for (int r = 0; r < 64; r++) {
                float4 pv = *(const float4*)&KP[r * 68 + 4 * ty];
                float2 vv = *(const float2*)&Vs[r * 32 + 2 * tx];
                float pa[4] = {pv.x, pv.y, pv.z, pv.w};
#pragma unroll
                for (int i = 0; i < 4; i++) {
                    acc[i][0] += pa[i] * vv.x;
                    acc[i][1] += pa[i] * vv.y;
                }
            }
        }

        float gb = g_b[br];
#pragma unroll
        for (int i = 0; i < 4; i++) {
            float inv = gb / l[i];
            fout[i][0] += acc[i][0] * inv;
            fout[i][1] += acc[i][1] * inv;
        }
    }

#pragma unroll
    for (int i = 0; i < 4; i++) {
        int q = q0 + 4 * ty + i;
        float2 o = make_float2(fout[i][0], fout[i][1]);
        *(float2*)(outp + (b * TT + q) * (HH * VD) + h * VD + 2 * tx) = o;
    }
}

// ---------------- launcher ----------------
extern "C" void kernel_launch(void* const* d_in, const int* in_sizes, int n_in,
                              void* d_out, int out_size) {
    const float* x         = (const float*)d_in[0];
    const float* w_cq      = (const float*)d_in[1];
    const float* g_qnorm   = (const float*)d_in[2];
    const float* w_dq_nope = (const float*)d_in[3];
    const float* w_dq_rope = (const float*)d_in[4];
    const float* w_ckv     = (const float*)d_in[5];
    const float* g_kvnorm  = (const float*)d_in[6];
    const float* w_dk_nope = (const float*)d_in[7];
    const float* w_dv      = (const float*)d_in[8];
    const float* w_krope   = (const float*)d_in[9];
    const float* w_imp     = (const float*)d_in[10];
    const float* w_selk    = (const float*)d_in[11];
    const float* w_selv    = (const float*)d_in[12];
    const float* w_wink    = (const float*)d_in[13];
    const float* w_winv    = (const float*)d_in[14];
    const float* w_gate    = (const float*)d_in[15];
    const float* w_proj    = (const float*)d_in[16];
    float* out = (float*)d_out;

    float* base = nullptr;
    cudaGetSymbolAddress((void**)&base, g_scratch);

    float* nq     = base + OFF_NQ;
    float* ckv    = base + OFF_CKV;
    float* qnope  = base + OFF_QNOPE;
    float* qrope  = base + OFF_QROPE;
    float* knope  = base + OFF_KNOPE;
    float* v1raw  = base + OFF_V1RAW;
    float* krope  = base + OFF_KROPE;
    float* kwraw  = base + OFF_KWRAW;
    float* vwraw  = base + OFF_VWRAW;
    float* selx   = base + OFF_SELX;
    float* ksraw  = base + OFF_KSRAW;
    float* vsraw  = base + OFF_VSRAW;
    float* xmean  = base + OFF_XMEAN;
    float* gate   = base + OFF_GATE;
    float* scores = base + OFF_SCORES;
    int*   idx    = (int*)(base + OFF_IDX);
    float* Qb     = base + OFF_Q;
    float* K1b    = base + OFF_K1;
    float* V1b    = base + OFF_V1;
    float* KWb    = base + OFF_KW;
    float* VWb    = base + OFF_VW;
    float* KSb    = base + OFF_KS;
    float* VSb    = base + OFF_VS;
    float* attnb  = base + OFF_ATTN;

    const int M = BB * TT;  // 2048
    const int FLASH_SMEM = (96 * 64 + 96 * 64 + 64 * 32) * 4;  // 56 KB
    cudaFuncSetAttribute(attn_flash, cudaFuncAttributeMaxDynamicSharedMemorySize, FLASH_SMEM);

    // Q path
    gemm64<<<dim3(2, M / 64), 256>>>(x, w_cq, nq, M, QL, CC);
    rms_kernel<<<M, 128>>>(nq, g_qnorm, QL);
    gemm_tc<<<dim3(4, M / 128), 256>>>(nq, w_dq_nope, qnope, M, 512, QL);
    gemm_tc<<<dim3(8, M / 128), 256>>>(nq, w_dq_rope, qrope, M, 1024, QL);

    // KV path
    gemm64<<<dim3(1, M / 64), 256>>>(x, w_ckv, ckv, M, KVL, CC);
    rms_kernel<<<M, 128>>>(ckv, g_kvnorm, KVL);
    gemm128<<<dim3(8, M / 128), 256>>>(ckv, w_dk_nope, knope, M, 512, KVL);
    gemm128<<<dim3(8, M / 128), 256>>>(ckv, w_dv, v1raw, M, 512, KVL);
    gemm128<<<dim3(1, M / 128), 256>>>(x, w_krope, krope, M, RD, CC);

    // window K/V (tensor cores)
    gemm_tc<<<dim3(12, M / 128), 256>>>(x, w_wink, kwraw, M, 1536, CC);
    gemm_tc<<<dim3(4, M / 128), 256>>>(x, w_winv, vwraw, M, 512, CC);

    // gate
    xmean_kernel<<<dim3(4, BB), 256>>>(x, xmean);
    gate_kernel<<<BB, 32>>>(xmean, w_gate, gate);

    // selection
    scores_kernel<<<M, 256>>>(x, w_imp, scores);
    topk_kernel<<<BB, 1024>>>(scores, idx);
    gather_kernel<<<BB * KEEP_, 256>>>(x, idx, selx);
    gemm_tc<<<dim3(12, (BB * KEEP_) / 128), 256>>>(selx, w_selk, ksraw, BB * KEEP_, 1536, CC);
    gemm_tc<<<dim3(4, (BB * KEEP_) / 128), 256>>>(selx, w_selv, vsraw, BB * KEEP_, 512, CC);

    // assemble (rope + layout)
    assemble_q_kernel<<<M, 512>>>(qnope, qrope, Qb);
    assemble_k1v1_kernel<<<M, 512>>>(knope, v1raw, krope, K1b, V1b);
    assemble_kv_kernel<<<BB * KEEP_, 512>>>(ksraw, vsraw, KSb, VSb, KEEP_);
    assemble_kv_kernel<<<M, 512>>>(kwraw, vwraw, KWb, VWb, TT);

    // flash attention (3 branches + gate fused)
    attn_flash<<<dim3(16, HH, BB), 256, FLASH_SMEM>>>(Qb, K1b, V1b, KSb, VSb, KWb, VWb, gate, attnb);

    // output projection (tensor cores)
    gemm_tc<<<dim3(8, M / 128), 256>>>(attnb, w_proj, out, M, CC, 512);
}

// round 4
// speedup vs baseline: 4.0111x; 1.3567x over previous
#include <cuda_runtime.h>
#include <math.h>
#include <stdint.h>

// ---------------- problem constants ----------------
#define BB 2
#define TT 1024
#define CC 1024
#define HH 16
#define VD 32
#define NOPE_ 32
#define RP 32      // rope pairs (ROPE_D/2)
#define RD 64
#define DQK 96
#define KEEP_ 256
#define QL 96
#define KVL 32

#define LOG1E4_OVER_32 0.28782313662425572f   // ln(10000)/32
#define ATTN_SCALE 0.10206207261596577f       // 1/sqrt(96)

// ---------------- scratch ----------------
constexpr int OFF_NQ     = 0;
constexpr int OFF_CKV    = OFF_NQ     + BB*TT*QL;
constexpr int OFF_QNOPE  = OFF_CKV    + BB*TT*KVL;
constexpr int OFF_QROPE  = OFF_QNOPE  + BB*TT*512;
constexpr int OFF_KNOPE  = OFF_QROPE  + BB*TT*1024;
constexpr int OFF_V1RAW  = OFF_KNOPE  + BB*TT*512;
constexpr int OFF_KROPE  = OFF_V1RAW  + BB*TT*512;
constexpr int OFF_KWRAW  = OFF_KROPE  + BB*TT*RD;
constexpr int OFF_VWRAW  = OFF_KWRAW  + BB*TT*1536;
constexpr int OFF_SELX   = OFF_VWRAW  + BB*TT*512;
constexpr int OFF_KSRAW  = OFF_SELX   + BB*KEEP_*CC;
constexpr int OFF_VSRAW  = OFF_KSRAW  + BB*KEEP_*1536;
constexpr int OFF_XMEAN  = OFF_VSRAW  + BB*KEEP_*512;
constexpr int OFF_GATE   = OFF_XMEAN  + BB*CC;
constexpr int OFF_SCORES = OFF_GATE   + 8;
constexpr int OFF_IDX    = OFF_SCORES + BB*TT;
constexpr int OFF_Q      = OFF_IDX    + BB*KEEP_;
constexpr int OFF_K1     = OFF_Q      + BB*HH*TT*DQK;
constexpr int OFF_V1     = OFF_K1     + BB*HH*TT*DQK;
constexpr int OFF_KW     = OFF_V1     + BB*HH*TT*VD;
constexpr int OFF_VW     = OFF_KW     + BB*HH*TT*DQK;
constexpr int OFF_KS     = OFF_VW     + BB*HH*TT*VD;
constexpr int OFF_VS     = OFF_KS     + BB*HH*KEEP_*DQK;
constexpr int OFF_ATTN   = OFF_VS     + BB*HH*KEEP_*VD;
constexpr int SCRATCH_TOTAL = OFF_ATTN + BB*TT*HH*VD;

__device__ float g_scratch[SCRATCH_TOTAL];

// ---------------- tf32 helpers ----------------
__device__ __forceinline__ void split_tf32(float v, float& hi, float& lo) {
    uint32_t h;
    asm("cvt.rna.tf32.f32 %0, %1;" : "=r"(h) : "f"(v));
    float hf = __uint_as_float(h);
    float lf = v - hf;
    uint32_t l;
    asm("cvt.rna.tf32.f32 %0, %1;" : "=r"(l) : "f"(lf));
    hi = hf;
    lo = __uint_as_float(l);
}

__device__ __forceinline__ float to_tf32(float v) {
    uint32_t u;
    asm("cvt.rna.tf32.f32 %0, %1;" : "=r"(u) : "f"(v));
    return __uint_as_float(u);
}

__device__ __forceinline__ void mma_tf32(float* d, const uint32_t* a, const uint32_t* b) {
    asm volatile(
        "mma.sync.aligned.m16n8k8.row.col.f32.tf32.tf32.f32 "
        "{%0,%1,%2,%3}, {%4,%5,%6,%7}, {%8,%9}, {%0,%1,%2,%3};\n"
        : "+f"(d[0]), "+f"(d[1]), "+f"(d[2]), "+f"(d[3])
        : "r"(a[0]), "r"(a[1]), "r"(a[2]), "r"(a[3]), "r"(b[0]), "r"(b[1]));
}

// ---------------- tensor-core GEMM: 128x128 tile, 3-pass tf32, double-buffered ----------
// Requirements: M%128==0, N%128==0, K%16==0.
// dynamic smem: Ah[2][128*20] Al[2][128*20] Bh[2][16*136] Bl[2][16*136] = 75776 B
constexpr int GTC_A = 128 * 20;   // 2560
constexpr int GTC_B = 16 * 136;   // 2176
constexpr int GTC_SMEM = (4 * GTC_A + 4 * GTC_B) * 4;

__global__ void __launch_bounds__(256)
gemm_tc(const float* __restrict__ A, const float* __restrict__ B,
        float* __restrict__ C, int M, int N, int K) {
    extern __shared__ float gsm[];
    float* AhB = gsm;                       // 2 buffers of GTC_A
    float* AlB = gsm + 2 * GTC_A;
    float* BhB = gsm + 4 * GTC_A;           // 2 buffers of GTC_B
    float* BlB = gsm + 4 * GTC_A + 2 * GTC_B;

    int tid = threadIdx.x;
    int warp = tid >> 5, lane = tid & 31;
    int g = lane >> 2, tg = lane & 3;
    int wm = warp >> 2;   // 0..1
    int wn = warp & 3;    // 0..3
    int row0 = blockIdx.y * 128, col0 = blockIdx.x * 128;

    // per-thread staging indices
    int arow = tid >> 1, acol4 = (tid & 1) * 2;          // A: 2 float4 per thread: rows tid>>1, k cols {acol4, acol4+1}*4
    int bk = tid >> 4, bn4 = (tid & 15) * 2;             // B: 2 float4: k rows {bk,bk+8}? -- recompute below

    float d[4][4][4];
#pragma unroll
    for (int mi = 0; mi < 4; mi++)
#pragma unroll
        for (int ni = 0; ni < 4; ni++)
#pragma unroll
            for (int r = 0; r < 4; r++) d[mi][ni][r] = 0.f;

    int nk = K / 16;

    // staging lambda (manual): load k-tile kt into regs
    float4 ra0, ra1, rb0, rb1;
    {
        // A tile: 128 rows x 16 k = 512 float4; thread i -> (row=i>>2, kc=i&3) twice
        int i0 = tid, i1 = tid + 256;
        ra0 = *(const float4*)(A + (row0 + (i0 >> 2)) * K + 0 + (i0 & 3) * 4);
        ra1 = *(const float4*)(A + (row0 + (i1 >> 2)) * K + 0 + (i1 & 3) * 4);
        rb0 = *(const float4*)(B + (0 + (i0 >> 5)) * N + col0 + (i0 & 31) * 4);
        rb1 = *(const float4*)(B + (0 + (i1 >> 5)) * N + col0 + (i1 & 31) * 4);
    }
    // store tile 0 into buffer 0
    {
        float* Ah = AhB; float* Al = AlB; float* Bh = BhB; float* Bl = BlB;
        int i0 = tid, i1 = tid + 256;
        float4 h4, l4;
        split_tf32(ra0.x, h4.x, l4.x); split_tf32(ra0.y, h4.y, l4.y);
        split_tf32(ra0.z, h4.z, l4.z); split_tf32(ra0.w, h4.w, l4.w);
        *(float4*)&Ah[(i0 >> 2) * 20 + (i0 & 3) * 4] = h4;
        *(float4*)&Al[(i0 >> 2) * 20 + (i0 & 3) * 4] = l4;
        split_tf32(ra1.x, h4.x, l4.x); split_tf32(ra1.y, h4.y, l4.y);
        split_tf32(ra1.z, h4.z, l4.z); split_tf32(ra1.w, h4.w, l4.w);
        *(float4*)&Ah[(i1 >> 2) * 20 + (i1 & 3) * 4] = h4;
        *(float4*)&Al[(i1 >> 2) * 20 + (i1 & 3) * 4] = l4;
        split_tf32(rb0.x, h4.x, l4.x); split_tf32(rb0.y, h4.y, l4.y);
        split_tf32(rb0.z, h4.z, l4.z); split_tf32(rb0.w, h4.w, l4.w);
        *(float4*)&Bh[(i0 >> 5) * 136 + (i0 & 31) * 4] = h4;
        *(float4*)&Bl[(i0 >> 5) * 136 + (i0 & 31) * 4] = l4;
        split_tf32(rb1.x, h4.x, l4.x); split_tf32(rb1.y, h4.y, l4.y);
        split_tf32(rb1.z, h4.z, l4.z); split_tf32(rb1.w, h4.w, l4.w);
        *(float4*)&Bh[(i1 >> 5) * 136 + (i1 & 31) * 4] = h4;
        *(float4*)&Bl[(i1 >> 5) * 136 + (i1 & 31) * 4] = l4;
    }
    __syncthreads();

    for (int kt = 0; kt < nk; kt++) {
        int cur = kt & 1;
        bool has_next = (kt + 1 < nk);
        if (has_next) {
            int k0 = (kt + 1) * 16;
            int i0 = tid, i1 = tid + 256;
            ra0 = *(const float4*)(A + (row0 + (i0 >> 2)) * K + k0 + (i0 & 3) * 4);
            ra1 = *(const float4*)(A + (row0 + (i1 >> 2)) * K + k0 + (i1 & 3) * 4);
            rb0 = *(const float4*)(B + (k0 + (i0 >> 5)) * N + col0 + (i0 & 31) * 4);
            rb1 = *(const float4*)(B + (k0 + (i1 >> 5)) * N + col0 + (i1 & 31) * 4);
        }

        float* Ah = AhB + cur * GTC_A;
        float* Al = AlB + cur * GTC_A;
        float* Bh = BhB + cur * GTC_B;
        float* Bl = BlB + cur * GTC_B;

#pragma unroll
        for (int ks = 0; ks < 16; ks += 8) {
            uint32_t ah[4][4], al[4][4], bh[4][2], bl[4][2];
#pragma unroll
            for (int mi = 0; mi < 4; mi++) {
                int r = wm * 64 + mi * 16;
                ah[mi][0] = __float_as_uint(Ah[(r + g) * 20 + ks + tg]);
                ah[mi][1] = __float_as_uint(Ah[(r + 8 + g) * 20 + ks + tg]);
                ah[mi][2] = __float_as_uint(Ah[(r + g) * 20 + ks + tg + 4]);
                ah[mi][3] = __float_as_uint(Ah[(r + 8 + g) * 20 + ks + tg + 4]);
                al[mi][0] = __float_as_uint(Al[(r + g) * 20 + ks + tg]);
                al[mi][1] = __float_as_uint(Al[(r + 8 + g) * 20 + ks + tg]);
                al[mi][2] = __float_as_uint(Al[(r + g) * 20 + ks + tg + 4]);
                al[mi][3] = __float_as_uint(Al[(r + 8 + g) * 20 + ks + tg + 4]);
            }
#pragma unroll
            for (int ni = 0; ni < 4; ni++) {
                int c = wn * 32 + ni * 8 + g;
                bh[ni][0] = __float_as_uint(Bh[(ks + tg) * 136 + c]);
                bh[ni][1] = __float_as_uint(Bh[(ks + tg + 4) * 136 + c]);
                bl[ni][0] = __float_as_uint(Bl[(ks + tg) * 136 + c]);
                bl[ni][1] = __float_as_uint(Bl[(ks + tg + 4) * 136 + c]);
            }
#pragma unroll
            for (int mi = 0; mi < 4; mi++)
#pragma unroll
                for (int ni = 0; ni < 4; ni++) mma_tf32(d[mi][ni], ah[mi], bh[ni]);
#pragma unroll
            for (int mi = 0; mi < 4; mi++)
#pragma unroll
                for (int ni = 0; ni < 4; ni++) mma_tf32(d[mi][ni], ah[mi], bl[ni]);
#pragma unroll
            for (int mi = 0; mi < 4; mi++)
#pragma unroll
                for (int ni = 0; ni < 4; ni++) mma_tf32(d[mi][ni], al[mi], bh[ni]);
        }

        if (has_next) {
            float* nAh = AhB + (cur ^ 1) * GTC_A;
            float* nAl = AlB + (cur ^ 1) * GTC_A;
            float* nBh = BhB + (cur ^ 1) * GTC_B;
            float* nBl = BlB + (cur ^ 1) * GTC_B;
            int i0 = tid, i1 = tid + 256;
            float4 h4, l4;
            split_tf32(ra0.x, h4.x, l4.x); split_tf32(ra0.y, h4.y, l4.y);
            split_tf32(ra0.z, h4.z, l4.z); split_tf32(ra0.w, h4.w, l4.w);
            *(float4*)&nAh[(i0 >> 2) * 20 + (i0 & 3) * 4] = h4;
            *(float4*)&nAl[(i0 >> 2) * 20 + (i0 & 3) * 4] = l4;
            split_tf32(ra1.x, h4.x, l4.x); split_tf32(ra1.y, h4.y, l4.y);
            split_tf32(ra1.z, h4.z, l4.z); split_tf32(ra1.w, h4.w, l4.w);
            *(float4*)&nAh[(i1 >> 2) * 20 + (i1 & 3) * 4] = h4;
            *(float4*)&nAl[(i1 >> 2) * 20 + (i1 & 3) * 4] = l4;
            split_tf32(rb0.x, h4.x, l4.x); split_tf32(rb0.y, h4.y, l4.y);
            split_tf32(rb0.z, h4.z, l4.z); split_tf32(rb0.w, h4.w, l4.w);
            *(float4*)&nBh[(i0 >> 5) * 136 + (i0 & 31) * 4] = h4;
            *(float4*)&nBl[(i0 >> 5) * 136 + (i0 & 31) * 4] = l4;
            split_tf32(rb1.x, h4.x, l4.x); split_tf32(rb1.y, h4.y, l4.y);
            split_tf32(rb1.z, h4.z, l4.z); split_tf32(rb1.w, h4.w, l4.w);
            *(float4*)&nBh[(i1 >> 5) * 136 + (i1 & 31) * 4] = h4;
            *(float4*)&nBl[(i1 >> 5) * 136 + (i1 & 31) * 4] = l4;
            __syncthreads();
        }
    }

    // epilogue
#pragma unroll
    for (int mi = 0; mi < 4; mi++) {
#pragma unroll
        for (int ni = 0; ni < 4; ni++) {
            int r = row0 + wm * 64 + mi * 16 + g;
            int c = col0 + wn * 32 + ni * 8 + 2 * tg;
            *(float2*)(C + r * N + c) = make_float2(d[mi][ni][0], d[mi][ni][1]);
            *(float2*)(C + (r + 8) * N + c) = make_float2(d[mi][ni][2], d[mi][ni][3]);
        }
    }
}

// ---------------- GEMM 64x64 tile (small-N cases) ----------------
__global__ void gemm64(const float* __restrict__ A, const float* __restrict__ B,
                       float* __restrict__ C, int M, int N, int K) {
    __shared__ float As[16][64];
    __shared__ float Bs[16][64];
    int tid = threadIdx.x;
    int tx = tid & 15, ty = tid >> 4;
    int col0 = blockIdx.x * 64, row0 = blockIdx.y * 64;

    float acc[4][4];
#pragma unroll
    for (int r = 0; r < 4; r++)
#pragma unroll
        for (int c = 0; c < 4; c++) acc[r][c] = 0.f;

    for (int k0 = 0; k0 < K; k0 += 16) {
        {
            int i = tid * 4;
            int m = i >> 4;
            int kk = i & 15;
            float4 av = *(const float4*)(A + (row0 + m) * K + k0 + kk);
            As[kk + 0][m] = av.x; As[kk + 1][m] = av.y;
            As[kk + 2][m] = av.z; As[kk + 3][m] = av.w;
        }
        {
            int i = tid * 4;
            int kk = i >> 6;
            int n = i & 63;
            int gc = col0 + n;
            float4 bv = make_float4(0.f, 0.f, 0.f, 0.f);
            if (gc < N) bv = *(const float4*)(B + (k0 + kk) * N + gc);
            *(float4*)&Bs[kk][n] = bv;
        }
        __syncthreads();
#pragma unroll
        for (int kk = 0; kk < 16; kk++) {
            float4 a4 = *(const float4*)&As[kk][ty * 4];
            float4 b4 = *(const float4*)&Bs[kk][tx * 4];
            float av[4] = {a4.x, a4.y, a4.z, a4.w};
            float bv[4] = {b4.x, b4.y, b4.z, b4.w};
#pragma unroll
            for (int r = 0; r < 4; r++)
#pragma unroll
                for (int c = 0; c < 4; c++) acc[r][c] += av[r] * bv[c];
        }
        __syncthreads();
    }
#pragma unroll
    for (int r = 0; r < 4; r++) {
        int gr = row0 + ty * 4 + r;
#pragma unroll
        for (int c = 0; c < 4; c++) {
            int gc = col0 + tx * 4 + c;
            if (gc < N) C[gr * N + gc] = acc[r][c];
        }
    }
}

// ---------------- GEMM 128x64 tile (fp32 fallback for small GEMMs) ----------------
__global__ void gemm128(const float* __restrict__ A, const float* __restrict__ B,
                        float* __restrict__ C, int M, int N, int K) {
    __shared__ float As[16][128];
    __shared__ float Bs[16][64];
    int tid = threadIdx.x;
    int tx = tid & 15, ty = tid >> 4;
    int col0 = blockIdx.x * 64, row0 = blockIdx.y * 128;

    float acc[8][4];
#pragma unroll
    for (int r = 0; r < 8; r++)
#pragma unroll
        for (int c = 0; c < 4; c++) acc[r][c] = 0.f;

    for (int k0 = 0; k0 < K; k0 += 16) {
#pragma unroll
        for (int half = 0; half < 2; half++) {
            int i = tid * 4 + half * 1024;
            int m = i >> 4;
            int kk = i & 15;
            float4 av = *(const float4*)(A + (row0 + m) * K + k0 + kk);
            As[kk + 0][m] = av.x; As[kk + 1][m] = av.y;
            As[kk + 2][m] = av.z; As[kk + 3][m] = av.w;
        }
        {
            int i = tid * 4;
            int kk = i >> 6;
            int n = i & 63;
            float4 bv = *(const float4*)(B + (k0 + kk) * N + col0 + n);
            *(float4*)&Bs[kk][n] = bv;
        }
        __syncthreads();
#pragma unroll
        for (int kk = 0; kk < 16; kk++) {
            float4 a0 = *(const float4*)&As[kk][ty * 8];
            float4 a1 = *(const float4*)&As[kk][ty * 8 + 4];
            float4 b4 = *(const float4*)&Bs[kk][tx * 4];
            float av[8] = {a0.x, a0.y, a0.z, a0.w, a1.x, a1.y, a1.z, a1.w};
            float bv[4] = {b4.x, b4.y, b4.z, b4.w};
#pragma unroll
            for (int r = 0; r < 8; r++)
#pragma unroll
                for (int c = 0; c < 4; c++) acc[r][c] += av[r] * bv[c];
        }
        __syncthreads();
    }
#pragma unroll
    for (int r = 0; r < 8; r++) {
        int gr = row0 + ty * 8 + r;
        float4 o = make_float4(acc[r][0], acc[r][1], acc[r][2], acc[r][3]);
        *(float4*)(C + gr * N + col0 + tx * 4) = o;
    }
}

// ---------------- RMS norm ----------------
__global__ void rms_kernel(float* __restrict__ data, const float* __restrict__ g, int N) {
    int row = blockIdx.x, tid = threadIdx.x;
    __shared__ float s4[4];
    float v = (tid < N) ? data[row * N + tid] : 0.f;
    float sq = v * v;
#pragma unroll
    for (int o = 16; o > 0; o >>= 1) sq += __shfl_xor_sync(0xffffffffu, sq, o);
    if ((tid & 31) == 0) s4[tid >> 5] = sq;
    __syncthreads();
    float tot = s4[0] + s4[1] + s4[2] + s4[3];
    float sc = rsqrtf(tot / (float)N + 1e-6f);
    if (tid < N) data[row * N + tid] = v * sc * g[tid];
}

// ---------------- xmean over T ----------------
__global__ void xmean_kernel(const float* __restrict__ x, float* __restrict__ xmean) {
    int c = blockIdx.x * 256 + threadIdx.x;
    int b = blockIdx.y;
    float s = 0.f;
    for (int t = 0; t < TT; t++) s += x[(b * TT + t) * CC + c];
    xmean[b * CC + c] = s * (1.f / (float)TT);
}

// ---------------- gate ----------------
__global__ void gate_kernel(const float* __restrict__ xmean, const float* __restrict__ wg,
                            float* __restrict__ gate) {
    int b = blockIdx.x, tid = threadIdx.x;
    __shared__ float sg[3];
    if (tid < 3) {
        float s = 0.f;
        for (int c = 0; c < CC; c++) s += xmean[b * CC + c] * wg[c * 3 + tid];
        sg[tid] = s;
    }
    __syncthreads();
    if (tid == 0) {
        float m = fmaxf(sg[0], fmaxf(sg[1], sg[2]));
        float e0 = expf(sg[0] - m), e1 = expf(sg[1] - m), e2 = expf(sg[2] - m);
        float inv = 1.f / (e0 + e1 + e2);
        gate[b * 4 + 0] = e0 * inv;
        gate[b * 4 + 1] = e1 * inv;
        gate[b * 4 + 2] = e2 * inv;
    }
}

// ---------------- importance scores ----------------
__global__ void scores_kernel(const float* __restrict__ x, const float* __restrict__ w,
                              float* __restrict__ out) {
    int row = blockIdx.x, tid = threadIdx.x;
    __shared__ float s8[8];
    float s = 0.f;
    for (int c = tid; c < CC; c += 256) s += x[row * CC + c] * w[c];
#pragma unroll
    for (int o = 16; o > 0; o >>= 1) s += __shfl_xor_sync(0xffffffffu, s, o);
    if ((tid & 31) == 0) s8[tid >> 5] = s;
    __syncthreads();
    if (tid == 0) {
        float t = 0.f;
#pragma unroll
        for (int i = 0; i < 8; i++) t += s8[i];
        out[row] = t;
    }
}

// ---------------- top-k(256) ----------------
__global__ void topk_kernel(const float* __restrict__ scores, int* __restrict__ idxout) {
    __shared__ float sv[1024];
    __shared__ int si[1024];
    __shared__ int ti[256];
    int b = blockIdx.x, tid = threadIdx.x;
    sv[tid] = scores[b * TT + tid];
    si[tid] = tid;
    __syncthreads();
    for (int k = 2; k <= 1024; k <<= 1) {
        for (int j = k >> 1; j > 0; j >>= 1) {
            int ixj = tid ^ j;
            if (ixj > tid) {
                bool desc = ((tid & k) == 0);
                float va = sv[tid], vb = sv[ixj];
                int ia = si[tid], ib = si[ixj];
                bool agtb = (va > vb) || (va == vb && ia < ib);
                if (desc ? !agtb : agtb) {
                    sv[tid] = vb; sv[ixj] = va;
                    si[tid] = ib; si[ixj] = ia;
                }
            }
            __syncthreads();
        }
    }
    if (tid < 256) ti[tid] = si[tid];
    __syncthreads();
    for (int k = 2; k <= 256; k <<= 1) {
        for (int j = k >> 1; j > 0; j >>= 1) {
            int ixj = tid ^ j;
            if (tid < 256 && ixj > tid) {
                bool asc = ((tid & k) == 0);
                int ia = ti[tid], ib = ti[ixj];
                if (asc ? (ia > ib) : (ia < ib)) { ti[tid] = ib; ti[ixj] = ia; }
            }
            __syncthreads();
        }
    }
    if (tid < 256) idxout[b * KEEP_ + tid] = ti[tid];
}

// ---------------- gather ----------------
__global__ void gather_kernel(const float* __restrict__ x, const int* __restrict__ idx,
                              float* __restrict__ selx) {
    int row = blockIdx.x;
    int b = row >> 8;
    int t = idx[row];
    for (int c = threadIdx.x; c < CC; c += 256)
        selx[row * CC + c] = x[(b * TT + t) * CC + c];
}

// ---------------- assembles (rope + layout) ----------------
__global__ void assemble_q_kernel(const float* __restrict__ qnope, const float* __restrict__ qrope,
                                  float* __restrict__ Q) {
    int row = blockIdx.x;
    int b = row >> 10, t = row & 1023;
    int j = threadIdx.x;
    int h = j >> 5, d = j & 31;
    int qb = (((b * HH + h) * TT) + t) * DQK;
    Q[qb + d] = qnope[row * 512 + j];
    float x1 = qrope[row * 1024 + h * RD + d];
    float x2 = qrope[row * 1024 + h * RD + RP + d];
    float f = expf(-LOG1E4_OVER_32 * (float)d);
    float sn, cs;
    sincosf((float)t * f, &sn, &cs);
    Q[qb + NOPE_ + d] = x1 * cs - x2 * sn;
    Q[qb + NOPE_ + RP + d] = x1 * sn + x2 * cs;
}

__global__ void assemble_k1v1_kernel(const float* __restrict__ knope, const float* __restrict__ v1raw,
                                     const float* __restrict__ kroperaw,
                                     float* __restrict__ K, float* __restrict__ V) {
    int row = blockIdx.x;
    int b = row >> 10, t = row & 1023;
    int j = threadIdx.x;
    int h = j >> 5, d = j & 31;
    int kb = (((b * HH + h) * TT) + t) * DQK;
    K[kb + d] = knope[row * 512 + j];
    float x1 = kroperaw[row * RD + d] * 0.0625f;
    float x2 = kroperaw[row * RD + RP + d] * 0.0625f;
    float f = expf(-LOG1E4_OVER_32 * (float)d);
    float sn, cs;
    sincosf((float)t * f, &sn, &cs);
    K[kb + NOPE_ + d] = x1 * cs - x2 * sn;
    K[kb + NOPE_ + RP + d] = x1 * sn + x2 * cs;
    V[(((b * HH + h) * TT) + t) * VD + d] = v1raw[row * 512 + j];
}

__global__ void assemble_kv_kernel(const float* __restrict__ kraw, const float* __restrict__ vraw,
                                   float* __restrict__ K, float* __restrict__ V, int S) {
    int row = blockIdx.x;
    int b = row / S, pos = row % S;
    int j = threadIdx.x;
    int h = j >> 5, d = j & 31;
    float nope = kraw[row * 1536 + h * DQK + d];
    float x1 = kraw[row * 1536 + h * DQK + NOPE_ + d];
    float x2 = kraw[row * 1536 + h * DQK + NOPE_ + RP + d];
    float f = expf(-LOG1E4_OVER_32 * (float)d);
    float sn, cs;
    sincosf((float)pos * f, &sn, &cs);
    int kb = (((b * HH + h) * S) + pos) * DQK;
    K[kb + d] = nope;
    K[kb + NOPE_ + d] = x1 * cs - x2 * sn;
    K[kb + NOPE_ + RP + d] = x1 * sn + x2 * cs;
    V[(((b * HH + h) * S) + pos) * VD + d] = vraw[row * 512 + h * VD + d];
}

// ---------------- tf32 MMA flash attention ----------------
// 128 queries per block, 64-key chunks, 8 warps each owning 16 query rows.
// smem: Qs[128][100] | Ks[96][72] (d-major) | Vs[64][40] | Ps[8][16][68]
constexpr int QS_STR = 100;
constexpr int KS_STR = 72;
constexpr int VS_STR = 40;
constexpr int PS_STR = 68;
constexpr int ASM_QS = 0;
constexpr int ASM_KS = 128 * QS_STR;            // 12800
constexpr int ASM_VS = ASM_KS + 96 * KS_STR;    // 19712
constexpr int ASM_PS = ASM_VS + 64 * VS_STR;    // 22272
constexpr int ATTN_SMEM = (ASM_PS + 8 * 16 * PS_STR) * 4;  // 123904 B

__global__ void __launch_bounds__(256)
attn_mma(const float* __restrict__ Q,
         const float* __restrict__ K1, const float* __restrict__ V1,
         const float* __restrict__ KS, const float* __restrict__ VS,
         const float* __restrict__ KW, const float* __restrict__ VW,
         const float* __restrict__ gate, float* __restrict__ outp) {
    extern __shared__ float sm[];
    float* Qs = sm + ASM_QS;
    float* Ks = sm + ASM_KS;
    float* Vs = sm + ASM_VS;

    int tid = threadIdx.x;
    int w = tid >> 5, lane = tid & 31;
    int g = lane >> 2, tg = lane & 3;
    float* Ps = sm + ASM_PS + w * 16 * PS_STR;

    int tile = 7 - blockIdx.x;         // heavy tiles first
    int h = blockIdx.y, b = blockIdx.z;
    int q0 = tile * 128;
    int bh = b * HH + h;
    int rowg = q0 + 16 * w + g;        // this thread's first query row

    // stage Q (tf32-rounded), layout Qs[q][d]
    const float* Qp = Q + (bh * TT + q0) * DQK;
    for (int i = tid; i < 128 * 24; i += 256) {
        int q = i / 24, dq = i % 24;
        float4 v = *(const float4*)(Qp + q * DQK + dq * 4);
        v.x = to_tf32(v.x); v.y = to_tf32(v.y);
        v.z = to_tf32(v.z); v.w = to_tf32(v.w);
        *(float4*)&Qs[q * QS_STR + dq * 4] = v;
    }

    float g_b[3];
    g_b[0] = gate[b * 4 + 0];
    g_b[1] = gate[b * 4 + 1];
    g_b[2] = gate[b * 4 + 2];

    float fout[4][4];
#pragma unroll
    for (int nv = 0; nv < 4; nv++)
#pragma unroll
        for (int r = 0; r < 4; r++) fout[nv][r] = 0.f;

    for (int br = 0; br < 3; br++) {
        const float* Kp;
        const float* Vp;
        int nchunk;
        bool causal;
        if (br == 0)      { Kp = K1 + bh * TT * DQK;    Vp = V1 + bh * TT * VD;    nchunk = 2 * (tile + 1); causal = true; }
        else if (br == 1) { Kp = KS + bh * KEEP_ * DQK; Vp = VS + bh * KEEP_ * VD; nchunk = 4;              causal = false; }
        else              { Kp = KW + bh * TT * DQK;    Vp = VW + bh * TT * VD;    nchunk = 2 * (tile + 1); causal = true; }

        float m0 = -1e30f, m1 = -1e30f, l0 = 0.f, l1 = 0.f;
        float acc[4][4];
#pragma unroll
        for (int nv = 0; nv < 4; nv++)
#pragma unroll
            for (int r = 0; r < 4; r++) acc[nv][r] = 0.f;

        for (int c = 0; c < nchunk; c++) {
            int k0 = c * 64;
            __syncthreads();   // prior chunk done with Ks/Vs (and Qs staged on first pass)

            // stage K chunk transposed: Ks[d][key], tf32
            for (int i = tid; i < 64 * 24; i += 256) {
                int key = i / 24, dq = i % 24;
                float4 v = *(const float4*)(Kp + (k0 + key) * DQK + dq * 4);
                Ks[(dq * 4 + 0) * KS_STR + key] = to_tf32(v.x);
                Ks[(dq * 4 + 1) * KS_STR + key] = to_tf32(v.y);
                Ks[(dq * 4 + 2) * KS_STR + key] = to_tf32(v.z);
                Ks[(dq * 4 + 3) * KS_STR + key] = to_tf32(v.w);
            }
            // stage V chunk: Vs[key][vd], tf32
            for (int i = tid; i < 64 * 8; i += 256) {
                int key = i >> 3, dq = i & 7;
                float4 v = *(const float4*)(Vp + (k0 + key) * VD + dq * 4);
                v.x = to_tf32(v.x); v.y = to_tf32(v.y);
                v.z = to_tf32(v.z); v.w = to_tf32(v.w);
                *(float4*)&Vs[key * VS_STR + dq * 4] = v;
            }
            __syncthreads();

            // S = Q @ K^T : per warp 16x64, fragments s[8][4]
            float s[8][4];
#pragma unroll
            for (int ni = 0; ni < 8; ni++)
#pragma unroll
                for (int r = 0; r < 4; r++) s[ni][r] = 0.f;

#pragma unroll
            for (int ks = 0; ks < 12; ks++) {
                int kb = ks * 8;
                const float* q0p = &Qs[(16 * w + g) * QS_STR + kb];
                const float* q1p = q0p + 8 * QS_STR;
                uint32_t Af[4];
                Af[0] = __float_as_uint(q0p[tg]);
                Af[1] = __float_as_uint(q1p[tg]);
                Af[2] = __float_as_uint(q0p[tg + 4]);
                Af[3] = __float_as_uint(q1p[tg + 4]);
#pragma unroll
                for (int ni = 0; ni < 8; ni++) {
                    uint32_t Bf[2];
                    Bf[0] = __float_as_uint(Ks[(kb + tg) * KS_STR + 8 * ni + g]);
                    Bf[1] = __float_as_uint(Ks[(kb + tg + 4) * KS_STR + 8 * ni + g]);
                    mma_tf32(s[ni], Af, Bf);
                }
            }

            // causal mask (only the two diagonal chunks need it)
            if (causal && (k0 + 64 > q0)) {
#pragma unroll
                for (int ni = 0; ni < 8; ni++) {
                    int key = k0 + 8 * ni + 2 * tg;
                    if (key > rowg)         s[ni][0] = -1e30f;
                    if (key + 1 > rowg)     s[ni][1] = -1e30f;
                    if (key > rowg + 8)     s[ni][2] = -1e30f;
                    if (key + 1 > rowg + 8) s[ni][3] = -1e30f;
                }
            }

            // row max (rows g and g+8), across regs then quad shuffles
            float cm0 = -1e30f, cm1 = -1e30f;
#pragma unroll
            for (int ni = 0; ni < 8; ni++) {
                cm0 = fmaxf(cm0, fmaxf(s[ni][0], s[ni][1]));
                cm1 = fmaxf(cm1, fmaxf(s[ni][2], s[ni][3]));
            }
            cm0 = fmaxf(cm0, __shfl_xor_sync(0xffffffffu, cm0, 1));
            cm0 = fmaxf(cm0, __shfl_xor_sync(0xffffffffu, cm0, 2));
            cm1 = fmaxf(cm1, __shfl_xor_sync(0xffffffffu, cm1, 1));
            cm1 = fmaxf(cm1, __shfl_xor_sync(0xffffffffu, cm1, 2));

            float nm0 = fmaxf(m0, cm0), nm1 = fmaxf(m1, cm1);
            float al0 = __expf((m0 - nm0) * ATTN_SCALE);
            float al1 = __expf((m1 - nm1) * ATTN_SCALE);
            m0 = nm0; m1 = nm1;

            float sum0 = 0.f, sum1 = 0.f;
#pragma unroll
            for (int ni = 0; ni < 8; ni++) {
                s[ni][0] = __expf((s[ni][0] - m0) * ATTN_SCALE);
                s[ni][1] = __expf((s[ni][1] - m0) * ATTN_SCALE);
                s[ni][2] = __expf((s[ni][2] - m1) * ATTN_SCALE);
                s[ni][3] = __expf((s[ni][3] - m1) * ATTN_SCALE);
                sum0 += s[ni][0] + s[ni][1];
                sum1 += s[ni][2] + s[ni][3];
            }
            sum0 += __shfl_xor_sync(0xffffffffu, sum0, 1);
            sum0 += __shfl_xor_sync(0xffffffffu, sum0, 2);
            sum1 += __shfl_xor_sync(0xffffffffu, sum1, 1);
            sum1 += __shfl_xor_sync(0xffffffffu, sum1, 2);
            l0 = l0 * al0 + sum0;
            l1 = l1 * al1 + sum1;

#pragma unroll
            for (int nv = 0; nv < 4; nv++) {
                acc[nv][0] *= al0; acc[nv][1] *= al0;
                acc[nv][2] *= al1; acc[nv][3] *= al1;
            }

            // write P (tf32) into warp-private pane, A-fragment layout [16][64]
            __syncwarp();
#pragma unroll
            for (int ni = 0; ni < 8; ni++) {
                *(float2*)&Ps[g * PS_STR + 8 * ni + 2 * tg] =
                    make_float2(to_tf32(s[ni][0]), to_tf32(s[ni][1]));
                *(float2*)&Ps[(g + 8) * PS_STR + 8 * ni + 2 * tg] =
                    make_float2(to_tf32(s[ni][2]), to_tf32(s[ni][3]));
            }
            __syncwarp();

            // PV: D(16x32) += P(16x64) @ V(64x32)
#pragma unroll
            for (int ks = 0; ks < 8; ks++) {
                int kb = ks * 8;
                uint32_t Af[4];
                Af[0] = __float_as_uint(Ps[g * PS_STR + kb + tg]);
                Af[1] = __float_as_uint(Ps[(g + 8) * PS_STR + kb + tg]);
                Af[2] = __float_as_uint(Ps[g * PS_STR + kb + tg + 4]);
                Af[3] = __float_as_uint(Ps[(g + 8) * PS_STR + kb + tg + 4]);
#pragma unroll
                for (int nv = 0; nv < 4; nv++) {
                    uint32_t Bf[2];
                    Bf[0] = __float_as_uint(Vs[(kb + tg) * VS_STR + 8 * nv + g]);
                    Bf[1] = __float_as_uint(Vs[(kb + tg + 4) * VS_STR + 8 * nv + g]);
                    mma_tf32(acc[nv], Af, Bf);
                }
            }
        }

        float gb = g_b[br];
        float inv0 = gb / l0, inv1 = gb / l1;
#pragma unroll
        for (int nv = 0; nv < 4; nv++) {
            fout[nv][0] += acc[nv][0] * inv0;
            fout[nv][1] += acc[nv][1] * inv0;
            fout[nv][2] += acc[nv][2] * inv1;
            fout[nv][3] += acc[nv][3] * inv1;
        }
    }

    // write output [b, t, h*32+d]
#pragma unroll
    for (int nv = 0; nv < 4; nv++) {
        int col = h * VD + 8 * nv + 2 * tg;
        *(float2*)(outp + (b * TT + rowg) * (HH * VD) + col) =
            make_float2(fout[nv][0], fout[nv][1]);
        *(float2*)(outp + (b * TT + rowg + 8) * (HH * VD) + col) =
            make_float2(fout[nv][2], fout[nv][3]);
    }
}

// ---------------- launcher ----------------
extern "C" void kernel_launch(void* const* d_in, const int* in_sizes, int n_in,
                              void* d_out, int out_size) {
    const float* x         = (const float*)d_in[0];
    const float* w_cq      = (const float*)d_in[1];
    const float* g_qnorm   = (const float*)d_in[2];
    const float* w_dq_nope = (const float*)d_in[3];
    const float* w_dq_rope = (const float*)d_in[4];
    const float* w_ckv     = (const float*)d_in[5];
    const float* g_kvnorm  = (const float*)d_in[6];
    const float* w_dk_nope = (const float*)d_in[7];
    const float* w_dv      = (const float*)d_in[8];
    const float* w_krope   = (const float*)d_in[9];
    const float* w_imp     = (const float*)d_in[10];
    const float* w_selk    = (const float*)d_in[11];
    const float* w_selv    = (const float*)d_in[12];
    const float* w_wink    = (const float*)d_in[13];
    const float* w_winv    = (const float*)d_in[14];
    const float* w_gate    = (const float*)d_in[15];
    const float* w_proj    = (const float*)d_in[16];
    float* out = (float*)d_out;

    float* base = nullptr;
    cudaGetSymbolAddress((void**)&base, g_scratch);

    float* nq     = base + OFF_NQ;
    float* ckv    = base + OFF_CKV;
    float* qnope  = base + OFF_QNOPE;
    float* qrope  = base + OFF_QROPE;
    float* knope  = base + OFF_KNOPE;
    float* v1raw  = base + OFF_V1RAW;
    float* krope  = base + OFF_KROPE;
    float* kwraw  = base + OFF_KWRAW;
    float* vwraw  = base + OFF_VWRAW;
    float* selx   = base + OFF_SELX;
    float* ksraw  = base + OFF_KSRAW;
    float* vsraw  = base + OFF_VSRAW;
    float* xmean  = base + OFF_XMEAN;
    float* gate   = base + OFF_GATE;
    float* scores = base + OFF_SCORES;
    int*   idx    = (int*)(base + OFF_IDX);
    float* Qb     = base + OFF_Q;
    float* K1b    = base + OFF_K1;
    float* V1b    = base + OFF_V1;
    float* KWb    = base + OFF_KW;
    float* VWb    = base + OFF_VW;
    float* KSb    = base + OFF_KS;
    float* VSb    = base + OFF_VS;
    float* attnb  = base + OFF_ATTN;

    const int M = BB * TT;  // 2048
    cudaFuncSetAttribute(gemm_tc, cudaFuncAttributeMaxDynamicSharedMemorySize, GTC_SMEM);
    cudaFuncSetAttribute(attn_mma, cudaFuncAttributeMaxDynamicSharedMemorySize, ATTN_SMEM);

    // Q path
    gemm64<<<dim3(2, M / 64), 256>>>(x, w_cq, nq, M, QL, CC);
    rms_kernel<<<M, 128>>>(nq, g_qnorm, QL);
    gemm_tc<<<dim3(4, M / 128), 256, GTC_SMEM>>>(nq, w_dq_nope, qnope, M, 512, QL);
    gemm_tc<<<dim3(8, M / 128), 256, GTC_SMEM>>>(nq, w_dq_rope, qrope, M, 1024, QL);

    // KV path
    gemm64<<<dim3(1, M / 64), 256>>>(x, w_ckv, ckv, M, KVL, CC);
    rms_kernel<<<M, 128>>>(ckv, g_kvnorm, KVL);
    gemm128<<<dim3(8, M / 128), 256>>>(ckv, w_dk_nope, knope, M, 512, KVL);
    gemm128<<<dim3(8, M / 128), 256>>>(ckv, w_dv, v1raw, M, 512, KVL);
    gemm128<<<dim3(1, M / 128), 256>>>(x, w_krope, krope, M, RD, CC);

    // window K/V (tensor cores)
    gemm_tc<<<dim3(12, M / 128), 256, GTC_SMEM>>>(x, w_wink, kwraw, M, 1536, CC);
    gemm_tc<<<dim3(4, M / 128), 256, GTC_SMEM>>>(x, w_winv, vwraw, M, 512, CC);

    // gate
    xmean_kernel<<<dim3(4, BB), 256>>>(x, xmean);
    gate_kernel<<<BB, 32>>>(xmean, w_gate, gate);

    // selection
    scores_kernel<<<M, 256>>>(x, w_imp, scores);
    topk_kernel<<<BB, 1024>>>(scores, idx);
    gather_kernel<<<BB * KEEP_, 256>>>(x, idx, selx);
    gemm_tc<<<dim3(12, (BB * KEEP_) / 128), 256, GTC_SMEM>>>(selx, w_selk, ksraw, BB * KEEP_, 1536, CC);
    gemm_tc<<<dim3(4, (BB * KEEP_) / 128), 256, GTC_SMEM>>>(selx, w_selv, vsraw, BB * KEEP_, 512, CC);

    // assemble (rope + layout)
    assemble_q_kernel<<<M, 512>>>(qnope, qrope, Qb);
    assemble_k1v1_kernel<<<M, 512>>>(knope, v1raw, krope, K1b, V1b);
    assemble_kv_kernel<<<BB * KEEP_, 512>>>(ksraw, vsraw, KSb, VSb, KEEP_);
    assemble_kv_kernel<<<M, 512>>>(kwraw, vwraw, KWb, VWb, TT);

    // tf32 mma flash attention (3 branches + gate fused)
    attn_mma<<<dim3(8, HH, BB), 256, ATTN_SMEM>>>(Qb, K1b, V1b, KSb, VSb, KWb, VWb, gate, attnb);

    // output projection (tensor cores)
    gemm_tc<<<dim3(8, M / 128), 256, GTC_SMEM>>>(attnb, w_proj, out, M, CC, 512);
}

// round 5
// speedup vs baseline: 5.1123x; 1.2745x over previous
#include <cuda_runtime.h>
#include <math.h>
#include <stdint.h>

// ---------------- problem constants ----------------
#define BB 2
#define TT 1024
#define CC 1024
#define HH 16
#define VD 32
#define NOPE_ 32
#define RP 32
#define RD 64
#define DQK 96
#define KEEP_ 256
#define QL 96
#define KVL 32

#define LOG1E4_OVER_32 0.28782313662425572f   // ln(10000)/32
#define ATTN_SCALE 0.10206207261596577f       // 1/sqrt(96)

// ---------------- scratch ----------------
constexpr int OFF_WC1    = 0;                          // [1024][256]
constexpr int OFF_WC2    = OFF_WC1    + 1024*256;      // [96][1536]
constexpr int OFF_WC3    = OFF_WC2    + 96*1536;       // [32][1024]
constexpr int OFF_WSEL   = OFF_WC3    + 32*1024;       // [1024][2048]
constexpr int OFF_WWIN   = OFF_WSEL   + 1024*2048;     // [1024][2048]
constexpr int OFF_F0     = OFF_WWIN   + 1024*2048;     // [2048][256]  nq|ckv|krope|pad
constexpr int OFF_QOUT   = OFF_F0     + 2048*256;      // [2048][1536] qnope|qrope
constexpr int OFF_KVOUT  = OFF_QOUT   + 2048*1536;     // [2048][1024] knope|v1
constexpr int OFF_WINOUT = OFF_KVOUT  + 2048*1024;     // [2048][2048] kw|vw
constexpr int OFF_SELX   = OFF_WINOUT + 2048*2048;     // [512][1024]
constexpr int OFF_SELKV  = OFF_SELX   + 512*1024;      // [512][2048]  ks|vs
constexpr int OFF_XMEAN  = OFF_SELKV  + 512*2048;
constexpr int OFF_GATE   = OFF_XMEAN  + BB*CC;
constexpr int OFF_SCORES = OFF_GATE   + 8;
constexpr int OFF_IDX    = OFF_SCORES + BB*TT;
constexpr int OFF_Q      = OFF_IDX    + BB*KEEP_;
constexpr int OFF_K1     = OFF_Q      + BB*HH*TT*DQK;
constexpr int OFF_V1     = OFF_K1     + BB*HH*TT*DQK;
constexpr int OFF_KW     = OFF_V1     + BB*HH*TT*VD;
constexpr int OFF_VW     = OFF_KW     + BB*HH*TT*DQK;
constexpr int OFF_KS     = OFF_VW     + BB*HH*TT*VD;
constexpr int OFF_VS     = OFF_KS     + BB*HH*KEEP_*DQK;
constexpr int OFF_ATTN   = OFF_VS     + BB*HH*KEEP_*VD;
constexpr int SCRATCH_TOTAL = OFF_ATTN + BB*TT*HH*VD;

__device__ __align__(256) float g_scratch[SCRATCH_TOTAL];

// ---------------- tf32 helpers ----------------
__device__ __forceinline__ float to_tf32(float v) {
    uint32_t u;
    asm("cvt.rna.tf32.f32 %0, %1;" : "=r"(u) : "f"(v));
    return __uint_as_float(u);
}

__device__ __forceinline__ void split_tf32(float v, uint32_t& hi, uint32_t& lo) {
    asm("cvt.rna.tf32.f32 %0, %1;" : "=r"(hi) : "f"(v));
    float lf = v - __uint_as_float(hi);
    asm("cvt.rna.tf32.f32 %0, %1;" : "=r"(lo) : "f"(lf));
}

__device__ __forceinline__ void mma_tf32(float* d, const uint32_t* a, const uint32_t* b) {
    asm volatile(
        "mma.sync.aligned.m16n8k8.row.col.f32.tf32.tf32.f32 "
        "{%0,%1,%2,%3}, {%4,%5,%6,%7}, {%8,%9}, {%0,%1,%2,%3};\n"
        : "+f"(d[0]), "+f"(d[1]), "+f"(d[2]), "+f"(d[3])
        : "r"(a[0]), "r"(a[1]), "r"(a[2]), "r"(a[3]), "r"(b[0]), "r"(b[1]));
}

__device__ __forceinline__ void cp16(uint32_t dst, const float* src) {
    asm volatile("cp.async.cg.shared.global [%0], [%1], 16;" :: "r"(dst), "l"(src));
}
#define CP_COMMIT() asm volatile("cp.async.commit_group;")
#define CP_WAIT_ALL() asm volatile("cp.async.wait_group 0;")

// ---------------- gemm_tc2: 128x128 tile, cp.async 2-stage, split-on-consume ----------
// Requirements: M%128==0, N%128==0, K%16==0.
constexpr int G2_A = 128 * 20;   // floats per A buffer
constexpr int G2_B = 16 * 136;   // floats per B buffer
constexpr int G2_SMEM = (2 * G2_A + 2 * G2_B) * 4;   // 37888 B

__global__ void __launch_bounds__(256, 2)
gemm_tc2(const float* __restrict__ A, int lda,
         const float* __restrict__ B, int ldb,
         float* __restrict__ C, int ldc,
         int M, int N, int K) {
    extern __shared__ float sm2[];
    float* As = sm2;               // 2 x G2_A
    float* Bs = sm2 + 2 * G2_A;    // 2 x G2_B

    int tid = threadIdx.x;
    int warp = tid >> 5, lane = tid & 31;
    int g = lane >> 2, tg = lane & 3;
    int wm = warp >> 2, wn = warp & 3;
    int row0 = blockIdx.y * 128, col0 = blockIdx.x * 128;

    uint32_t as_addr = (uint32_t)__cvta_generic_to_shared(As);
    uint32_t bs_addr = (uint32_t)__cvta_generic_to_shared(Bs);

    // copy-index precompute (2 float4 for A, 2 for B per thread per tile)
    const float* Ag0 = A + (size_t)(row0 + (tid >> 2)) * lda + (tid & 3) * 4;
    const float* Ag1 = A + (size_t)(row0 + 64 + (tid >> 2)) * lda + (tid & 3) * 4;
    const float* Bg0 = B + (size_t)(tid >> 5) * ldb + col0 + (tid & 31) * 4;
    const float* Bg1 = B + (size_t)(8 + (tid >> 5)) * ldb + col0 + (tid & 31) * 4;
    uint32_t offA0 = (((tid >> 2)) * 20 + (tid & 3) * 4) * 4;
    uint32_t offA1 = (((tid >> 2) + 64) * 20 + (tid & 3) * 4) * 4;
    uint32_t offB0 = ((tid >> 5) * 136 + (tid & 31) * 4) * 4;
    uint32_t offB1 = ((8 + (tid >> 5)) * 136 + (tid & 31) * 4) * 4;

    float d[4][4][4];
#pragma unroll
    for (int mi = 0; mi < 4; mi++)
#pragma unroll
        for (int ni = 0; ni < 4; ni++)
#pragma unroll
            for (int r = 0; r < 4; r++) d[mi][ni][r] = 0.f;

    int nk = K / 16;

    // stage tile 0
    {
        uint32_t ab = as_addr, bb = bs_addr;
        cp16(ab + offA0, Ag0);
        cp16(ab + offA1, Ag1);
        cp16(bb + offB0, Bg0);
        cp16(bb + offB1, Bg1);
        CP_COMMIT();
    }

    for (int kt = 0; kt < nk; kt++) {
        int cur = kt & 1;
        CP_WAIT_ALL();
        __syncthreads();

        if (kt + 1 < nk) {
            int k0 = (kt + 1) * 16;
            uint32_t ab = as_addr + (cur ^ 1) * G2_A * 4;
            uint32_t bb = bs_addr + (cur ^ 1) * G2_B * 4;
            cp16(ab + offA0, Ag0 + k0);
            cp16(ab + offA1, Ag1 + k0);
            cp16(bb + offB0, Bg0 + (size_t)k0 * ldb);
            cp16(bb + offB1, Bg1 + (size_t)k0 * ldb);
            CP_COMMIT();
        }

        const float* Ac = As + cur * G2_A;
        const float* Bc = Bs + cur * G2_B;

#pragma unroll
        for (int ks = 0; ks < 16; ks += 8) {
            uint32_t bh[4][2], bl[4][2];
#pragma unroll
            for (int ni = 0; ni < 4; ni++) {
                int c = wn * 32 + ni * 8 + g;
                split_tf32(Bc[(ks + tg) * 136 + c], bh[ni][0], bl[ni][0]);
                split_tf32(Bc[(ks + tg + 4) * 136 + c], bh[ni][1], bl[ni][1]);
            }
#pragma unroll
            for (int mi = 0; mi < 4; mi++) {
                int r = wm * 64 + mi * 16;
                uint32_t ah[4], al[4];
                split_tf32(Ac[(r + g) * 20 + ks + tg], ah[0], al[0]);
                split_tf32(Ac[(r + 8 + g) * 20 + ks + tg], ah[1], al[1]);
                split_tf32(Ac[(r + g) * 20 + ks + tg + 4], ah[2], al[2]);
                split_tf32(Ac[(r + 8 + g) * 20 + ks + tg + 4], ah[3], al[3]);
#pragma unroll
                for (int ni = 0; ni < 4; ni++) {
                    mma_tf32(d[mi][ni], ah, bh[ni]);
                    mma_tf32(d[mi][ni], ah, bl[ni]);
                    mma_tf32(d[mi][ni], al, bh[ni]);
                }
            }
        }
    }

    // epilogue
#pragma unroll
    for (int mi = 0; mi < 4; mi++) {
#pragma unroll
        for (int ni = 0; ni < 4; ni++) {
            int r = row0 + wm * 64 + mi * 16 + g;
            int c = col0 + wn * 32 + ni * 8 + 2 * tg;
            *(float2*)(C + (size_t)r * ldc + c) = make_float2(d[mi][ni][0], d[mi][ni][1]);
            *(float2*)(C + (size_t)(r + 8) * ldc + c) = make_float2(d[mi][ni][2], d[mi][ni][3]);
        }
    }
}

// ---------------- weight column-packing ----------------
__global__ void pack_cols(float* __restrict__ dst, int W,
                          const float* __restrict__ s0, int n0,
                          const float* __restrict__ s1, int n1,
                          const float* __restrict__ s2, int n2) {
    int k = blockIdx.x;
    for (int c = threadIdx.x; c < W; c += blockDim.x) {
        float v = 0.f;
        if (c < n0) v = s0[k * n0 + c];
        else if (c < n0 + n1) v = s1[k * n1 + (c - n0)];
        else if (c < n0 + n1 + n2) v = s2[k * n2 + (c - n0 - n1)];
        dst[k * W + c] = v;
    }
}

// ---------------- fused RMS norm on packed f0: cols 0..95 (q), 96..127 (ckv) ----------
__global__ void rms2_kernel(float* __restrict__ f0,
                            const float* __restrict__ gq, const float* __restrict__ gkv) {
    int row = blockIdx.x, tid = threadIdx.x;  // 128 threads
    float* dd = f0 + row * 256;
    __shared__ float s4[4];
    float v = (tid < 96) ? dd[tid] : 0.f;
    float sq = v * v;
#pragma unroll
    for (int o = 16; o > 0; o >>= 1) sq += __shfl_xor_sync(0xffffffffu, sq, o);
    if ((tid & 31) == 0) s4[tid >> 5] = sq;
    __syncthreads();
    float tot = s4[0] + s4[1] + s4[2] + s4[3];
    float sc = rsqrtf(tot / 96.f + 1e-6f);
    if (tid < 96) dd[tid] = v * sc * gq[tid];
    __syncthreads();
    if (tid < 32) {
        float v2 = dd[96 + tid];
        float sq2 = v2 * v2;
#pragma unroll
        for (int o = 16; o > 0; o >>= 1) sq2 += __shfl_xor_sync(0xffffffffu, sq2, o);
        float sc2 = rsqrtf(sq2 / 32.f + 1e-6f);
        dd[96 + tid] = v2 * sc2 * gkv[tid];
    }
}

// ---------------- xmean over T ----------------
__global__ void xmean_kernel(const float* __restrict__ x, float* __restrict__ xmean) {
    int c = blockIdx.x * 256 + threadIdx.x;
    int b = blockIdx.y;
    float s = 0.f;
    for (int t = 0; t < TT; t++) s += x[(b * TT + t) * CC + c];
    xmean[b * CC + c] = s * (1.f / (float)TT);
}

// ---------------- gate ----------------
__global__ void gate_kernel(const float* __restrict__ xmean, const float* __restrict__ wg,
                            float* __restrict__ gate) {
    int b = blockIdx.x, tid = threadIdx.x;
    __shared__ float sg[3];
    if (tid < 3) {
        float s = 0.f;
        for (int c = 0; c < CC; c++) s += xmean[b * CC + c] * wg[c * 3 + tid];
        sg[tid] = s;
    }
    __syncthreads();
    if (tid == 0) {
        float m = fmaxf(sg[0], fmaxf(sg[1], sg[2]));
        float e0 = expf(sg[0] - m), e1 = expf(sg[1] - m), e2 = expf(sg[2] - m);
        float inv = 1.f / (e0 + e1 + e2);
        gate[b * 4 + 0] = e0 * inv;
        gate[b * 4 + 1] = e1 * inv;
        gate[b * 4 + 2] = e2 * inv;
    }
}

// ---------------- importance scores ----------------
__global__ void scores_kernel(const float* __restrict__ x, const float* __restrict__ w,
                              float* __restrict__ out) {
    int row = blockIdx.x, tid = threadIdx.x;
    __shared__ float s8[8];
    float s = 0.f;
    for (int c = tid; c < CC; c += 256) s += x[row * CC + c] * w[c];
#pragma unroll
    for (int o = 16; o > 0; o >>= 1) s += __shfl_xor_sync(0xffffffffu, s, o);
    if ((tid & 31) == 0) s8[tid >> 5] = s;
    __syncthreads();
    if (tid == 0) {
        float t = 0.f;
#pragma unroll
        for (int i = 0; i < 8; i++) t += s8[i];
        out[row] = t;
    }
}

// ---------------- top-k(256) ----------------
__global__ void topk_kernel(const float* __restrict__ scores, int* __restrict__ idxout) {
    __shared__ float sv[1024];
    __shared__ int si[1024];
    __shared__ int ti[256];
    int b = blockIdx.x, tid = threadIdx.x;
    sv[tid] = scores[b * TT + tid];
    si[tid] = tid;
    __syncthreads();
    for (int k = 2; k <= 1024; k <<= 1) {
        for (int j = k >> 1; j > 0; j >>= 1) {
            int ixj = tid ^ j;
            if (ixj > tid) {
                bool desc = ((tid & k) == 0);
                float va = sv[tid], vb = sv[ixj];
                int ia = si[tid], ib = si[ixj];
                bool agtb = (va > vb) || (va == vb && ia < ib);
                if (desc ? !agtb : agtb) {
                    sv[tid] = vb; sv[ixj] = va;
                    si[tid] = ib; si[ixj] = ia;
                }
            }
            __syncthreads();
        }
    }
    if (tid < 256) ti[tid] = si[tid];
    __syncthreads();
    for (int k = 2; k <= 256; k <<= 1) {
        for (int j = k >> 1; j > 0; j >>= 1) {
            int ixj = tid ^ j;
            if (tid < 256 && ixj > tid) {
                bool asc = ((tid & k) == 0);
                int ia = ti[tid], ib = ti[ixj];
                if (asc ? (ia > ib) : (ia < ib)) { ti[tid] = ib; ti[ixj] = ia; }
            }
            __syncthreads();
        }
    }
    if (tid < 256) idxout[b * KEEP_ + tid] = ti[tid];
}

// ---------------- gather ----------------
__global__ void gather_kernel(const float* __restrict__ x, const int* __restrict__ idx,
                              float* __restrict__ selx) {
    int row = blockIdx.x;
    int b = row >> 8;
    int t = idx[row];
    for (int c = threadIdx.x; c < CC; c += 256)
        selx[row * CC + c] = x[(b * TT + t) * CC + c];
}

// ---------------- assembles (rope + layout) ----------------
__global__ void assemble_q_kernel(const float* __restrict__ qout, float* __restrict__ Q) {
    int row = blockIdx.x;
    int b = row >> 10, t = row & 1023;
    int j = threadIdx.x;          // 512
    int h = j >> 5, d = j & 31;
    int qb = (((b * HH + h) * TT) + t) * DQK;
    Q[qb + d] = qout[row * 1536 + j];
    float x1 = qout[row * 1536 + 512 + h * RD + d];
    float x2 = qout[row * 1536 + 512 + h * RD + RP + d];
    float f = expf(-LOG1E4_OVER_32 * (float)d);
    float sn, cs;
    sincosf((float)t * f, &sn, &cs);
    Q[qb + NOPE_ + d] = x1 * cs - x2 * sn;
    Q[qb + NOPE_ + RP + d] = x1 * sn + x2 * cs;
}

__global__ void assemble_k1v1_kernel(const float* __restrict__ kvout, const float* __restrict__ f0,
                                     float* __restrict__ K, float* __restrict__ V) {
    int row = blockIdx.x;
    int b = row >> 10, t = row & 1023;
    int j = threadIdx.x;
    int h = j >> 5, d = j & 31;
    int kb = (((b * HH + h) * TT) + t) * DQK;
    K[kb + d] = kvout[row * 1024 + j];
    float x1 = f0[row * 256 + 128 + d] * 0.0625f;
    float x2 = f0[row * 256 + 128 + RP + d] * 0.0625f;
    float f = expf(-LOG1E4_OVER_32 * (float)d);
    float sn, cs;
    sincosf((float)t * f, &sn, &cs);
    K[kb + NOPE_ + d] = x1 * cs - x2 * sn;
    K[kb + NOPE_ + RP + d] = x1 * sn + x2 * cs;
    V[(((b * HH + h) * TT) + t) * VD + d] = kvout[row * 1024 + 512 + j];
}

// raw: [S rows][2048], k at col h*96+r, v at col 1536+h*32+d
__global__ void assemble_kv_kernel(const float* __restrict__ raw,
                                   float* __restrict__ K, float* __restrict__ V, int S) {
    int row = blockIdx.x;
    int b = row / S, pos = row % S;
    int j = threadIdx.x;
    int h = j >> 5, d = j & 31;
    float nope = raw[row * 2048 + h * DQK + d];
    float x1 = raw[row * 2048 + h * DQK + NOPE_ + d];
    float x2 = raw[row * 2048 + h * DQK + NOPE_ + RP + d];
    float f = expf(-LOG1E4_OVER_32 * (float)d);
    float sn, cs;
    sincosf((float)pos * f, &sn, &cs);
    int kb = (((b * HH + h) * S) + pos) * DQK;
    K[kb + d] = nope;
    K[kb + NOPE_ + d] = x1 * cs - x2 * sn;
    K[kb + NOPE_ + RP + d] = x1 * sn + x2 * cs;
    V[(((b * HH + h) * S) + pos) * VD + d] = raw[row * 2048 + 1536 + h * VD + d];
}

// ---------------- tf32 MMA flash attention (unchanged from R4) ----------------
constexpr int QS_STR = 100;
constexpr int KS_STR = 72;
constexpr int VS_STR = 40;
constexpr int PS_STR = 68;
constexpr int ASM_QS = 0;
constexpr int ASM_KS = 128 * QS_STR;
constexpr int ASM_VS = ASM_KS + 96 * KS_STR;
constexpr int ASM_PS = ASM_VS + 64 * VS_STR;
constexpr int ATTN_SMEM = (ASM_PS + 8 * 16 * PS_STR) * 4;

__global__ void __launch_bounds__(256)
attn_mma(const float* __restrict__ Q,
         const float* __restrict__ K1, const float* __restrict__ V1,
         const float* __restrict__ KS, const float* __restrict__ VS,
         const float* __restrict__ KW, const float* __restrict__ VW,
         const float* __restrict__ gate, float* __restrict__ outp) {
    extern __shared__ float sm[];
    float* Qs = sm + ASM_QS;
    float* Ks = sm + ASM_KS;
    float* Vs = sm + ASM_VS;

    int tid = threadIdx.x;
    int w = tid >> 5, lane = tid & 31;
    int g = lane >> 2, tg = lane & 3;
    float* Ps = sm + ASM_PS + w * 16 * PS_STR;

    int tile = 7 - blockIdx.x;
    int h = blockIdx.y, b = blockIdx.z;
    int q0 = tile * 128;
    int bh = b * HH + h;
    int rowg = q0 + 16 * w + g;

    const float* Qp = Q + (bh * TT + q0) * DQK;
    for (int i = tid; i < 128 * 24; i += 256) {
        int q = i / 24, dq = i % 24;
        float4 v = *(const float4*)(Qp + q * DQK + dq * 4);
        v.x = to_tf32(v.x); v.y = to_tf32(v.y);
        v.z = to_tf32(v.z); v.w = to_tf32(v.w);
        *(float4*)&Qs[q * QS_STR + dq * 4] = v;
    }

    float g_b[3];
    g_b[0] = gate[b * 4 + 0];
    g_b[1] = gate[b * 4 + 1];
    g_b[2] = gate[b * 4 + 2];

    float fout[4][4];
#pragma unroll
    for (int nv = 0; nv < 4; nv++)
#pragma unroll
        for (int r = 0; r < 4; r++) fout[nv][r] = 0.f;

    for (int br = 0; br < 3; br++) {
        const float* Kp;
        const float* Vp;
        int nchunk;
        bool causal;
        if (br == 0)      { Kp = K1 + bh * TT * DQK;    Vp = V1 + bh * TT * VD;    nchunk = 2 * (tile + 1); causal = true; }
        else if (br == 1) { Kp = KS + bh * KEEP_ * DQK; Vp = VS + bh * KEEP_ * VD; nchunk = 4;              causal = false; }
        else              { Kp = KW + bh * TT * DQK;    Vp = VW + bh * TT * VD;    nchunk = 2 * (tile + 1); causal = true; }

        float m0 = -1e30f, m1 = -1e30f, l0 = 0.f, l1 = 0.f;
        float acc[4][4];
#pragma unroll
        for (int nv = 0; nv < 4; nv++)
#pragma unroll
            for (int r = 0; r < 4; r++) acc[nv][r] = 0.f;

        for (int c = 0; c < nchunk; c++) {
            int k0 = c * 64;
            __syncthreads();

            for (int i = tid; i < 64 * 24; i += 256) {
                int key = i / 24, dq = i % 24;
                float4 v = *(const float4*)(Kp + (k0 + key) * DQK + dq * 4);
                Ks[(dq * 4 + 0) * KS_STR + key] = to_tf32(v.x);
                Ks[(dq * 4 + 1) * KS_STR + key] = to_tf32(v.y);
                Ks[(dq * 4 + 2) * KS_STR + key] = to_tf32(v.z);
                Ks[(dq * 4 + 3) * KS_STR + key] = to_tf32(v.w);
            }
            for (int i = tid; i < 64 * 8; i += 256) {
                int key = i >> 3, dq = i & 7;
                float4 v = *(const float4*)(Vp + (k0 + key) * VD + dq * 4);
                v.x = to_tf32(v.x); v.y = to_tf32(v.y);
                v.z = to_tf32(v.z); v.w = to_tf32(v.w);
                *(float4*)&Vs[key * VS_STR + dq * 4] = v;
            }
            __syncthreads();

            float s[8][4];
#pragma unroll
            for (int ni = 0; ni < 8; ni++)
#pragma unroll
                for (int r = 0; r < 4; r++) s[ni][r] = 0.f;

#pragma unroll
            for (int ks = 0; ks < 12; ks++) {
                int kb = ks * 8;
                const float* q0p = &Qs[(16 * w + g) * QS_STR + kb];
                const float* q1p = q0p + 8 * QS_STR;
                uint32_t Af[4];
                Af[0] = __float_as_uint(q0p[tg]);
                Af[1] = __float_as_uint(q1p[tg]);
                Af[2] = __float_as_uint(q0p[tg + 4]);
                Af[3] = __float_as_uint(q1p[tg + 4]);
#pragma unroll
                for (int ni = 0; ni < 8; ni++) {
                    uint32_t Bf[2];
                    Bf[0] = __float_as_uint(Ks[(kb + tg) * KS_STR + 8 * ni + g]);
                    Bf[1] = __float_as_uint(Ks[(kb + tg + 4) * KS_STR + 8 * ni + g]);
                    mma_tf32(s[ni], Af, Bf);
                }
            }

            if (causal && (k0 + 64 > q0)) {
#pragma unroll
                for (int ni = 0; ni < 8; ni++) {
                    int key = k0 + 8 * ni + 2 * tg;
                    if (key > rowg)         s[ni][0] = -1e30f;
                    if (key + 1 > rowg)     s[ni][1] = -1e30f;
                    if (key > rowg + 8)     s[ni][2] = -1e30f;
                    if (key + 1 > rowg + 8) s[ni][3] = -1e30f;
                }
            }

            float cm0 = -1e30f, cm1 = -1e30f;
#pragma unroll
            for (int ni = 0; ni < 8; ni++) {
                cm0 = fmaxf(cm0, fmaxf(s[ni][0], s[ni][1]));
                cm1 = fmaxf(cm1, fmaxf(s[ni][2], s[ni][3]));
            }
            cm0 = fmaxf(cm0, __shfl_xor_sync(0xffffffffu, cm0, 1));
            cm0 = fmaxf(cm0, __shfl_xor_sync(0xffffffffu, cm0, 2));
            cm1 = fmaxf(cm1, __shfl_xor_sync(0xffffffffu, cm1, 1));
            cm1 = fmaxf(cm1, __shfl_xor_sync(0xffffffffu, cm1, 2));

            float nm0 = fmaxf(m0, cm0), nm1 = fmaxf(m1, cm1);
            float al0 = __expf((m0 - nm0) * ATTN_SCALE);
            float al1 = __expf((m1 - nm1) * ATTN_SCALE);
            m0 = nm0; m1 = nm1;

            float sum0 = 0.f, sum1 = 0.f;
#pragma unroll
            for (int ni = 0; ni < 8; ni++) {
                s[ni][0] = __expf((s[ni][0] - m0) * ATTN_SCALE);
                s[ni][1] = __expf((s[ni][1] - m0) * ATTN_SCALE);
                s[ni][2] = __expf((s[ni][2] - m1) * ATTN_SCALE);
                s[ni][3] = __expf((s[ni][3] - m1) * ATTN_SCALE);
                sum0 += s[ni][0] + s[ni][1];
                sum1 += s[ni][2] + s[ni][3];
            }
            sum0 += __shfl_xor_sync(0xffffffffu, sum0, 1);
            sum0 += __shfl_xor_sync(0xffffffffu, sum0, 2);
            sum1 += __shfl_xor_sync(0xffffffffu, sum1, 1);
            sum1 += __shfl_xor_sync(0xffffffffu, sum1, 2);
            l0 = l0 * al0 + sum0;
            l1 = l1 * al1 + sum1;

#pragma unroll
            for (int nv = 0; nv < 4; nv++) {
                acc[nv][0] *= al0; acc[nv][1] *= al0;
                acc[nv][2] *= al1; acc[nv][3] *= al1;
            }

            __syncwarp();
#pragma unroll
            for (int ni = 0; ni < 8; ni++) {
                *(float2*)&Ps[g * PS_STR + 8 * ni + 2 * tg] =
                    make_float2(to_tf32(s[ni][0]), to_tf32(s[ni][1]));
                *(float2*)&Ps[(g + 8) * PS_STR + 8 * ni + 2 * tg] =
                    make_float2(to_tf32(s[ni][2]), to_tf32(s[ni][3]));
            }
            __syncwarp();

#pragma unroll
            for (int ks = 0; ks < 8; ks++) {
                int kb = ks * 8;
                uint32_t Af[4];
                Af[0] = __float_as_uint(Ps[g * PS_STR + kb + tg]);
                Af[1] = __float_as_uint(Ps[(g + 8) * PS_STR + kb + tg]);
                Af[2] = __float_as_uint(Ps[g * PS_STR + kb + tg + 4]);
                Af[3] = __float_as_uint(Ps[(g + 8) * PS_STR + kb + tg + 4]);
#pragma unroll
                for (int nv = 0; nv < 4; nv++) {
                    uint32_t Bf[2];
                    Bf[0] = __float_as_uint(Vs[(kb + tg) * VS_STR + 8 * nv + g]);
                    Bf[1] = __float_as_uint(Vs[(kb + tg + 4) * VS_STR + 8 * nv + g]);
                    mma_tf32(acc[nv], Af, Bf);
                }
            }
        }

        float gb = g_b[br];
        float inv0 = gb / l0, inv1 = gb / l1;
#pragma unroll
        for (int nv = 0; nv < 4; nv++) {
            fout[nv][0] += acc[nv][0] * inv0;
            fout[nv][1] += acc[nv][1] * inv0;
            fout[nv][2] += acc[nv][2] * inv1;
            fout[nv][3] += acc[nv][3] * inv1;
        }
    }

#pragma unroll
    for (int nv = 0; nv < 4; nv++) {
        int col = h * VD + 8 * nv + 2 * tg;
        *(float2*)(outp + (b * TT + rowg) * (HH * VD) + col) =
            make_float2(fout[nv][0], fout[nv][1]);
        *(float2*)(outp + (b * TT + rowg + 8) * (HH * VD) + col) =
            make_float2(fout[nv][2], fout[nv][3]);
    }
}

// ---------------- launcher ----------------
extern "C" void kernel_launch(void* const* d_in, const int* in_sizes, int n_in,
                              void* d_out, int out_size) {
    const float* x         = (const float*)d_in[0];
    const float* w_cq      = (const float*)d_in[1];
    const float* g_qnorm   = (const float*)d_in[2];
    const float* w_dq_nope = (const float*)d_in[3];
    const float* w_dq_rope = (const float*)d_in[4];
    const float* w_ckv     = (const float*)d_in[5];
    const float* g_kvnorm  = (const float*)d_in[6];
    const float* w_dk_nope = (const float*)d_in[7];
    const float* w_dv      = (const float*)d_in[8];
    const float* w_krope   = (const float*)d_in[9];
    const float* w_imp     = (const float*)d_in[10];
    const float* w_selk    = (const float*)d_in[11];
    const float* w_selv    = (const float*)d_in[12];
    const float* w_wink    = (const float*)d_in[13];
    const float* w_winv    = (const float*)d_in[14];
    const float* w_gate    = (const float*)d_in[15];
    const float* w_proj    = (const float*)d_in[16];
    float* out = (float*)d_out;

    float* base = nullptr;
    cudaGetSymbolAddress((void**)&base, g_scratch);

    float* wc1    = base + OFF_WC1;
    float* wc2    = base + OFF_WC2;
    float* wc3    = base + OFF_WC3;
    float* wsel   = base + OFF_WSEL;
    float* wwin   = base + OFF_WWIN;
    float* f0     = base + OFF_F0;
    float* qout   = base + OFF_QOUT;
    float* kvout  = base + OFF_KVOUT;
    float* winout = base + OFF_WINOUT;
    float* selx   = base + OFF_SELX;
    float* selkv  = base + OFF_SELKV;
    float* xmean  = base + OFF_XMEAN;
    float* gate   = base + OFF_GATE;
    float* scores = base + OFF_SCORES;
    int*   idx    = (int*)(base + OFF_IDX);
    float* Qb     = base + OFF_Q;
    float* K1b    = base + OFF_K1;
    float* V1b    = base + OFF_V1;
    float* KWb    = base + OFF_KW;
    float* VWb    = base + OFF_VW;
    float* KSb    = base + OFF_KS;
    float* VSb    = base + OFF_VS;
    float* attnb  = base + OFF_ATTN;

    const int M = BB * TT;  // 2048
    const float* nullp = nullptr;

    cudaFuncSetAttribute(gemm_tc2, cudaFuncAttributeMaxDynamicSharedMemorySize, G2_SMEM);
    cudaFuncSetAttribute(attn_mma, cudaFuncAttributeMaxDynamicSharedMemorySize, ATTN_SMEM);

    // ---- pack weights ----
    pack_cols<<<1024, 256>>>(wc1, 256, w_cq, 96, w_ckv, 32, w_krope, 64);
    pack_cols<<<96, 256>>>(wc2, 1536, w_dq_nope, 512, w_dq_rope, 1024, nullp, 0);
    pack_cols<<<32, 256>>>(wc3, 1024, w_dk_nope, 512, w_dv, 512, nullp, 0);
    pack_cols<<<1024, 256>>>(wsel, 2048, w_selk, 1536, w_selv, 512, nullp, 0);
    pack_cols<<<1024, 256>>>(wwin, 2048, w_wink, 1536, w_winv, 512, nullp, 0);

    // ---- projections ----
    // f0 = x @ [cq|ckv|krope|0]   (2048x256, K=1024)
    gemm_tc2<<<dim3(2, M / 128), 256, G2_SMEM>>>(x, CC, wc1, 256, f0, 256, M, 256, CC);
    rms2_kernel<<<M, 128>>>(f0, g_qnorm, g_kvnorm);
    // qout = nq @ [dq_nope|dq_rope]  (2048x1536, K=96, A=f0 cols 0..95)
    gemm_tc2<<<dim3(12, M / 128), 256, G2_SMEM>>>(f0, 256, wc2, 1536, qout, 1536, M, 1536, 96);
    // kvout = ckv @ [dk_nope|dv]  (2048x1024, K=32, A=f0 cols 96..127)
    gemm_tc2<<<dim3(8, M / 128), 256, G2_SMEM>>>(f0 + 96, 256, wc3, 1024, kvout, 1024, M, 1024, 32);
    // winout = x @ [wink|winv]  (2048x2048, K=1024)
    gemm_tc2<<<dim3(16, M / 128), 256, G2_SMEM>>>(x, CC, wwin, 2048, winout, 2048, M, 2048, CC);

    // ---- gate ----
    xmean_kernel<<<dim3(4, BB), 256>>>(x, xmean);
    gate_kernel<<<BB, 32>>>(xmean, w_gate, gate);

    // ---- selection ----
    scores_kernel<<<M, 256>>>(x, w_imp, scores);
    topk_kernel<<<BB, 1024>>>(scores, idx);
    gather_kernel<<<BB * KEEP_, 256>>>(x, idx, selx);
    // selkv = selx @ [selk|selv]  (512x2048, K=1024)
    gemm_tc2<<<dim3(16, (BB * KEEP_) / 128), 256, G2_SMEM>>>(selx, CC, wsel, 2048, selkv, 2048,
                                                            BB * KEEP_, 2048, CC);

    // ---- assemble ----
    assemble_q_kernel<<<M, 512>>>(qout, Qb);
    assemble_k1v1_kernel<<<M, 512>>>(kvout, f0, K1b, V1b);
    assemble_kv_kernel<<<BB * KEEP_, 512>>>(selkv, KSb, VSb, KEEP_);
    assemble_kv_kernel<<<M, 512>>>(winout, KWb, VWb, TT);

    // ---- attention ----
    attn_mma<<<dim3(8, HH, BB), 256, ATTN_SMEM>>>(Qb, K1b, V1b, KSb, VSb, KWb, VWb, gate, attnb);

    // ---- output projection ----
    gemm_tc2<<<dim3(8, M / 128), 256, G2_SMEM>>>(attnb, HH * VD, w_proj, CC, out, CC, M, CC, HH * VD);
}

// round 6
// speedup vs baseline: 6.5555x; 1.2823x over previous
#include <cuda_runtime.h>
#include <math.h>
#include <stdint.h>

// ---------------- problem constants ----------------
#define BB 2
#define TT 1024
#define CC 1024
#define HH 16
#define VD 32
#define NOPE_ 32
#define RP 32
#define RD 64
#define DQK 96
#define KEEP_ 256
#define QL 96
#define KVL 32

#define LOG1E4_OVER_32 0.28782313662425572f   // ln(10000)/32
#define ATTN_SCALE 0.10206207261596577f       // 1/sqrt(96)

// ---------------- scratch ----------------
constexpr int OFF_WC1    = 0;                          // [1024][256]
constexpr int OFF_F0     = OFF_WC1    + 1024*256;      // [2048][256]  nq|ckv|krope|pad
constexpr int OFF_QOUT   = OFF_F0     + 2048*256;      // [2048][1536] qnope|qrope
constexpr int OFF_KVOUT  = OFF_QOUT   + 2048*1536;     // [2048][1024] knope|v1
constexpr int OFF_WINOUT = OFF_KVOUT  + 2048*1024;     // [2048][2048] kw|vw
constexpr int OFF_SELX   = OFF_WINOUT + 2048*2048;     // [512][1024]
constexpr int OFF_SELKV  = OFF_SELX   + 512*1024;      // [512][2048]  ks|vs
constexpr int OFF_XMEAN  = OFF_SELKV  + 512*2048;
constexpr int OFF_GATE   = OFF_XMEAN  + BB*CC;
constexpr int OFF_SCORES = OFF_GATE   + 8;
constexpr int OFF_IDX    = OFF_SCORES + BB*TT;
constexpr int OFF_Q      = OFF_IDX    + BB*KEEP_;
constexpr int OFF_K1     = OFF_Q      + BB*HH*TT*DQK;
constexpr int OFF_V1     = OFF_K1     + BB*HH*TT*DQK;
constexpr int OFF_KW     = OFF_V1     + BB*HH*TT*VD;
constexpr int OFF_VW     = OFF_KW     + BB*HH*TT*DQK;
constexpr int OFF_KS     = OFF_VW     + BB*HH*TT*VD;
constexpr int OFF_VS     = OFF_KS     + BB*HH*KEEP_*DQK;
constexpr int OFF_ATTN   = OFF_VS     + BB*HH*KEEP_*VD;
constexpr int SCRATCH_TOTAL = OFF_ATTN + BB*TT*HH*VD;

__device__ __align__(256) float g_scratch[SCRATCH_TOTAL];

// ---------------- tf32 helpers ----------------
__device__ __forceinline__ float to_tf32(float v) {
    uint32_t u;
    asm("cvt.rna.tf32.f32 %0, %1;" : "=r"(u) : "f"(v));
    return __uint_as_float(u);
}

__device__ __forceinline__ uint32_t f2tf(float v) {
    uint32_t u;
    asm("cvt.rna.tf32.f32 %0, %1;" : "=r"(u) : "f"(v));
    return u;
}

__device__ __forceinline__ void split_tf32(float v, uint32_t& hi, uint32_t& lo) {
    asm("cvt.rna.tf32.f32 %0, %1;" : "=r"(hi) : "f"(v));
    float lf = v - __uint_as_float(hi);
    asm("cvt.rna.tf32.f32 %0, %1;" : "=r"(lo) : "f"(lf));
}

__device__ __forceinline__ void mma_tf32(float* d, const uint32_t* a, const uint32_t* b) {
    asm volatile(
        "mma.sync.aligned.m16n8k8.row.col.f32.tf32.tf32.f32 "
        "{%0,%1,%2,%3}, {%4,%5,%6,%7}, {%8,%9}, {%0,%1,%2,%3};\n"
        : "+f"(d[0]), "+f"(d[1]), "+f"(d[2]), "+f"(d[3])
        : "r"(a[0]), "r"(a[1]), "r"(a[2]), "r"(a[3]), "r"(b[0]), "r"(b[1]));
}

__device__ __forceinline__ void cp16(uint32_t dst, const float* src) {
    asm volatile("cp.async.cg.shared.global [%0], [%1], 16;" :: "r"(dst), "l"(src));
}
#define CP_COMMIT() asm volatile("cp.async.commit_group;")

// ---------------- gemm_tc2: 128x128 tile, cp.async 3-stage, split-B, split-on-consume ---
// Requirements: M%128==0, N%128==0, K%16==0, column split n0 % 128 == 0.
constexpr int G2_A = 128 * 20;
constexpr int G2_B = 16 * 136;
constexpr int G2_SMEM = 3 * (G2_A + G2_B) * 4;   // 56832 B

__global__ void __launch_bounds__(256, 2)
gemm_tc2(const float* __restrict__ A, int lda,
         const float* __restrict__ B0, int ldb0, int n0,
         const float* __restrict__ B1, int ldb1,
         float* __restrict__ C, int ldc,
         int M, int N, int K) {
    extern __shared__ float sm2[];
    float* As = sm2;               // 3 x G2_A
    float* Bs = sm2 + 3 * G2_A;    // 3 x G2_B

    int tid = threadIdx.x;
    int warp = tid >> 5, lane = tid & 31;
    int g = lane >> 2, tg = lane & 3;
    int wm = warp >> 2, wn = warp & 3;
    int row0 = blockIdx.y * 128, col0 = blockIdx.x * 128;

    // pick B source for this CTA's 128-column slice
    const float* Bsrc;
    int ldb;
    if (col0 < n0) { Bsrc = B0 + col0; ldb = ldb0; }
    else           { Bsrc = B1 + (col0 - n0); ldb = ldb1; }

    uint32_t as_addr = (uint32_t)__cvta_generic_to_shared(As);
    uint32_t bs_addr = (uint32_t)__cvta_generic_to_shared(Bs);

    const float* Ag0 = A + (size_t)(row0 + (tid >> 2)) * lda + (tid & 3) * 4;
    const float* Ag1 = A + (size_t)(row0 + 64 + (tid >> 2)) * lda + (tid & 3) * 4;
    const float* Bg0 = Bsrc + (size_t)(tid >> 5) * ldb + (tid & 31) * 4;
    const float* Bg1 = Bsrc + (size_t)(8 + (tid >> 5)) * ldb + (tid & 31) * 4;
    uint32_t offA0 = (((tid >> 2)) * 20 + (tid & 3) * 4) * 4;
    uint32_t offA1 = (((tid >> 2) + 64) * 20 + (tid & 3) * 4) * 4;
    uint32_t offB0 = ((tid >> 5) * 136 + (tid & 31) * 4) * 4;
    uint32_t offB1 = ((8 + (tid >> 5)) * 136 + (tid & 31) * 4) * 4;

    float d[4][4][4];
#pragma unroll
    for (int mi = 0; mi < 4; mi++)
#pragma unroll
        for (int ni = 0; ni < 4; ni++)
#pragma unroll
            for (int r = 0; r < 4; r++) d[mi][ni][r] = 0.f;

    int nk = K / 16;

    // stage tiles 0 and 1
    {
        cp16(as_addr + offA0, Ag0);
        cp16(as_addr + offA1, Ag1);
        cp16(bs_addr + offB0, Bg0);
        cp16(bs_addr + offB1, Bg1);
        CP_COMMIT();
    }
    if (nk > 1) {
        uint32_t ab = as_addr + G2_A * 4, bb = bs_addr + G2_B * 4;
        cp16(ab + offA0, Ag0 + 16);
        cp16(ab + offA1, Ag1 + 16);
        cp16(bb + offB0, Bg0 + (size_t)16 * ldb);
        cp16(bb + offB1, Bg1 + (size_t)16 * ldb);
        CP_COMMIT();
    }

    for (int kt = 0; kt < nk; kt++) {
        if (kt + 1 < nk) { asm volatile("cp.async.wait_group 1;"); }
        else             { asm volatile("cp.async.wait_group 0;"); }
        __syncthreads();

        if (kt + 2 < nk) {
            int s = (kt + 2) % 3;
            int k0 = (kt + 2) * 16;
            uint32_t ab = as_addr + s * G2_A * 4, bb = bs_addr + s * G2_B * 4;
            cp16(ab + offA0, Ag0 + k0);
            cp16(ab + offA1, Ag1 + k0);
            cp16(bb + offB0, Bg0 + (size_t)k0 * ldb);
            cp16(bb + offB1, Bg1 + (size_t)k0 * ldb);
            CP_COMMIT();
        }

        const float* Ac = As + (kt % 3) * G2_A;
        const float* Bc = Bs + (kt % 3) * G2_B;

#pragma unroll
        for (int ks = 0; ks < 16; ks += 8) {
            uint32_t bh[4][2], bl[4][2];
#pragma unroll
            for (int ni = 0; ni < 4; ni++) {
                int c = wn * 32 + ni * 8 + g;
                split_tf32(Bc[(ks + tg) * 136 + c], bh[ni][0], bl[ni][0]);
                split_tf32(Bc[(ks + tg + 4) * 136 + c], bh[ni][1], bl[ni][1]);
            }
#pragma unroll
            for (int mi = 0; mi < 4; mi++) {
                int r = wm * 64 + mi * 16;
                uint32_t ah[4], al[4];
                split_tf32(Ac[(r + g) * 20 + ks + tg], ah[0], al[0]);
                split_tf32(Ac[(r + 8 + g) * 20 + ks + tg], ah[1], al[1]);
                split_tf32(Ac[(r + g) * 20 + ks + tg + 4], ah[2], al[2]);
                split_tf32(Ac[(r + 8 + g) * 20 + ks + tg + 4], ah[3], al[3]);
#pragma unroll
                for (int ni = 0; ni < 4; ni++) {
                    mma_tf32(d[mi][ni], ah, bh[ni]);
                    mma_tf32(d[mi][ni], ah, bl[ni]);
                    mma_tf32(d[mi][ni], al, bh[ni]);
                }
            }
        }
    }

    // epilogue
#pragma unroll
    for (int mi = 0; mi < 4; mi++) {
#pragma unroll
        for (int ni = 0; ni < 4; ni++) {
            int r = row0 + wm * 64 + mi * 16 + g;
            int c = col0 + wn * 32 + ni * 8 + 2 * tg;
            *(float2*)(C + (size_t)r * ldc + c) = make_float2(d[mi][ni][0], d[mi][ni][1]);
            *(float2*)(C + (size_t)(r + 8) * ldc + c) = make_float2(d[mi][ni][2], d[mi][ni][3]);
        }
    }
}

// ---------------- weight column-packing (only wc1 now) ----------------
__global__ void pack_cols(float* __restrict__ dst, int W,
                          const float* __restrict__ s0, int n0,
                          const float* __restrict__ s1, int n1,
                          const float* __restrict__ s2, int n2) {
    int k = blockIdx.x;
    for (int c = threadIdx.x; c < W; c += blockDim.x) {
        float v = 0.f;
        if (c < n0) v = s0[k * n0 + c];
        else if (c < n0 + n1) v = s1[k * n1 + (c - n0)];
        else if (c < n0 + n1 + n2) v = s2[k * n2 + (c - n0 - n1)];
        dst[k * W + c] = v;
    }
}

// ---------------- fused RMS norm on packed f0 ----------------
__global__ void rms2_kernel(float* __restrict__ f0,
                            const float* __restrict__ gq, const float* __restrict__ gkv) {
    int row = blockIdx.x, tid = threadIdx.x;  // 128 threads
    float* dd = f0 + row * 256;
    __shared__ float s4[4];
    float v = (tid < 96) ? dd[tid] : 0.f;
    float sq = v * v;
#pragma unroll
    for (int o = 16; o > 0; o >>= 1) sq += __shfl_xor_sync(0xffffffffu, sq, o);
    if ((tid & 31) == 0) s4[tid >> 5] = sq;
    __syncthreads();
    float tot = s4[0] + s4[1] + s4[2] + s4[3];
    float sc = rsqrtf(tot / 96.f + 1e-6f);
    if (tid < 96) dd[tid] = v * sc * gq[tid];
    __syncthreads();
    if (tid < 32) {
        float v2 = dd[96 + tid];
        float sq2 = v2 * v2;
#pragma unroll
        for (int o = 16; o > 0; o >>= 1) sq2 += __shfl_xor_sync(0xffffffffu, sq2, o);
        float sc2 = rsqrtf(sq2 / 32.f + 1e-6f);
        dd[96 + tid] = v2 * sc2 * gkv[tid];
    }
}

// ---------------- xmean ----------------
__global__ void xmean_kernel(const float* __restrict__ x, float* __restrict__ xmean) {
    int c = blockIdx.x * 256 + threadIdx.x;
    int b = blockIdx.y;
    float s = 0.f;
    for (int t = 0; t < TT; t++) s += x[(b * TT + t) * CC + c];
    xmean[b * CC + c] = s * (1.f / (float)TT);
}

// ---------------- gate ----------------
__global__ void gate_kernel(const float* __restrict__ xmean, const float* __restrict__ wg,
                            float* __restrict__ gate) {
    int b = blockIdx.x, tid = threadIdx.x;
    __shared__ float sg[3];
    if (tid < 3) {
        float s = 0.f;
        for (int c = 0; c < CC; c++) s += xmean[b * CC + c] * wg[c * 3 + tid];
        sg[tid] = s;
    }
    __syncthreads();
    if (tid == 0) {
        float m = fmaxf(sg[0], fmaxf(sg[1], sg[2]));
        float e0 = expf(sg[0] - m), e1 = expf(sg[1] - m), e2 = expf(sg[2] - m);
        float inv = 1.f / (e0 + e1 + e2);
        gate[b * 4 + 0] = e0 * inv;
        gate[b * 4 + 1] = e1 * inv;
        gate[b * 4 + 2] = e2 * inv;
    }
}

// ---------------- importance scores ----------------
__global__ void scores_kernel(const float* __restrict__ x, const float* __restrict__ w,
                              float* __restrict__ out) {
    int row = blockIdx.x, tid = threadIdx.x;
    __shared__ float s8[8];
    float s = 0.f;
    for (int c = tid; c < CC; c += 256) s += x[row * CC + c] * w[c];
#pragma unroll
    for (int o = 16; o > 0; o >>= 1) s += __shfl_xor_sync(0xffffffffu, s, o);
    if ((tid & 31) == 0) s8[tid >> 5] = s;
    __syncthreads();
    if (tid == 0) {
        float t = 0.f;
#pragma unroll
        for (int i = 0; i < 8; i++) t += s8[i];
        out[row] = t;
    }
}

// ---------------- top-k(256) ----------------
__global__ void topk_kernel(const float* __restrict__ scores, int* __restrict__ idxout) {
    __shared__ float sv[1024];
    __shared__ int si[1024];
    __shared__ int ti[256];
    int b = blockIdx.x, tid = threadIdx.x;
    sv[tid] = scores[b * TT + tid];
    si[tid] = tid;
    __syncthreads();
    for (int k = 2; k <= 1024; k <<= 1) {
        for (int j = k >> 1; j > 0; j >>= 1) {
            int ixj = tid ^ j;
            if (ixj > tid) {
                bool desc = ((tid & k) == 0);
                float va = sv[tid], vb = sv[ixj];
                int ia = si[tid], ib = si[ixj];
                bool agtb = (va > vb) || (va == vb && ia < ib);
                if (desc ? !agtb : agtb) {
                    sv[tid] = vb; sv[ixj] = va;
                    si[tid] = ib; si[ixj] = ia;
                }
            }
            __syncthreads();
        }
    }
    if (tid < 256) ti[tid] = si[tid];
    __syncthreads();
    for (int k = 2; k <= 256; k <<= 1) {
        for (int j = k >> 1; j > 0; j >>= 1) {
            int ixj = tid ^ j;
            if (tid < 256 && ixj > tid) {
                bool asc = ((tid & k) == 0);
                int ia = ti[tid], ib = ti[ixj];
                if (asc ? (ia > ib) : (ia < ib)) { ti[tid] = ib; ti[ixj] = ia; }
            }
            __syncthreads();
        }
    }
    if (tid < 256) idxout[b * KEEP_ + tid] = ti[tid];
}

// ---------------- gather ----------------
__global__ void gather_kernel(const float* __restrict__ x, const int* __restrict__ idx,
                              float* __restrict__ selx) {
    int row = blockIdx.x;
    int b = row >> 8;
    int t = idx[row];
    for (int c = threadIdx.x; c < CC; c += 256)
        selx[row * CC + c] = x[(b * TT + t) * CC + c];
}

// ---------------- assembles (rope + layout) ----------------
__global__ void assemble_q_kernel(const float* __restrict__ qout, float* __restrict__ Q) {
    int row = blockIdx.x;
    int b = row >> 10, t = row & 1023;
    int j = threadIdx.x;
    int h = j >> 5, d = j & 31;
    int qb = (((b * HH + h) * TT) + t) * DQK;
    Q[qb + d] = qout[row * 1536 + j];
    float x1 = qout[row * 1536 + 512 + h * RD + d];
    float x2 = qout[row * 1536 + 512 + h * RD + RP + d];
    float f = expf(-LOG1E4_OVER_32 * (float)d);
    float sn, cs;
    sincosf((float)t * f, &sn, &cs);
    Q[qb + NOPE_ + d] = x1 * cs - x2 * sn;
    Q[qb + NOPE_ + RP + d] = x1 * sn + x2 * cs;
}

__global__ void assemble_k1v1_kernel(const float* __restrict__ kvout, const float* __restrict__ f0,
                                     float* __restrict__ K, float* __restrict__ V) {
    int row = blockIdx.x;
    int b = row >> 10, t = row & 1023;
    int j = threadIdx.x;
    int h = j >> 5, d = j & 31;
    int kb = (((b * HH + h) * TT) + t) * DQK;
    K[kb + d] = kvout[row * 1024 + j];
    float x1 = f0[row * 256 + 128 + d] * 0.0625f;
    float x2 = f0[row * 256 + 128 + RP + d] * 0.0625f;
    float f = expf(-LOG1E4_OVER_32 * (float)d);
    float sn, cs;
    sincosf((float)t * f, &sn, &cs);
    K[kb + NOPE_ + d] = x1 * cs - x2 * sn;
    K[kb + NOPE_ + RP + d] = x1 * sn + x2 * cs;
    V[(((b * HH + h) * TT) + t) * VD + d] = kvout[row * 1024 + 512 + j];
}

__global__ void assemble_kv_kernel(const float* __restrict__ raw,
                                   float* __restrict__ K, float* __restrict__ V, int S) {
    int row = blockIdx.x;
    int b = row / S, pos = row % S;
    int j = threadIdx.x;
    int h = j >> 5, d = j & 31;
    float nope = raw[row * 2048 + h * DQK + d];
    float x1 = raw[row * 2048 + h * DQK + NOPE_ + d];
    float x2 = raw[row * 2048 + h * DQK + NOPE_ + RP + d];
    float f = expf(-LOG1E4_OVER_32 * (float)d);
    float sn, cs;
    sincosf((float)pos * f, &sn, &cs);
    int kb = (((b * HH + h) * S) + pos) * DQK;
    K[kb + d] = nope;
    K[kb + NOPE_ + d] = x1 * cs - x2 * sn;
    K[kb + NOPE_ + RP + d] = x1 * sn + x2 * cs;
    V[(((b * HH + h) * S) + pos) * VD + d] = raw[row * 2048 + 1536 + h * VD + d];
}

// ---------------- pipelined tf32 MMA flash attention ----------------
// 128 queries/block, 64-key chunks, 8 warps x 16 query rows.
// smem: Qs[128][100] | Ks[2][64][100] (row-major, cp.async) | Vs[2][64][40] | Ps[8][16][68]
constexpr int QS_STR = 100;
constexpr int KS_STR = 100;
constexpr int VS_STR = 40;
constexpr int PS_STR = 68;
constexpr int KBUF = 64 * KS_STR;   // 6400
constexpr int VBUF = 64 * VS_STR;   // 2560
constexpr int ASM_QS = 0;
constexpr int ASM_KS = 128 * QS_STR;            // 12800
constexpr int ASM_VS = ASM_KS + 2 * KBUF;       // 25600
constexpr int ASM_PS = ASM_VS + 2 * VBUF;       // 30720
constexpr int ATTN_SMEM = (ASM_PS + 8 * 16 * PS_STR) * 4;  // 157696 B

__global__ void __launch_bounds__(256)
attn_mma(const float* __restrict__ Q,
         const float* __restrict__ K1, const float* __restrict__ V1,
         const float* __restrict__ KS, const float* __restrict__ VS,
         const float* __restrict__ KW, const float* __restrict__ VW,
         const float* __restrict__ gate, float* __restrict__ outp) {
    extern __shared__ float sm[];
    float* Qs = sm + ASM_QS;

    int tid = threadIdx.x;
    int w = tid >> 5, lane = tid & 31;
    int g = lane >> 2, tg = lane & 3;
    float* Ps = sm + ASM_PS + w * 16 * PS_STR;

    int tile = 7 - blockIdx.x;
    int h = blockIdx.y, b = blockIdx.z;
    int q0 = tile * 128;
    int bh = b * HH + h;
    int rowg = q0 + 16 * w + g;

    uint32_t smem_u32 = (uint32_t)__cvta_generic_to_shared(sm);

    // stage Q once (tf32-rounded), row-major [q][d]
    const float* Qp = Q + (bh * TT + q0) * DQK;
    for (int i = tid; i < 128 * 24; i += 256) {
        int q = i / 24, dq = i % 24;
        float4 v = *(const float4*)(Qp + q * DQK + dq * 4);
        v.x = to_tf32(v.x); v.y = to_tf32(v.y);
        v.z = to_tf32(v.z); v.w = to_tf32(v.w);
        *(float4*)&Qs[q * QS_STR + dq * 4] = v;
    }

    const float* Kpa[3] = {K1 + bh * TT * DQK, KS + bh * KEEP_ * DQK, KW + bh * TT * DQK};
    const float* Vpa[3] = {V1 + bh * TT * VD, VS + bh * KEEP_ * VD, VW + bh * TT * VD};
    int ncha[3] = {2 * (tile + 1), 4, 2 * (tile + 1)};

    float g_b[3];
    g_b[0] = gate[b * 4 + 0];
    g_b[1] = gate[b * 4 + 1];
    g_b[2] = gate[b * 4 + 2];

    float fout[4][4];
#pragma unroll
    for (int nv = 0; nv < 4; nv++)
#pragma unroll
        for (int r = 0; r < 4; r++) fout[nv][r] = 0.f;

    // ---- staging helper (cp.async, row-major, no conversion) ----
    auto stage = [&](int buf, const float* Kp, const float* Vp, int k0) {
        uint32_t kaddr = smem_u32 + (ASM_KS + buf * KBUF) * 4;
        uint32_t vaddr = smem_u32 + (ASM_VS + buf * VBUF) * 4;
#pragma unroll
        for (int it = 0; it < 6; it++) {
            int i = tid + it * 256;
            int key = i / 24, dq = i % 24;
            cp16(kaddr + (key * KS_STR + dq * 4) * 4, Kp + (k0 + key) * DQK + dq * 4);
        }
#pragma unroll
        for (int it = 0; it < 2; it++) {
            int i = tid + it * 256;
            int key = i >> 3, dq = i & 7;
            cp16(vaddr + (key * VS_STR + dq * 4) * 4, Vp + (k0 + key) * VD + dq * 4);
        }
        CP_COMMIT();
    };

    // prefetch first chunk
    stage(0, Kpa[0], Vpa[0], 0);
    int buf = 0;

    for (int br = 0; br < 3; br++) {
        bool causal = (br != 1);
        int nchunk = ncha[br];

        float m0 = -1e30f, m1 = -1e30f, l0 = 0.f, l1 = 0.f;
        float acc[4][4];
#pragma unroll
        for (int nv = 0; nv < 4; nv++)
#pragma unroll
            for (int r = 0; r < 4; r++) acc[nv][r] = 0.f;

        for (int c = 0; c < nchunk; c++) {
            int k0 = c * 64;
            // next chunk coordinates (lookahead across branch boundary)
            int nbr = br, nc = c + 1;
            if (nc == nchunk) { nbr = br + 1; nc = 0; }

            __syncthreads();   // all warps done reading buf^1 (previous compute)
            if (nbr < 3) {
                stage(buf ^ 1, Kpa[nbr], Vpa[nbr], nc * 64);
                asm volatile("cp.async.wait_group 1;");
            } else {
                asm volatile("cp.async.wait_group 0;");
            }
            __syncthreads();   // staged data visible to all

            const float* Kc = sm + ASM_KS + buf * KBUF;
            const float* Vc = sm + ASM_VS + buf * VBUF;

            // S = Q @ K^T (K consumed raw fp32 -> HW tf32 truncation)
            float s[8][4];
#pragma unroll
            for (int ni = 0; ni < 8; ni++)
#pragma unroll
                for (int r = 0; r < 4; r++) s[ni][r] = 0.f;

#pragma unroll
            for (int ks = 0; ks < 12; ks++) {
                int kb = ks * 8;
                const float* q0p = &Qs[(16 * w + g) * QS_STR + kb];
                const float* q1p = q0p + 8 * QS_STR;
                uint32_t Af[4];
                Af[0] = __float_as_uint(q0p[tg]);
                Af[1] = __float_as_uint(q1p[tg]);
                Af[2] = __float_as_uint(q0p[tg + 4]);
                Af[3] = __float_as_uint(q1p[tg + 4]);
#pragma unroll
                for (int ni = 0; ni < 8; ni++) {
                    uint32_t Bf[2];
                    Bf[0] = __float_as_uint(Kc[(8 * ni + g) * KS_STR + kb + tg]);
                    Bf[1] = __float_as_uint(Kc[(8 * ni + g) * KS_STR + kb + tg + 4]);
                    mma_tf32(s[ni], Af, Bf);
                }
            }

            if (causal && (k0 + 64 > q0)) {
#pragma unroll
                for (int ni = 0; ni < 8; ni++) {
                    int key = k0 + 8 * ni + 2 * tg;
                    if (key > rowg)         s[ni][0] = -1e30f;
                    if (key + 1 > rowg)     s[ni][1] = -1e30f;
                    if (key > rowg + 8)     s[ni][2] = -1e30f;
                    if (key + 1 > rowg + 8) s[ni][3] = -1e30f;
                }
            }

            float cm0 = -1e30f, cm1 = -1e30f;
#pragma unroll
            for (int ni = 0; ni < 8; ni++) {
                cm0 = fmaxf(cm0, fmaxf(s[ni][0], s[ni][1]));
                cm1 = fmaxf(cm1, fmaxf(s[ni][2], s[ni][3]));
            }
            cm0 = fmaxf(cm0, __shfl_xor_sync(0xffffffffu, cm0, 1));
            cm0 = fmaxf(cm0, __shfl_xor_sync(0xffffffffu, cm0, 2));
            cm1 = fmaxf(cm1, __shfl_xor_sync(0xffffffffu, cm1, 1));
            cm1 = fmaxf(cm1, __shfl_xor_sync(0xffffffffu, cm1, 2));

            float nm0 = fmaxf(m0, cm0), nm1 = fmaxf(m1, cm1);
            float al0 = __expf((m0 - nm0) * ATTN_SCALE);
            float al1 = __expf((m1 - nm1) * ATTN_SCALE);
            m0 = nm0; m1 = nm1;

            float sum0 = 0.f, sum1 = 0.f;
#pragma unroll
            for (int ni = 0; ni < 8; ni++) {
                s[ni][0] = __expf((s[ni][0] - m0) * ATTN_SCALE);
                s[ni][1] = __expf((s[ni][1] - m0) * ATTN_SCALE);
                s[ni][2] = __expf((s[ni][2] - m1) * ATTN_SCALE);
                s[ni][3] = __expf((s[ni][3] - m1) * ATTN_SCALE);
                sum0 += s[ni][0] + s[ni][1];
                sum1 += s[ni][2] + s[ni][3];
            }
            sum0 += __shfl_xor_sync(0xffffffffu, sum0, 1);
            sum0 += __shfl_xor_sync(0xffffffffu, sum0, 2);
            sum1 += __shfl_xor_sync(0xffffffffu, sum1, 1);
            sum1 += __shfl_xor_sync(0xffffffffu, sum1, 2);
            l0 = l0 * al0 + sum0;
            l1 = l1 * al1 + sum1;

#pragma unroll
            for (int nv = 0; nv < 4; nv++) {
                acc[nv][0] *= al0; acc[nv][1] *= al0;
                acc[nv][2] *= al1; acc[nv][3] *= al1;
            }

            // write P (tf32-rounded) to warp-private pane (A-fragment layout)
            __syncwarp();
#pragma unroll
            for (int ni = 0; ni < 8; ni++) {
                *(float2*)&Ps[g * PS_STR + 8 * ni + 2 * tg] =
                    make_float2(to_tf32(s[ni][0]), to_tf32(s[ni][1]));
                *(float2*)&Ps[(g + 8) * PS_STR + 8 * ni + 2 * tg] =
                    make_float2(to_tf32(s[ni][2]), to_tf32(s[ni][3]));
            }
            __syncwarp();

            // PV: D(16x32) += P(16x64) @ V(64x32)   (V rounded at consume)
#pragma unroll
            for (int ks = 0; ks < 8; ks++) {
                int kb = ks * 8;
                uint32_t Af[4];
                Af[0] = __float_as_uint(Ps[g * PS_STR + kb + tg]);
                Af[1] = __float_as_uint(Ps[(g + 8) * PS_STR + kb + tg]);
                Af[2] = __float_as_uint(Ps[g * PS_STR + kb + tg + 4]);
                Af[3] = __float_as_uint(Ps[(g + 8) * PS_STR + kb + tg + 4]);
#pragma unroll
                for (int nv = 0; nv < 4; nv++) {
                    uint32_t Bf[2];
                    Bf[0] = f2tf(Vc[(kb + tg) * VS_STR + 8 * nv + g]);
                    Bf[1] = f2tf(Vc[(kb + tg + 4) * VS_STR + 8 * nv + g]);
                    mma_tf32(acc[nv], Af, Bf);
                }
            }
            buf ^= 1;
        }

        float gb = g_b[br];
        float inv0 = gb / l0, inv1 = gb / l1;
#pragma unroll
        for (int nv = 0; nv < 4; nv++) {
            fout[nv][0] += acc[nv][0] * inv0;
            fout[nv][1] += acc[nv][1] * inv0;
            fout[nv][2] += acc[nv][2] * inv1;
            fout[nv][3] += acc[nv][3] * inv1;
        }
    }

#pragma unroll
    for (int nv = 0; nv < 4; nv++) {
        int col = h * VD + 8 * nv + 2 * tg;
        *(float2*)(outp + (b * TT + rowg) * (HH * VD) + col) =
            make_float2(fout[nv][0], fout[nv][1]);
        *(float2*)(outp + (b * TT + rowg + 8) * (HH * VD) + col) =
            make_float2(fout[nv][2], fout[nv][3]);
    }
}

// ---------------- launcher ----------------
extern "C" void kernel_launch(void* const* d_in, const int* in_sizes, int n_in,
                              void* d_out, int out_size) {
    const float* x         = (const float*)d_in[0];
    const float* w_cq      = (const float*)d_in[1];
    const float* g_qnorm   = (const float*)d_in[2];
    const float* w_dq_nope = (const float*)d_in[3];
    const float* w_dq_rope = (const float*)d_in[4];
    const float* w_ckv     = (const float*)d_in[5];
    const float* g_kvnorm  = (const float*)d_in[6];
    const float* w_dk_nope = (const float*)d_in[7];
    const float* w_dv      = (const float*)d_in[8];
    const float* w_krope   = (const float*)d_in[9];
    const float* w_imp     = (const float*)d_in[10];
    const float* w_selk    = (const float*)d_in[11];
    const float* w_selv    = (const float*)d_in[12];
    const float* w_wink    = (const float*)d_in[13];
    const float* w_winv    = (const float*)d_in[14];
    const float* w_gate    = (const float*)d_in[15];
    const float* w_proj    = (const float*)d_in[16];
    float* out = (float*)d_out;

    float* base = nullptr;
    cudaGetSymbolAddress((void**)&base, g_scratch);

    float* wc1    = base + OFF_WC1;
    float* f0     = base + OFF_F0;
    float* qout   = base + OFF_QOUT;
    float* kvout  = base + OFF_KVOUT;
    float* winout = base + OFF_WINOUT;
    float* selx   = base + OFF_SELX;
    float* selkv  = base + OFF_SELKV;
    float* xmean  = base + OFF_XMEAN;
    float* gate   = base + OFF_GATE;
    float* scores = base + OFF_SCORES;
    int*   idx    = (int*)(base + OFF_IDX);
    float* Qb     = base + OFF_Q;
    float* K1b    = base + OFF_K1;
    float* V1b    = base + OFF_V1;
    float* KWb    = base + OFF_KW;
    float* VWb    = base + OFF_VW;
    float* KSb    = base + OFF_KS;
    float* VSb    = base + OFF_VS;
    float* attnb  = base + OFF_ATTN;

    const int M = BB * TT;  // 2048

    cudaFuncSetAttribute(gemm_tc2, cudaFuncAttributeMaxDynamicSharedMemorySize, G2_SMEM);
    cudaFuncSetAttribute(attn_mma, cudaFuncAttributeMaxDynamicSharedMemorySize, ATTN_SMEM);

    // ---- pack only the 3-way small weight concat ----
    pack_cols<<<1024, 256>>>(wc1, 256, w_cq, 96, w_ckv, 32, w_krope, 64);

    // ---- projections (split-B where the concat is 128-aligned) ----
    // f0 = x @ [cq|ckv|krope|0]
    gemm_tc2<<<dim3(2, M / 128), 256, G2_SMEM>>>(x, CC, wc1, 256, 256, wc1, 256,
                                                 f0, 256, M, 256, CC);
    rms2_kernel<<<M, 128>>>(f0, g_qnorm, g_kvnorm);
    // qout = nq @ [dq_nope | dq_rope]
    gemm_tc2<<<dim3(12, M / 128), 256, G2_SMEM>>>(f0, 256, w_dq_nope, 512, 512,
                                                  w_dq_rope, 1024, qout, 1536, M, 1536, 96);
    // kvout = ckv @ [dk_nope | dv]
    gemm_tc2<<<dim3(8, M / 128), 256, G2_SMEM>>>(f0 + 96, 256, w_dk_nope, 512, 512,
                                                 w_dv, 512, kvout, 1024, M, 1024, 32);
    // winout = x @ [wink | winv]
    gemm_tc2<<<dim3(16, M / 128), 256, G2_SMEM>>>(x, CC, w_wink, 1536, 1536,
                                                  w_winv, 512, winout, 2048, M, 2048, CC);

    // ---- gate ----
    xmean_kernel<<<dim3(4, BB), 256>>>(x, xmean);
    gate_kernel<<<BB, 32>>>(xmean, w_gate, gate);

    // ---- selection ----
    scores_kernel<<<M, 256>>>(x, w_imp, scores);
    topk_kernel<<<BB, 1024>>>(scores, idx);
    gather_kernel<<<BB * KEEP_, 256>>>(x, idx, selx);
    // selkv = selx @ [selk | selv]
    gemm_tc2<<<dim3(16, (BB * KEEP_) / 128), 256, G2_SMEM>>>(selx, CC, w_selk, 1536, 1536,
                                                             w_selv, 512, selkv, 2048,
                                                             BB * KEEP_, 2048, CC);

    // ---- assemble ----
    assemble_q_kernel<<<M, 512>>>(qout, Qb);
    assemble_k1v1_kernel<<<M, 512>>>(kvout, f0, K1b, V1b);
    assemble_kv_kernel<<<BB * KEEP_, 512>>>(selkv, KSb, VSb, KEEP_);
    assemble_kv_kernel<<<M, 512>>>(winout, KWb, VWb, TT);

    // ---- attention ----
    attn_mma<<<dim3(8, HH, BB), 256, ATTN_SMEM>>>(Qb, K1b, V1b, KSb, VSb, KWb, VWb, gate, attnb);

    // ---- output projection ----
    gemm_tc2<<<dim3(8, M / 128), 256, G2_SMEM>>>(attnb, HH * VD, w_proj, CC, CC,
                                                 w_proj, CC, out, CC, M, CC, HH * VD);
}

// round 8
// speedup vs baseline: 8.4986x; 1.2964x over previous
#include <cuda_runtime.h>
#include <math.h>
#include <stdint.h>

// ---------------- problem constants ----------------
#define BB 2
#define TT 1024
#define CC 1024
#define HH 16
#define VD 32
#define NOPE_ 32
#define RP 32
#define RD 64
#define DQK 96
#define KEEP_ 256
#define QL 96
#define KVL 32

#define LOG1E4_OVER_32 0.28782313662425572f   // ln(10000)/32
#define ATTN_SCALE 0.10206207261596577f       // 1/sqrt(96)

// ---------------- scratch ----------------
constexpr int OFF_WC1    = 0;                          // [1024][256]
constexpr int OFF_F0     = OFF_WC1    + 1024*256;      // [2048][256]  nq|ckv|krope|pad
constexpr int OFF_QOUT   = OFF_F0     + 2048*256;      // [2048][1536] qnope|qrope
constexpr int OFF_KVOUT  = OFF_QOUT   + 2048*1536;     // [2048][1024] knope|v1
constexpr int OFF_WINOUT = OFF_KVOUT  + 2048*1024;     // [2048][2048] kw|vw
constexpr int OFF_SELX   = OFF_WINOUT + 2048*2048;     // [512][1024]
constexpr int OFF_SELKV  = OFF_SELX   + 512*1024;      // [512][2048]  ks|vs
constexpr int OFF_XMEAN  = OFF_SELKV  + 512*2048;
constexpr int OFF_GATE   = OFF_XMEAN  + BB*CC;
constexpr int OFF_SCORES = OFF_GATE   + 8;
constexpr int OFF_IDX    = OFF_SCORES + BB*TT;
constexpr int OFF_Q      = OFF_IDX    + BB*KEEP_;
constexpr int OFF_K1     = OFF_Q      + BB*HH*TT*DQK;
constexpr int OFF_V1     = OFF_K1     + BB*HH*TT*DQK;
constexpr int OFF_KW     = OFF_V1     + BB*HH*TT*VD;
constexpr int OFF_VW     = OFF_KW     + BB*HH*TT*DQK;
constexpr int OFF_KS     = OFF_VW     + BB*HH*TT*VD;
constexpr int OFF_VS     = OFF_KS     + BB*HH*KEEP_*DQK;
constexpr int OFF_ATTN   = OFF_VS     + BB*HH*KEEP_*VD;
constexpr int SCRATCH_TOTAL = OFF_ATTN + BB*TT*HH*VD;

__device__ __align__(256) float g_scratch[SCRATCH_TOTAL];

// ---------------- tf32 helpers ----------------
__device__ __forceinline__ float to_tf32(float v) {
    uint32_t u;
    asm("cvt.rna.tf32.f32 %0, %1;" : "=r"(u) : "f"(v));
    return __uint_as_float(u);
}

__device__ __forceinline__ uint32_t f2tf(float v) {
    uint32_t u;
    asm("cvt.rna.tf32.f32 %0, %1;" : "=r"(u) : "f"(v));
    return u;
}

__device__ __forceinline__ void split_tf32(float v, uint32_t& hi, uint32_t& lo) {
    asm("cvt.rna.tf32.f32 %0, %1;" : "=r"(hi) : "f"(v));
    float lf = v - __uint_as_float(hi);
    asm("cvt.rna.tf32.f32 %0, %1;" : "=r"(lo) : "f"(lf));
}

__device__ __forceinline__ void mma_tf32(float* d, const uint32_t* a, const uint32_t* b) {
    asm volatile(
        "mma.sync.aligned.m16n8k8.row.col.f32.tf32.tf32.f32 "
        "{%0,%1,%2,%3}, {%4,%5,%6,%7}, {%8,%9}, {%0,%1,%2,%3};\n"
        : "+f"(d[0]), "+f"(d[1]), "+f"(d[2]), "+f"(d[3])
        : "r"(a[0]), "r"(a[1]), "r"(a[2]), "r"(a[3]), "r"(b[0]), "r"(b[1]));
}

__device__ __forceinline__ void cp16(uint32_t dst, const float* src) {
    asm volatile("cp.async.cg.shared.global [%0], [%1], 16;" :: "r"(dst), "l"(src));
}
#define CP_COMMIT() asm volatile("cp.async.commit_group;")

// ---------------- multi-GEMM job table ----------------
struct GemmJob {
    const float* A; int lda;
    const float* B0; int ldb0; int n0;
    const float* B1; int ldb1;
    float* C; int ldc;
    int K;
    int ctaStart;   // first linear CTA id of this job
    int nx;         // N/128
};
struct GemmJobs { GemmJob j[3]; };

constexpr int G2_A = 128 * 20;
constexpr int G2_B = 16 * 136;
constexpr int G2_SMEM = 3 * (G2_A + G2_B) * 4;   // 56832 B

// gemm_multi: up to 3 independent GEMMs in one launch. 128x128 tiles,
// cp.async 3-stage, split-B, tf32 3-pass split-on-consume.
__global__ void __launch_bounds__(256, 2)
gemm_multi(GemmJobs jobs, int njobs) {
    extern __shared__ float sm2[];
    float* As = sm2;
    float* Bs = sm2 + 3 * G2_A;

    // decode job
    int linear = blockIdx.x;
    int ji = njobs - 1;
#pragma unroll
    for (int t = 1; t < 3; t++)
        if (t < njobs && linear < jobs.j[t].ctaStart) { ji = t - 1; break; }
    const GemmJob& J = jobs.j[ji];
    int local = linear - J.ctaStart;
    int bx = local % J.nx, by = local / J.nx;

    const float* A = J.A; int lda = J.lda;
    float* C = J.C; int ldc = J.ldc;
    int K = J.K;
    int row0 = by * 128, col0 = bx * 128;

    const float* Bsrc;
    int ldb;
    if (col0 < J.n0) { Bsrc = J.B0 + col0; ldb = J.ldb0; }
    else             { Bsrc = J.B1 + (col0 - J.n0); ldb = J.ldb1; }

    int tid = threadIdx.x;
    int warp = tid >> 5, lane = tid & 31;
    int g = lane >> 2, tg = lane & 3;
    int wm = warp >> 2, wn = warp & 3;

    uint32_t as_addr = (uint32_t)__cvta_generic_to_shared(As);
    uint32_t bs_addr = (uint32_t)__cvta_generic_to_shared(Bs);

    const float* Ag0 = A + (size_t)(row0 + (tid >> 2)) * lda + (tid & 3) * 4;
    const float* Ag1 = A + (size_t)(row0 + 64 + (tid >> 2)) * lda + (tid & 3) * 4;
    const float* Bg0 = Bsrc + (size_t)(tid >> 5) * ldb + (tid & 31) * 4;
    const float* Bg1 = Bsrc + (size_t)(8 + (tid >> 5)) * ldb + (tid & 31) * 4;
    uint32_t offA0 = (((tid >> 2)) * 20 + (tid & 3) * 4) * 4;
    uint32_t offA1 = (((tid >> 2) + 64) * 20 + (tid & 3) * 4) * 4;
    uint32_t offB0 = ((tid >> 5) * 136 + (tid & 31) * 4) * 4;
    uint32_t offB1 = ((8 + (tid >> 5)) * 136 + (tid & 31) * 4) * 4;

    float d[4][4][4];
#pragma unroll
    for (int mi = 0; mi < 4; mi++)
#pragma unroll
        for (int ni = 0; ni < 4; ni++)
#pragma unroll
            for (int r = 0; r < 4; r++) d[mi][ni][r] = 0.f;

    int nk = K / 16;

    {
        cp16(as_addr + offA0, Ag0);
        cp16(as_addr + offA1, Ag1);
        cp16(bs_addr + offB0, Bg0);
        cp16(bs_addr + offB1, Bg1);
        CP_COMMIT();
    }
    if (nk > 1) {
        uint32_t ab = as_addr + G2_A * 4, bb = bs_addr + G2_B * 4;
        cp16(ab + offA0, Ag0 + 16);
        cp16(ab + offA1, Ag1 + 16);
        cp16(bb + offB0, Bg0 + (size_t)16 * ldb);
        cp16(bb + offB1, Bg1 + (size_t)16 * ldb);
        CP_COMMIT();
    }

    for (int kt = 0; kt < nk; kt++) {
        if (kt + 1 < nk) { asm volatile("cp.async.wait_group 1;"); }
        else             { asm volatile("cp.async.wait_group 0;"); }
        __syncthreads();

        if (kt + 2 < nk) {
            int s = (kt + 2) % 3;
            int k0 = (kt + 2) * 16;
            uint32_t ab = as_addr + s * G2_A * 4, bb = bs_addr + s * G2_B * 4;
            cp16(ab + offA0, Ag0 + k0);
            cp16(ab + offA1, Ag1 + k0);
            cp16(bb + offB0, Bg0 + (size_t)k0 * ldb);
            cp16(bb + offB1, Bg1 + (size_t)k0 * ldb);
            CP_COMMIT();
        }

        const float* Ac = As + (kt % 3) * G2_A;
        const float* Bc = Bs + (kt % 3) * G2_B;

#pragma unroll
        for (int ks = 0; ks < 16; ks += 8) {
            uint32_t bh[4][2], bl[4][2];
#pragma unroll
            for (int ni = 0; ni < 4; ni++) {
                int c = wn * 32 + ni * 8 + g;
                split_tf32(Bc[(ks + tg) * 136 + c], bh[ni][0], bl[ni][0]);
                split_tf32(Bc[(ks + tg + 4) * 136 + c], bh[ni][1], bl[ni][1]);
            }
#pragma unroll
            for (int mi = 0; mi < 4; mi++) {
                int r = wm * 64 + mi * 16;
                uint32_t ah[4], al[4];
                split_tf32(Ac[(r + g) * 20 + ks + tg], ah[0], al[0]);
                split_tf32(Ac[(r + 8 + g) * 20 + ks + tg], ah[1], al[1]);
                split_tf32(Ac[(r + g) * 20 + ks + tg + 4], ah[2], al[2]);
                split_tf32(Ac[(r + 8 + g) * 20 + ks + tg + 4], ah[3], al[3]);
#pragma unroll
                for (int ni = 0; ni < 4; ni++) {
                    mma_tf32(d[mi][ni], ah, bh[ni]);
                    mma_tf32(d[mi][ni], ah, bl[ni]);
                    mma_tf32(d[mi][ni], al, bh[ni]);
                }
            }
        }
    }

#pragma unroll
    for (int mi = 0; mi < 4; mi++) {
#pragma unroll
        for (int ni = 0; ni < 4; ni++) {
            int r = row0 + wm * 64 + mi * 16 + g;
            int c = col0 + wn * 32 + ni * 8 + 2 * tg;
            *(float2*)(C + (size_t)r * ldc + c) = make_float2(d[mi][ni][0], d[mi][ni][1]);
            *(float2*)(C + (size_t)(r + 8) * ldc + c) = make_float2(d[mi][ni][2], d[mi][ni][3]);
        }
    }
}

// ---------------- fused prep: scores | xmean | pack_wc1 ----------------
// blocks 0..2047: scores row; 2048..2055: xmean; 2056..3079: pack wc1 row
__global__ void prep_kernel(const float* __restrict__ x, const float* __restrict__ w_imp,
                            float* __restrict__ scores, float* __restrict__ xmean,
                            const float* __restrict__ w_cq, const float* __restrict__ w_ckv,
                            const float* __restrict__ w_krope, float* __restrict__ wc1) {
    int blk = blockIdx.x, tid = threadIdx.x;   // 256 threads
    if (blk < 2048) {
        __shared__ float s8[8];
        int row = blk;
        float s = 0.f;
        for (int c = tid; c < CC; c += 256) s += x[row * CC + c] * w_imp[c];
#pragma unroll
        for (int o = 16; o > 0; o >>= 1) s += __shfl_xor_sync(0xffffffffu, s, o);
        if ((tid & 31) == 0) s8[tid >> 5] = s;
        __syncthreads();
        if (tid == 0) {
            float t = 0.f;
#pragma unroll
            for (int i = 0; i < 8; i++) t += s8[i];
            scores[row] = t;
        }
    } else if (blk < 2056) {
        int i = blk - 2048;
        int b = i >> 2;
        int c = (i & 3) * 256 + tid;
        float s = 0.f;
        for (int t = 0; t < TT; t++) s += x[(b * TT + t) * CC + c];
        xmean[b * CC + c] = s * (1.f / (float)TT);
    } else {
        int k = blk - 2056;   // 0..1023
        float v;
        if (tid < 96) v = w_cq[k * 96 + tid];
        else if (tid < 128) v = w_ckv[k * 32 + (tid - 96)];
        else if (tid < 192) v = w_krope[k * 64 + (tid - 128)];
        else v = 0.f;
        wc1[k * 256 + tid] = v;
    }
}

// ---------------- fused topk + gate ----------------
// blocks 0..1: topk(batch blk); blocks 2..3: gate(batch blk-2). 1024 threads.
__global__ void topk_gate_kernel(const float* __restrict__ scores, int* __restrict__ idxout,
                                 const float* __restrict__ xmean, const float* __restrict__ wg,
                                 float* __restrict__ gate) {
    int blk = blockIdx.x, tid = threadIdx.x;
    if (blk < 2) {
        __shared__ float sv[1024];
        __shared__ int si[1024];
        __shared__ int ti[256];
        int b = blk;
        sv[tid] = scores[b * TT + tid];
        si[tid] = tid;
        __syncthreads();
        for (int k = 2; k <= 1024; k <<= 1) {
            for (int j = k >> 1; j > 0; j >>= 1) {
                int ixj = tid ^ j;
                if (ixj > tid) {
                    bool desc = ((tid & k) == 0);
                    float va = sv[tid], vb = sv[ixj];
                    int ia = si[tid], ib = si[ixj];
                    bool agtb = (va > vb) || (va == vb && ia < ib);
                    if (desc ? !agtb : agtb) {
                        sv[tid] = vb; sv[ixj] = va;
                        si[tid] = ib; si[ixj] = ia;
                    }
                }
                __syncthreads();
            }
        }
        if (tid < 256) ti[tid] = si[tid];
        __syncthreads();
        for (int k = 2; k <= 256; k <<= 1) {
            for (int j = k >> 1; j > 0; j >>= 1) {
                int ixj = tid ^ j;
                if (tid < 256 && ixj > tid) {
                    bool asc = ((tid & k) == 0);
                    int ia = ti[tid], ib = ti[ixj];
                    if (asc ? (ia > ib) : (ia < ib)) { ti[tid] = ib; ti[ixj] = ia; }
                }
                __syncthreads();
            }
        }
        if (tid < 256) idxout[b * KEEP_ + tid] = ti[tid];
    } else {
        int b = blk - 2;
        __shared__ float sg[3];
        int w = tid >> 5, lane = tid & 31;
        if (w < 3) {
            float s = 0.f;
            for (int c = lane; c < CC; c += 32) s += xmean[b * CC + c] * wg[c * 3 + w];
#pragma unroll
            for (int o = 16; o > 0; o >>= 1) s += __shfl_xor_sync(0xffffffffu, s, o);
            if (lane == 0) sg[w] = s;
        }
        __syncthreads();
        if (tid == 0) {
            float m = fmaxf(sg[0], fmaxf(sg[1], sg[2]));
            float e0 = expf(sg[0] - m), e1 = expf(sg[1] - m), e2 = expf(sg[2] - m);
            float inv = 1.f / (e0 + e1 + e2);
            gate[b * 4 + 0] = e0 * inv;
            gate[b * 4 + 1] = e1 * inv;
            gate[b * 4 + 2] = e2 * inv;
        }
    }
}

// ---------------- gather ----------------
__global__ void gather_kernel(const float* __restrict__ x, const int* __restrict__ idx,
                              float* __restrict__ selx) {
    int row = blockIdx.x;
    int b = row >> 8;
    int t = idx[row];
    for (int c = threadIdx.x; c < CC; c += 256)
        selx[row * CC + c] = x[(b * TT + t) * CC + c];
}

// ---------------- fused RMS norm on packed f0 ----------------
__global__ void rms2_kernel(float* __restrict__ f0,
                            const float* __restrict__ gq, const float* __restrict__ gkv) {
    int row = blockIdx.x, tid = threadIdx.x;
    float* dd = f0 + row * 256;
    __shared__ float s4[4];
    float v = (tid < 96) ? dd[tid] : 0.f;
    float sq = v * v;
#pragma unroll
    for (int o = 16; o > 0; o >>= 1) sq += __shfl_xor_sync(0xffffffffu, sq, o);
    if ((tid & 31) == 0) s4[tid >> 5] = sq;
    __syncthreads();
    float tot = s4[0] + s4[1] + s4[2] + s4[3];
    float sc = rsqrtf(tot / 96.f + 1e-6f);
    if (tid < 96) dd[tid] = v * sc * gq[tid];
    __syncthreads();
    if (tid < 32) {
        float v2 = dd[96 + tid];
        float sq2 = v2 * v2;
#pragma unroll
        for (int o = 16; o > 0; o >>= 1) sq2 += __shfl_xor_sync(0xffffffffu, sq2, o);
        float sc2 = rsqrtf(sq2 / 32.f + 1e-6f);
        dd[96 + tid] = v2 * sc2 * gkv[tid];
    }
}

// ---------------- fused assembles (rope + layout), 512 threads ----------------
// blocks 0..2047: Q; 2048..4095: K1/V1; 4096..4607: KS/VS; 4608..6655: KW/VW
__global__ void assemble_all_kernel(const float* __restrict__ qout,
                                    const float* __restrict__ kvout,
                                    const float* __restrict__ f0,
                                    const float* __restrict__ selkv,
                                    const float* __restrict__ winout,
                                    float* __restrict__ Q,
                                    float* __restrict__ K1, float* __restrict__ V1,
                                    float* __restrict__ KSb, float* __restrict__ VSb,
                                    float* __restrict__ KWb, float* __restrict__ VWb) {
    int blk = blockIdx.x;
    int j = threadIdx.x;
    int h = j >> 5, d = j & 31;
    float f = expf(-LOG1E4_OVER_32 * (float)d);

    if (blk < 2048) {
        int row = blk;
        int b = row >> 10, t = row & 1023;
        int qb = (((b * HH + h) * TT) + t) * DQK;
        Q[qb + d] = qout[row * 1536 + j];
        float x1 = qout[row * 1536 + 512 + h * RD + d];
        float x2 = qout[row * 1536 + 512 + h * RD + RP + d];
        float sn, cs;
        sincosf((float)t * f, &sn, &cs);
        Q[qb + NOPE_ + d] = x1 * cs - x2 * sn;
        Q[qb + NOPE_ + RP + d] = x1 * sn + x2 * cs;
    } else if (blk < 4096) {
        int row = blk - 2048;
        int b = row >> 10, t = row & 1023;
        int kb = (((b * HH + h) * TT) + t) * DQK;
        K1[kb + d] = kvout[row * 1024 + j];
        float x1 = f0[row * 256 + 128 + d] * 0.0625f;
        float x2 = f0[row * 256 + 128 + RP + d] * 0.0625f;
        float sn, cs;
        sincosf((float)t * f, &sn, &cs);
        K1[kb + NOPE_ + d] = x1 * cs - x2 * sn;
        K1[kb + NOPE_ + RP + d] = x1 * sn + x2 * cs;
        V1[(((b * HH + h) * TT) + t) * VD + d] = kvout[row * 1024 + 512 + j];
    } else {
        const float* raw;
        float* K;
        float* V;
        int row, S;
        if (blk < 4608) { row = blk - 4096; S = KEEP_; raw = selkv; K = KSb; V = VSb; }
        else            { row = blk - 4608; S = TT;    raw = winout; K = KWb; V = VWb; }
        int b = row / S, pos = row % S;
        float nope = raw[row * 2048 + h * DQK + d];
        float x1 = raw[row * 2048 + h * DQK + NOPE_ + d];
        float x2 = raw[row * 2048 + h * DQK + NOPE_ + RP + d];
        float sn, cs;
        sincosf((float)pos * f, &sn, &cs);
        int kb = (((b * HH + h) * S) + pos) * DQK;
        K[kb + d] = nope;
        K[kb + NOPE_ + d] = x1 * cs - x2 * sn;
        K[kb + NOPE_ + RP + d] = x1 * sn + x2 * cs;
        V[(((b * HH + h) * S) + pos) * VD + d] = raw[row * 2048 + 1536 + h * VD + d];
    }
}

// ---------------- pipelined tf32 MMA flash attention ----------------
constexpr int QS_STR = 100;
constexpr int KS_STR = 100;
constexpr int VS_STR = 40;
constexpr int PS_STR = 68;
constexpr int KBUF = 64 * KS_STR;
constexpr int VBUF = 64 * VS_STR;
constexpr int ASM_QS = 0;
constexpr int ASM_KS = 128 * QS_STR;
constexpr int ASM_VS = ASM_KS + 2 * KBUF;
constexpr int ASM_PS = ASM_VS + 2 * VBUF;
constexpr int ATTN_SMEM = (ASM_PS + 8 * 16 * PS_STR) * 4;

__global__ void __launch_bounds__(256)
attn_mma(const float* __restrict__ Q,
         const float* __restrict__ K1, const float* __restrict__ V1,
         const float* __restrict__ KS, const float* __restrict__ VS,
         const float* __restrict__ KW, const float* __restrict__ VW,
         const float* __restrict__ gate, float* __restrict__ outp) {
    extern __shared__ float sm[];
    float* Qs = sm + ASM_QS;

    int tid = threadIdx.x;
    int w = tid >> 5, lane = tid & 31;
    int g = lane >> 2, tg = lane & 3;
    float* Ps = sm + ASM_PS + w * 16 * PS_STR;

    int tile = 7 - blockIdx.x;
    int h = blockIdx.y, b = blockIdx.z;
    int q0 = tile * 128;
    int bh = b * HH + h;
    int rowg = q0 + 16 * w + g;

    uint32_t smem_u32 = (uint32_t)__cvta_generic_to_shared(sm);

    const float* Qp = Q + (bh * TT + q0) * DQK;
    for (int i = tid; i < 128 * 24; i += 256) {
        int q = i / 24, dq = i % 24;
        float4 v = *(const float4*)(Qp + q * DQK + dq * 4);
        v.x = to_tf32(v.x); v.y = to_tf32(v.y);
        v.z = to_tf32(v.z); v.w = to_tf32(v.w);
        *(float4*)&Qs[q * QS_STR + dq * 4] = v;
    }

    const float* Kpa[3] = {K1 + bh * TT * DQK, KS + bh * KEEP_ * DQK, KW + bh * TT * DQK};
    const float* Vpa[3] = {V1 + bh * TT * VD, VS + bh * KEEP_ * VD, VW + bh * TT * VD};
    int ncha[3] = {2 * (tile + 1), 4, 2 * (tile + 1)};

    float g_b[3];
    g_b[0] = gate[b * 4 + 0];
    g_b[1] = gate[b * 4 + 1];
    g_b[2] = gate[b * 4 + 2];

    float fout[4][4];
#pragma unroll
    for (int nv = 0; nv < 4; nv++)
#pragma unroll
        for (int r = 0; r < 4; r++) fout[nv][r] = 0.f;

    auto stage = [&](int buf, const float* Kp, const float* Vp, int k0) {
        uint32_t kaddr = smem_u32 + (ASM_KS + buf * KBUF) * 4;
        uint32_t vaddr = smem_u32 + (ASM_VS + buf * VBUF) * 4;
#pragma unroll
        for (int it = 0; it < 6; it++) {
            int i = tid + it * 256;
            int key = i / 24, dq = i % 24;
            cp16(kaddr + (key * KS_STR + dq * 4) * 4, Kp + (k0 + key) * DQK + dq * 4);
        }
#pragma unroll
        for (int it = 0; it < 2; it++) {
            int i = tid + it * 256;
            int key = i >> 3, dq = i & 7;
            cp16(vaddr + (key * VS_STR + dq * 4) * 4, Vp + (k0 + key) * VD + dq * 4);
        }
        CP_COMMIT();
    };

    stage(0, Kpa[0], Vpa[0], 0);
    int buf = 0;

    for (int br = 0; br < 3; br++) {
        bool causal = (br != 1);
        int nchunk = ncha[br];

        float m0 = -1e30f, m1 = -1e30f, l0 = 0.f, l1 = 0.f;
        float acc[4][4];
#pragma unroll
        for (int nv = 0; nv < 4; nv++)
#pragma unroll
            for (int r = 0; r < 4; r++) acc[nv][r] = 0.f;

        for (int c = 0; c < nchunk; c++) {
            int k0 = c * 64;
            int nbr = br, nc = c + 1;
            if (nc == nchunk) { nbr = br + 1; nc = 0; }

            __syncthreads();
            if (nbr < 3) {
                stage(buf ^ 1, Kpa[nbr], Vpa[nbr], nc * 64);
                asm volatile("cp.async.wait_group 1;");
            } else {
                asm volatile("cp.async.wait_group 0;");
            }
            __syncthreads();

            const float* Kc = sm + ASM_KS + buf * KBUF;
            const float* Vc = sm + ASM_VS + buf * VBUF;

            float s[8][4];
#pragma unroll
            for (int ni = 0; ni < 8; ni++)
#pragma unroll
                for (int r = 0; r < 4; r++) s[ni][r] = 0.f;

#pragma unroll
            for (int ks = 0; ks < 12; ks++) {
                int kb = ks * 8;
                const float* q0p = &Qs[(16 * w + g) * QS_STR + kb];
                const float* q1p = q0p + 8 * QS_STR;
                uint32_t Af[4];
                Af[0] = __float_as_uint(q0p[tg]);
                Af[1] = __float_as_uint(q1p[tg]);
                Af[2] = __float_as_uint(q0p[tg + 4]);
                Af[3] = __float_as_uint(q1p[tg + 4]);
#pragma unroll
                for (int ni = 0; ni < 8; ni++) {
                    uint32_t Bf[2];
                    Bf[0] = __float_as_uint(Kc[(8 * ni + g) * KS_STR + kb + tg]);
                    Bf[1] = __float_as_uint(Kc[(8 * ni + g) * KS_STR + kb + tg + 4]);
                    mma_tf32(s[ni], Af, Bf);
                }
            }

            if (causal && (k0 + 64 > q0)) {
#pragma unroll
                for (int ni = 0; ni < 8; ni++) {
                    int key = k0 + 8 * ni + 2 * tg;
                    if (key > rowg)         s[ni][0] = -1e30f;
                    if (key + 1 > rowg)     s[ni][1] = -1e30f;
                    if (key > rowg + 8)     s[ni][2] = -1e30f;
                    if (key + 1 > rowg + 8) s[ni][3] = -1e30f;
                }
            }

            float cm0 = -1e30f, cm1 = -1e30f;
#pragma unroll
            for (int ni = 0; ni < 8; ni++) {
                cm0 = fmaxf(cm0, fmaxf(s[ni][0], s[ni][1]));
                cm1 = fmaxf(cm1, fmaxf(s[ni][2], s[ni][3]));
            }
            cm0 = fmaxf(cm0, __shfl_xor_sync(0xffffffffu, cm0, 1));
            cm0 = fmaxf(cm0, __shfl_xor_sync(0xffffffffu, cm0, 2));
            cm1 = fmaxf(cm1, __shfl_xor_sync(0xffffffffu, cm1, 1));
            cm1 = fmaxf(cm1, __shfl_xor_sync(0xffffffffu, cm1, 2));

            float nm0 = fmaxf(m0, cm0), nm1 = fmaxf(m1, cm1);
            float al0 = __expf((m0 - nm0) * ATTN_SCALE);
            float al1 = __expf((m1 - nm1) * ATTN_SCALE);
            m0 = nm0; m1 = nm1;

            float sum0 = 0.f, sum1 = 0.f;
#pragma unroll
            for (int ni = 0; ni < 8; ni++) {
                s[ni][0] = __expf((s[ni][0] - m0) * ATTN_SCALE);
                s[ni][1] = __expf((s[ni][1] - m0) * ATTN_SCALE);
                s[ni][2] = __expf((s[ni][2] - m1) * ATTN_SCALE);
                s[ni][3] = __expf((s[ni][3] - m1) * ATTN_SCALE);
                sum0 += s[ni][0] + s[ni][1];
                sum1 += s[ni][2] + s[ni][3];
            }
            sum0 += __shfl_xor_sync(0xffffffffu, sum0, 1);
            sum0 += __shfl_xor_sync(0xffffffffu, sum0, 2);
            sum1 += __shfl_xor_sync(0xffffffffu, sum1, 1);
            sum1 += __shfl_xor_sync(0xffffffffu, sum1, 2);
            l0 = l0 * al0 + sum0;
            l1 = l1 * al1 + sum1;

#pragma unroll
            for (int nv = 0; nv < 4; nv++) {
                acc[nv][0] *= al0; acc[nv][1] *= al0;
                acc[nv][2] *= al1; acc[nv][3] *= al1;
            }

            __syncwarp();
#pragma unroll
            for (int ni = 0; ni < 8; ni++) {
                *(float2*)&Ps[g * PS_STR + 8 * ni + 2 * tg] =
                    make_float2(to_tf32(s[ni][0]), to_tf32(s[ni][1]));
                *(float2*)&Ps[(g + 8) * PS_STR + 8 * ni + 2 * tg] =
                    make_float2(to_tf32(s[ni][2]), to_tf32(s[ni][3]));
            }
            __syncwarp();

#pragma unroll
            for (int ks = 0; ks < 8; ks++) {
                int kb = ks * 8;
                uint32_t Af[4];
                Af[0] = __float_as_uint(Ps[g * PS_STR + kb + tg]);
                Af[1] = __float_as_uint(Ps[(g + 8) * PS_STR + kb + tg]);
                Af[2] = __float_as_uint(Ps[g * PS_STR + kb + tg + 4]);
                Af[3] = __float_as_uint(Ps[(g + 8) * PS_STR + kb + tg + 4]);
#pragma unroll
                for (int nv = 0; nv < 4; nv++) {
                    uint32_t Bf[2];
                    Bf[0] = f2tf(Vc[(kb + tg) * VS_STR + 8 * nv + g]);
                    Bf[1] = f2tf(Vc[(kb + tg + 4) * VS_STR + 8 * nv + g]);
                    mma_tf32(acc[nv], Af, Bf);
                }
            }
            buf ^= 1;
        }

        float gb = g_b[br];
        float inv0 = gb / l0, inv1 = gb / l1;
#pragma unroll
        for (int nv = 0; nv < 4; nv++) {
            fout[nv][0] += acc[nv][0] * inv0;
            fout[nv][1] += acc[nv][1] * inv0;
            fout[nv][2] += acc[nv][2] * inv1;
            fout[nv][3] += acc[nv][3] * inv1;
        }
    }

#pragma unroll
    for (int nv = 0; nv < 4; nv++) {
        int col = h * VD + 8 * nv + 2 * tg;
        *(float2*)(outp + (b * TT + rowg) * (HH * VD) + col) =
            make_float2(fout[nv][0], fout[nv][1]);
        *(float2*)(outp + (b * TT + rowg + 8) * (HH * VD) + col) =
            make_float2(fout[nv][2], fout[nv][3]);
    }
}

// ---------------- launcher ----------------
extern "C" void kernel_launch(void* const* d_in, const int* in_sizes, int n_in,
                              void* d_out, int out_size) {
    const float* x         = (const float*)d_in[0];
    const float* w_cq      = (const float*)d_in[1];
    const float* g_qnorm   = (const float*)d_in[2];
    const float* w_dq_nope = (const float*)d_in[3];
    const float* w_dq_rope = (const float*)d_in[4];
    const float* w_ckv     = (const float*)d_in[5];
    const float* g_kvnorm  = (const float*)d_in[6];
    const float* w_dk_nope = (const float*)d_in[7];
    const float* w_dv      = (const float*)d_in[8];
    const float* w_krope   = (const float*)d_in[9];
    const float* w_imp     = (const float*)d_in[10];
    const float* w_selk    = (const float*)d_in[11];
    const float* w_selv    = (const float*)d_in[12];
    const float* w_wink    = (const float*)d_in[13];
    const float* w_winv    = (const float*)d_in[14];
    const float* w_gate    = (const float*)d_in[15];
    const float* w_proj    = (const float*)d_in[16];
    float* out = (float*)d_out;

    float* base = nullptr;
    cudaGetSymbolAddress((void**)&base, g_scratch);

    float* wc1    = base + OFF_WC1;
    float* f0     = base + OFF_F0;
    float* qout   = base + OFF_QOUT;
    float* kvout  = base + OFF_KVOUT;
    float* winout = base + OFF_WINOUT;
    float* selx   = base + OFF_SELX;
    float* selkv  = base + OFF_SELKV;
    float* xmean  = base + OFF_XMEAN;
    float* gate   = base + OFF_GATE;
    float* scores = base + OFF_SCORES;
    int*   idx    = (int*)(base + OFF_IDX);
    float* Qb     = base + OFF_Q;
    float* K1b    = base + OFF_K1;
    float* V1b    = base + OFF_V1;
    float* KWb    = base + OFF_KW;
    float* VWb    = base + OFF_VW;
    float* KSb    = base + OFF_KS;
    float* VSb    = base + OFF_VS;
    float* attnb  = base + OFF_ATTN;

    const int M = BB * TT;  // 2048

    cudaFuncSetAttribute(gemm_multi, cudaFuncAttributeMaxDynamicSharedMemorySize, G2_SMEM);
    cudaFuncSetAttribute(attn_mma, cudaFuncAttributeMaxDynamicSharedMemorySize, ATTN_SMEM);

    // 1) prep: scores | xmean | pack wc1
    prep_kernel<<<3080, 256>>>(x, w_imp, scores, xmean, w_cq, w_ckv, w_krope, wc1);

    // 2) topk + gate
    topk_gate_kernel<<<4, 1024>>>(scores, idx, xmean, w_gate, gate);

    // 3) gather
    gather_kernel<<<BB * KEEP_, 256>>>(x, idx, selx);

    // 4) mega GEMM 1: winout | f0 | selkv
    {
        GemmJobs jobs;
        // winout = x @ [wink|winv]   (16x16 = 256 CTAs)
        jobs.j[0] = {x, CC, w_wink, 1536, 1536, w_winv, 512, winout, 2048, CC, 0, 16};
        // f0 = x @ wc1               (2x16 = 32 CTAs)
        jobs.j[1] = {x, CC, wc1, 256, 256, wc1, 256, f0, 256, CC, 256, 2};
        // selkv = selx @ [selk|selv] (16x4 = 64 CTAs)
        jobs.j[2] = {selx, CC, w_selk, 1536, 1536, w_selv, 512, selkv, 2048, CC, 288, 16};
        gemm_multi<<<352, 256, G2_SMEM>>>(jobs, 3);
    }

    // 5) rms on f0
    rms2_kernel<<<M, 128>>>(f0, g_qnorm, g_kvnorm);

    // 6) mega GEMM 2: qout | kvout
    {
        GemmJobs jobs;
        // qout = nq @ [dq_nope|dq_rope]  (12x16 = 192 CTAs)
        jobs.j[0] = {f0, 256, w_dq_nope, 512, 512, w_dq_rope, 1024, qout, 1536, 96, 0, 12};
        // kvout = ckv @ [dk_nope|dv]     (8x16 = 128 CTAs)
        jobs.j[1] = {f0 + 96, 256, w_dk_nope, 512, 512, w_dv, 512, kvout, 1024, 32, 192, 8};
        jobs.j[2] = jobs.j[1];
        gemm_multi<<<320, 256, G2_SMEM>>>(jobs, 2);
    }

    // 7) all assembles
    assemble_all_kernel<<<6656, 512>>>(qout, kvout, f0, selkv, winout,
                                       Qb, K1b, V1b, KSb, VSb, KWb, VWb);

    // 8) attention
    attn_mma<<<dim3(8, HH, BB), 256, ATTN_SMEM>>>(Qb, K1b, V1b, KSb, VSb, KWb, VWb, gate, attnb);

    // 9) output projection
    {
        GemmJobs jobs;
        jobs.j[0] = {attnb, HH * VD, w_proj, CC, CC, w_proj, CC, out, CC, HH * VD, 0, 8};
        jobs.j[1] = jobs.j[0];
        jobs.j[2] = jobs.j[0];
        gemm_multi<<<128, 256, G2_SMEM>>>(jobs, 1);
    }
}

// round 9
// speedup vs baseline: 11.9932x; 1.4112x over previous
#include <cuda_runtime.h>
#include <math.h>
#include <stdint.h>

// ---------------- problem constants ----------------
#define BB 2
#define TT 1024
#define CC 1024
#define HH 16
#define VD 32
#define NOPE_ 32
#define RP 32
#define RD 64
#define DQK 96
#define KEEP_ 256
#define QL 96
#define KVL 32

#define LOG1E4_OVER_32 0.28782313662425572f   // ln(10000)/32
#define ATTN_SCALE 0.10206207261596577f       // 1/sqrt(96)

// ---------------- scratch ----------------
constexpr int OFF_WC1    = 0;                          // [1024][256]
constexpr int OFF_F0     = OFF_WC1    + 1024*256;      // [2048][256]  nq|ckv|krope|pad
constexpr int OFF_QOUT   = OFF_F0     + 2048*256;      // [2048][1536] qnope|qrope
constexpr int OFF_KVOUT  = OFF_QOUT   + 2048*1536;     // [2048][1024] knope|v1
constexpr int OFF_WINOUT = OFF_KVOUT  + 2048*1024;     // [2048][2048] kw|vw
constexpr int OFF_SELX   = OFF_WINOUT + 2048*2048;     // [512][1024]
constexpr int OFF_SELKV  = OFF_SELX   + 512*1024;      // [512][2048]  ks|vs
constexpr int OFF_XMEAN  = OFF_SELKV  + 512*2048;
constexpr int OFF_GATE   = OFF_XMEAN  + BB*CC;
constexpr int OFF_SCORES = OFF_GATE   + 8;
constexpr int OFF_IDX    = OFF_SCORES + BB*TT;
constexpr int OFF_Q      = OFF_IDX    + BB*KEEP_;
constexpr int OFF_K1     = OFF_Q      + BB*HH*TT*DQK;
constexpr int OFF_V1     = OFF_K1     + BB*HH*TT*DQK;
constexpr int OFF_KW     = OFF_V1     + BB*HH*TT*VD;
constexpr int OFF_VW     = OFF_KW     + BB*HH*TT*DQK;
constexpr int OFF_KS     = OFF_VW     + BB*HH*TT*VD;
constexpr int OFF_VS     = OFF_KS     + BB*HH*KEEP_*DQK;
constexpr int OFF_ATTN   = OFF_VS     + BB*HH*KEEP_*VD;
constexpr int SCRATCH_TOTAL = OFF_ATTN + BB*TT*HH*VD;

__device__ __align__(256) float g_scratch[SCRATCH_TOTAL];

// ---------------- tf32 helpers ----------------
__device__ __forceinline__ float to_tf32(float v) {
    uint32_t u;
    asm("cvt.rna.tf32.f32 %0, %1;" : "=r"(u) : "f"(v));
    return __uint_as_float(u);
}

__device__ __forceinline__ uint32_t f2tf(float v) {
    uint32_t u;
    asm("cvt.rna.tf32.f32 %0, %1;" : "=r"(u) : "f"(v));
    return u;
}

__device__ __forceinline__ void mma_tf32(float* d, const uint32_t* a, const uint32_t* b) {
    asm volatile(
        "mma.sync.aligned.m16n8k8.row.col.f32.tf32.tf32.f32 "
        "{%0,%1,%2,%3}, {%4,%5,%6,%7}, {%8,%9}, {%0,%1,%2,%3};\n"
        : "+f"(d[0]), "+f"(d[1]), "+f"(d[2]), "+f"(d[3])
        : "r"(a[0]), "r"(a[1]), "r"(a[2]), "r"(a[3]), "r"(b[0]), "r"(b[1]));
}

__device__ __forceinline__ void cp16(uint32_t dst, const float* src) {
    asm volatile("cp.async.cg.shared.global [%0], [%1], 16;" :: "r"(dst), "l"(src));
}
#define CP_COMMIT() asm volatile("cp.async.commit_group;")

// ---------------- multi-GEMM job table ----------------
struct GemmJob {
    const float* A; int lda;
    const float* B0; int ldb0; int n0;
    const float* B1; int ldb1;
    float* C; int ldc;
    int K;
    int ctaStart;   // first linear CTA id of this job
    int nx;         // N/128
};
struct GemmJobs { GemmJob j[3]; };

constexpr int G2_A = 128 * 20;
constexpr int G2_B = 16 * 136;
constexpr int G2_SMEM = 3 * (G2_A + G2_B) * 4;   // 56832 B

// gemm_multi: up to 3 independent GEMMs in one launch. 128x128 tiles,
// cp.async 3-stage, split-B, SINGLE-PASS tf32 (cvt.rna on consume).
__global__ void __launch_bounds__(256, 2)
gemm_multi(GemmJobs jobs, int njobs) {
    extern __shared__ float sm2[];
    float* As = sm2;
    float* Bs = sm2 + 3 * G2_A;

    // decode job
    int linear = blockIdx.x;
    int ji = njobs - 1;
#pragma unroll
    for (int t = 1; t < 3; t++)
        if (t < njobs && linear < jobs.j[t].ctaStart) { ji = t - 1; break; }
    const GemmJob& J = jobs.j[ji];
    int local = linear - J.ctaStart;
    int bx = local % J.nx, by = local / J.nx;

    const float* A = J.A; int lda = J.lda;
    float* C = J.C; int ldc = J.ldc;
    int K = J.K;
    int row0 = by * 128, col0 = bx * 128;

    const float* Bsrc;
    int ldb;
    if (col0 < J.n0) { Bsrc = J.B0 + col0; ldb = J.ldb0; }
    else             { Bsrc = J.B1 + (col0 - J.n0); ldb = J.ldb1; }

    int tid = threadIdx.x;
    int warp = tid >> 5, lane = tid & 31;
    int g = lane >> 2, tg = lane & 3;
    int wm = warp >> 2, wn = warp & 3;

    uint32_t as_addr = (uint32_t)__cvta_generic_to_shared(As);
    uint32_t bs_addr = (uint32_t)__cvta_generic_to_shared(Bs);

    const float* Ag0 = A + (size_t)(row0 + (tid >> 2)) * lda + (tid & 3) * 4;
    const float* Ag1 = A + (size_t)(row0 + 64 + (tid >> 2)) * lda + (tid & 3) * 4;
    const float* Bg0 = Bsrc + (size_t)(tid >> 5) * ldb + (tid & 31) * 4;
    const float* Bg1 = Bsrc + (size_t)(8 + (tid >> 5)) * ldb + (tid & 31) * 4;
    uint32_t offA0 = (((tid >> 2)) * 20 + (tid & 3) * 4) * 4;
    uint32_t offA1 = (((tid >> 2) + 64) * 20 + (tid & 3) * 4) * 4;
    uint32_t offB0 = ((tid >> 5) * 136 + (tid & 31) * 4) * 4;
    uint32_t offB1 = ((8 + (tid >> 5)) * 136 + (tid & 31) * 4) * 4;

    float d[4][4][4];
#pragma unroll
    for (int mi = 0; mi < 4; mi++)
#pragma unroll
        for (int ni = 0; ni < 4; ni++)
#pragma unroll
            for (int r = 0; r < 4; r++) d[mi][ni][r] = 0.f;

    int nk = K / 16;

    {
        cp16(as_addr + offA0, Ag0);
        cp16(as_addr + offA1, Ag1);
        cp16(bs_addr + offB0, Bg0);
        cp16(bs_addr + offB1, Bg1);
        CP_COMMIT();
    }
    if (nk > 1) {
        uint32_t ab = as_addr + G2_A * 4, bb = bs_addr + G2_B * 4;
        cp16(ab + offA0, Ag0 + 16);
        cp16(ab + offA1, Ag1 + 16);
        cp16(bb + offB0, Bg0 + (size_t)16 * ldb);
        cp16(bb + offB1, Bg1 + (size_t)16 * ldb);
        CP_COMMIT();
    }

    for (int kt = 0; kt < nk; kt++) {
        if (kt + 1 < nk) { asm volatile("cp.async.wait_group 1;"); }
        else             { asm volatile("cp.async.wait_group 0;"); }
        __syncthreads();

        if (kt + 2 < nk) {
            int s = (kt + 2) % 3;
            int k0 = (kt + 2) * 16;
            uint32_t ab = as_addr + s * G2_A * 4, bb = bs_addr + s * G2_B * 4;
            cp16(ab + offA0, Ag0 + k0);
            cp16(ab + offA1, Ag1 + k0);
            cp16(bb + offB0, Bg0 + (size_t)k0 * ldb);
            cp16(bb + offB1, Bg1 + (size_t)k0 * ldb);
            CP_COMMIT();
        }

        const float* Ac = As + (kt % 3) * G2_A;
        const float* Bc = Bs + (kt % 3) * G2_B;

#pragma unroll
        for (int ks = 0; ks < 16; ks += 8) {
            // single-pass tf32: cvt.rna both fragments at consume
            uint32_t bf[4][2];
#pragma unroll
            for (int ni = 0; ni < 4; ni++) {
                int c = wn * 32 + ni * 8 + g;
                bf[ni][0] = f2tf(Bc[(ks + tg) * 136 + c]);
                bf[ni][1] = f2tf(Bc[(ks + tg + 4) * 136 + c]);
            }
#pragma unroll
            for (int mi = 0; mi < 4; mi++) {
                int r = wm * 64 + mi * 16;
                uint32_t af[4];
                af[0] = f2tf(Ac[(r + g) * 20 + ks + tg]);
                af[1] = f2tf(Ac[(r + 8 + g) * 20 + ks + tg]);
                af[2] = f2tf(Ac[(r + g) * 20 + ks + tg + 4]);
                af[3] = f2tf(Ac[(r + 8 + g) * 20 + ks + tg + 4]);
#pragma unroll
                for (int ni = 0; ni < 4; ni++) {
                    mma_tf32(d[mi][ni], af, bf[ni]);
                }
            }
        }
    }

#pragma unroll
    for (int mi = 0; mi < 4; mi++) {
#pragma unroll
        for (int ni = 0; ni < 4; ni++) {
            int r = row0 + wm * 64 + mi * 16 + g;
            int c = col0 + wn * 32 + ni * 8 + 2 * tg;
            *(float2*)(C + (size_t)r * ldc + c) = make_float2(d[mi][ni][0], d[mi][ni][1]);
            *(float2*)(C + (size_t)(r + 8) * ldc + c) = make_float2(d[mi][ni][2], d[mi][ni][3]);
        }
    }
}

// ---------------- fused prep: scores | xmean | pack_wc1 ----------------
__global__ void prep_kernel(const float* __restrict__ x, const float* __restrict__ w_imp,
                            float* __restrict__ scores, float* __restrict__ xmean,
                            const float* __restrict__ w_cq, const float* __restrict__ w_ckv,
                            const float* __restrict__ w_krope, float* __restrict__ wc1) {
    int blk = blockIdx.x, tid = threadIdx.x;   // 256 threads
    if (blk < 2048) {
        __shared__ float s8[8];
        int row = blk;
        float s = 0.f;
        for (int c = tid; c < CC; c += 256) s += x[row * CC + c] * w_imp[c];
#pragma unroll
        for (int o = 16; o > 0; o >>= 1) s += __shfl_xor_sync(0xffffffffu, s, o);
        if ((tid & 31) == 0) s8[tid >> 5] = s;
        __syncthreads();
        if (tid == 0) {
            float t = 0.f;
#pragma unroll
            for (int i = 0; i < 8; i++) t += s8[i];
            scores[row] = t;
        }
    } else if (blk < 2056) {
        int i = blk - 2048;
        int b = i >> 2;
        int c = (i & 3) * 256 + tid;
        float s = 0.f;
        for (int t = 0; t < TT; t++) s += x[(b * TT + t) * CC + c];
        xmean[b * CC + c] = s * (1.f / (float)TT);
    } else {
        int k = blk - 2056;   // 0..1023
        float v;
        if (tid < 96) v = w_cq[k * 96 + tid];
        else if (tid < 128) v = w_ckv[k * 32 + (tid - 96)];
        else if (tid < 192) v = w_krope[k * 64 + (tid - 128)];
        else v = 0.f;
        wc1[k * 256 + tid] = v;
    }
}

// ---------------- fused topk + gate ----------------
__global__ void topk_gate_kernel(const float* __restrict__ scores, int* __restrict__ idxout,
                                 const float* __restrict__ xmean, const float* __restrict__ wg,
                                 float* __restrict__ gate) {
    int blk = blockIdx.x, tid = threadIdx.x;
    if (blk < 2) {
        __shared__ float sv[1024];
        __shared__ int si[1024];
        __shared__ int ti[256];
        int b = blk;
        sv[tid] = scores[b * TT + tid];
        si[tid] = tid;
        __syncthreads();
        for (int k = 2; k <= 1024; k <<= 1) {
            for (int j = k >> 1; j > 0; j >>= 1) {
                int ixj = tid ^ j;
                if (ixj > tid) {
                    bool desc = ((tid & k) == 0);
                    float va = sv[tid], vb = sv[ixj];
                    int ia = si[tid], ib = si[ixj];
                    bool agtb = (va > vb) || (va == vb && ia < ib);
                    if (desc ? !agtb : agtb) {
                        sv[tid] = vb; sv[ixj] = va;
                        si[tid] = ib; si[ixj] = ia;
                    }
                }
                __syncthreads();
            }
        }
        if (tid < 256) ti[tid] = si[tid];
        __syncthreads();
        for (int k = 2; k <= 256; k <<= 1) {
            for (int j = k >> 1; j > 0; j >>= 1) {
                int ixj = tid ^ j;
                if (tid < 256 && ixj > tid) {
                    bool asc = ((tid & k) == 0);
                    int ia = ti[tid], ib = ti[ixj];
                    if (asc ? (ia > ib) : (ia < ib)) { ti[tid] = ib; ti[ixj] = ia; }
                }
                __syncthreads();
            }
        }
        if (tid < 256) idxout[b * KEEP_ + tid] = ti[tid];
    } else {
        int b = blk - 2;
        __shared__ float sg[3];
        int w = tid >> 5, lane = tid & 31;
        if (w < 3) {
            float s = 0.f;
            for (int c = lane; c < CC; c += 32) s += xmean[b * CC + c] * wg[c * 3 + w];
#pragma unroll
            for (int o = 16; o > 0; o >>= 1) s += __shfl_xor_sync(0xffffffffu, s, o);
            if (lane == 0) sg[w] = s;
        }
        __syncthreads();
        if (tid == 0) {
            float m = fmaxf(sg[0], fmaxf(sg[1], sg[2]));
            float e0 = expf(sg[0] - m), e1 = expf(sg[1] - m), e2 = expf(sg[2] - m);
            float inv = 1.f / (e0 + e1 + e2);
            gate[b * 4 + 0] = e0 * inv;
            gate[b * 4 + 1] = e1 * inv;
            gate[b * 4 + 2] = e2 * inv;
        }
    }
}

// ---------------- gather ----------------
__global__ void gather_kernel(const float* __restrict__ x, const int* __restrict__ idx,
                              float* __restrict__ selx) {
    int row = blockIdx.x;
    int b = row >> 8;
    int t = idx[row];
    for (int c = threadIdx.x; c < CC; c += 256)
        selx[row * CC + c] = x[(b * TT + t) * CC + c];
}

// ---------------- fused RMS norm on packed f0 ----------------
__global__ void rms2_kernel(float* __restrict__ f0,
                            const float* __restrict__ gq, const float* __restrict__ gkv) {
    int row = blockIdx.x, tid = threadIdx.x;
    float* dd = f0 + row * 256;
    __shared__ float s4[4];
    float v = (tid < 96) ? dd[tid] : 0.f;
    float sq = v * v;
#pragma unroll
    for (int o = 16; o > 0; o >>= 1) sq += __shfl_xor_sync(0xffffffffu, sq, o);
    if ((tid & 31) == 0) s4[tid >> 5] = sq;
    __syncthreads();
    float tot = s4[0] + s4[1] + s4[2] + s4[3];
    float sc = rsqrtf(tot / 96.f + 1e-6f);
    if (tid < 96) dd[tid] = v * sc * gq[tid];
    __syncthreads();
    if (tid < 32) {
        float v2 = dd[96 + tid];
        float sq2 = v2 * v2;
#pragma unroll
        for (int o = 16; o > 0; o >>= 1) sq2 += __shfl_xor_sync(0xffffffffu, sq2, o);
        float sc2 = rsqrtf(sq2 / 32.f + 1e-6f);
        dd[96 + tid] = v2 * sc2 * gkv[tid];
    }
}

// ---------------- fused assembles (rope + layout), 512 threads ----------------
__global__ void assemble_all_kernel(const float* __restrict__ qout,
                                    const float* __restrict__ kvout,
                                    const float* __restrict__ f0,
                                    const float* __restrict__ selkv,
                                    const float* __restrict__ winout,
                                    float* __restrict__ Q,
                                    float* __restrict__ K1, float* __restrict__ V1,
                                    float* __restrict__ KSb, float* __restrict__ VSb,
                                    float* __restrict__ KWb, float* __restrict__ VWb) {
    int blk = blockIdx.x;
    int j = threadIdx.x;
    int h = j >> 5, d = j & 31;
    float f = expf(-LOG1E4_OVER_32 * (float)d);

    if (blk < 2048) {
        int row = blk;
        int b = row >> 10, t = row & 1023;
        int qb = (((b * HH + h) * TT) + t) * DQK;
        Q[qb + d] = qout[row * 1536 + j];
        float x1 = qout[row * 1536 + 512 + h * RD + d];
        float x2 = qout[row * 1536 + 512 + h * RD + RP + d];
        float sn, cs;
        sincosf((float)t * f, &sn, &cs);
        Q[qb + NOPE_ + d] = x1 * cs - x2 * sn;
        Q[qb + NOPE_ + RP + d] = x1 * sn + x2 * cs;
    } else if (blk < 4096) {
        int row = blk - 2048;
        int b = row >> 10, t = row & 1023;
        int kb = (((b * HH + h) * TT) + t) * DQK;
        K1[kb + d] = kvout[row * 1024 + j];
        float x1 = f0[row * 256 + 128 + d] * 0.0625f;
        float x2 = f0[row * 256 + 128 + RP + d] * 0.0625f;
        float sn, cs;
        sincosf((float)t * f, &sn, &cs);
        K1[kb + NOPE_ + d] = x1 * cs - x2 * sn;
        K1[kb + NOPE_ + RP + d] = x1 * sn + x2 * cs;
        V1[(((b * HH + h) * TT) + t) * VD + d] = kvout[row * 1024 + 512 + j];
    } else {
        const float* raw;
        float* K;
        float* V;
        int row, S;
        if (blk < 4608) { row = blk - 4096; S = KEEP_; raw = selkv; K = KSb; V = VSb; }
        else            { row = blk - 4608; S = TT;    raw = winout; K = KWb; V = VWb; }
        int b = row / S, pos = row % S;
        float nope = raw[row * 2048 + h * DQK + d];
        float x1 = raw[row * 2048 + h * DQK + NOPE_ + d];
        float x2 = raw[row * 2048 + h * DQK + NOPE_ + RP + d];
        float sn, cs;
        sincosf((float)pos * f, &sn, &cs);
        int kb = (((b * HH + h) * S) + pos) * DQK;
        K[kb + d] = nope;
        K[kb + NOPE_ + d] = x1 * cs - x2 * sn;
        K[kb + NOPE_ + RP + d] = x1 * sn + x2 * cs;
        V[(((b * HH + h) * S) + pos) * VD + d] = raw[row * 2048 + 1536 + h * VD + d];
    }
}

// ---------------- pipelined tf32 MMA flash attention ----------------
constexpr int QS_STR = 100;
constexpr int KS_STR = 100;
constexpr int VS_STR = 40;
constexpr int PS_STR = 68;
constexpr int KBUF = 64 * KS_STR;
constexpr int VBUF = 64 * VS_STR;
constexpr int ASM_QS = 0;
constexpr int ASM_KS = 128 * QS_STR;
constexpr int ASM_VS = ASM_KS + 2 * KBUF;
constexpr int ASM_PS = ASM_VS + 2 * VBUF;
constexpr int ATTN_SMEM = (ASM_PS + 8 * 16 * PS_STR) * 4;

__global__ void __launch_bounds__(256)
attn_mma(const float* __restrict__ Q,
         const float* __restrict__ K1, const float* __restrict__ V1,
         const float* __restrict__ KS, const float* __restrict__ VS,
         const float* __restrict__ KW, const float* __restrict__ VW,
         const float* __restrict__ gate, float* __restrict__ outp) {
    extern __shared__ float sm[];
    float* Qs = sm + ASM_QS;

    int tid = threadIdx.x;
    int w = tid >> 5, lane = tid & 31;
    int g = lane >> 2, tg = lane & 3;
    float* Ps = sm + ASM_PS + w * 16 * PS_STR;

    int tile = 7 - blockIdx.x;
    int h = blockIdx.y, b = blockIdx.z;
    int q0 = tile * 128;
    int bh = b * HH + h;
    int rowg = q0 + 16 * w + g;

    uint32_t smem_u32 = (uint32_t)__cvta_generic_to_shared(sm);

    const float* Qp = Q + (bh * TT + q0) * DQK;
    for (int i = tid; i < 128 * 24; i += 256) {
        int q = i / 24, dq = i % 24;
        float4 v = *(const float4*)(Qp + q * DQK + dq * 4);
        v.x = to_tf32(v.x); v.y = to_tf32(v.y);
        v.z = to_tf32(v.z); v.w = to_tf32(v.w);
        *(float4*)&Qs[q * QS_STR + dq * 4] = v;
    }

    const float* Kpa[3] = {K1 + bh * TT * DQK, KS + bh * KEEP_ * DQK, KW + bh * TT * DQK};
    const float* Vpa[3] = {V1 + bh * TT * VD, VS + bh * KEEP_ * VD, VW + bh * TT * VD};
    int ncha[3] = {2 * (tile + 1), 4, 2 * (tile + 1)};

    float g_b[3];
    g_b[0] = gate[b * 4 + 0];
    g_b[1] = gate[b * 4 + 1];
    g_b[2] = gate[b * 4 + 2];

    float fout[4][4];
#pragma unroll
    for (int nv = 0; nv < 4; nv++)
#pragma unroll
        for (int r = 0; r < 4; r++) fout[nv][r] = 0.f;

    auto stage = [&](int buf, const float* Kp, const float* Vp, int k0) {
        uint32_t kaddr = smem_u32 + (ASM_KS + buf * KBUF) * 4;
        uint32_t vaddr = smem_u32 + (ASM_VS + buf * VBUF) * 4;
#pragma unroll
        for (int it = 0; it < 6; it++) {
            int i = tid + it * 256;
            int key = i / 24, dq = i % 24;
            cp16(kaddr + (key * KS_STR + dq * 4) * 4, Kp + (k0 + key) * DQK + dq * 4);
        }
#pragma unroll
        for (int it = 0; it < 2; it++) {
            int i = tid + it * 256;
            int key = i >> 3, dq = i & 7;
            cp16(vaddr + (key * VS_STR + dq * 4) * 4, Vp + (k0 + key) * VD + dq * 4);
        }
        CP_COMMIT();
    };

    stage(0, Kpa[0], Vpa[0], 0);
    int buf = 0;

    for (int br = 0; br < 3; br++) {
        bool causal = (br != 1);
        int nchunk = ncha[br];

        float m0 = -1e30f, m1 = -1e30f, l0 = 0.f, l1 = 0.f;
        float acc[4][4];
#pragma unroll
        for (int nv = 0; nv < 4; nv++)
#pragma unroll
            for (int r = 0; r < 4; r++) acc[nv][r] = 0.f;

        for (int c = 0; c < nchunk; c++) {
            int k0 = c * 64;
            int nbr = br, nc = c + 1;
            if (nc == nchunk) { nbr = br + 1; nc = 0; }

            __syncthreads();
            if (nbr < 3) {
                stage(buf ^ 1, Kpa[nbr], Vpa[nbr], nc * 64);
                asm volatile("cp.async.wait_group 1;");
            } else {
                asm volatile("cp.async.wait_group 0;");
            }
            __syncthreads();

            const float* Kc = sm + ASM_KS + buf * KBUF;
            const float* Vc = sm + ASM_VS + buf * VBUF;

            float s[8][4];
#pragma unroll
            for (int ni = 0; ni < 8; ni++)
#pragma unroll
                for (int r = 0; r < 4; r++) s[ni][r] = 0.f;

#pragma unroll
            for (int ks = 0; ks < 12; ks++) {
                int kb = ks * 8;
                const float* q0p = &Qs[(16 * w + g) * QS_STR + kb];
                const float* q1p = q0p + 8 * QS_STR;
                uint32_t Af[4];
                Af[0] = __float_as_uint(q0p[tg]);
                Af[1] = __float_as_uint(q1p[tg]);
                Af[2] = __float_as_uint(q0p[tg + 4]);
                Af[3] = __float_as_uint(q1p[tg + 4]);
#pragma unroll
                for (int ni = 0; ni < 8; ni++) {
                    uint32_t Bf[2];
                    Bf[0] = __float_as_uint(Kc[(8 * ni + g) * KS_STR + kb + tg]);
                    Bf[1] = __float_as_uint(Kc[(8 * ni + g) * KS_STR + kb + tg + 4]);
                    mma_tf32(s[ni], Af, Bf);
                }
            }

            if (causal && (k0 + 64 > q0)) {
#pragma unroll
                for (int ni = 0; ni < 8; ni++) {
                    int key = k0 + 8 * ni + 2 * tg;
                    if (key > rowg)         s[ni][0] = -1e30f;
                    if (key + 1 > rowg)     s[ni][1] = -1e30f;
                    if (key > rowg + 8)     s[ni][2] = -1e30f;
                    if (key + 1 > rowg + 8) s[ni][3] = -1e30f;
                }
            }

            float cm0 = -1e30f, cm1 = -1e30f;
#pragma unroll
            for (int ni = 0; ni < 8; ni++) {
                cm0 = fmaxf(cm0, fmaxf(s[ni][0], s[ni][1]));
                cm1 = fmaxf(cm1, fmaxf(s[ni][2], s[ni][3]));
            }
            cm0 = fmaxf(cm0, __shfl_xor_sync(0xffffffffu, cm0, 1));
            cm0 = fmaxf(cm0, __shfl_xor_sync(0xffffffffu, cm0, 2));
            cm1 = fmaxf(cm1, __shfl_xor_sync(0xffffffffu, cm1, 1));
            cm1 = fmaxf(cm1, __shfl_xor_sync(0xffffffffu, cm1, 2));

            float nm0 = fmaxf(m0, cm0), nm1 = fmaxf(m1, cm1);
            float al0 = __expf((m0 - nm0) * ATTN_SCALE);
            float al1 = __expf((m1 - nm1) * ATTN_SCALE);
            m0 = nm0; m1 = nm1;

            float sum0 = 0.f, sum1 = 0.f;
#pragma unroll
            for (int ni = 0; ni < 8; ni++) {
                s[ni][0] = __expf((s[ni][0] - m0) * ATTN_SCALE);
                s[ni][1] = __expf((s[ni][1] - m0) * ATTN_SCALE);
                s[ni][2] = __expf((s[ni][2] - m1) * ATTN_SCALE);
                s[ni][3] = __expf((s[ni][3] - m1) * ATTN_SCALE);
                sum0 += s[ni][0] + s[ni][1];
                sum1 += s[ni][2] + s[ni][3];
            }
            sum0 += __shfl_xor_sync(0xffffffffu, sum0, 1);
            sum0 += __shfl_xor_sync(0xffffffffu, sum0, 2);
            sum1 += __shfl_xor_sync(0xffffffffu, sum1, 1);
            sum1 += __shfl_xor_sync(0xffffffffu, sum1, 2);
            l0 = l0 * al0 + sum0;
            l1 = l1 * al1 + sum1;

#pragma unroll
            for (int nv = 0; nv < 4; nv++) {
                acc[nv][0] *= al0; acc[nv][1] *= al0;
                acc[nv][2] *= al1; acc[nv][3] *= al1;
            }

            __syncwarp();
#pragma unroll
            for (int ni = 0; ni < 8; ni++) {
                *(float2*)&Ps[g * PS_STR + 8 * ni + 2 * tg] =
                    make_float2(to_tf32(s[ni][0]), to_tf32(s[ni][1]));
                *(float2*)&Ps[(g + 8) * PS_STR + 8 * ni + 2 * tg] =
                    make_float2(to_tf32(s[ni][2]), to_tf32(s[ni][3]));
            }
            __syncwarp();

#pragma unroll
            for (int ks = 0; ks < 8; ks++) {
                int kb = ks * 8;
                uint32_t Af[4];
                Af[0] = __float_as_uint(Ps[g * PS_STR + kb + tg]);
                Af[1] = __float_as_uint(Ps[(g + 8) * PS_STR + kb + tg]);
                Af[2] = __float_as_uint(Ps[g * PS_STR + kb + tg + 4]);
                Af[3] = __float_as_uint(Ps[(g + 8) * PS_STR + kb + tg + 4]);
#pragma unroll
                for (int nv = 0; nv < 4; nv++) {
                    uint32_t Bf[2];
                    Bf[0] = f2tf(Vc[(kb + tg) * VS_STR + 8 * nv + g]);
                    Bf[1] = f2tf(Vc[(kb + tg + 4) * VS_STR + 8 * nv + g]);
                    mma_tf32(acc[nv], Af, Bf);
                }
            }
            buf ^= 1;
        }

        float gb = g_b[br];
        float inv0 = gb / l0, inv1 = gb / l1;
#pragma unroll
        for (int nv = 0; nv < 4; nv++) {
            fout[nv][0] += acc[nv][0] * inv0;
            fout[nv][1] += acc[nv][1] * inv0;
            fout[nv][2] += acc[nv][2] * inv1;
            fout[nv][3] += acc[nv][3] * inv1;
        }
    }

#pragma unroll
    for (int nv = 0; nv < 4; nv++) {
        int col = h * VD + 8 * nv + 2 * tg;
        *(float2*)(outp + (b * TT + rowg) * (HH * VD) + col) =
            make_float2(fout[nv][0], fout[nv][1]);
        *(float2*)(outp + (b * TT + rowg + 8) * (HH * VD) + col) =
            make_float2(fout[nv][2], fout[nv][3]);
    }
}

// ---------------- launcher ----------------
extern "C" void kernel_launch(void* const* d_in, const int* in_sizes, int n_in,
                              void* d_out, int out_size) {
    const float* x         = (const float*)d_in[0];
    const float* w_cq      = (const float*)d_in[1];
    const float* g_qnorm   = (const float*)d_in[2];
    const float* w_dq_nope = (const float*)d_in[3];
    const float* w_dq_rope = (const float*)d_in[4];
    const float* w_ckv     = (const float*)d_in[5];
    const float* g_kvnorm  = (const float*)d_in[6];
    const float* w_dk_nope = (const float*)d_in[7];
    const float* w_dv      = (const float*)d_in[8];
    const float* w_krope   = (const float*)d_in[9];
    const float* w_imp     = (const float*)d_in[10];
    const float* w_selk    = (const float*)d_in[11];
    const float* w_selv    = (const float*)d_in[12];
    const float* w_wink    = (const float*)d_in[13];
    const float* w_winv    = (const float*)d_in[14];
    const float* w_gate    = (const float*)d_in[15];
    const float* w_proj    = (const float*)d_in[16];
    float* out = (float*)d_out;

    float* base = nullptr;
    cudaGetSymbolAddress((void**)&base, g_scratch);

    float* wc1    = base + OFF_WC1;
    float* f0     = base + OFF_F0;
    float* qout   = base + OFF_QOUT;
    float* kvout  = base + OFF_KVOUT;
    float* winout = base + OFF_WINOUT;
    float* selx   = base + OFF_SELX;
    float* selkv  = base + OFF_SELKV;
    float* xmean  = base + OFF_XMEAN;
    float* gate   = base + OFF_GATE;
    float* scores = base + OFF_SCORES;
    int*   idx    = (int*)(base + OFF_IDX);
    float* Qb     = base + OFF_Q;
    float* K1b    = base + OFF_K1;
    float* V1b    = base + OFF_V1;
    float* KWb    = base + OFF_KW;
    float* VWb    = base + OFF_VW;
    float* KSb    = base + OFF_KS;
    float* VSb    = base + OFF_VS;
    float* attnb  = base + OFF_ATTN;

    const int M = BB * TT;  // 2048

    cudaFuncSetAttribute(gemm_multi, cudaFuncAttributeMaxDynamicSharedMemorySize, G2_SMEM);
    cudaFuncSetAttribute(attn_mma, cudaFuncAttributeMaxDynamicSharedMemorySize, ATTN_SMEM);

    // 1) prep: scores | xmean | pack wc1
    prep_kernel<<<3080, 256>>>(x, w_imp, scores, xmean, w_cq, w_ckv, w_krope, wc1);

    // 2) topk + gate
    topk_gate_kernel<<<4, 1024>>>(scores, idx, xmean, w_gate, gate);

    // 3) gather
    gather_kernel<<<BB * KEEP_, 256>>>(x, idx, selx);

    // 4) mega GEMM 1: winout | f0 | selkv
    {
        GemmJobs jobs;
        jobs.j[0] = {x, CC, w_wink, 1536, 1536, w_winv, 512, winout, 2048, CC, 0, 16};
        jobs.j[1] = {x, CC, wc1, 256, 256, wc1, 256, f0, 256, CC, 256, 2};
        jobs.j[2] = {selx, CC, w_selk, 1536, 1536, w_selv, 512, selkv, 2048, CC, 288, 16};
        gemm_multi<<<352, 256, G2_SMEM>>>(jobs, 3);
    }

    // 5) rms on f0
    rms2_kernel<<<M, 128>>>(f0, g_qnorm, g_kvnorm);

    // 6) mega GEMM 2: qout | kvout
    {
        GemmJobs jobs;
        jobs.j[0] = {f0, 256, w_dq_nope, 512, 512, w_dq_rope, 1024, qout, 1536, 96, 0, 12};
        jobs.j[1] = {f0 + 96, 256, w_dk_nope, 512, 512, w_dv, 512, kvout, 1024, 32, 192, 8};
        jobs.j[2] = jobs.j[1];
        gemm_multi<<<320, 256, G2_SMEM>>>(jobs, 2);
    }

    // 7) all assembles
    assemble_all_kernel<<<6656, 512>>>(qout, kvout, f0, selkv, winout,
                                       Qb, K1b, V1b, KSb, VSb, KWb, VWb);

    // 8) attention
    attn_mma<<<dim3(8, HH, BB), 256, ATTN_SMEM>>>(Qb, K1b, V1b, KSb, VSb, KWb, VWb, gate, attnb);

    // 9) output projection
    {
        GemmJobs jobs;
        jobs.j[0] = {attnb, HH * VD, w_proj, CC, CC, w_proj, CC, out, CC, HH * VD, 0, 8};
        jobs.j[1] = jobs.j[0];
        jobs.j[2] = jobs.j[0];
        gemm_multi<<<128, 256, G2_SMEM>>>(jobs, 1);
    }
}

// round 10
// speedup vs baseline: 12.4342x; 1.0368x over previous
#include <cuda_runtime.h>
#include <math.h>
#include <stdint.h>

// ---------------- problem constants ----------------
#define BB 2
#define TT 1024
#define CC 1024
#define HH 16
#define VD 32
#define NOPE_ 32
#define RP 32
#define RD 64
#define DQK 96
#define KEEP_ 256
#define QL 96
#define KVL 32

#define LOG1E4_OVER_32 0.28782313662425572f   // ln(10000)/32
#define ATTN_SCALE 0.10206207261596577f       // 1/sqrt(96)

// ---------------- scratch ----------------
constexpr int OFF_WC1    = 0;                          // [1024][256]
constexpr int OFF_F0     = OFF_WC1    + 1024*256;      // [2048][256]  nq|ckv|krope|pad
constexpr int OFF_QOUT   = OFF_F0     + 2048*256;      // [2048][1536] qnope|qrope
constexpr int OFF_KVOUT  = OFF_QOUT   + 2048*1536;     // [2048][1024] knope|v1
constexpr int OFF_WINOUT = OFF_KVOUT  + 2048*1024;     // [2048][2048] kw|vw
constexpr int OFF_SELX   = OFF_WINOUT + 2048*2048;     // [512][1024]
constexpr int OFF_SELKV  = OFF_SELX   + 512*1024;      // [512][2048]  ks|vs
constexpr int OFF_XMEAN  = OFF_SELKV  + 512*2048;
constexpr int OFF_GATE   = OFF_XMEAN  + BB*CC;
constexpr int OFF_SCORES = OFF_GATE   + 8;
constexpr int OFF_IDX    = OFF_SCORES + BB*TT;
constexpr int OFF_Q      = OFF_IDX    + BB*KEEP_;
constexpr int OFF_K1     = OFF_Q      + BB*HH*TT*DQK;
constexpr int OFF_V1     = OFF_K1     + BB*HH*TT*DQK;
constexpr int OFF_KW     = OFF_V1     + BB*HH*TT*VD;
constexpr int OFF_VW     = OFF_KW     + BB*HH*TT*DQK;
constexpr int OFF_KS     = OFF_VW     + BB*HH*TT*VD;
constexpr int OFF_VS     = OFF_KS     + BB*HH*KEEP_*DQK;
constexpr int OFF_ATTN   = OFF_VS     + BB*HH*KEEP_*VD;
constexpr int SCRATCH_TOTAL = OFF_ATTN + BB*TT*HH*VD;

__device__ __align__(256) float g_scratch[SCRATCH_TOTAL];

// ---------------- tf32 helpers ----------------
__device__ __forceinline__ float to_tf32(float v) {
    uint32_t u;
    asm("cvt.rna.tf32.f32 %0, %1;" : "=r"(u) : "f"(v));
    return __uint_as_float(u);
}

__device__ __forceinline__ uint32_t f2tf(float v) {
    uint32_t u;
    asm("cvt.rna.tf32.f32 %0, %1;" : "=r"(u) : "f"(v));
    return u;
}

__device__ __forceinline__ void mma_tf32(float* d, const uint32_t* a, const uint32_t* b) {
    asm volatile(
        "mma.sync.aligned.m16n8k8.row.col.f32.tf32.tf32.f32 "
        "{%0,%1,%2,%3}, {%4,%5,%6,%7}, {%8,%9}, {%0,%1,%2,%3};\n"
        : "+f"(d[0]), "+f"(d[1]), "+f"(d[2]), "+f"(d[3])
        : "r"(a[0]), "r"(a[1]), "r"(a[2]), "r"(a[3]), "r"(b[0]), "r"(b[1]));
}

__device__ __forceinline__ void cp16(uint32_t dst, const float* src) {
    asm volatile("cp.async.cg.shared.global [%0], [%1], 16;" :: "r"(dst), "l"(src));
}
#define CP_COMMIT() asm volatile("cp.async.commit_group;")

// ---------------- multi-GEMM job table ----------------
struct GemmJob {
    const float* A; int lda;
    const float* B0; int ldb0; int n0;
    const float* B1; int ldb1;
    float* C; int ldc;
    int K;
    int ctaStart;   // first linear CTA id of this job
    int nx;         // N/128
    int acc;        // 1 = accumulate into existing C
};
struct GemmJobs { GemmJob j[3]; };

constexpr int G2_A = 128 * 20;
constexpr int G2_B = 16 * 136;
constexpr int G2_SMEM = 3 * (G2_A + G2_B) * 4;   // 56832 B

// gemm_multi: up to 3 independent GEMMs in one launch. 128x128 tiles,
// cp.async 3-stage, split-B, single-pass tf32 (cvt.rna on consume),
// optional accumulate-into-C epilogue (for split-K across launches).
__global__ void __launch_bounds__(256, 2)
gemm_multi(GemmJobs jobs, int njobs) {
    extern __shared__ float sm2[];
    float* As = sm2;
    float* Bs = sm2 + 3 * G2_A;

    // decode job
    int linear = blockIdx.x;
    int ji = njobs - 1;
#pragma unroll
    for (int t = 1; t < 3; t++)
        if (t < njobs && linear < jobs.j[t].ctaStart) { ji = t - 1; break; }
    const GemmJob& J = jobs.j[ji];
    int local = linear - J.ctaStart;
    int bx = local % J.nx, by = local / J.nx;

    const float* A = J.A; int lda = J.lda;
    float* C = J.C; int ldc = J.ldc;
    int K = J.K;
    int row0 = by * 128, col0 = bx * 128;

    const float* Bsrc;
    int ldb;
    if (col0 < J.n0) { Bsrc = J.B0 + col0; ldb = J.ldb0; }
    else             { Bsrc = J.B1 + (col0 - J.n0); ldb = J.ldb1; }

    int tid = threadIdx.x;
    int warp = tid >> 5, lane = tid & 31;
    int g = lane >> 2, tg = lane & 3;
    int wm = warp >> 2, wn = warp & 3;

    uint32_t as_addr = (uint32_t)__cvta_generic_to_shared(As);
    uint32_t bs_addr = (uint32_t)__cvta_generic_to_shared(Bs);

    const float* Ag0 = A + (size_t)(row0 + (tid >> 2)) * lda + (tid & 3) * 4;
    const float* Ag1 = A + (size_t)(row0 + 64 + (tid >> 2)) * lda + (tid & 3) * 4;
    const float* Bg0 = Bsrc + (size_t)(tid >> 5) * ldb + (tid & 31) * 4;
    const float* Bg1 = Bsrc + (size_t)(8 + (tid >> 5)) * ldb + (tid & 31) * 4;
    uint32_t offA0 = (((tid >> 2)) * 20 + (tid & 3) * 4) * 4;
    uint32_t offA1 = (((tid >> 2) + 64) * 20 + (tid & 3) * 4) * 4;
    uint32_t offB0 = ((tid >> 5) * 136 + (tid & 31) * 4) * 4;
    uint32_t offB1 = ((8 + (tid >> 5)) * 136 + (tid & 31) * 4) * 4;

    float d[4][4][4];
#pragma unroll
    for (int mi = 0; mi < 4; mi++)
#pragma unroll
        for (int ni = 0; ni < 4; ni++)
#pragma unroll
            for (int r = 0; r < 4; r++) d[mi][ni][r] = 0.f;

    int nk = K / 16;

    {
        cp16(as_addr + offA0, Ag0);
        cp16(as_addr + offA1, Ag1);
        cp16(bs_addr + offB0, Bg0);
        cp16(bs_addr + offB1, Bg1);
        CP_COMMIT();
    }
    if (nk > 1) {
        uint32_t ab = as_addr + G2_A * 4, bb = bs_addr + G2_B * 4;
        cp16(ab + offA0, Ag0 + 16);
        cp16(ab + offA1, Ag1 + 16);
        cp16(bb + offB0, Bg0 + (size_t)16 * ldb);
        cp16(bb + offB1, Bg1 + (size_t)16 * ldb);
        CP_COMMIT();
    }

    for (int kt = 0; kt < nk; kt++) {
        if (kt + 1 < nk) { asm volatile("cp.async.wait_group 1;"); }
        else             { asm volatile("cp.async.wait_group 0;"); }
        __syncthreads();

        if (kt + 2 < nk) {
            int s = (kt + 2) % 3;
            int k0 = (kt + 2) * 16;
            uint32_t ab = as_addr + s * G2_A * 4, bb = bs_addr + s * G2_B * 4;
            cp16(ab + offA0, Ag0 + k0);
            cp16(ab + offA1, Ag1 + k0);
            cp16(bb + offB0, Bg0 + (size_t)k0 * ldb);
            cp16(bb + offB1, Bg1 + (size_t)k0 * ldb);
            CP_COMMIT();
        }

        const float* Ac = As + (kt % 3) * G2_A;
        const float* Bc = Bs + (kt % 3) * G2_B;

#pragma unroll
        for (int ks = 0; ks < 16; ks += 8) {
            uint32_t bf[4][2];
#pragma unroll
            for (int ni = 0; ni < 4; ni++) {
                int c = wn * 32 + ni * 8 + g;
                bf[ni][0] = f2tf(Bc[(ks + tg) * 136 + c]);
                bf[ni][1] = f2tf(Bc[(ks + tg + 4) * 136 + c]);
            }
#pragma unroll
            for (int mi = 0; mi < 4; mi++) {
                int r = wm * 64 + mi * 16;
                uint32_t af[4];
                af[0] = f2tf(Ac[(r + g) * 20 + ks + tg]);
                af[1] = f2tf(Ac[(r + 8 + g) * 20 + ks + tg]);
                af[2] = f2tf(Ac[(r + g) * 20 + ks + tg + 4]);
                af[3] = f2tf(Ac[(r + 8 + g) * 20 + ks + tg + 4]);
#pragma unroll
                for (int ni = 0; ni < 4; ni++) {
                    mma_tf32(d[mi][ni], af, bf[ni]);
                }
            }
        }
    }

    if (J.acc) {
#pragma unroll
        for (int mi = 0; mi < 4; mi++) {
#pragma unroll
            for (int ni = 0; ni < 4; ni++) {
                int r = row0 + wm * 64 + mi * 16 + g;
                int c = col0 + wn * 32 + ni * 8 + 2 * tg;
                float2 o0 = *(float2*)(C + (size_t)r * ldc + c);
                float2 o1 = *(float2*)(C + (size_t)(r + 8) * ldc + c);
                o0.x += d[mi][ni][0]; o0.y += d[mi][ni][1];
                o1.x += d[mi][ni][2]; o1.y += d[mi][ni][3];
                *(float2*)(C + (size_t)r * ldc + c) = o0;
                *(float2*)(C + (size_t)(r + 8) * ldc + c) = o1;
            }
        }
    } else {
#pragma unroll
        for (int mi = 0; mi < 4; mi++) {
#pragma unroll
            for (int ni = 0; ni < 4; ni++) {
                int r = row0 + wm * 64 + mi * 16 + g;
                int c = col0 + wn * 32 + ni * 8 + 2 * tg;
                *(float2*)(C + (size_t)r * ldc + c) = make_float2(d[mi][ni][0], d[mi][ni][1]);
                *(float2*)(C + (size_t)(r + 8) * ldc + c) = make_float2(d[mi][ni][2], d[mi][ni][3]);
            }
        }
    }
}

// ---------------- fused prep: scores | xmean | pack_wc1 ----------------
__global__ void prep_kernel(const float* __restrict__ x, const float* __restrict__ w_imp,
                            float* __restrict__ scores, float* __restrict__ xmean,
                            const float* __restrict__ w_cq, const float* __restrict__ w_ckv,
                            const float* __restrict__ w_krope, float* __restrict__ wc1) {
    int blk = blockIdx.x, tid = threadIdx.x;   // 256 threads
    if (blk < 2048) {
        __shared__ float s8[8];
        int row = blk;
        float s = 0.f;
        for (int c = tid; c < CC; c += 256) s += x[row * CC + c] * w_imp[c];
#pragma unroll
        for (int o = 16; o > 0; o >>= 1) s += __shfl_xor_sync(0xffffffffu, s, o);
        if ((tid & 31) == 0) s8[tid >> 5] = s;
        __syncthreads();
        if (tid == 0) {
            float t = 0.f;
#pragma unroll
            for (int i = 0; i < 8; i++) t += s8[i];
            scores[row] = t;
        }
    } else if (blk < 2056) {
        int i = blk - 2048;
        int b = i >> 2;
        int c = (i & 3) * 256 + tid;
        float s = 0.f;
        for (int t = 0; t < TT; t++) s += x[(b * TT + t) * CC + c];
        xmean[b * CC + c] = s * (1.f / (float)TT);
    } else {
        int k = blk - 2056;   // 0..1023
        float v;
        if (tid < 96) v = w_cq[k * 96 + tid];
        else if (tid < 128) v = w_ckv[k * 32 + (tid - 96)];
        else if (tid < 192) v = w_krope[k * 64 + (tid - 128)];
        else v = 0.f;
        wc1[k * 256 + tid] = v;
    }
}

// ---------------- fused topk + gate ----------------
__global__ void topk_gate_kernel(const float* __restrict__ scores, int* __restrict__ idxout,
                                 const float* __restrict__ xmean, const float* __restrict__ wg,
                                 float* __restrict__ gate) {
    int blk = blockIdx.x, tid = threadIdx.x;
    if (blk < 2) {
        __shared__ float sv[1024];
        __shared__ int si[1024];
        __shared__ int ti[256];
        int b = blk;
        sv[tid] = scores[b * TT + tid];
        si[tid] = tid;
        __syncthreads();
        for (int k = 2; k <= 1024; k <<= 1) {
            for (int j = k >> 1; j > 0; j >>= 1) {
                int ixj = tid ^ j;
                if (ixj > tid) {
                    bool desc = ((tid & k) == 0);
                    float va = sv[tid], vb = sv[ixj];
                    int ia = si[tid], ib = si[ixj];
                    bool agtb = (va > vb) || (va == vb && ia < ib);
                    if (desc ? !agtb : agtb) {
                        sv[tid] = vb; sv[ixj] = va;
                        si[tid] = ib; si[ixj] = ia;
                    }
                }
                __syncthreads();
            }
        }
        if (tid < 256) ti[tid] = si[tid];
        __syncthreads();
        for (int k = 2; k <= 256; k <<= 1) {
            for (int j = k >> 1; j > 0; j >>= 1) {
                int ixj = tid ^ j;
                if (tid < 256 && ixj > tid) {
                    bool asc = ((tid & k) == 0);
                    int ia = ti[tid], ib = ti[ixj];
                    if (asc ? (ia > ib) : (ia < ib)) { ti[tid] = ib; ti[ixj] = ia; }
                }
                __syncthreads();
            }
        }
        if (tid < 256) idxout[b * KEEP_ + tid] = ti[tid];
    } else {
        int b = blk - 2;
        __shared__ float sg[3];
        int w = tid >> 5, lane = tid & 31;
        if (w < 3) {
            float s = 0.f;
            for (int c = lane; c < CC; c += 32) s += xmean[b * CC + c] * wg[c * 3 + w];
#pragma unroll
            for (int o = 16; o > 0; o >>= 1) s += __shfl_xor_sync(0xffffffffu, s, o);
            if (lane == 0) sg[w] = s;
        }
        __syncthreads();
        if (tid == 0) {
            float m = fmaxf(sg[0], fmaxf(sg[1], sg[2]));
            float e0 = expf(sg[0] - m), e1 = expf(sg[1] - m), e2 = expf(sg[2] - m);
            float inv = 1.f / (e0 + e1 + e2);
            gate[b * 4 + 0] = e0 * inv;
            gate[b * 4 + 1] = e1 * inv;
            gate[b * 4 + 2] = e2 * inv;
        }
    }
}

// ---------------- gather ----------------
__global__ void gather_kernel(const float* __restrict__ x, const int* __restrict__ idx,
                              float* __restrict__ selx) {
    int row = blockIdx.x;
    int b = row >> 8;
    int t = idx[row];
    for (int c = threadIdx.x; c < CC; c += 256)
        selx[row * CC + c] = x[(b * TT + t) * CC + c];
}

// ---------------- fused RMS norm on packed f0 ----------------
__global__ void rms2_kernel(float* __restrict__ f0,
                            const float* __restrict__ gq, const float* __restrict__ gkv) {
    int row = blockIdx.x, tid = threadIdx.x;
    float* dd = f0 + row * 256;
    __shared__ float s4[4];
    float v = (tid < 96) ? dd[tid] : 0.f;
    float sq = v * v;
#pragma unroll
    for (int o = 16; o > 0; o >>= 1) sq += __shfl_xor_sync(0xffffffffu, sq, o);
    if ((tid & 31) == 0) s4[tid >> 5] = sq;
    __syncthreads();
    float tot = s4[0] + s4[1] + s4[2] + s4[3];
    float sc = rsqrtf(tot / 96.f + 1e-6f);
    if (tid < 96) dd[tid] = v * sc * gq[tid];
    __syncthreads();
    if (tid < 32) {
        float v2 = dd[96 + tid];
        float sq2 = v2 * v2;
#pragma unroll
        for (int o = 16; o > 0; o >>= 1) sq2 += __shfl_xor_sync(0xffffffffu, sq2, o);
        float sc2 = rsqrtf(sq2 / 32.f + 1e-6f);
        dd[96 + tid] = v2 * sc2 * gkv[tid];
    }
}

// ---------------- fused assembles (rope + layout), 512 threads ----------------
__global__ void assemble_all_kernel(const float* __restrict__ qout,
                                    const float* __restrict__ kvout,
                                    const float* __restrict__ f0,
                                    const float* __restrict__ selkv,
                                    const float* __restrict__ winout,
                                    float* __restrict__ Q,
                                    float* __restrict__ K1, float* __restrict__ V1,
                                    float* __restrict__ KSb, float* __restrict__ VSb,
                                    float* __restrict__ KWb, float* __restrict__ VWb) {
    int blk = blockIdx.x;
    int j = threadIdx.x;
    int h = j >> 5, d = j & 31;
    float f = expf(-LOG1E4_OVER_32 * (float)d);

    if (blk < 2048) {
        int row = blk;
        int b = row >> 10, t = row & 1023;
        int qb = (((b * HH + h) * TT) + t) * DQK;
        Q[qb + d] = qout[row * 1536 + j];
        float x1 = qout[row * 1536 + 512 + h * RD + d];
        float x2 = qout[row * 1536 + 512 + h * RD + RP + d];
        float sn, cs;
        sincosf((float)t * f, &sn, &cs);
        Q[qb + NOPE_ + d] = x1 * cs - x2 * sn;
        Q[qb + NOPE_ + RP + d] = x1 * sn + x2 * cs;
    } else if (blk < 4096) {
        int row = blk - 2048;
        int b = row >> 10, t = row & 1023;
        int kb = (((b * HH + h) * TT) + t) * DQK;
        K1[kb + d] = kvout[row * 1024 + j];
        float x1 = f0[row * 256 + 128 + d] * 0.0625f;
        float x2 = f0[row * 256 + 128 + RP + d] * 0.0625f;
        float sn, cs;
        sincosf((float)t * f, &sn, &cs);
        K1[kb + NOPE_ + d] = x1 * cs - x2 * sn;
        K1[kb + NOPE_ + RP + d] = x1 * sn + x2 * cs;
        V1[(((b * HH + h) * TT) + t) * VD + d] = kvout[row * 1024 + 512 + j];
    } else {
        const float* raw;
        float* K;
        float* V;
        int row, S;
        if (blk < 4608) { row = blk - 4096; S = KEEP_; raw = selkv; K = KSb; V = VSb; }
        else            { row = blk - 4608; S = TT;    raw = winout; K = KWb; V = VWb; }
        int b = row / S, pos = row % S;
        float nope = raw[row * 2048 + h * DQK + d];
        float x1 = raw[row * 2048 + h * DQK + NOPE_ + d];
        float x2 = raw[row * 2048 + h * DQK + NOPE_ + RP + d];
        float sn, cs;
        sincosf((float)pos * f, &sn, &cs);
        int kb = (((b * HH + h) * S) + pos) * DQK;
        K[kb + d] = nope;
        K[kb + NOPE_ + d] = x1 * cs - x2 * sn;
        K[kb + NOPE_ + RP + d] = x1 * sn + x2 * cs;
        V[(((b * HH + h) * S) + pos) * VD + d] = raw[row * 2048 + 1536 + h * VD + d];
    }
}

// ---------------- pipelined tf32 MMA flash attention (Q fragments in registers) ------
constexpr int QS_STR = 100;
constexpr int KS_STR = 100;
constexpr int VS_STR = 40;
constexpr int PS_STR = 68;
constexpr int KBUF = 64 * KS_STR;
constexpr int VBUF = 64 * VS_STR;
constexpr int ASM_QS = 0;
constexpr int ASM_KS = 128 * QS_STR;
constexpr int ASM_VS = ASM_KS + 2 * KBUF;
constexpr int ASM_PS = ASM_VS + 2 * VBUF;
constexpr int ATTN_SMEM = (ASM_PS + 8 * 16 * PS_STR) * 4;

__global__ void __launch_bounds__(256)
attn_mma(const float* __restrict__ Q,
         const float* __restrict__ K1, const float* __restrict__ V1,
         const float* __restrict__ KS, const float* __restrict__ VS,
         const float* __restrict__ KW, const float* __restrict__ VW,
         const float* __restrict__ gate, float* __restrict__ outp) {
    extern __shared__ float sm[];
    float* Qs = sm + ASM_QS;

    int tid = threadIdx.x;
    int w = tid >> 5, lane = tid & 31;
    int g = lane >> 2, tg = lane & 3;
    float* Ps = sm + ASM_PS + w * 16 * PS_STR;

    int tile = 7 - blockIdx.x;
    int h = blockIdx.y, b = blockIdx.z;
    int q0 = tile * 128;
    int bh = b * HH + h;
    int rowg = q0 + 16 * w + g;

    uint32_t smem_u32 = (uint32_t)__cvta_generic_to_shared(sm);

    const float* Qp = Q + (bh * TT + q0) * DQK;
    for (int i = tid; i < 128 * 24; i += 256) {
        int q = i / 24, dq = i % 24;
        float4 v = *(const float4*)(Qp + q * DQK + dq * 4);
        v.x = to_tf32(v.x); v.y = to_tf32(v.y);
        v.z = to_tf32(v.z); v.w = to_tf32(v.w);
        *(float4*)&Qs[q * QS_STR + dq * 4] = v;
    }

    const float* Kpa[3] = {K1 + bh * TT * DQK, KS + bh * KEEP_ * DQK, KW + bh * TT * DQK};
    const float* Vpa[3] = {V1 + bh * TT * VD, VS + bh * KEEP_ * VD, VW + bh * TT * VD};
    int ncha[3] = {2 * (tile + 1), 4, 2 * (tile + 1)};

    float g_b[3];
    g_b[0] = gate[b * 4 + 0];
    g_b[1] = gate[b * 4 + 1];
    g_b[2] = gate[b * 4 + 2];

    float fout[4][4];
#pragma unroll
    for (int nv = 0; nv < 4; nv++)
#pragma unroll
        for (int r = 0; r < 4; r++) fout[nv][r] = 0.f;

    auto stage = [&](int buf, const float* Kp, const float* Vp, int k0) {
        uint32_t kaddr = smem_u32 + (ASM_KS + buf * KBUF) * 4;
        uint32_t vaddr = smem_u32 + (ASM_VS + buf * VBUF) * 4;
#pragma unroll
        for (int it = 0; it < 6; it++) {
            int i = tid + it * 256;
            int key = i / 24, dq = i % 24;
            cp16(kaddr + (key * KS_STR + dq * 4) * 4, Kp + (k0 + key) * DQK + dq * 4);
        }
#pragma unroll
        for (int it = 0; it < 2; it++) {
            int i = tid + it * 256;
            int key = i >> 3, dq = i & 7;
            cp16(vaddr + (key * VS_STR + dq * 4) * 4, Vp + (k0 + key) * VD + dq * 4);
        }
        CP_COMMIT();
    };

    stage(0, Kpa[0], Vpa[0], 0);
    int buf = 0;

    // wait for Q staging, then preload Q fragments into registers (reused for
    // every chunk of every branch — removes 48 LDS per chunk from the S phase)
    __syncthreads();
    uint32_t Qf[12][4];
    {
        const float* q0p = &Qs[(16 * w + g) * QS_STR];
        const float* q1p = q0p + 8 * QS_STR;
#pragma unroll
        for (int ks = 0; ks < 12; ks++) {
            Qf[ks][0] = __float_as_uint(q0p[8 * ks + tg]);
            Qf[ks][1] = __float_as_uint(q1p[8 * ks + tg]);
            Qf[ks][2] = __float_as_uint(q0p[8 * ks + tg + 4]);
            Qf[ks][3] = __float_as_uint(q1p[8 * ks + tg + 4]);
        }
    }

    for (int br = 0; br < 3; br++) {
        bool causal = (br != 1);
        int nchunk = ncha[br];

        float m0 = -1e30f, m1 = -1e30f, l0 = 0.f, l1 = 0.f;
        float acc[4][4];
#pragma unroll
        for (int nv = 0; nv < 4; nv++)
#pragma unroll
            for (int r = 0; r < 4; r++) acc[nv][r] = 0.f;

        for (int c = 0; c < nchunk; c++) {
            int k0 = c * 64;
            int nbr = br, nc = c + 1;
            if (nc == nchunk) { nbr = br + 1; nc = 0; }

            __syncthreads();
            if (nbr < 3) {
                stage(buf ^ 1, Kpa[nbr], Vpa[nbr], nc * 64);
                asm volatile("cp.async.wait_group 1;");
            } else {
                asm volatile("cp.async.wait_group 0;");
            }
            __syncthreads();

            const float* Kc = sm + ASM_KS + buf * KBUF;
            const float* Vc = sm + ASM_VS + buf * VBUF;

            float s[8][4];
#pragma unroll
            for (int ni = 0; ni < 8; ni++)
#pragma unroll
                for (int r = 0; r < 4; r++) s[ni][r] = 0.f;

#pragma unroll
            for (int ks = 0; ks < 12; ks++) {
                int kb = ks * 8;
#pragma unroll
                for (int ni = 0; ni < 8; ni++) {
                    uint32_t Bf[2];
                    Bf[0] = __float_as_uint(Kc[(8 * ni + g) * KS_STR + kb + tg]);
                    Bf[1] = __float_as_uint(Kc[(8 * ni + g) * KS_STR + kb + tg + 4]);
                    mma_tf32(s[ni], Qf[ks], Bf);
                }
            }

            if (causal && (k0 + 64 > q0)) {
#pragma unroll
                for (int ni = 0; ni < 8; ni++) {
                    int key = k0 + 8 * ni + 2 * tg;
                    if (key > rowg)         s[ni][0] = -1e30f;
                    if (key + 1 > rowg)     s[ni][1] = -1e30f;
                    if (key > rowg + 8)     s[ni][2] = -1e30f;
                    if (key + 1 > rowg + 8) s[ni][3] = -1e30f;
                }
            }

            float cm0 = -1e30f, cm1 = -1e30f;
#pragma unroll
            for (int ni = 0; ni < 8; ni++) {
                cm0 = fmaxf(cm0, fmaxf(s[ni][0], s[ni][1]));
                cm1 = fmaxf(cm1, fmaxf(s[ni][2], s[ni][3]));
            }
            cm0 = fmaxf(cm0, __shfl_xor_sync(0xffffffffu, cm0, 1));
            cm0 = fmaxf(cm0, __shfl_xor_sync(0xffffffffu, cm0, 2));
            cm1 = fmaxf(cm1, __shfl_xor_sync(0xffffffffu, cm1, 1));
            cm1 = fmaxf(cm1, __shfl_xor_sync(0xffffffffu, cm1, 2));

            float nm0 = fmaxf(m0, cm0), nm1 = fmaxf(m1, cm1);
            float al0 = __expf((m0 - nm0) * ATTN_SCALE);
            float al1 = __expf((m1 - nm1) * ATTN_SCALE);
            m0 = nm0; m1 = nm1;

            float sum0 = 0.f, sum1 = 0.f;
#pragma unroll
            for (int ni = 0; ni < 8; ni++) {
                s[ni][0] = __expf((s[ni][0] - m0) * ATTN_SCALE);
                s[ni][1] = __expf((s[ni][1] - m0) * ATTN_SCALE);
                s[ni][2] = __expf((s[ni][2] - m1) * ATTN_SCALE);
                s[ni][3] = __expf((s[ni][3] - m1) * ATTN_SCALE);
                sum0 += s[ni][0] + s[ni][1];
                sum1 += s[ni][2] + s[ni][3];
            }
            sum0 += __shfl_xor_sync(0xffffffffu, sum0, 1);
            sum0 += __shfl_xor_sync(0xffffffffu, sum0, 2);
            sum1 += __shfl_xor_sync(0xffffffffu, sum1, 1);
            sum1 += __shfl_xor_sync(0xffffffffu, sum1, 2);
            l0 = l0 * al0 + sum0;
            l1 = l1 * al1 + sum1;

#pragma unroll
            for (int nv = 0; nv < 4; nv++) {
                acc[nv][0] *= al0; acc[nv][1] *= al0;
                acc[nv][2] *= al1; acc[nv][3] *= al1;
            }

            __syncwarp();
#pragma unroll
            for (int ni = 0; ni < 8; ni++) {
                *(float2*)&Ps[g * PS_STR + 8 * ni + 2 * tg] =
                    make_float2(to_tf32(s[ni][0]), to_tf32(s[ni][1]));
                *(float2*)&Ps[(g + 8) * PS_STR + 8 * ni + 2 * tg] =
                    make_float2(to_tf32(s[ni][2]), to_tf32(s[ni][3]));
            }
            __syncwarp();

#pragma unroll
            for (int ks = 0; ks < 8; ks++) {
                int kb = ks * 8;
                uint32_t Af[4];
                Af[0] = __float_as_uint(Ps[g * PS_STR + kb + tg]);
                Af[1] = __float_as_uint(Ps[(g + 8) * PS_STR + kb + tg]);
                Af[2] = __float_as_uint(Ps[g * PS_STR + kb + tg + 4]);
                Af[3] = __float_as_uint(Ps[(g + 8) * PS_STR + kb + tg + 4]);
#pragma unroll
                for (int nv = 0; nv < 4; nv++) {
                    uint32_t Bf[2];
                    Bf[0] = f2tf(Vc[(kb + tg) * VS_STR + 8 * nv + g]);
                    Bf[1] = f2tf(Vc[(kb + tg + 4) * VS_STR + 8 * nv + g]);
                    mma_tf32(acc[nv], Af, Bf);
                }
            }
            buf ^= 1;
        }

        float gb = g_b[br];
        float inv0 = gb / l0, inv1 = gb / l1;
#pragma unroll
        for (int nv = 0; nv < 4; nv++) {
            fout[nv][0] += acc[nv][0] * inv0;
            fout[nv][1] += acc[nv][1] * inv0;
            fout[nv][2] += acc[nv][2] * inv1;
            fout[nv][3] += acc[nv][3] * inv1;
        }
    }

#pragma unroll
    for (int nv = 0; nv < 4; nv++) {
        int col = h * VD + 8 * nv + 2 * tg;
        *(float2*)(outp + (b * TT + rowg) * (HH * VD) + col) =
            make_float2(fout[nv][0], fout[nv][1]);
        *(float2*)(outp + (b * TT + rowg + 8) * (HH * VD) + col) =
            make_float2(fout[nv][2], fout[nv][3]);
    }
}

// ---------------- launcher ----------------
extern "C" void kernel_launch(void* const* d_in, const int* in_sizes, int n_in,
                              void* d_out, int out_size) {
    const float* x         = (const float*)d_in[0];
    const float* w_cq      = (const float*)d_in[1];
    const float* g_qnorm   = (const float*)d_in[2];
    const float* w_dq_nope = (const float*)d_in[3];
    const float* w_dq_rope = (const float*)d_in[4];
    const float* w_ckv     = (const float*)d_in[5];
    const float* g_kvnorm  = (const float*)d_in[6];
    const float* w_dk_nope = (const float*)d_in[7];
    const float* w_dv      = (const float*)d_in[8];
    const float* w_krope   = (const float*)d_in[9];
    const float* w_imp     = (const float*)d_in[10];
    const float* w_selk    = (const float*)d_in[11];
    const float* w_selv    = (const float*)d_in[12];
    const float* w_wink    = (const float*)d_in[13];
    const float* w_winv    = (const float*)d_in[14];
    const float* w_gate    = (const float*)d_in[15];
    const float* w_proj    = (const float*)d_in[16];
    float* out = (float*)d_out;

    float* base = nullptr;
    cudaGetSymbolAddress((void**)&base, g_scratch);

    float* wc1    = base + OFF_WC1;
    float* f0     = base + OFF_F0;
    float* qout   = base + OFF_QOUT;
    float* kvout  = base + OFF_KVOUT;
    float* winout = base + OFF_WINOUT;
    float* selx   = base + OFF_SELX;
    float* selkv  = base + OFF_SELKV;
    float* xmean  = base + OFF_XMEAN;
    float* gate   = base + OFF_GATE;
    float* scores = base + OFF_SCORES;
    int*   idx    = (int*)(base + OFF_IDX);
    float* Qb     = base + OFF_Q;
    float* K1b    = base + OFF_K1;
    float* V1b    = base + OFF_V1;
    float* KWb    = base + OFF_KW;
    float* VWb    = base + OFF_VW;
    float* KSb    = base + OFF_KS;
    float* VSb    = base + OFF_VS;
    float* attnb  = base + OFF_ATTN;

    const int M = BB * TT;  // 2048

    cudaFuncSetAttribute(gemm_multi, cudaFuncAttributeMaxDynamicSharedMemorySize, G2_SMEM);
    cudaFuncSetAttribute(attn_mma, cudaFuncAttributeMaxDynamicSharedMemorySize, ATTN_SMEM);

    // 1) prep: scores | xmean | pack wc1
    prep_kernel<<<3080, 256>>>(x, w_imp, scores, xmean, w_cq, w_ckv, w_krope, wc1);

    // 2) topk + gate
    topk_gate_kernel<<<4, 1024>>>(scores, idx, xmean, w_gate, gate);

    // 3) gather
    gather_kernel<<<BB * KEEP_, 256>>>(x, idx, selx);

    // 4) mega GEMM 1: winout | f0 | selkv (first K half) — 320 tile-equivalents
    //    on 296 residency slots (was 352): selkv half-K tiles act as tail fillers.
    {
        GemmJobs jobs;
        jobs.j[0] = {x, CC, w_wink, 1536, 1536, w_winv, 512, winout, 2048, CC, 0, 16, 0};
        jobs.j[1] = {x, CC, wc1, 256, 256, wc1, 256, f0, 256, CC, 256, 2, 0};
        jobs.j[2] = {selx, CC, w_selk, 1536, 1536, w_selv, 512, selkv, 2048, 512, 288, 16, 0};
        gemm_multi<<<352, 256, G2_SMEM>>>(jobs, 3);
    }

    // 5) rms on f0
    rms2_kernel<<<M, 128>>>(f0, g_qnorm, g_kvnorm);

    // 6) mega GEMM 2: selkv (second K half, accumulate) | qout | kvout
    {
        GemmJobs jobs;
        jobs.j[0] = {selx + 512, CC, w_selk + 512 * 1536, 1536, 1536,
                     w_selv + 512 * 512, 512, selkv, 2048, 512, 0, 16, 1};
        jobs.j[1] = {f0, 256, w_dq_nope, 512, 512, w_dq_rope, 1024, qout, 1536, 96, 64, 12, 0};
        jobs.j[2] = {f0 + 96, 256, w_dk_nope, 512, 512, w_dv, 512, kvout, 1024, 32, 256, 8, 0};
        gemm_multi<<<384, 256, G2_SMEM>>>(jobs, 3);
    }

    // 7) all assembles
    assemble_all_kernel<<<6656, 512>>>(qout, kvout, f0, selkv, winout,
                                       Qb, K1b, V1b, KSb, VSb, KWb, VWb);

    // 8) attention
    attn_mma<<<dim3(8, HH, BB), 256, ATTN_SMEM>>>(Qb, K1b, V1b, KSb, VSb, KWb, VWb, gate, attnb);

    // 9) output projection
    {
        GemmJobs jobs;
        jobs.j[0] = {attnb, HH * VD, w_proj, CC, CC, w_proj, CC, out, CC, HH * VD, 0, 8, 0};
        jobs.j[1] = jobs.j[0];
        jobs.j[2] = jobs.j[0];
        gemm_multi<<<128, 256, G2_SMEM>>>(jobs, 1);
    }
}

// round 11
// speedup vs baseline: 12.6683x; 1.0188x over previous
#include <cuda_runtime.h>
#include <math.h>
#include <stdint.h>

// ---------------- problem constants ----------------
#define BB 2
#define TT 1024
#define CC 1024
#define HH 16
#define VD 32
#define NOPE_ 32
#define RP 32
#define RD 64
#define DQK 96
#define KEEP_ 256
#define QL 96
#define KVL 32

#define LOG1E4_OVER_32 0.28782313662425572f   // ln(10000)/32
#define ATTN_SCALE 0.10206207261596577f       // 1/sqrt(96)

// ---------------- scratch ----------------
constexpr int OFF_WC1    = 0;                          // [1024][256]
constexpr int OFF_F0     = OFF_WC1    + 1024*256;      // [2048][256]
constexpr int OFF_QOUT   = OFF_F0     + 2048*256;      // [2048][1536]
constexpr int OFF_KVOUT  = OFF_QOUT   + 2048*1536;     // [2048][1024]
constexpr int OFF_WINOUT = OFF_KVOUT  + 2048*1024;     // [2048][2048]
constexpr int OFF_SELX   = OFF_WINOUT + 2048*2048;     // [512][1024]
constexpr int OFF_SELKV  = OFF_SELX   + 512*1024;      // [512][2048]
constexpr int OFF_XMEAN  = OFF_SELKV  + 512*2048;
constexpr int OFF_GATE   = OFF_XMEAN  + BB*CC;
constexpr int OFF_SCORES = OFF_GATE   + 8;
constexpr int OFF_IDX    = OFF_SCORES + BB*TT;
constexpr int OFF_Q      = OFF_IDX    + BB*KEEP_;
constexpr int OFF_K1     = OFF_Q      + BB*HH*TT*DQK;
constexpr int OFF_V1     = OFF_K1     + BB*HH*TT*DQK;
constexpr int OFF_KW     = OFF_V1     + BB*HH*TT*VD;
constexpr int OFF_VW     = OFF_KW     + BB*HH*TT*DQK;
constexpr int OFF_KS     = OFF_VW     + BB*HH*TT*VD;
constexpr int OFF_VS     = OFF_KS     + BB*HH*KEEP_*DQK;
constexpr int OFF_ATTN   = OFF_VS     + BB*HH*KEEP_*VD;   // att0 (also final sum)
constexpr int OFF_ATTN2  = OFF_ATTN   + BB*TT*HH*VD;      // att1
constexpr int SCRATCH_TOTAL = OFF_ATTN2 + BB*TT*HH*VD;

__device__ __align__(256) float g_scratch[SCRATCH_TOTAL];

// ---------------- tf32 helpers ----------------
__device__ __forceinline__ float to_tf32(float v) {
    uint32_t u;
    asm("cvt.rna.tf32.f32 %0, %1;" : "=r"(u) : "f"(v));
    return __uint_as_float(u);
}

__device__ __forceinline__ uint32_t f2tf(float v) {
    uint32_t u;
    asm("cvt.rna.tf32.f32 %0, %1;" : "=r"(u) : "f"(v));
    return u;
}

__device__ __forceinline__ void mma_tf32(float* d, const uint32_t* a, const uint32_t* b) {
    asm volatile(
        "mma.sync.aligned.m16n8k8.row.col.f32.tf32.tf32.f32 "
        "{%0,%1,%2,%3}, {%4,%5,%6,%7}, {%8,%9}, {%0,%1,%2,%3};\n"
        : "+f"(d[0]), "+f"(d[1]), "+f"(d[2]), "+f"(d[3])
        : "r"(a[0]), "r"(a[1]), "r"(a[2]), "r"(a[3]), "r"(b[0]), "r"(b[1]));
}

__device__ __forceinline__ void cp16(uint32_t dst, const float* src) {
    asm volatile("cp.async.cg.shared.global [%0], [%1], 16;" :: "r"(dst), "l"(src));
}
#define CP_COMMIT() asm volatile("cp.async.commit_group;")

// ---------------- multi-GEMM job table ----------------
struct GemmJob {
    const float* A; int lda;
    const float* B0; int ldb0; int n0;
    const float* B1; int ldb1;
    float* C; int ldc;
    int K;
    int ctaStart;
    int nx;
};
struct GemmJobs { GemmJob j[3]; };

constexpr int G2_A = 128 * 20;
constexpr int G2_B = 16 * 136;
constexpr int G2_SMEM = 3 * (G2_A + G2_B) * 4;   // 56832 B

__global__ void __launch_bounds__(256, 2)
gemm_multi(GemmJobs jobs, int njobs) {
    extern __shared__ float sm2[];
    float* As = sm2;
    float* Bs = sm2 + 3 * G2_A;

    int linear = blockIdx.x;
    int ji = njobs - 1;
#pragma unroll
    for (int t = 1; t < 3; t++)
        if (t < njobs && linear < jobs.j[t].ctaStart) { ji = t - 1; break; }
    const GemmJob& J = jobs.j[ji];
    int local = linear - J.ctaStart;
    int bx = local % J.nx, by = local / J.nx;

    const float* A = J.A; int lda = J.lda;
    float* C = J.C; int ldc = J.ldc;
    int K = J.K;
    int row0 = by * 128, col0 = bx * 128;

    const float* Bsrc;
    int ldb;
    if (col0 < J.n0) { Bsrc = J.B0 + col0; ldb = J.ldb0; }
    else             { Bsrc = J.B1 + (col0 - J.n0); ldb = J.ldb1; }

    int tid = threadIdx.x;
    int warp = tid >> 5, lane = tid & 31;
    int g = lane >> 2, tg = lane & 3;
    int wm = warp >> 2, wn = warp & 3;

    uint32_t as_addr = (uint32_t)__cvta_generic_to_shared(As);
    uint32_t bs_addr = (uint32_t)__cvta_generic_to_shared(Bs);

    const float* Ag0 = A + (size_t)(row0 + (tid >> 2)) * lda + (tid & 3) * 4;
    const float* Ag1 = A + (size_t)(row0 + 64 + (tid >> 2)) * lda + (tid & 3) * 4;
    const float* Bg0 = Bsrc + (size_t)(tid >> 5) * ldb + (tid & 31) * 4;
    const float* Bg1 = Bsrc + (size_t)(8 + (tid >> 5)) * ldb + (tid & 31) * 4;
    uint32_t offA0 = (((tid >> 2)) * 20 + (tid & 3) * 4) * 4;
    uint32_t offA1 = (((tid >> 2) + 64) * 20 + (tid & 3) * 4) * 4;
    uint32_t offB0 = ((tid >> 5) * 136 + (tid & 31) * 4) * 4;
    uint32_t offB1 = ((8 + (tid >> 5)) * 136 + (tid & 31) * 4) * 4;

    float d[4][4][4];
#pragma unroll
    for (int mi = 0; mi < 4; mi++)
#pragma unroll
        for (int ni = 0; ni < 4; ni++)
#pragma unroll
            for (int r = 0; r < 4; r++) d[mi][ni][r] = 0.f;

    int nk = K / 16;

    {
        cp16(as_addr + offA0, Ag0);
        cp16(as_addr + offA1, Ag1);
        cp16(bs_addr + offB0, Bg0);
        cp16(bs_addr + offB1, Bg1);
        CP_COMMIT();
    }
    if (nk > 1) {
        uint32_t ab = as_addr + G2_A * 4, bb = bs_addr + G2_B * 4;
        cp16(ab + offA0, Ag0 + 16);
        cp16(ab + offA1, Ag1 + 16);
        cp16(bb + offB0, Bg0 + (size_t)16 * ldb);
        cp16(bb + offB1, Bg1 + (size_t)16 * ldb);
        CP_COMMIT();
    }

    for (int kt = 0; kt < nk; kt++) {
        if (kt + 1 < nk) { asm volatile("cp.async.wait_group 1;"); }
        else             { asm volatile("cp.async.wait_group 0;"); }
        __syncthreads();

        if (kt + 2 < nk) {
            int s = (kt + 2) % 3;
            int k0 = (kt + 2) * 16;
            uint32_t ab = as_addr + s * G2_A * 4, bb = bs_addr + s * G2_B * 4;
            cp16(ab + offA0, Ag0 + k0);
            cp16(ab + offA1, Ag1 + k0);
            cp16(bb + offB0, Bg0 + (size_t)k0 * ldb);
            cp16(bb + offB1, Bg1 + (size_t)k0 * ldb);
            CP_COMMIT();
        }

        const float* Ac = As + (kt % 3) * G2_A;
        const float* Bc = Bs + (kt % 3) * G2_B;

#pragma unroll
        for (int ks = 0; ks < 16; ks += 8) {
            uint32_t bf[4][2];
#pragma unroll
            for (int ni = 0; ni < 4; ni++) {
                int c = wn * 32 + ni * 8 + g;
                bf[ni][0] = f2tf(Bc[(ks + tg) * 136 + c]);
                bf[ni][1] = f2tf(Bc[(ks + tg + 4) * 136 + c]);
            }
#pragma unroll
            for (int mi = 0; mi < 4; mi++) {
                int r = wm * 64 + mi * 16;
                uint32_t af[4];
                af[0] = f2tf(Ac[(r + g) * 20 + ks + tg]);
                af[1] = f2tf(Ac[(r + 8 + g) * 20 + ks + tg]);
                af[2] = f2tf(Ac[(r + g) * 20 + ks + tg + 4]);
                af[3] = f2tf(Ac[(r + 8 + g) * 20 + ks + tg + 4]);
#pragma unroll
                for (int ni = 0; ni < 4; ni++) {
                    mma_tf32(d[mi][ni], af, bf[ni]);
                }
            }
        }
    }

#pragma unroll
    for (int mi = 0; mi < 4; mi++) {
#pragma unroll
        for (int ni = 0; ni < 4; ni++) {
            int r = row0 + wm * 64 + mi * 16 + g;
            int c = col0 + wn * 32 + ni * 8 + 2 * tg;
            *(float2*)(C + (size_t)r * ldc + c) = make_float2(d[mi][ni][0], d[mi][ni][1]);
            *(float2*)(C + (size_t)(r + 8) * ldc + c) = make_float2(d[mi][ni][2], d[mi][ni][3]);
        }
    }
}

// ---------------- fused prep: scores | xmean | pack_wc1 ----------------
__global__ void prep_kernel(const float* __restrict__ x, const float* __restrict__ w_imp,
                            float* __restrict__ scores, float* __restrict__ xmean,
                            const float* __restrict__ w_cq, const float* __restrict__ w_ckv,
                            const float* __restrict__ w_krope, float* __restrict__ wc1) {
    int blk = blockIdx.x, tid = threadIdx.x;
    if (blk < 2048) {
        __shared__ float s8[8];
        int row = blk;
        float s = 0.f;
        for (int c = tid; c < CC; c += 256) s += x[row * CC + c] * w_imp[c];
#pragma unroll
        for (int o = 16; o > 0; o >>= 1) s += __shfl_xor_sync(0xffffffffu, s, o);
        if ((tid & 31) == 0) s8[tid >> 5] = s;
        __syncthreads();
        if (tid == 0) {
            float t = 0.f;
#pragma unroll
            for (int i = 0; i < 8; i++) t += s8[i];
            scores[row] = t;
        }
    } else if (blk < 2056) {
        int i = blk - 2048;
        int b = i >> 2;
        int c = (i & 3) * 256 + tid;
        float s = 0.f;
        for (int t = 0; t < TT; t++) s += x[(b * TT + t) * CC + c];
        xmean[b * CC + c] = s * (1.f / (float)TT);
    } else {
        int k = blk - 2056;
        float v;
        if (tid < 96) v = w_cq[k * 96 + tid];
        else if (tid < 128) v = w_ckv[k * 32 + (tid - 96)];
        else if (tid < 192) v = w_krope[k * 64 + (tid - 128)];
        else v = 0.f;
        wc1[k * 256 + tid] = v;
    }
}

// ---------------- fused topk + gate ----------------
__global__ void topk_gate_kernel(const float* __restrict__ scores, int* __restrict__ idxout,
                                 const float* __restrict__ xmean, const float* __restrict__ wg,
                                 float* __restrict__ gate) {
    int blk = blockIdx.x, tid = threadIdx.x;
    if (blk < 2) {
        __shared__ float sv[1024];
        __shared__ int si[1024];
        __shared__ int ti[256];
        int b = blk;
        sv[tid] = scores[b * TT + tid];
        si[tid] = tid;
        __syncthreads();
        for (int k = 2; k <= 1024; k <<= 1) {
            for (int j = k >> 1; j > 0; j >>= 1) {
                int ixj = tid ^ j;
                if (ixj > tid) {
                    bool desc = ((tid & k) == 0);
                    float va = sv[tid], vb = sv[ixj];
                    int ia = si[tid], ib = si[ixj];
                    bool agtb = (va > vb) || (va == vb && ia < ib);
                    if (desc ? !agtb : agtb) {
                        sv[tid] = vb; sv[ixj] = va;
                        si[tid] = ib; si[ixj] = ia;
                    }
                }
                __syncthreads();
            }
        }
        if (tid < 256) ti[tid] = si[tid];
        __syncthreads();
        for (int k = 2; k <= 256; k <<= 1) {
            for (int j = k >> 1; j > 0; j >>= 1) {
                int ixj = tid ^ j;
                if (tid < 256 && ixj > tid) {
                    bool asc = ((tid & k) == 0);
                    int ia = ti[tid], ib = ti[ixj];
                    if (asc ? (ia > ib) : (ia < ib)) { ti[tid] = ib; ti[ixj] = ia; }
                }
                __syncthreads();
            }
        }
        if (tid < 256) idxout[b * KEEP_ + tid] = ti[tid];
    } else {
        int b = blk - 2;
        __shared__ float sg[3];
        int w = tid >> 5, lane = tid & 31;
        if (w < 3) {
            float s = 0.f;
            for (int c = lane; c < CC; c += 32) s += xmean[b * CC + c] * wg[c * 3 + w];
#pragma unroll
            for (int o = 16; o > 0; o >>= 1) s += __shfl_xor_sync(0xffffffffu, s, o);
            if (lane == 0) sg[w] = s;
        }
        __syncthreads();
        if (tid == 0) {
            float m = fmaxf(sg[0], fmaxf(sg[1], sg[2]));
            float e0 = expf(sg[0] - m), e1 = expf(sg[1] - m), e2 = expf(sg[2] - m);
            float inv = 1.f / (e0 + e1 + e2);
            gate[b * 4 + 0] = e0 * inv;
            gate[b * 4 + 1] = e1 * inv;
            gate[b * 4 + 2] = e2 * inv;
        }
    }
}

// ---------------- gather ----------------
__global__ void gather_kernel(const float* __restrict__ x, const int* __restrict__ idx,
                              float* __restrict__ selx) {
    int row = blockIdx.x;
    int b = row >> 8;
    int t = idx[row];
    for (int c = threadIdx.x; c < CC; c += 256)
        selx[row * CC + c] = x[(b * TT + t) * CC + c];
}

// ---------------- fused RMS norm on packed f0 ----------------
__global__ void rms2_kernel(float* __restrict__ f0,
                            const float* __restrict__ gq, const float* __restrict__ gkv) {
    int row = blockIdx.x, tid = threadIdx.x;
    float* dd = f0 + row * 256;
    __shared__ float s4[4];
    float v = (tid < 96) ? dd[tid] : 0.f;
    float sq = v * v;
#pragma unroll
    for (int o = 16; o > 0; o >>= 1) sq += __shfl_xor_sync(0xffffffffu, sq, o);
    if ((tid & 31) == 0) s4[tid >> 5] = sq;
    __syncthreads();
    float tot = s4[0] + s4[1] + s4[2] + s4[3];
    float sc = rsqrtf(tot / 96.f + 1e-6f);
    if (tid < 96) dd[tid] = v * sc * gq[tid];
    __syncthreads();
    if (tid < 32) {
        float v2 = dd[96 + tid];
        float sq2 = v2 * v2;
#pragma unroll
        for (int o = 16; o > 0; o >>= 1) sq2 += __shfl_xor_sync(0xffffffffu, sq2, o);
        float sc2 = rsqrtf(sq2 / 32.f + 1e-6f);
        dd[96 + tid] = v2 * sc2 * gkv[tid];
    }
}

// ---------------- fused assembles (rope + layout), 512 threads ----------------
__global__ void assemble_all_kernel(const float* __restrict__ qout,
                                    const float* __restrict__ kvout,
                                    const float* __restrict__ f0,
                                    const float* __restrict__ selkv,
                                    const float* __restrict__ winout,
                                    float* __restrict__ Q,
                                    float* __restrict__ K1, float* __restrict__ V1,
                                    float* __restrict__ KSb, float* __restrict__ VSb,
                                    float* __restrict__ KWb, float* __restrict__ VWb) {
    int blk = blockIdx.x;
    int j = threadIdx.x;
    int h = j >> 5, d = j & 31;
    float f = expf(-LOG1E4_OVER_32 * (float)d);

    if (blk < 2048) {
        int row = blk;
        int b = row >> 10, t = row & 1023;
        int qb = (((b * HH + h) * TT) + t) * DQK;
        Q[qb + d] = qout[row * 1536 + j];
        float x1 = qout[row * 1536 + 512 + h * RD + d];
        float x2 = qout[row * 1536 + 512 + h * RD + RP + d];
        float sn, cs;
        sincosf((float)t * f, &sn, &cs);
        Q[qb + NOPE_ + d] = x1 * cs - x2 * sn;
        Q[qb + NOPE_ + RP + d] = x1 * sn + x2 * cs;
    } else if (blk < 4096) {
        int row = blk - 2048;
        int b = row >> 10, t = row & 1023;
        int kb = (((b * HH + h) * TT) + t) * DQK;
        K1[kb + d] = kvout[row * 1024 + j];
        float x1 = f0[row * 256 + 128 + d] * 0.0625f;
        float x2 = f0[row * 256 + 128 + RP + d] * 0.0625f;
        float sn, cs;
        sincosf((float)t * f, &sn, &cs);
        K1[kb + NOPE_ + d] = x1 * cs - x2 * sn;
        K1[kb + NOPE_ + RP + d] = x1 * sn + x2 * cs;
        V1[(((b * HH + h) * TT) + t) * VD + d] = kvout[row * 1024 + 512 + j];
    } else {
        const float* raw;
        float* K;
        float* V;
        int row, S;
        if (blk < 4608) { row = blk - 4096; S = KEEP_; raw = selkv; K = KSb; V = VSb; }
        else            { row = blk - 4608; S = TT;    raw = winout; K = KWb; V = VWb; }
        int b = row / S, pos = row % S;
        float nope = raw[row * 2048 + h * DQK + d];
        float x1 = raw[row * 2048 + h * DQK + NOPE_ + d];
        float x2 = raw[row * 2048 + h * DQK + NOPE_ + RP + d];
        float sn, cs;
        sincosf((float)pos * f, &sn, &cs);
        int kb = (((b * HH + h) * S) + pos) * DQK;
        K[kb + d] = nope;
        K[kb + NOPE_ + d] = x1 * cs - x2 * sn;
        K[kb + NOPE_ + RP + d] = x1 * sn + x2 * cs;
        V[(((b * HH + h) * S) + pos) * VD + d] = raw[row * 2048 + 1536 + h * VD + d];
    }
}

// ---------------- add att0+att1 -> att0 ----------------
__global__ void attadd_kernel(float* __restrict__ a0, const float* __restrict__ a1) {
    int i = (blockIdx.x * 256 + threadIdx.x) * 4;
    float4 v0 = *(float4*)(a0 + i);
    float4 v1 = *(const float4*)(a1 + i);
    v0.x += v1.x; v0.y += v1.y; v0.z += v1.z; v0.w += v1.w;
    *(float4*)(a0 + i) = v0;
}

// ---------------- pipelined tf32 MMA flash attention, branch-split ----------------
// blockIdx.x in 0..15: part = x&1 (0: branches {0,1} -> att0; 1: branch {2} -> att1),
// tile = 7 - (x>>1) (heavy first). Q fragments register-resident.
constexpr int QS_STR = 100;
constexpr int KS_STR = 100;
constexpr int VS_STR = 40;
constexpr int PS_STR = 68;
constexpr int KBUF = 64 * KS_STR;
constexpr int VBUF = 64 * VS_STR;
constexpr int ASM_QS = 0;
constexpr int ASM_KS = 128 * QS_STR;
constexpr int ASM_VS = ASM_KS + 2 * KBUF;
constexpr int ASM_PS = ASM_VS + 2 * VBUF;
constexpr int ATTN_SMEM = (ASM_PS + 8 * 16 * PS_STR) * 4;

__global__ void __launch_bounds__(256)
attn_mma(const float* __restrict__ Q,
         const float* __restrict__ K1, const float* __restrict__ V1,
         const float* __restrict__ KS, const float* __restrict__ VS,
         const float* __restrict__ KW, const float* __restrict__ VW,
         const float* __restrict__ gate,
         float* __restrict__ att0, float* __restrict__ att1) {
    extern __shared__ float sm[];
    float* Qs = sm + ASM_QS;

    int tid = threadIdx.x;
    int w = tid >> 5, lane = tid & 31;
    int g = lane >> 2, tg = lane & 3;
    float* Ps = sm + ASM_PS + w * 16 * PS_STR;

    int xid = blockIdx.x;
    int part = xid & 1;
    int tile = 7 - (xid >> 1);
    int h = blockIdx.y, b = blockIdx.z;
    int q0 = tile * 128;
    int bh = b * HH + h;
    int rowg = q0 + 16 * w + g;
    float* outp = part ? att1 : att0;

    uint32_t smem_u32 = (uint32_t)__cvta_generic_to_shared(sm);

    const float* Qp = Q + (bh * TT + q0) * DQK;
    for (int i = tid; i < 128 * 24; i += 256) {
        int q = i / 24, dq = i % 24;
        float4 v = *(const float4*)(Qp + q * DQK + dq * 4);
        v.x = to_tf32(v.x); v.y = to_tf32(v.y);
        v.z = to_tf32(v.z); v.w = to_tf32(v.w);
        *(float4*)&Qs[q * QS_STR + dq * 4] = v;
    }

    const float* Kpa[3] = {K1 + bh * TT * DQK, KS + bh * KEEP_ * DQK, KW + bh * TT * DQK};
    const float* Vpa[3] = {V1 + bh * TT * VD, VS + bh * KEEP_ * VD, VW + bh * TT * VD};
    int ncha[3] = {2 * (tile + 1), 4, 2 * (tile + 1)};

    // this part's branch list
    int brs[2];
    int nbr;
    if (part == 0) { brs[0] = 0; brs[1] = 1; nbr = 2; }
    else           { brs[0] = 2; brs[1] = 2; nbr = 1; }

    float fout[4][4];
#pragma unroll
    for (int nv = 0; nv < 4; nv++)
#pragma unroll
        for (int r = 0; r < 4; r++) fout[nv][r] = 0.f;

    auto stage = [&](int buf, const float* Kp, const float* Vp, int k0) {
        uint32_t kaddr = smem_u32 + (ASM_KS + buf * KBUF) * 4;
        uint32_t vaddr = smem_u32 + (ASM_VS + buf * VBUF) * 4;
#pragma unroll
        for (int it = 0; it < 6; it++) {
            int i = tid + it * 256;
            int key = i / 24, dq = i % 24;
            cp16(kaddr + (key * KS_STR + dq * 4) * 4, Kp + (k0 + key) * DQK + dq * 4);
        }
#pragma unroll
        for (int it = 0; it < 2; it++) {
            int i = tid + it * 256;
            int key = i >> 3, dq = i & 7;
            cp16(vaddr + (key * VS_STR + dq * 4) * 4, Vp + (k0 + key) * VD + dq * 4);
        }
        CP_COMMIT();
    };

    stage(0, Kpa[brs[0]], Vpa[brs[0]], 0);
    int buf = 0;

    // wait for Q staging, preload Q fragments (reused across all chunks)
    __syncthreads();
    uint32_t Qf[12][4];
    {
        const float* q0p = &Qs[(16 * w + g) * QS_STR];
        const float* q1p = q0p + 8 * QS_STR;
#pragma unroll
        for (int ks = 0; ks < 12; ks++) {
            Qf[ks][0] = __float_as_uint(q0p[8 * ks + tg]);
            Qf[ks][1] = __float_as_uint(q1p[8 * ks + tg]);
            Qf[ks][2] = __float_as_uint(q0p[8 * ks + tg + 4]);
            Qf[ks][3] = __float_as_uint(q1p[8 * ks + tg + 4]);
        }
    }

    for (int bi = 0; bi < nbr; bi++) {
        int br = brs[bi];
        bool causal = (br != 1);
        int nchunk = ncha[br];

        float m0 = -1e30f, m1 = -1e30f, l0 = 0.f, l1 = 0.f;
        float acc[4][4];
#pragma unroll
        for (int nv = 0; nv < 4; nv++)
#pragma unroll
            for (int r = 0; r < 4; r++) acc[nv][r] = 0.f;

        for (int c = 0; c < nchunk; c++) {
            int k0 = c * 64;
            int nbi = bi, nc = c + 1;
            if (nc == nchunk) { nbi = bi + 1; nc = 0; }

            __syncthreads();
            if (nbi < nbr) {
                stage(buf ^ 1, Kpa[brs[nbi]], Vpa[brs[nbi]], nc * 64);
                asm volatile("cp.async.wait_group 1;");
            } else {
                asm volatile("cp.async.wait_group 0;");
            }
            __syncthreads();

            const float* Kc = sm + ASM_KS + buf * KBUF;
            const float* Vc = sm + ASM_VS + buf * VBUF;

            float s[8][4];
#pragma unroll
            for (int ni = 0; ni < 8; ni++)
#pragma unroll
                for (int r = 0; r < 4; r++) s[ni][r] = 0.f;

#pragma unroll
            for (int ks = 0; ks < 12; ks++) {
                int kb = ks * 8;
#pragma unroll
                for (int ni = 0; ni < 8; ni++) {
                    uint32_t Bf[2];
                    Bf[0] = __float_as_uint(Kc[(8 * ni + g) * KS_STR + kb + tg]);
                    Bf[1] = __float_as_uint(Kc[(8 * ni + g) * KS_STR + kb + tg + 4]);
                    mma_tf32(s[ni], Qf[ks], Bf);
                }
            }

            if (causal && (k0 + 64 > q0)) {
#pragma unroll
                for (int ni = 0; ni < 8; ni++) {
                    int key = k0 + 8 * ni + 2 * tg;
                    if (key > rowg)         s[ni][0] = -1e30f;
                    if (key + 1 > rowg)     s[ni][1] = -1e30f;
                    if (key > rowg + 8)     s[ni][2] = -1e30f;
                    if (key + 1 > rowg + 8) s[ni][3] = -1e30f;
                }
            }

            float cm0 = -1e30f, cm1 = -1e30f;
#pragma unroll
            for (int ni = 0; ni < 8; ni++) {
                cm0 = fmaxf(cm0, fmaxf(s[ni][0], s[ni][1]));
                cm1 = fmaxf(cm1, fmaxf(s[ni][2], s[ni][3]));
            }
            cm0 = fmaxf(cm0, __shfl_xor_sync(0xffffffffu, cm0, 1));
            cm0 = fmaxf(cm0, __shfl_xor_sync(0xffffffffu, cm0, 2));
            cm1 = fmaxf(cm1, __shfl_xor_sync(0xffffffffu, cm1, 1));
            cm1 = fmaxf(cm1, __shfl_xor_sync(0xffffffffu, cm1, 2));

            float nm0 = fmaxf(m0, cm0), nm1 = fmaxf(m1, cm1);
            float al0 = __expf((m0 - nm0) * ATTN_SCALE);
            float al1 = __expf((m1 - nm1) * ATTN_SCALE);
            m0 = nm0; m1 = nm1;

            float sum0 = 0.f, sum1 = 0.f;
#pragma unroll
            for (int ni = 0; ni < 8; ni++) {
                s[ni][0] = __expf((s[ni][0] - m0) * ATTN_SCALE);
                s[ni][1] = __expf((s[ni][1] - m0) * ATTN_SCALE);
                s[ni][2] = __expf((s[ni][2] - m1) * ATTN_SCALE);
                s[ni][3] = __expf((s[ni][3] - m1) * ATTN_SCALE);
                sum0 += s[ni][0] + s[ni][1];
                sum1 += s[ni][2] + s[ni][3];
            }
            sum0 += __shfl_xor_sync(0xffffffffu, sum0, 1);
            sum0 += __shfl_xor_sync(0xffffffffu, sum0, 2);
            sum1 += __shfl_xor_sync(0xffffffffu, sum1, 1);
            sum1 += __shfl_xor_sync(0xffffffffu, sum1, 2);
            l0 = l0 * al0 + sum0;
            l1 = l1 * al1 + sum1;

#pragma unroll
            for (int nv = 0; nv < 4; nv++) {
                acc[nv][0] *= al0; acc[nv][1] *= al0;
                acc[nv][2] *= al1; acc[nv][3] *= al1;
            }

            __syncwarp();
#pragma unroll
            for (int ni = 0; ni < 8; ni++) {
                *(float2*)&Ps[g * PS_STR + 8 * ni + 2 * tg] =
                    make_float2(to_tf32(s[ni][0]), to_tf32(s[ni][1]));
                *(float2*)&Ps[(g + 8) * PS_STR + 8 * ni + 2 * tg] =
                    make_float2(to_tf32(s[ni][2]), to_tf32(s[ni][3]));
            }
            __syncwarp();

#pragma unroll
            for (int ks = 0; ks < 8; ks++) {
                int kb = ks * 8;
                uint32_t Af[4];
                Af[0] = __float_as_uint(Ps[g * PS_STR + kb + tg]);
                Af[1] = __float_as_uint(Ps[(g + 8) * PS_STR + kb + tg]);
                Af[2] = __float_as_uint(Ps[g * PS_STR + kb + tg + 4]);
                Af[3] = __float_as_uint(Ps[(g + 8) * PS_STR + kb + tg + 4]);
#pragma unroll
                for (int nv = 0; nv < 4; nv++) {
                    uint32_t Bf[2];
                    Bf[0] = f2tf(Vc[(kb + tg) * VS_STR + 8 * nv + g]);
                    Bf[1] = f2tf(Vc[(kb + tg + 4) * VS_STR + 8 * nv + g]);
                    mma_tf32(acc[nv], Af, Bf);
                }
            }
            buf ^= 1;
        }

        float gb = gate[b * 4 + br];
        float inv0 = gb / l0, inv1 = gb / l1;
#pragma unroll
        for (int nv = 0; nv < 4; nv++) {
            fout[nv][0] += acc[nv][0] * inv0;
            fout[nv][1] += acc[nv][1] * inv0;
            fout[nv][2] += acc[nv][2] * inv1;
            fout[nv][3] += acc[nv][3] * inv1;
        }
    }

#pragma unroll
    for (int nv = 0; nv < 4; nv++) {
        int col = h * VD + 8 * nv + 2 * tg;
        *(float2*)(outp + (b * TT + rowg) * (HH * VD) + col) =
            make_float2(fout[nv][0], fout[nv][1]);
        *(float2*)(outp + (b * TT + rowg + 8) * (HH * VD) + col) =
            make_float2(fout[nv][2], fout[nv][3]);
    }
}

// ---------------- launcher ----------------
extern "C" void kernel_launch(void* const* d_in, const int* in_sizes, int n_in,
                              void* d_out, int out_size) {
    const float* x         = (const float*)d_in[0];
    const float* w_cq      = (const float*)d_in[1];
    const float* g_qnorm   = (const float*)d_in[2];
    const float* w_dq_nope = (const float*)d_in[3];
    const float* w_dq_rope = (const float*)d_in[4];
    const float* w_ckv     = (const float*)d_in[5];
    const float* g_kvnorm  = (const float*)d_in[6];
    const float* w_dk_nope = (const float*)d_in[7];
    const float* w_dv      = (const float*)d_in[8];
    const float* w_krope   = (const float*)d_in[9];
    const float* w_imp     = (const float*)d_in[10];
    const float* w_selk    = (const float*)d_in[11];
    const float* w_selv    = (const float*)d_in[12];
    const float* w_wink    = (const float*)d_in[13];
    const float* w_winv    = (const float*)d_in[14];
    const float* w_gate    = (const float*)d_in[15];
    const float* w_proj    = (const float*)d_in[16];
    float* out = (float*)d_out;

    float* base = nullptr;
    cudaGetSymbolAddress((void**)&base, g_scratch);

    float* wc1    = base + OFF_WC1;
    float* f0     = base + OFF_F0;
    float* qout   = base + OFF_QOUT;
    float* kvout  = base + OFF_KVOUT;
    float* winout = base + OFF_WINOUT;
    float* selx   = base + OFF_SELX;
    float* selkv  = base + OFF_SELKV;
    float* xmean  = base + OFF_XMEAN;
    float* gate   = base + OFF_GATE;
    float* scores = base + OFF_SCORES;
    int*   idx    = (int*)(base + OFF_IDX);
    float* Qb     = base + OFF_Q;
    float* K1b    = base + OFF_K1;
    float* V1b    = base + OFF_V1;
    float* KWb    = base + OFF_KW;
    float* VWb    = base + OFF_VW;
    float* KSb    = base + OFF_KS;
    float* VSb    = base + OFF_VS;
    float* att0   = base + OFF_ATTN;
    float* att1   = base + OFF_ATTN2;

    const int M = BB * TT;  // 2048

    cudaFuncSetAttribute(gemm_multi, cudaFuncAttributeMaxDynamicSharedMemorySize, G2_SMEM);
    cudaFuncSetAttribute(attn_mma, cudaFuncAttributeMaxDynamicSharedMemorySize, ATTN_SMEM);

    // 1) prep: scores | xmean | pack wc1
    prep_kernel<<<3080, 256>>>(x, w_imp, scores, xmean, w_cq, w_ckv, w_krope, wc1);

    // 2) topk + gate
    topk_gate_kernel<<<4, 1024>>>(scores, idx, xmean, w_gate, gate);

    // 3) gather
    gather_kernel<<<BB * KEEP_, 256>>>(x, idx, selx);

    // 4) mega GEMM 1: winout | f0 | selkv (full K — split-K reverted, it just moved the tail)
    {
        GemmJobs jobs;
        jobs.j[0] = {x, CC, w_wink, 1536, 1536, w_winv, 512, winout, 2048, CC, 0, 16};
        jobs.j[1] = {x, CC, wc1, 256, 256, wc1, 256, f0, 256, CC, 256, 2};
        jobs.j[2] = {selx, CC, w_selk, 1536, 1536, w_selv, 512, selkv, 2048, CC, 288, 16};
        gemm_multi<<<352, 256, G2_SMEM>>>(jobs, 3);
    }

    // 5) rms on f0
    rms2_kernel<<<M, 128>>>(f0, g_qnorm, g_kvnorm);

    // 6) mega GEMM 2: qout | kvout (small)
    {
        GemmJobs jobs;
        jobs.j[0] = {f0, 256, w_dq_nope, 512, 512, w_dq_rope, 1024, qout, 1536, 96, 0, 12};
        jobs.j[1] = {f0 + 96, 256, w_dk_nope, 512, 512, w_dv, 512, kvout, 1024, 32, 192, 8};
        jobs.j[2] = jobs.j[1];
        gemm_multi<<<320, 256, G2_SMEM>>>(jobs, 2);
    }

    // 7) all assembles
    assemble_all_kernel<<<6656, 512>>>(qout, kvout, f0, selkv, winout,
                                       Qb, K1b, V1b, KSb, VSb, KWb, VWb);

    // 8) attention, branch-split into 2 parts (512 CTAs)
    attn_mma<<<dim3(16, HH, BB), 256, ATTN_SMEM>>>(Qb, K1b, V1b, KSb, VSb, KWb, VWb,
                                                   gate, att0, att1);

    // 8b) att0 += att1
    attadd_kernel<<<(M * HH * VD) / 1024, 256>>>(att0, att1);

    // 9) output projection
    {
        GemmJobs jobs;
        jobs.j[0] = {att0, HH * VD, w_proj, CC, CC, w_proj, CC, out, CC, HH * VD, 0, 8};
        jobs.j[1] = jobs.j[0];
        jobs.j[2] = jobs.j[0];
        gemm_multi<<<128, 256, G2_SMEM>>>(jobs, 1);
    }
}

// round 12
// speedup vs baseline: 12.8415x; 1.0137x over previous
#include <cuda_runtime.h>
#include <math.h>
#include <stdint.h>

// ---------------- problem constants ----------------
#define BB 2
#define TT 1024
#define CC 1024
#define HH 16
#define VD 32
#define NOPE_ 32
#define RP 32
#define RD 64
#define DQK 96
#define KEEP_ 256
#define QL 96
#define KVL 32

#define LOG1E4_OVER_32 0.28782313662425572f   // ln(10000)/32
#define ATTN_SCALE 0.10206207261596577f       // 1/sqrt(96)

// ---------------- scratch ----------------
constexpr int OFF_WC1     = 0;                           // [1024][256]
constexpr int OFF_F0      = OFF_WC1     + 1024*256;      // [2048][256]
constexpr int OFF_F0B     = OFF_F0      + 2048*256;      // [2048][256]
constexpr int OFF_QOUT    = OFF_F0B     + 2048*256;      // [2048][1536]
constexpr int OFF_KVOUT   = OFF_QOUT    + 2048*1536;     // [2048][1024]
constexpr int OFF_WINOUT  = OFF_KVOUT   + 2048*1024;     // [2048][2048]
constexpr int OFF_WINOUT2 = OFF_WINOUT  + 2048*2048;     // [2048][2048]
constexpr int OFF_SELKV   = OFF_WINOUT2 + 2048*2048;     // [512][2048]
constexpr int OFF_SELKV2  = OFF_SELKV   + 512*2048;      // [512][2048]
constexpr int OFF_XMEAN   = OFF_SELKV2  + 512*2048;
constexpr int OFF_GATE    = OFF_XMEAN   + BB*CC;
constexpr int OFF_SCORES  = OFF_GATE    + 8;
constexpr int OFF_IDX     = OFF_SCORES  + BB*TT;
constexpr int OFF_Q       = OFF_IDX     + BB*KEEP_;
constexpr int OFF_K1      = OFF_Q       + BB*HH*TT*DQK;
constexpr int OFF_V1      = OFF_K1      + BB*HH*TT*DQK;
constexpr int OFF_KW      = OFF_V1      + BB*HH*TT*VD;
constexpr int OFF_VW      = OFF_KW      + BB*HH*TT*DQK;
constexpr int OFF_KS      = OFF_VW      + BB*HH*TT*VD;
constexpr int OFF_VS      = OFF_KS      + BB*HH*KEEP_*DQK;
constexpr int OFF_ATTN    = OFF_VS      + BB*HH*KEEP_*VD;   // att0 (final attn sum)
constexpr int OFF_ATTN2   = OFF_ATTN    + BB*TT*HH*VD;      // att1
constexpr int OFF_ATTN3   = OFF_ATTN2   + BB*TT*HH*VD;      // att2
constexpr int OFF_PROJA   = OFF_ATTN3   + BB*TT*HH*VD;      // [2048][1024]
constexpr int OFF_PROJB   = OFF_PROJA   + 2048*1024;
constexpr int SCRATCH_TOTAL = OFF_PROJB + 2048*1024;

__device__ __align__(256) float g_scratch[SCRATCH_TOTAL];

// ---------------- tf32 helpers ----------------
__device__ __forceinline__ float to_tf32(float v) {
    uint32_t u;
    asm("cvt.rna.tf32.f32 %0, %1;" : "=r"(u) : "f"(v));
    return __uint_as_float(u);
}

__device__ __forceinline__ uint32_t f2tf(float v) {
    uint32_t u;
    asm("cvt.rna.tf32.f32 %0, %1;" : "=r"(u) : "f"(v));
    return u;
}

__device__ __forceinline__ void mma_tf32(float* d, const uint32_t* a, const uint32_t* b) {
    asm volatile(
        "mma.sync.aligned.m16n8k8.row.col.f32.tf32.tf32.f32 "
        "{%0,%1,%2,%3}, {%4,%5,%6,%7}, {%8,%9}, {%0,%1,%2,%3};\n"
        : "+f"(d[0]), "+f"(d[1]), "+f"(d[2]), "+f"(d[3])
        : "r"(a[0]), "r"(a[1]), "r"(a[2]), "r"(a[3]), "r"(b[0]), "r"(b[1]));
}

__device__ __forceinline__ void cp16(uint32_t dst, const float* src) {
    asm volatile("cp.async.cg.shared.global [%0], [%1], 16;" :: "r"(dst), "l"(src));
}
#define CP_COMMIT() asm volatile("cp.async.commit_group;")

// ---------------- multi-GEMM job table (up to 6 jobs, optional row indirection) -------
struct GemmJob {
    const float* A; int lda;
    const float* B0; int ldb0; int n0;
    const float* B1; int ldb1;
    float* C; int ldc;
    int K;
    int ctaStart;
    int nx;
    const int* rowIdx;   // optional: global A-row indices (gathered GEMM)
};
struct GemmJobs { GemmJob j[6]; };

constexpr int G2_A = 128 * 20;
constexpr int G2_B = 16 * 136;
constexpr int G2_SMEM = 3 * (G2_A + G2_B) * 4;   // 56832 B

__global__ void __launch_bounds__(256, 2)
gemm_multi(GemmJobs jobs, int njobs) {
    extern __shared__ float sm2[];
    float* As = sm2;
    float* Bs = sm2 + 3 * G2_A;

    int linear = blockIdx.x;
    int ji = njobs - 1;
#pragma unroll
    for (int t = 1; t < 6; t++)
        if (t < njobs && linear < jobs.j[t].ctaStart) { ji = t - 1; break; }
    const GemmJob& J = jobs.j[ji];
    int local = linear - J.ctaStart;
    int bx = local % J.nx, by = local / J.nx;

    const float* A = J.A; int lda = J.lda;
    float* C = J.C; int ldc = J.ldc;
    int K = J.K;
    int row0 = by * 128, col0 = bx * 128;

    const float* Bsrc;
    int ldb;
    if (col0 < J.n0) { Bsrc = J.B0 + col0; ldb = J.ldb0; }
    else             { Bsrc = J.B1 + (col0 - J.n0); ldb = J.ldb1; }

    int tid = threadIdx.x;
    int warp = tid >> 5, lane = tid & 31;
    int g = lane >> 2, tg = lane & 3;
    int wm = warp >> 2, wn = warp & 3;

    uint32_t as_addr = (uint32_t)__cvta_generic_to_shared(As);
    uint32_t bs_addr = (uint32_t)__cvta_generic_to_shared(Bs);

    // A row resolution (optionally via index array)
    int ar0 = row0 + (tid >> 2);
    int ar1 = row0 + 64 + (tid >> 2);
    if (J.rowIdx) { ar0 = J.rowIdx[ar0]; ar1 = J.rowIdx[ar1]; }
    const float* Ag0 = A + (size_t)ar0 * lda + (tid & 3) * 4;
    const float* Ag1 = A + (size_t)ar1 * lda + (tid & 3) * 4;
    const float* Bg0 = Bsrc + (size_t)(tid >> 5) * ldb + (tid & 31) * 4;
    const float* Bg1 = Bsrc + (size_t)(8 + (tid >> 5)) * ldb + (tid & 31) * 4;
    uint32_t offA0 = (((tid >> 2)) * 20 + (tid & 3) * 4) * 4;
    uint32_t offA1 = (((tid >> 2) + 64) * 20 + (tid & 3) * 4) * 4;
    uint32_t offB0 = ((tid >> 5) * 136 + (tid & 31) * 4) * 4;
    uint32_t offB1 = ((8 + (tid >> 5)) * 136 + (tid & 31) * 4) * 4;

    float d[4][4][4];
#pragma unroll
    for (int mi = 0; mi < 4; mi++)
#pragma unroll
        for (int ni = 0; ni < 4; ni++)
#pragma unroll
            for (int r = 0; r < 4; r++) d[mi][ni][r] = 0.f;

    int nk = K / 16;

    {
        cp16(as_addr + offA0, Ag0);
        cp16(as_addr + offA1, Ag1);
        cp16(bs_addr + offB0, Bg0);
        cp16(bs_addr + offB1, Bg1);
        CP_COMMIT();
    }
    if (nk > 1) {
        uint32_t ab = as_addr + G2_A * 4, bb = bs_addr + G2_B * 4;
        cp16(ab + offA0, Ag0 + 16);
        cp16(ab + offA1, Ag1 + 16);
        cp16(bb + offB0, Bg0 + (size_t)16 * ldb);
        cp16(bb + offB1, Bg1 + (size_t)16 * ldb);
        CP_COMMIT();
    }

    for (int kt = 0; kt < nk; kt++) {
        if (kt + 1 < nk) { asm volatile("cp.async.wait_group 1;"); }
        else             { asm volatile("cp.async.wait_group 0;"); }
        __syncthreads();

        if (kt + 2 < nk) {
            int s = (kt + 2) % 3;
            int k0 = (kt + 2) * 16;
            uint32_t ab = as_addr + s * G2_A * 4, bb = bs_addr + s * G2_B * 4;
            cp16(ab + offA0, Ag0 + k0);
            cp16(ab + offA1, Ag1 + k0);
            cp16(bb + offB0, Bg0 + (size_t)k0 * ldb);
            cp16(bb + offB1, Bg1 + (size_t)k0 * ldb);
            CP_COMMIT();
        }

        const float* Ac = As + (kt % 3) * G2_A;
        const float* Bc = Bs + (kt % 3) * G2_B;

#pragma unroll
        for (int ks = 0; ks < 16; ks += 8) {
            uint32_t bf[4][2];
#pragma unroll
            for (int ni = 0; ni < 4; ni++) {
                int c = wn * 32 + ni * 8 + g;
                bf[ni][0] = f2tf(Bc[(ks + tg) * 136 + c]);
                bf[ni][1] = f2tf(Bc[(ks + tg + 4) * 136 + c]);
            }
#pragma unroll
            for (int mi = 0; mi < 4; mi++) {
                int r = wm * 64 + mi * 16;
                uint32_t af[4];
                af[0] = f2tf(Ac[(r + g) * 20 + ks + tg]);
                af[1] = f2tf(Ac[(r + 8 + g) * 20 + ks + tg]);
                af[2] = f2tf(Ac[(r + g) * 20 + ks + tg + 4]);
                af[3] = f2tf(Ac[(r + 8 + g) * 20 + ks + tg + 4]);
#pragma unroll
                for (int ni = 0; ni < 4; ni++) {
                    mma_tf32(d[mi][ni], af, bf[ni]);
                }
            }
        }
    }

#pragma unroll
    for (int mi = 0; mi < 4; mi++) {
#pragma unroll
        for (int ni = 0; ni < 4; ni++) {
            int r = row0 + wm * 64 + mi * 16 + g;
            int c = col0 + wn * 32 + ni * 8 + 2 * tg;
            *(float2*)(C + (size_t)r * ldc + c) = make_float2(d[mi][ni][0], d[mi][ni][1]);
            *(float2*)(C + (size_t)(r + 8) * ldc + c) = make_float2(d[mi][ni][2], d[mi][ni][3]);
        }
    }
}

// ---------------- fused prep: scores | xmean | pack_wc1 ----------------
__global__ void prep_kernel(const float* __restrict__ x, const float* __restrict__ w_imp,
                            float* __restrict__ scores, float* __restrict__ xmean,
                            const float* __restrict__ w_cq, const float* __restrict__ w_ckv,
                            const float* __restrict__ w_krope, float* __restrict__ wc1) {
    int blk = blockIdx.x, tid = threadIdx.x;
    if (blk < 2048) {
        __shared__ float s8[8];
        int row = blk;
        float s = 0.f;
        for (int c = tid; c < CC; c += 256) s += x[row * CC + c] * w_imp[c];
#pragma unroll
        for (int o = 16; o > 0; o >>= 1) s += __shfl_xor_sync(0xffffffffu, s, o);
        if ((tid & 31) == 0) s8[tid >> 5] = s;
        __syncthreads();
        if (tid == 0) {
            float t = 0.f;
#pragma unroll
            for (int i = 0; i < 8; i++) t += s8[i];
            scores[row] = t;
        }
    } else if (blk < 2056) {
        int i = blk - 2048;
        int b = i >> 2;
        int c = (i & 3) * 256 + tid;
        float s = 0.f;
        for (int t = 0; t < TT; t++) s += x[(b * TT + t) * CC + c];
        xmean[b * CC + c] = s * (1.f / (float)TT);
    } else {
        int k = blk - 2056;
        float v;
        if (tid < 96) v = w_cq[k * 96 + tid];
        else if (tid < 128) v = w_ckv[k * 32 + (tid - 96)];
        else if (tid < 192) v = w_krope[k * 64 + (tid - 128)];
        else v = 0.f;
        wc1[k * 256 + tid] = v;
    }
}

// ---------------- fused topk + gate (topk emits GLOBAL row ids) ----------------
__global__ void topk_gate_kernel(const float* __restrict__ scores, int* __restrict__ idxout,
                                 const float* __restrict__ xmean, const float* __restrict__ wg,
                                 float* __restrict__ gate) {
    int blk = blockIdx.x, tid = threadIdx.x;
    if (blk < 2) {
        __shared__ float sv[1024];
        __shared__ int si[1024];
        __shared__ int ti[256];
        int b = blk;
        sv[tid] = scores[b * TT + tid];
        si[tid] = tid;
        __syncthreads();
        for (int k = 2; k <= 1024; k <<= 1) {
            for (int j = k >> 1; j > 0; j >>= 1) {
                int ixj = tid ^ j;
                if (ixj > tid) {
                    bool desc = ((tid & k) == 0);
                    float va = sv[tid], vb = sv[ixj];
                    int ia = si[tid], ib = si[ixj];
                    bool agtb = (va > vb) || (va == vb && ia < ib);
                    if (desc ? !agtb : agtb) {
                        sv[tid] = vb; sv[ixj] = va;
                        si[tid] = ib; si[ixj] = ia;
                    }
                }
                __syncthreads();
            }
        }
        if (tid < 256) ti[tid] = si[tid];
        __syncthreads();
        for (int k = 2; k <= 256; k <<= 1) {
            for (int j = k >> 1; j > 0; j >>= 1) {
                int ixj = tid ^ j;
                if (tid < 256 && ixj > tid) {
                    bool asc = ((tid & k) == 0);
                    int ia = ti[tid], ib = ti[ixj];
                    if (asc ? (ia > ib) : (ia < ib)) { ti[tid] = ib; ti[ixj] = ia; }
                }
                __syncthreads();
            }
        }
        if (tid < 256) idxout[b * KEEP_ + tid] = b * TT + ti[tid];   // global x row
    } else {
        int b = blk - 2;
        __shared__ float sg[3];
        int w = tid >> 5, lane = tid & 31;
        if (w < 3) {
            float s = 0.f;
            for (int c = lane; c < CC; c += 32) s += xmean[b * CC + c] * wg[c * 3 + w];
#pragma unroll
            for (int o = 16; o > 0; o >>= 1) s += __shfl_xor_sync(0xffffffffu, s, o);
            if (lane == 0) sg[w] = s;
        }
        __syncthreads();
        if (tid == 0) {
            float m = fmaxf(sg[0], fmaxf(sg[1], sg[2]));
            float e0 = expf(sg[0] - m), e1 = expf(sg[1] - m), e2 = expf(sg[2] - m);
            float inv = 1.f / (e0 + e1 + e2);
            gate[b * 4 + 0] = e0 * inv;
            gate[b * 4 + 1] = e1 * inv;
            gate[b * 4 + 2] = e2 * inv;
        }
    }
}

// ---------------- RMS norm, now also sums the f0 split-K halves ----------------
__global__ void rms2_kernel(float* __restrict__ f0, const float* __restrict__ f0b,
                            const float* __restrict__ gq, const float* __restrict__ gkv) {
    int row = blockIdx.x, tid = threadIdx.x;   // 128 threads
    float* dd = f0 + row * 256;
    const float* db = f0b + row * 256;
    __shared__ float s4[4];
    float v = (tid < 96) ? (dd[tid] + db[tid]) : 0.f;
    float sq = v * v;
#pragma unroll
    for (int o = 16; o > 0; o >>= 1) sq += __shfl_xor_sync(0xffffffffu, sq, o);
    if ((tid & 31) == 0) s4[tid >> 5] = sq;
    __syncthreads();
    float tot = s4[0] + s4[1] + s4[2] + s4[3];
    float sc = rsqrtf(tot / 96.f + 1e-6f);
    if (tid < 96) dd[tid] = v * sc * gq[tid];
    // krope cols: just sum halves
    dd[128 + tid] = dd[128 + tid] + db[128 + tid];
    __syncthreads();
    if (tid < 32) {
        float v2 = dd[96 + tid] + db[96 + tid];
        float sq2 = v2 * v2;
#pragma unroll
        for (int o = 16; o > 0; o >>= 1) sq2 += __shfl_xor_sync(0xffffffffu, sq2, o);
        float sc2 = rsqrtf(sq2 / 32.f + 1e-6f);
        dd[96 + tid] = v2 * sc2 * gkv[tid];
    }
}

// ---------------- fused assembles (rope + layout), sums split-K halves ----------------
__global__ void assemble_all_kernel(const float* __restrict__ qout,
                                    const float* __restrict__ kvout,
                                    const float* __restrict__ f0,
                                    const float* __restrict__ selkv,
                                    const float* __restrict__ selkv2,
                                    const float* __restrict__ winout,
                                    const float* __restrict__ winout2,
                                    float* __restrict__ Q,
                                    float* __restrict__ K1, float* __restrict__ V1,
                                    float* __restrict__ KSb, float* __restrict__ VSb,
                                    float* __restrict__ KWb, float* __restrict__ VWb) {
    int blk = blockIdx.x;
    int j = threadIdx.x;
    int h = j >> 5, d = j & 31;
    float f = expf(-LOG1E4_OVER_32 * (float)d);

    if (blk < 2048) {
        int row = blk;
        int b = row >> 10, t = row & 1023;
        int qb = (((b * HH + h) * TT) + t) * DQK;
        Q[qb + d] = qout[row * 1536 + j];
        float x1 = qout[row * 1536 + 512 + h * RD + d];
        float x2 = qout[row * 1536 + 512 + h * RD + RP + d];
        float sn, cs;
        sincosf((float)t * f, &sn, &cs);
        Q[qb + NOPE_ + d] = x1 * cs - x2 * sn;
        Q[qb + NOPE_ + RP + d] = x1 * sn + x2 * cs;
    } else if (blk < 4096) {
        int row = blk - 2048;
        int b = row >> 10, t = row & 1023;
        int kb = (((b * HH + h) * TT) + t) * DQK;
        K1[kb + d] = kvout[row * 1024 + j];
        float x1 = f0[row * 256 + 128 + d] * 0.0625f;
        float x2 = f0[row * 256 + 128 + RP + d] * 0.0625f;
        float sn, cs;
        sincosf((float)t * f, &sn, &cs);
        K1[kb + NOPE_ + d] = x1 * cs - x2 * sn;
        K1[kb + NOPE_ + RP + d] = x1 * sn + x2 * cs;
        V1[(((b * HH + h) * TT) + t) * VD + d] = kvout[row * 1024 + 512 + j];
    } else {
        const float* raw;
        const float* raw2;
        float* K;
        float* V;
        int row, S;
        if (blk < 4608) { row = blk - 4096; S = KEEP_; raw = selkv; raw2 = selkv2; K = KSb; V = VSb; }
        else            { row = blk - 4608; S = TT;    raw = winout; raw2 = winout2; K = KWb; V = VWb; }
        int b = row / S, pos = row % S;
        size_t base = (size_t)row * 2048;
        float nope = raw[base + h * DQK + d] + raw2[base + h * DQK + d];
        float x1 = raw[base + h * DQK + NOPE_ + d] + raw2[base + h * DQK + NOPE_ + d];
        float x2 = raw[base + h * DQK + NOPE_ + RP + d] + raw2[base + h * DQK + NOPE_ + RP + d];
        float sn, cs;
        sincosf((float)pos * f, &sn, &cs);
        int kb = (((b * HH + h) * S) + pos) * DQK;
        K[kb + d] = nope;
        K[kb + NOPE_ + d] = x1 * cs - x2 * sn;
        K[kb + NOPE_ + RP + d] = x1 * sn + x2 * cs;
        V[(((b * HH + h) * S) + pos) * VD + d] =
            raw[base + 1536 + h * VD + d] + raw2[base + 1536 + h * VD + d];
    }
}

// ---------------- adds ----------------
__global__ void attadd3_kernel(float* __restrict__ a0, const float* __restrict__ a1,
                               const float* __restrict__ a2) {
    int i = (blockIdx.x * 256 + threadIdx.x) * 4;
    float4 v0 = *(float4*)(a0 + i);
    float4 v1 = *(const float4*)(a1 + i);
    float4 v2 = *(const float4*)(a2 + i);
    v0.x += v1.x + v2.x; v0.y += v1.y + v2.y;
    v0.z += v1.z + v2.z; v0.w += v1.w + v2.w;
    *(float4*)(a0 + i) = v0;
}

__global__ void outadd_kernel(float* __restrict__ o, const float* __restrict__ pa,
                              const float* __restrict__ pb) {
    int i = (blockIdx.x * 256 + threadIdx.x) * 4;
    float4 va = *(const float4*)(pa + i);
    float4 vb = *(const float4*)(pb + i);
    va.x += vb.x; va.y += vb.y; va.z += vb.z; va.w += vb.w;
    *(float4*)(o + i) = va;
}

// ---------------- pipelined tf32 MMA flash attention, 3-way branch split ----------------
// blockIdx.x 0..23: tile = 7-(x/3), part = x%3. part0: br0->att0, part1: br2->att1,
// part2: br1->att2. Q fragments register-resident.
constexpr int QS_STR = 100;
constexpr int KS_STR = 100;
constexpr int VS_STR = 40;
constexpr int PS_STR = 68;
constexpr int KBUF = 64 * KS_STR;
constexpr int VBUF = 64 * VS_STR;
constexpr int ASM_QS = 0;
constexpr int ASM_KS = 128 * QS_STR;
constexpr int ASM_VS = ASM_KS + 2 * KBUF;
constexpr int ASM_PS = ASM_VS + 2 * VBUF;
constexpr int ATTN_SMEM = (ASM_PS + 8 * 16 * PS_STR) * 4;

__global__ void __launch_bounds__(256)
attn_mma(const float* __restrict__ Q,
         const float* __restrict__ K1, const float* __restrict__ V1,
         const float* __restrict__ KS, const float* __restrict__ VS,
         const float* __restrict__ KW, const float* __restrict__ VW,
         const float* __restrict__ gate,
         float* __restrict__ att0, float* __restrict__ att1, float* __restrict__ att2) {
    extern __shared__ float sm[];
    float* Qs = sm + ASM_QS;

    int tid = threadIdx.x;
    int w = tid >> 5, lane = tid & 31;
    int g = lane >> 2, tg = lane & 3;
    float* Ps = sm + ASM_PS + w * 16 * PS_STR;

    int xid = blockIdx.x;
    int part = xid % 3;
    int tile = 7 - (xid / 3);
    int h = blockIdx.y, b = blockIdx.z;
    int q0 = tile * 128;
    int bh = b * HH + h;
    int rowg = q0 + 16 * w + g;

    int br = (part == 0) ? 0 : ((part == 1) ? 2 : 1);
    float* outp = (part == 0) ? att0 : ((part == 1) ? att1 : att2);
    bool causal = (br != 1);
    int nchunk = (br == 1) ? 4 : 2 * (tile + 1);

    const float* Kp = (br == 0) ? K1 + bh * TT * DQK
                    : (br == 1) ? KS + bh * KEEP_ * DQK
                                : KW + bh * TT * DQK;
    const float* Vp = (br == 0) ? V1 + bh * TT * VD
                    : (br == 1) ? VS + bh * KEEP_ * VD
                                : VW + bh * TT * VD;

    uint32_t smem_u32 = (uint32_t)__cvta_generic_to_shared(sm);

    const float* Qp = Q + (bh * TT + q0) * DQK;
    for (int i = tid; i < 128 * 24; i += 256) {
        int q = i / 24, dq = i % 24;
        float4 v = *(const float4*)(Qp + q * DQK + dq * 4);
        v.x = to_tf32(v.x); v.y = to_tf32(v.y);
        v.z = to_tf32(v.z); v.w = to_tf32(v.w);
        *(float4*)&Qs[q * QS_STR + dq * 4] = v;
    }

    auto stage = [&](int buf, int k0) {
        uint32_t kaddr = smem_u32 + (ASM_KS + buf * KBUF) * 4;
        uint32_t vaddr = smem_u32 + (ASM_VS + buf * VBUF) * 4;
#pragma unroll
        for (int it = 0; it < 6; it++) {
            int i = tid + it * 256;
            int key = i / 24, dq = i % 24;
            cp16(kaddr + (key * KS_STR + dq * 4) * 4, Kp + (k0 + key) * DQK + dq * 4);
        }
#pragma unroll
        for (int it = 0; it < 2; it++) {
            int i = tid + it * 256;
            int key = i >> 3, dq = i & 7;
            cp16(vaddr + (key * VS_STR + dq * 4) * 4, Vp + (k0 + key) * VD + dq * 4);
        }
        CP_COMMIT();
    };

    stage(0, 0);
    int buf = 0;

    __syncthreads();
    uint32_t Qf[12][4];
    {
        const float* q0p = &Qs[(16 * w + g) * QS_STR];
        const float* q1p = q0p + 8 * QS_STR;
#pragma unroll
        for (int ks = 0; ks < 12; ks++) {
            Qf[ks][0] = __float_as_uint(q0p[8 * ks + tg]);
            Qf[ks][1] = __float_as_uint(q1p[8 * ks + tg]);
            Qf[ks][2] = __float_as_uint(q0p[8 * ks + tg + 4]);
            Qf[ks][3] = __float_as_uint(q1p[8 * ks + tg + 4]);
        }
    }

    float m0 = -1e30f, m1 = -1e30f, l0 = 0.f, l1 = 0.f;
    float acc[4][4];
#pragma unroll
    for (int nv = 0; nv < 4; nv++)
#pragma unroll
        for (int r = 0; r < 4; r++) acc[nv][r] = 0.f;

    for (int c = 0; c < nchunk; c++) {
        int k0 = c * 64;

        __syncthreads();
        if (c + 1 < nchunk) {
            stage(buf ^ 1, (c + 1) * 64);
            asm volatile("cp.async.wait_group 1;");
        } else {
            asm volatile("cp.async.wait_group 0;");
        }
        __syncthreads();

        const float* Kc = sm + ASM_KS + buf * KBUF;
        const float* Vc = sm + ASM_VS + buf * VBUF;

        float s[8][4];
#pragma unroll
        for (int ni = 0; ni < 8; ni++)
#pragma unroll
            for (int r = 0; r < 4; r++) s[ni][r] = 0.f;

#pragma unroll
        for (int ks = 0; ks < 12; ks++) {
            int kb = ks * 8;
#pragma unroll
            for (int ni = 0; ni < 8; ni++) {
                uint32_t Bf[2];
                Bf[0] = __float_as_uint(Kc[(8 * ni + g) * KS_STR + kb + tg]);
                Bf[1] = __float_as_uint(Kc[(8 * ni + g) * KS_STR + kb + tg + 4]);
                mma_tf32(s[ni], Qf[ks], Bf);
            }
        }

        if (causal && (k0 + 64 > q0)) {
#pragma unroll
            for (int ni = 0; ni < 8; ni++) {
                int key = k0 + 8 * ni + 2 * tg;
                if (key > rowg)         s[ni][0] = -1e30f;
                if (key + 1 > rowg)     s[ni][1] = -1e30f;
                if (key > rowg + 8)     s[ni][2] = -1e30f;
                if (key + 1 > rowg + 8) s[ni][3] = -1e30f;
            }
        }

        float cm0 = -1e30f, cm1 = -1e30f;
#pragma unroll
        for (int ni = 0; ni < 8; ni++) {
            cm0 = fmaxf(cm0, fmaxf(s[ni][0], s[ni][1]));
            cm1 = fmaxf(cm1, fmaxf(s[ni][2], s[ni][3]));
        }
        cm0 = fmaxf(cm0, __shfl_xor_sync(0xffffffffu, cm0, 1));
        cm0 = fmaxf(cm0, __shfl_xor_sync(0xffffffffu, cm0, 2));
        cm1 = fmaxf(cm1, __shfl_xor_sync(0xffffffffu, cm1, 1));
        cm1 = fmaxf(cm1, __shfl_xor_sync(0xffffffffu, cm1, 2));

        float nm0 = fmaxf(m0, cm0), nm1 = fmaxf(m1, cm1);
        float al0 = __expf((m0 - nm0) * ATTN_SCALE);
        float al1 = __expf((m1 - nm1) * ATTN_SCALE);
        m0 = nm0; m1 = nm1;

        float sum0 = 0.f, sum1 = 0.f;
#pragma unroll
        for (int ni = 0; ni < 8; ni++) {
            s[ni][0] = __expf((s[ni][0] - m0) * ATTN_SCALE);
            s[ni][1] = __expf((s[ni][1] - m0) * ATTN_SCALE);
            s[ni][2] = __expf((s[ni][2] - m1) * ATTN_SCALE);
            s[ni][3] = __expf((s[ni][3] - m1) * ATTN_SCALE);
            sum0 += s[ni][0] + s[ni][1];
            sum1 += s[ni][2] + s[ni][3];
        }
        sum0 += __shfl_xor_sync(0xffffffffu, sum0, 1);
        sum0 += __shfl_xor_sync(0xffffffffu, sum0, 2);
        sum1 += __shfl_xor_sync(0xffffffffu, sum1, 1);
        sum1 += __shfl_xor_sync(0xffffffffu, sum1, 2);
        l0 = l0 * al0 + sum0;
        l1 = l1 * al1 + sum1;

#pragma unroll
        for (int nv = 0; nv < 4; nv++) {
            acc[nv][0] *= al0; acc[nv][1] *= al0;
            acc[nv][2] *= al1; acc[nv][3] *= al1;
        }

        __syncwarp();
#pragma unroll
        for (int ni = 0; ni < 8; ni++) {
            *(float2*)&Ps[g * PS_STR + 8 * ni + 2 * tg] =
                make_float2(to_tf32(s[ni][0]), to_tf32(s[ni][1]));
            *(float2*)&Ps[(g + 8) * PS_STR + 8 * ni + 2 * tg] =
                make_float2(to_tf32(s[ni][2]), to_tf32(s[ni][3]));
        }
        __syncwarp();

#pragma unroll
        for (int ks = 0; ks < 8; ks++) {
            int kb = ks * 8;
            uint32_t Af[4];
            Af[0] = __float_as_uint(Ps[g * PS_STR + kb + tg]);
            Af[1] = __float_as_uint(Ps[(g + 8) * PS_STR + kb + tg]);
            Af[2] = __float_as_uint(Ps[g * PS_STR + kb + tg + 4]);
            Af[3] = __float_as_uint(Ps[(g + 8) * PS_STR + kb + tg + 4]);
#pragma unroll
            for (int nv = 0; nv < 4; nv++) {
                uint32_t Bf[2];
                Bf[0] = f2tf(Vc[(kb + tg) * VS_STR + 8 * nv + g]);
                Bf[1] = f2tf(Vc[(kb + tg + 4) * VS_STR + 8 * nv + g]);
                mma_tf32(acc[nv], Af, Bf);
            }
        }
        buf ^= 1;
    }

    float gb = gate[b * 4 + br];
    float inv0 = gb / l0, inv1 = gb / l1;
#pragma unroll
    for (int nv = 0; nv < 4; nv++) {
        int col = h * VD + 8 * nv + 2 * tg;
        *(float2*)(outp + (b * TT + rowg) * (HH * VD) + col) =
            make_float2(acc[nv][0] * inv0, acc[nv][1] * inv0);
        *(float2*)(outp + (b * TT + rowg + 8) * (HH * VD) + col) =
            make_float2(acc[nv][2] * inv1, acc[nv][3] * inv1);
    }
}

// ---------------- launcher ----------------
extern "C" void kernel_launch(void* const* d_in, const int* in_sizes, int n_in,
                              void* d_out, int out_size) {
    const float* x         = (const float*)d_in[0];
    const float* w_cq      = (const float*)d_in[1];
    const float* g_qnorm   = (const float*)d_in[2];
    const float* w_dq_nope = (const float*)d_in[3];
    const float* w_dq_rope = (const float*)d_in[4];
    const float* w_ckv     = (const float*)d_in[5];
    const float* g_kvnorm  = (const float*)d_in[6];
    const float* w_dk_nope = (const float*)d_in[7];
    const float* w_dv      = (const float*)d_in[8];
    const float* w_krope   = (const float*)d_in[9];
    const float* w_imp     = (const float*)d_in[10];
    const float* w_selk    = (const float*)d_in[11];
    const float* w_selv    = (const float*)d_in[12];
    const float* w_wink    = (const float*)d_in[13];
    const float* w_winv    = (const float*)d_in[14];
    const float* w_gate    = (const float*)d_in[15];
    const float* w_proj    = (const float*)d_in[16];
    float* out = (float*)d_out;

    float* base = nullptr;
    cudaGetSymbolAddress((void**)&base, g_scratch);

    float* wc1     = base + OFF_WC1;
    float* f0      = base + OFF_F0;
    float* f0b     = base + OFF_F0B;
    float* qout    = base + OFF_QOUT;
    float* kvout   = base + OFF_KVOUT;
    float* winout  = base + OFF_WINOUT;
    float* winout2 = base + OFF_WINOUT2;
    float* selkv   = base + OFF_SELKV;
    float* selkv2  = base + OFF_SELKV2;
    float* xmean   = base + OFF_XMEAN;
    float* gate    = base + OFF_GATE;
    float* scores  = base + OFF_SCORES;
    int*   idx     = (int*)(base + OFF_IDX);
    float* Qb      = base + OFF_Q;
    float* K1b     = base + OFF_K1;
    float* V1b     = base + OFF_V1;
    float* KWb     = base + OFF_KW;
    float* VWb     = base + OFF_VW;
    float* KSb     = base + OFF_KS;
    float* VSb     = base + OFF_VS;
    float* att0    = base + OFF_ATTN;
    float* att1    = base + OFF_ATTN2;
    float* att2    = base + OFF_ATTN3;
    float* projA   = base + OFF_PROJA;
    float* projB   = base + OFF_PROJB;

    const int M = BB * TT;  // 2048

    cudaFuncSetAttribute(gemm_multi, cudaFuncAttributeMaxDynamicSharedMemorySize, G2_SMEM);
    cudaFuncSetAttribute(attn_mma, cudaFuncAttributeMaxDynamicSharedMemorySize, ATTN_SMEM);

    // 1) prep: scores | xmean | pack wc1
    prep_kernel<<<3080, 256>>>(x, w_imp, scores, xmean, w_cq, w_ckv, w_krope, wc1);

    // 2) topk + gate (topk emits global row ids -> gather fused into GEMM)
    topk_gate_kernel<<<4, 1024>>>(scores, idx, xmean, w_gate, gate);

    // 3) mega GEMM 1: all jobs split-K into halves -> 704 equal half-tiles
    //    (kills the 352-on-296 two-wave quantization; consumers sum the halves)
    {
        GemmJobs jobs;
        jobs.j[0] = {x, CC, w_wink, 1536, 1536, w_winv, 512,
                     winout, 2048, 512, 0, 16, nullptr};
        jobs.j[1] = {x + 512, CC, w_wink + 512 * 1536, 1536, 1536, w_winv + 512 * 512, 512,
                     winout2, 2048, 512, 256, 16, nullptr};
        jobs.j[2] = {x, CC, w_selk, 1536, 1536, w_selv, 512,
                     selkv, 2048, 512, 512, 16, idx};
        jobs.j[3] = {x + 512, CC, w_selk + 512 * 1536, 1536, 1536, w_selv + 512 * 512, 512,
                     selkv2, 2048, 512, 576, 16, idx};
        jobs.j[4] = {x, CC, wc1, 256, 256, wc1, 256,
                     f0, 256, 512, 640, 2, nullptr};
        jobs.j[5] = {x + 512, CC, wc1 + 512 * 256, 256, 256, wc1 + 512 * 256, 256,
                     f0b, 256, 512, 704 - 32, 2, nullptr};
        gemm_multi<<<704, 256, G2_SMEM>>>(jobs, 6);
    }

    // 4) rms on f0 (sums f0 halves)
    rms2_kernel<<<M, 128>>>(f0, f0b, g_qnorm, g_kvnorm);

    // 5) mega GEMM 2: qout | kvout
    {
        GemmJobs jobs;
        jobs.j[0] = {f0, 256, w_dq_nope, 512, 512, w_dq_rope, 1024,
                     qout, 1536, 96, 0, 12, nullptr};
        jobs.j[1] = {f0 + 96, 256, w_dk_nope, 512, 512, w_dv, 512,
                     kvout, 1024, 32, 192, 8, nullptr};
        gemm_multi<<<320, 256, G2_SMEM>>>(jobs, 2);
    }

    // 6) all assembles (sums winout/selkv halves)
    assemble_all_kernel<<<6656, 512>>>(qout, kvout, f0, selkv, selkv2, winout, winout2,
                                       Qb, K1b, V1b, KSb, VSb, KWb, VWb);

    // 7) attention, 3-way branch split (768 CTAs, heavy tiles first)
    attn_mma<<<dim3(24, HH, BB), 256, ATTN_SMEM>>>(Qb, K1b, V1b, KSb, VSb, KWb, VWb,
                                                   gate, att0, att1, att2);

    // 7b) att0 += att1 + att2
    attadd3_kernel<<<(M * HH * VD) / 1024, 256>>>(att0, att1, att2);

    // 8) output projection, split-K halves (256 CTAs, one wave)
    {
        GemmJobs jobs;
        jobs.j[0] = {att0, HH * VD, w_proj, CC, CC, w_proj, CC,
                     projA, CC, 256, 0, 8, nullptr};
        jobs.j[1] = {att0 + 256, HH * VD, w_proj + 256 * CC, CC, CC, w_proj + 256 * CC, CC,
                     projB, CC, 256, 128, 8, nullptr};
        gemm_multi<<<256, 256, G2_SMEM>>>(jobs, 2);
    }

    // 8b) out = projA + projB
    outadd_kernel<<<(M * CC) / 1024, 256>>>(out, projA, projB);
}

// round 13
// speedup vs baseline: 12.8505x; 1.0007x over previous
#include <cuda_runtime.h>
#include <math.h>
#include <stdint.h>

// ---------------- problem constants ----------------
#define BB 2
#define TT 1024
#define CC 1024
#define HH 16
#define VD 32
#define NOPE_ 32
#define RP 32
#define RD 64
#define DQK 96
#define KEEP_ 256
#define QL 96
#define KVL 32

#define LOG1E4_OVER_32 0.28782313662425572f   // ln(10000)/32
#define ATTN_SCALE 0.10206207261596577f       // 1/sqrt(96)

// ---------------- scratch ----------------
constexpr int OFF_WC1     = 0;                           // [1024][256]
constexpr int OFF_F0      = OFF_WC1     + 1024*256;      // [2048][256]
constexpr int OFF_QOUT    = OFF_F0      + 2048*256;      // [2048][1536]
constexpr int OFF_KVOUT   = OFF_QOUT    + 2048*1536;     // [2048][1024] knope|v1
constexpr int OFF_WINOUT  = OFF_KVOUT   + 2048*1024;     // [2048][2048] kw|vw
constexpr int OFF_SELKV   = OFF_WINOUT  + 2048*2048;     // [512][2048]  ks|vs
constexpr int OFF_XMEAN   = OFF_SELKV   + 512*2048;
constexpr int OFF_GATE    = OFF_XMEAN   + BB*CC;
constexpr int OFF_SCORES  = OFF_GATE    + 8;
constexpr int OFF_IDX     = OFF_SCORES  + BB*TT;
constexpr int OFF_Q       = OFF_IDX     + BB*KEEP_;
constexpr int OFF_K1      = OFF_Q       + BB*HH*TT*DQK;
constexpr int OFF_KW      = OFF_K1      + BB*HH*TT*DQK;
constexpr int OFF_KS      = OFF_KW      + BB*HH*TT*DQK;
constexpr int OFF_ATTN    = OFF_KS      + BB*HH*KEEP_*DQK;  // att0 (final attn sum)
constexpr int OFF_ATTN2   = OFF_ATTN    + BB*TT*HH*VD;      // att1
constexpr int OFF_ATTN3   = OFF_ATTN2   + BB*TT*HH*VD;      // att2
constexpr int OFF_PROJA   = OFF_ATTN3   + BB*TT*HH*VD;      // [2048][1024]
constexpr int OFF_PROJB   = OFF_PROJA   + 2048*1024;
constexpr int SCRATCH_TOTAL = OFF_PROJB + 2048*1024;

__device__ __align__(256) float g_scratch[SCRATCH_TOTAL];

// ---------------- tf32 helpers ----------------
__device__ __forceinline__ float to_tf32(float v) {
    uint32_t u;
    asm("cvt.rna.tf32.f32 %0, %1;" : "=r"(u) : "f"(v));
    return __uint_as_float(u);
}

__device__ __forceinline__ uint32_t f2tf(float v) {
    uint32_t u;
    asm("cvt.rna.tf32.f32 %0, %1;" : "=r"(u) : "f"(v));
    return u;
}

__device__ __forceinline__ void mma_tf32(float* d, const uint32_t* a, const uint32_t* b) {
    asm volatile(
        "mma.sync.aligned.m16n8k8.row.col.f32.tf32.tf32.f32 "
        "{%0,%1,%2,%3}, {%4,%5,%6,%7}, {%8,%9}, {%0,%1,%2,%3};\n"
        : "+f"(d[0]), "+f"(d[1]), "+f"(d[2]), "+f"(d[3])
        : "r"(a[0]), "r"(a[1]), "r"(a[2]), "r"(a[3]), "r"(b[0]), "r"(b[1]));
}

__device__ __forceinline__ void cp16(uint32_t dst, const float* src) {
    asm volatile("cp.async.cg.shared.global [%0], [%1], 16;" :: "r"(dst), "l"(src));
}
#define CP_COMMIT() asm volatile("cp.async.commit_group;")

// ---------------- multi-GEMM job table ----------------
struct GemmJob {
    const float* A; int lda;
    const float* B0; int ldb0; int n0;
    const float* B1; int ldb1;
    float* C; int ldc;
    int K;
    int ctaStart;
    int nx;
    const int* rowIdx;   // optional: global A-row indices (gathered GEMM)
};
struct GemmJobs { GemmJob j[3]; };

constexpr int G2_A = 128 * 20;
constexpr int G2_B = 16 * 136;
constexpr int G2_SMEM = 3 * (G2_A + G2_B) * 4;   // 56832 B

__global__ void __launch_bounds__(256, 2)
gemm_multi(GemmJobs jobs, int njobs) {
    extern __shared__ float sm2[];
    float* As = sm2;
    float* Bs = sm2 + 3 * G2_A;

    int linear = blockIdx.x;
    int ji = njobs - 1;
#pragma unroll
    for (int t = 1; t < 3; t++)
        if (t < njobs && linear < jobs.j[t].ctaStart) { ji = t - 1; break; }
    const GemmJob& J = jobs.j[ji];
    int local = linear - J.ctaStart;
    int bx = local % J.nx, by = local / J.nx;

    const float* A = J.A; int lda = J.lda;
    float* C = J.C; int ldc = J.ldc;
    int K = J.K;
    int row0 = by * 128, col0 = bx * 128;

    const float* Bsrc;
    int ldb;
    if (col0 < J.n0) { Bsrc = J.B0 + col0; ldb = J.ldb0; }
    else             { Bsrc = J.B1 + (col0 - J.n0); ldb = J.ldb1; }

    int tid = threadIdx.x;
    int warp = tid >> 5, lane = tid & 31;
    int g = lane >> 2, tg = lane & 3;
    int wm = warp >> 2, wn = warp & 3;

    uint32_t as_addr = (uint32_t)__cvta_generic_to_shared(As);
    uint32_t bs_addr = (uint32_t)__cvta_generic_to_shared(Bs);

    int ar0 = row0 + (tid >> 2);
    int ar1 = row0 + 64 + (tid >> 2);
    if (J.rowIdx) { ar0 = J.rowIdx[ar0]; ar1 = J.rowIdx[ar1]; }
    const float* Ag0 = A + (size_t)ar0 * lda + (tid & 3) * 4;
    const float* Ag1 = A + (size_t)ar1 * lda + (tid & 3) * 4;
    const float* Bg0 = Bsrc + (size_t)(tid >> 5) * ldb + (tid & 31) * 4;
    const float* Bg1 = Bsrc + (size_t)(8 + (tid >> 5)) * ldb + (tid & 31) * 4;
    uint32_t offA0 = (((tid >> 2)) * 20 + (tid & 3) * 4) * 4;
    uint32_t offA1 = (((tid >> 2) + 64) * 20 + (tid & 3) * 4) * 4;
    uint32_t offB0 = ((tid >> 5) * 136 + (tid & 31) * 4) * 4;
    uint32_t offB1 = ((8 + (tid >> 5)) * 136 + (tid & 31) * 4) * 4;

    float d[4][4][4];
#pragma unroll
    for (int mi = 0; mi < 4; mi++)
#pragma unroll
        for (int ni = 0; ni < 4; ni++)
#pragma unroll
            for (int r = 0; r < 4; r++) d[mi][ni][r] = 0.f;

    int nk = K / 16;

    {
        cp16(as_addr + offA0, Ag0);
        cp16(as_addr + offA1, Ag1);
        cp16(bs_addr + offB0, Bg0);
        cp16(bs_addr + offB1, Bg1);
        CP_COMMIT();
    }
    if (nk > 1) {
        uint32_t ab = as_addr + G2_A * 4, bb = bs_addr + G2_B * 4;
        cp16(ab + offA0, Ag0 + 16);
        cp16(ab + offA1, Ag1 + 16);
        cp16(bb + offB0, Bg0 + (size_t)16 * ldb);
        cp16(bb + offB1, Bg1 + (size_t)16 * ldb);
        CP_COMMIT();
    }

    for (int kt = 0; kt < nk; kt++) {
        if (kt + 1 < nk) { asm volatile("cp.async.wait_group 1;"); }
        else             { asm volatile("cp.async.wait_group 0;"); }
        __syncthreads();

        if (kt + 2 < nk) {
            int s = (kt + 2) % 3;
            int k0 = (kt + 2) * 16;
            uint32_t ab = as_addr + s * G2_A * 4, bb = bs_addr + s * G2_B * 4;
            cp16(ab + offA0, Ag0 + k0);
            cp16(ab + offA1, Ag1 + k0);
            cp16(bb + offB0, Bg0 + (size_t)k0 * ldb);
            cp16(bb + offB1, Bg1 + (size_t)k0 * ldb);
            CP_COMMIT();
        }

        const float* Ac = As + (kt % 3) * G2_A;
        const float* Bc = Bs + (kt % 3) * G2_B;

#pragma unroll
        for (int ks = 0; ks < 16; ks += 8) {
            uint32_t bf[4][2];
#pragma unroll
            for (int ni = 0; ni < 4; ni++) {
                int c = wn * 32 + ni * 8 + g;
                bf[ni][0] = f2tf(Bc[(ks + tg) * 136 + c]);
                bf[ni][1] = f2tf(Bc[(ks + tg + 4) * 136 + c]);
            }
#pragma unroll
            for (int mi = 0; mi < 4; mi++) {
                int r = wm * 64 + mi * 16;
                uint32_t af[4];
                af[0] = f2tf(Ac[(r + g) * 20 + ks + tg]);
                af[1] = f2tf(Ac[(r + 8 + g) * 20 + ks + tg]);
                af[2] = f2tf(Ac[(r + g) * 20 + ks + tg + 4]);
                af[3] = f2tf(Ac[(r + 8 + g) * 20 + ks + tg + 4]);
#pragma unroll
                for (int ni = 0; ni < 4; ni++) {
                    mma_tf32(d[mi][ni], af, bf[ni]);
                }
            }
        }
    }

#pragma unroll
    for (int mi = 0; mi < 4; mi++) {
#pragma unroll
        for (int ni = 0; ni < 4; ni++) {
            int r = row0 + wm * 64 + mi * 16 + g;
            int c = col0 + wn * 32 + ni * 8 + 2 * tg;
            *(float2*)(C + (size_t)r * ldc + c) = make_float2(d[mi][ni][0], d[mi][ni][1]);
            *(float2*)(C + (size_t)(r + 8) * ldc + c) = make_float2(d[mi][ni][2], d[mi][ni][3]);
        }
    }
}

// ---------------- fused prep: scores | xmean | pack_wc1 ----------------
__global__ void prep_kernel(const float* __restrict__ x, const float* __restrict__ w_imp,
                            float* __restrict__ scores, float* __restrict__ xmean,
                            const float* __restrict__ w_cq, const float* __restrict__ w_ckv,
                            const float* __restrict__ w_krope, float* __restrict__ wc1) {
    int blk = blockIdx.x, tid = threadIdx.x;
    if (blk < 2048) {
        __shared__ float s8[8];
        int row = blk;
        float s = 0.f;
        for (int c = tid; c < CC; c += 256) s += x[row * CC + c] * w_imp[c];
#pragma unroll
        for (int o = 16; o > 0; o >>= 1) s += __shfl_xor_sync(0xffffffffu, s, o);
        if ((tid & 31) == 0) s8[tid >> 5] = s;
        __syncthreads();
        if (tid == 0) {
            float t = 0.f;
#pragma unroll
            for (int i = 0; i < 8; i++) t += s8[i];
            scores[row] = t;
        }
    } else if (blk < 2056) {
        int i = blk - 2048;
        int b = i >> 2;
        int c = (i & 3) * 256 + tid;
        float s = 0.f;
        for (int t = 0; t < TT; t++) s += x[(b * TT + t) * CC + c];
        xmean[b * CC + c] = s * (1.f / (float)TT);
    } else {
        int k = blk - 2056;
        float v;
        if (tid < 96) v = w_cq[k * 96 + tid];
        else if (tid < 128) v = w_ckv[k * 32 + (tid - 96)];
        else if (tid < 192) v = w_krope[k * 64 + (tid - 128)];
        else v = 0.f;
        wc1[k * 256 + tid] = v;
    }
}

// ---------------- fused topk + gate (topk emits GLOBAL row ids) ----------------
__global__ void topk_gate_kernel(const float* __restrict__ scores, int* __restrict__ idxout,
                                 const float* __restrict__ xmean, const float* __restrict__ wg,
                                 float* __restrict__ gate) {
    int blk = blockIdx.x, tid = threadIdx.x;
    if (blk < 2) {
        __shared__ float sv[1024];
        __shared__ int si[1024];
        __shared__ int ti[256];
        int b = blk;
        sv[tid] = scores[b * TT + tid];
        si[tid] = tid;
        __syncthreads();
        for (int k = 2; k <= 1024; k <<= 1) {
            for (int j = k >> 1; j > 0; j >>= 1) {
                int ixj = tid ^ j;
                if (ixj > tid) {
                    bool desc = ((tid & k) == 0);
                    float va = sv[tid], vb = sv[ixj];
                    int ia = si[tid], ib = si[ixj];
                    bool agtb = (va > vb) || (va == vb && ia < ib);
                    if (desc ? !agtb : agtb) {
                        sv[tid] = vb; sv[ixj] = va;
                        si[tid] = ib; si[ixj] = ia;
                    }
                }
                __syncthreads();
            }
        }
        if (tid < 256) ti[tid] = si[tid];
        __syncthreads();
        for (int k = 2; k <= 256; k <<= 1) {
            for (int j = k >> 1; j > 0; j >>= 1) {
                int ixj = tid ^ j;
                if (tid < 256 && ixj > tid) {
                    bool asc = ((tid & k) == 0);
                    int ia = ti[tid], ib = ti[ixj];
                    if (asc ? (ia > ib) : (ia < ib)) { ti[tid] = ib; ti[ixj] = ia; }
                }
                __syncthreads();
            }
        }
        if (tid < 256) idxout[b * KEEP_ + tid] = b * TT + ti[tid];   // global x row
    } else {
        int b = blk - 2;
        __shared__ float sg[3];
        int w = tid >> 5, lane = tid & 31;
        if (w < 3) {
            float s = 0.f;
            for (int c = lane; c < CC; c += 32) s += xmean[b * CC + c] * wg[c * 3 + w];
#pragma unroll
            for (int o = 16; o > 0; o >>= 1) s += __shfl_xor_sync(0xffffffffu, s, o);
            if (lane == 0) sg[w] = s;
        }
        __syncthreads();
        if (tid == 0) {
            float m = fmaxf(sg[0], fmaxf(sg[1], sg[2]));
            float e0 = expf(sg[0] - m), e1 = expf(sg[1] - m), e2 = expf(sg[2] - m);
            float inv = 1.f / (e0 + e1 + e2);
            gate[b * 4 + 0] = e0 * inv;
            gate[b * 4 + 1] = e1 * inv;
            gate[b * 4 + 2] = e2 * inv;
        }
    }
}

// ---------------- RMS norm on f0 ----------------
__global__ void rms2_kernel(float* __restrict__ f0,
                            const float* __restrict__ gq, const float* __restrict__ gkv) {
    int row = blockIdx.x, tid = threadIdx.x;   // 128 threads
    float* dd = f0 + row * 256;
    __shared__ float s4[4];
    float v = (tid < 96) ? dd[tid] : 0.f;
    float sq = v * v;
#pragma unroll
    for (int o = 16; o > 0; o >>= 1) sq += __shfl_xor_sync(0xffffffffu, sq, o);
    if ((tid & 31) == 0) s4[tid >> 5] = sq;
    __syncthreads();
    float tot = s4[0] + s4[1] + s4[2] + s4[3];
    float sc = rsqrtf(tot / 96.f + 1e-6f);
    if (tid < 96) dd[tid] = v * sc * gq[tid];
    __syncthreads();
    if (tid < 32) {
        float v2 = dd[96 + tid];
        float sq2 = v2 * v2;
#pragma unroll
        for (int o = 16; o > 0; o >>= 1) sq2 += __shfl_xor_sync(0xffffffffu, sq2, o);
        float sc2 = rsqrtf(sq2 / 32.f + 1e-6f);
        dd[96 + tid] = v2 * sc2 * gkv[tid];
    }
}

// ---------------- fused assembles: Q + K only (V read in-place by attn) --------------
// Writes are tf32-pre-rounded (cvt.rna) so attention consumes without converting.
__global__ void assemble_all_kernel(const float* __restrict__ qout,
                                    const float* __restrict__ kvout,
                                    const float* __restrict__ f0,
                                    const float* __restrict__ selkv,
                                    const float* __restrict__ winout,
                                    float* __restrict__ Q,
                                    float* __restrict__ K1,
                                    float* __restrict__ KSb,
                                    float* __restrict__ KWb) {
    int blk = blockIdx.x;
    int j = threadIdx.x;
    int h = j >> 5, d = j & 31;
    float f = expf(-LOG1E4_OVER_32 * (float)d);

    if (blk < 2048) {
        int row = blk;
        int b = row >> 10, t = row & 1023;
        int qb = (((b * HH + h) * TT) + t) * DQK;
        Q[qb + d] = to_tf32(qout[row * 1536 + j]);
        float x1 = qout[row * 1536 + 512 + h * RD + d];
        float x2 = qout[row * 1536 + 512 + h * RD + RP + d];
        float sn, cs;
        sincosf((float)t * f, &sn, &cs);
        Q[qb + NOPE_ + d] = to_tf32(x1 * cs - x2 * sn);
        Q[qb + NOPE_ + RP + d] = to_tf32(x1 * sn + x2 * cs);
    } else if (blk < 4096) {
        int row = blk - 2048;
        int b = row >> 10, t = row & 1023;
        int kb = (((b * HH + h) * TT) + t) * DQK;
        K1[kb + d] = to_tf32(kvout[row * 1024 + j]);
        float x1 = f0[row * 256 + 128 + d] * 0.0625f;
        float x2 = f0[row * 256 + 128 + RP + d] * 0.0625f;
        float sn, cs;
        sincosf((float)t * f, &sn, &cs);
        K1[kb + NOPE_ + d] = to_tf32(x1 * cs - x2 * sn);
        K1[kb + NOPE_ + RP + d] = to_tf32(x1 * sn + x2 * cs);
    } else {
        const float* raw;
        float* K;
        int row, S;
        if (blk < 4608) { row = blk - 4096; S = KEEP_; raw = selkv; K = KSb; }
        else            { row = blk - 4608; S = TT;    raw = winout; K = KWb; }
        int b = row / S, pos = row % S;
        size_t base = (size_t)row * 2048;
        float nope = raw[base + h * DQK + d];
        float x1 = raw[base + h * DQK + NOPE_ + d];
        float x2 = raw[base + h * DQK + NOPE_ + RP + d];
        float sn, cs;
        sincosf((float)pos * f, &sn, &cs);
        int kb = (((b * HH + h) * S) + pos) * DQK;
        K[kb + d] = to_tf32(nope);
        K[kb + NOPE_ + d] = to_tf32(x1 * cs - x2 * sn);
        K[kb + NOPE_ + RP + d] = to_tf32(x1 * sn + x2 * cs);
    }
}

// ---------------- adds ----------------
__global__ void attadd3_kernel(float* __restrict__ a0, const float* __restrict__ a1,
                               const float* __restrict__ a2) {
    int i = (blockIdx.x * 256 + threadIdx.x) * 4;
    float4 v0 = *(float4*)(a0 + i);
    float4 v1 = *(const float4*)(a1 + i);
    float4 v2 = *(const float4*)(a2 + i);
    v0.x += v1.x + v2.x; v0.y += v1.y + v2.y;
    v0.z += v1.z + v2.z; v0.w += v1.w + v2.w;
    *(float4*)(a0 + i) = v0;
}

__global__ void outadd_kernel(float* __restrict__ o, const float* __restrict__ pa,
                              const float* __restrict__ pb) {
    int i = (blockIdx.x * 256 + threadIdx.x) * 4;
    float4 va = *(const float4*)(pa + i);
    float4 vb = *(const float4*)(pb + i);
    va.x += vb.x; va.y += vb.y; va.z += vb.z; va.w += vb.w;
    *(float4*)(o + i) = va;
}

// ---------------- pipelined tf32 MMA flash attention, 3-way branch split -------------
// V is read directly from the GEMM outputs (kvout/selkv/winout) via strided cp.async.
// Q/K are pre-rounded by assemble; only V needs f2tf at consume.
constexpr int QS_STR = 100;
constexpr int KS_STR = 100;
constexpr int VS_STR = 40;
constexpr int PS_STR = 68;
constexpr int KBUF = 64 * KS_STR;
constexpr int VBUF = 64 * VS_STR;
constexpr int ASM_QS = 0;
constexpr int ASM_KS = 128 * QS_STR;
constexpr int ASM_VS = ASM_KS + 2 * KBUF;
constexpr int ASM_PS = ASM_VS + 2 * VBUF;
constexpr int ATTN_SMEM = (ASM_PS + 8 * 16 * PS_STR) * 4;

__global__ void __launch_bounds__(256)
attn_mma(const float* __restrict__ Q,
         const float* __restrict__ K1, const float* __restrict__ KS,
         const float* __restrict__ KW,
         const float* __restrict__ kvout, const float* __restrict__ selkv,
         const float* __restrict__ winout,
         const float* __restrict__ gate,
         float* __restrict__ att0, float* __restrict__ att1, float* __restrict__ att2) {
    extern __shared__ float sm[];
    float* Qs = sm + ASM_QS;

    int tid = threadIdx.x;
    int w = tid >> 5, lane = tid & 31;
    int g = lane >> 2, tg = lane & 3;
    float* Ps = sm + ASM_PS + w * 16 * PS_STR;

    int xid = blockIdx.x;
    int part = xid % 3;
    int tile = 7 - (xid / 3);
    int h = blockIdx.y, b = blockIdx.z;
    int q0 = tile * 128;
    int bh = b * HH + h;
    int rowg = q0 + 16 * w + g;

    int br = (part == 0) ? 0 : ((part == 1) ? 2 : 1);
    float* outp = (part == 0) ? att0 : ((part == 1) ? att1 : att2);
    bool causal = (br != 1);
    int nchunk = (br == 1) ? 4 : 2 * (tile + 1);

    const float* Kp = (br == 0) ? K1 + bh * TT * DQK
                    : (br == 1) ? KS + bh * KEEP_ * DQK
                                : KW + bh * TT * DQK;
    // V read in place from the GEMM outputs
    const float* Vp;
    int vld;
    if (br == 0)      { Vp = kvout + (size_t)(b * TT) * 1024 + 512 + h * VD;    vld = 1024; }
    else if (br == 1) { Vp = selkv + (size_t)(b * KEEP_) * 2048 + 1536 + h * VD; vld = 2048; }
    else              { Vp = winout + (size_t)(b * TT) * 2048 + 1536 + h * VD;   vld = 2048; }

    uint32_t smem_u32 = (uint32_t)__cvta_generic_to_shared(sm);

    // Q already tf32-rounded by assemble — plain copy
    const float* Qp = Q + (bh * TT + q0) * DQK;
    for (int i = tid; i < 128 * 24; i += 256) {
        int q = i / 24, dq = i % 24;
        float4 v = *(const float4*)(Qp + q * DQK + dq * 4);
        *(float4*)&Qs[q * QS_STR + dq * 4] = v;
    }

    auto stage = [&](int buf, int k0) {
        uint32_t kaddr = smem_u32 + (ASM_KS + buf * KBUF) * 4;
        uint32_t vaddr = smem_u32 + (ASM_VS + buf * VBUF) * 4;
#pragma unroll
        for (int it = 0; it < 6; it++) {
            int i = tid + it * 256;
            int key = i / 24, dq = i % 24;
            cp16(kaddr + (key * KS_STR + dq * 4) * 4, Kp + (k0 + key) * DQK + dq * 4);
        }
#pragma unroll
        for (int it = 0; it < 2; it++) {
            int i = tid + it * 256;
            int key = i >> 3, dq = i & 7;
            cp16(vaddr + (key * VS_STR + dq * 4) * 4, Vp + (size_t)(k0 + key) * vld + dq * 4);
        }
        CP_COMMIT();
    };

    stage(0, 0);
    int buf = 0;

    __syncthreads();
    uint32_t Qf[12][4];
    {
        const float* q0p = &Qs[(16 * w + g) * QS_STR];
        const float* q1p = q0p + 8 * QS_STR;
#pragma unroll
        for (int ks = 0; ks < 12; ks++) {
            Qf[ks][0] = __float_as_uint(q0p[8 * ks + tg]);
            Qf[ks][1] = __float_as_uint(q1p[8 * ks + tg]);
            Qf[ks][2] = __float_as_uint(q0p[8 * ks + tg + 4]);
            Qf[ks][3] = __float_as_uint(q1p[8 * ks + tg + 4]);
        }
    }

    float m0 = -1e30f, m1 = -1e30f, l0 = 0.f, l1 = 0.f;
    float acc[4][4];
#pragma unroll
    for (int nv = 0; nv < 4; nv++)
#pragma unroll
        for (int r = 0; r < 4; r++) acc[nv][r] = 0.f;

    for (int c = 0; c < nchunk; c++) {
        int k0 = c * 64;

        __syncthreads();
        if (c + 1 < nchunk) {
            stage(buf ^ 1, (c + 1) * 64);
            asm volatile("cp.async.wait_group 1;");
        } else {
            asm volatile("cp.async.wait_group 0;");
        }
        __syncthreads();

        const float* Kc = sm + ASM_KS + buf * KBUF;
        const float* Vc = sm + ASM_VS + buf * VBUF;

        float s[8][4];
#pragma unroll
        for (int ni = 0; ni < 8; ni++)
#pragma unroll
            for (int r = 0; r < 4; r++) s[ni][r] = 0.f;

#pragma unroll
        for (int ks = 0; ks < 12; ks++) {
            int kb = ks * 8;
#pragma unroll
            for (int ni = 0; ni < 8; ni++) {
                uint32_t Bf[2];
                Bf[0] = __float_as_uint(Kc[(8 * ni + g) * KS_STR + kb + tg]);
                Bf[1] = __float_as_uint(Kc[(8 * ni + g) * KS_STR + kb + tg + 4]);
                mma_tf32(s[ni], Qf[ks], Bf);
            }
        }

        if (causal && (k0 + 64 > q0)) {
#pragma unroll
            for (int ni = 0; ni < 8; ni++) {
                int key = k0 + 8 * ni + 2 * tg;
                if (key > rowg)         s[ni][0] = -1e30f;
                if (key + 1 > rowg)     s[ni][1] = -1e30f;
                if (key > rowg + 8)     s[ni][2] = -1e30f;
                if (key + 1 > rowg + 8) s[ni][3] = -1e30f;
            }
        }

        float cm0 = -1e30f, cm1 = -1e30f;
#pragma unroll
        for (int ni = 0; ni < 8; ni++) {
            cm0 = fmaxf(cm0, fmaxf(s[ni][0], s[ni][1]));
            cm1 = fmaxf(cm1, fmaxf(s[ni][2], s[ni][3]));
        }
        cm0 = fmaxf(cm0, __shfl_xor_sync(0xffffffffu, cm0, 1));
        cm0 = fmaxf(cm0, __shfl_xor_sync(0xffffffffu, cm0, 2));
        cm1 = fmaxf(cm1, __shfl_xor_sync(0xffffffffu, cm1, 1));
        cm1 = fmaxf(cm1, __shfl_xor_sync(0xffffffffu, cm1, 2));

        float nm0 = fmaxf(m0, cm0), nm1 = fmaxf(m1, cm1);
        float al0 = __expf((m0 - nm0) * ATTN_SCALE);
        float al1 = __expf((m1 - nm1) * ATTN_SCALE);
        m0 = nm0; m1 = nm1;

        float sum0 = 0.f, sum1 = 0.f;
#pragma unroll
        for (int ni = 0; ni < 8; ni++) {
            s[ni][0] = __expf((s[ni][0] - m0) * ATTN_SCALE);
            s[ni][1] = __expf((s[ni][1] - m0) * ATTN_SCALE);
            s[ni][2] = __expf((s[ni][2] - m1) * ATTN_SCALE);
            s[ni][3] = __expf((s[ni][3] - m1) * ATTN_SCALE);
            sum0 += s[ni][0] + s[ni][1];
            sum1 += s[ni][2] + s[ni][3];
        }
        sum0 += __shfl_xor_sync(0xffffffffu, sum0, 1);
        sum0 += __shfl_xor_sync(0xffffffffu, sum0, 2);
        sum1 += __shfl_xor_sync(0xffffffffu, sum1, 1);
        sum1 += __shfl_xor_sync(0xffffffffu, sum1, 2);
        l0 = l0 * al0 + sum0;
        l1 = l1 * al1 + sum1;

#pragma unroll
        for (int nv = 0; nv < 4; nv++) {
            acc[nv][0] *= al0; acc[nv][1] *= al0;
            acc[nv][2] *= al1; acc[nv][3] *= al1;
        }

        __syncwarp();
#pragma unroll
        for (int ni = 0; ni < 8; ni++) {
            *(float2*)&Ps[g * PS_STR + 8 * ni + 2 * tg] =
                make_float2(to_tf32(s[ni][0]), to_tf32(s[ni][1]));
            *(float2*)&Ps[(g + 8) * PS_STR + 8 * ni + 2 * tg] =
                make_float2(to_tf32(s[ni][2]), to_tf32(s[ni][3]));
        }
        __syncwarp();

#pragma unroll
        for (int ks = 0; ks < 8; ks++) {
            int kb = ks * 8;
            uint32_t Af[4];
            Af[0] = __float_as_uint(Ps[g * PS_STR + kb + tg]);
            Af[1] = __float_as_uint(Ps[(g + 8) * PS_STR + kb + tg]);
            Af[2] = __float_as_uint(Ps[g * PS_STR + kb + tg + 4]);
            Af[3] = __float_as_uint(Ps[(g + 8) * PS_STR + kb + tg + 4]);
#pragma unroll
            for (int nv = 0; nv < 4; nv++) {
                uint32_t Bf[2];
                Bf[0] = f2tf(Vc[(kb + tg) * VS_STR + 8 * nv + g]);
                Bf[1] = f2tf(Vc[(kb + tg + 4) * VS_STR + 8 * nv + g]);
                mma_tf32(acc[nv], Af, Bf);
            }
        }
        buf ^= 1;
    }

    float gb = gate[b * 4 + br];
    float inv0 = gb / l0, inv1 = gb / l1;
#pragma unroll
    for (int nv = 0; nv < 4; nv++) {
        int col = h * VD + 8 * nv + 2 * tg;
        *(float2*)(outp + (b * TT + rowg) * (HH * VD) + col) =
            make_float2(acc[nv][0] * inv0, acc[nv][1] * inv0);
        *(float2*)(outp + (b * TT + rowg + 8) * (HH * VD) + col) =
            make_float2(acc[nv][2] * inv1, acc[nv][3] * inv1);
    }
}

// ---------------- launcher ----------------
extern "C" void kernel_launch(void* const* d_in, const int* in_sizes, int n_in,
                              void* d_out, int out_size) {
    const float* x         = (const float*)d_in[0];
    const float* w_cq      = (const float*)d_in[1];
    const float* g_qnorm   = (const float*)d_in[2];
    const float* w_dq_nope = (const float*)d_in[3];
    const float* w_dq_rope = (const float*)d_in[4];
    const float* w_ckv     = (const float*)d_in[5];
    const float* g_kvnorm  = (const float*)d_in[6];
    const float* w_dk_nope = (const float*)d_in[7];
    const float* w_dv      = (const float*)d_in[8];
    const float* w_krope   = (const float*)d_in[9];
    const float* w_imp     = (const float*)d_in[10];
    const float* w_selk    = (const float*)d_in[11];
    const float* w_selv    = (const float*)d_in[12];
    const float* w_wink    = (const float*)d_in[13];
    const float* w_winv    = (const float*)d_in[14];
    const float* w_gate    = (const float*)d_in[15];
    const float* w_proj    = (const float*)d_in[16];
    float* out = (float*)d_out;

    float* base = nullptr;
    cudaGetSymbolAddress((void**)&base, g_scratch);

    float* wc1    = base + OFF_WC1;
    float* f0     = base + OFF_F0;
    float* qout   = base + OFF_QOUT;
    float* kvout  = base + OFF_KVOUT;
    float* winout = base + OFF_WINOUT;
    float* selkv  = base + OFF_SELKV;
    float* xmean  = base + OFF_XMEAN;
    float* gate   = base + OFF_GATE;
    float* scores = base + OFF_SCORES;
    int*   idx    = (int*)(base + OFF_IDX);
    float* Qb     = base + OFF_Q;
    float* K1b    = base + OFF_K1;
    float* KWb    = base + OFF_KW;
    float* KSb    = base + OFF_KS;
    float* att0   = base + OFF_ATTN;
    float* att1   = base + OFF_ATTN2;
    float* att2   = base + OFF_ATTN3;
    float* projA  = base + OFF_PROJA;
    float* projB  = base + OFF_PROJB;

    const int M = BB * TT;  // 2048

    cudaFuncSetAttribute(gemm_multi, cudaFuncAttributeMaxDynamicSharedMemorySize, G2_SMEM);
    cudaFuncSetAttribute(attn_mma, cudaFuncAttributeMaxDynamicSharedMemorySize, ATTN_SMEM);

    // 1) prep: scores | xmean | pack wc1
    prep_kernel<<<3080, 256>>>(x, w_imp, scores, xmean, w_cq, w_ckv, w_krope, wc1);

    // 2) topk + gate (global row ids; gather fused into selkv GEMM)
    topk_gate_kernel<<<4, 1024>>>(scores, idx, xmean, w_gate, gate);

    // 3) mega GEMM 1: winout | f0 | selkv (full-K; split-K reverted — measured neutral)
    {
        GemmJobs jobs;
        jobs.j[0] = {x, CC, w_wink, 1536, 1536, w_winv, 512,
                     winout, 2048, CC, 0, 16, nullptr};
        jobs.j[1] = {x, CC, wc1, 256, 256, wc1, 256,
                     f0, 256, CC, 256, 2, nullptr};
        jobs.j[2] = {x, CC, w_selk, 1536, 1536, w_selv, 512,
                     selkv, 2048, CC, 288, 16, idx};
        gemm_multi<<<352, 256, G2_SMEM>>>(jobs, 3);
    }

    // 4) rms on f0
    rms2_kernel<<<M, 128>>>(f0, g_qnorm, g_kvnorm);

    // 5) mega GEMM 2: qout | kvout
    {
        GemmJobs jobs;
        jobs.j[0] = {f0, 256, w_dq_nope, 512, 512, w_dq_rope, 1024,
                     qout, 1536, 96, 0, 12, nullptr};
        jobs.j[1] = {f0 + 96, 256, w_dk_nope, 512, 512, w_dv, 512,
                     kvout, 1024, 32, 192, 8, nullptr};
        jobs.j[2] = jobs.j[1];
        gemm_multi<<<320, 256, G2_SMEM>>>(jobs, 2);
    }

    // 6) assembles: Q + K only, tf32-pre-rounded (V consumed in place by attention)
    assemble_all_kernel<<<6656, 512>>>(qout, kvout, f0, selkv, winout,
                                       Qb, K1b, KSb, KWb);

    // 7) attention, 3-way branch split (768 CTAs, heavy tiles first)
    attn_mma<<<dim3(24, HH, BB), 256, ATTN_SMEM>>>(Qb, K1b, KSb, KWb,
                                                   kvout, selkv, winout,
                                                   gate, att0, att1, att2);

    // 7b) att0 += att1 + att2
    attadd3_kernel<<<(M * HH * VD) / 1024, 256>>>(att0, att1, att2);

    // 8) output projection, split-K halves (256 CTAs, one wave)
    {
        GemmJobs jobs;
        jobs.j[0] = {att0, HH * VD, w_proj, CC, CC, w_proj, CC,
                     projA, CC, 256, 0, 8, nullptr};
        jobs.j[1] = {att0 + 256, HH * VD, w_proj + 256 * CC, CC, CC, w_proj + 256 * CC, CC,
                     projB, CC, 256, 128, 8, nullptr};
        jobs.j[2] = jobs.j[1];
        gemm_multi<<<256, 256, G2_SMEM>>>(jobs, 2);
    }

    // 8b) out = projA + projB
    outadd_kernel<<<(M * CC) / 1024, 256>>>(out, projA, projB);
}

// round 14
// speedup vs baseline: 13.2228x; 1.0290x over previous
#include <cuda_runtime.h>
#include <math.h>
#include <stdint.h>

// ---------------- problem constants ----------------
#define BB 2
#define TT 1024
#define CC 1024
#define HH 16
#define VD 32
#define NOPE_ 32
#define RP 32
#define RD 64
#define DQK 96
#define KEEP_ 256
#define QL 96
#define KVL 32

#define LOG1E4_OVER_32 0.28782313662425572f   // ln(10000)/32
#define ATTN_SCALE 0.10206207261596577f       // 1/sqrt(96)

// ---------------- scratch ----------------
constexpr int OFF_WC1     = 0;                           // [1024][256]
constexpr int OFF_XTF     = OFF_WC1     + 1024*256;      // [2048][1024] tf32-rounded x
constexpr int OFF_F0      = OFF_XTF     + 2048*1024;     // [2048][256]
constexpr int OFF_QOUT    = OFF_F0      + 2048*256;      // [2048][1536]
constexpr int OFF_KVOUT   = OFF_QOUT    + 2048*1536;     // [2048][1024] knope|v1
constexpr int OFF_WINOUT  = OFF_KVOUT   + 2048*1024;     // [2048][2048] kw|vw
constexpr int OFF_SELKV   = OFF_WINOUT  + 2048*2048;     // [512][2048]  ks|vs
constexpr int OFF_XMEAN   = OFF_SELKV   + 512*2048;
constexpr int OFF_GATE    = OFF_XMEAN   + BB*CC;
constexpr int OFF_SCORES  = OFF_GATE    + 8;
constexpr int OFF_IDX     = OFF_SCORES  + BB*TT;
constexpr int OFF_Q       = OFF_IDX     + BB*KEEP_;
constexpr int OFF_K1      = OFF_Q       + BB*HH*TT*DQK;
constexpr int OFF_KW      = OFF_K1      + BB*HH*TT*DQK;
constexpr int OFF_KS      = OFF_KW      + BB*HH*TT*DQK;
constexpr int OFF_ATTN    = OFF_KS      + BB*HH*KEEP_*DQK;  // att0 (final attn sum)
constexpr int OFF_ATTN2   = OFF_ATTN    + BB*TT*HH*VD;      // att1
constexpr int OFF_ATTN3   = OFF_ATTN2   + BB*TT*HH*VD;      // att2
constexpr int OFF_PROJA   = OFF_ATTN3   + BB*TT*HH*VD;      // [2048][1024]
constexpr int OFF_PROJB   = OFF_PROJA   + 2048*1024;
constexpr int SCRATCH_TOTAL = OFF_PROJB + 2048*1024;

__device__ __align__(256) float g_scratch[SCRATCH_TOTAL];

// ---------------- tf32 helpers ----------------
__device__ __forceinline__ float to_tf32(float v) {
    uint32_t u;
    asm("cvt.rna.tf32.f32 %0, %1;" : "=r"(u) : "f"(v));
    return __uint_as_float(u);
}

__device__ __forceinline__ uint32_t f2tf(float v) {
    uint32_t u;
    asm("cvt.rna.tf32.f32 %0, %1;" : "=r"(u) : "f"(v));
    return u;
}

__device__ __forceinline__ void mma_tf32(float* d, const uint32_t* a, const uint32_t* b) {
    asm volatile(
        "mma.sync.aligned.m16n8k8.row.col.f32.tf32.tf32.f32 "
        "{%0,%1,%2,%3}, {%4,%5,%6,%7}, {%8,%9}, {%0,%1,%2,%3};\n"
        : "+f"(d[0]), "+f"(d[1]), "+f"(d[2]), "+f"(d[3])
        : "r"(a[0]), "r"(a[1]), "r"(a[2]), "r"(a[3]), "r"(b[0]), "r"(b[1]));
}

__device__ __forceinline__ void cp16(uint32_t dst, const float* src) {
    asm volatile("cp.async.cg.shared.global [%0], [%1], 16;" :: "r"(dst), "l"(src));
}
#define CP_COMMIT() asm volatile("cp.async.commit_group;")

// ---------------- multi-GEMM job table ----------------
struct GemmJob {
    const float* A; int lda;     // A must be tf32-pre-rounded
    const float* B0; int ldb0; int n0;
    const float* B1; int ldb1;
    float* C; int ldc;
    int K;
    int ctaStart;
    int nx;
    const int* rowIdx;   // optional: global A-row indices (gathered GEMM)
    int rnd;             // 1 = write C tf32-rounded
};
struct GemmJobs { GemmJob j[3]; };

constexpr int G2_A = 128 * 20;
constexpr int G2_B = 16 * 136;
constexpr int G2_SMEM = 3 * (G2_A + G2_B) * 4;   // 56832 B

__global__ void __launch_bounds__(256, 2)
gemm_multi(GemmJobs jobs, int njobs) {
    extern __shared__ float sm2[];
    float* As = sm2;
    float* Bs = sm2 + 3 * G2_A;

    int linear = blockIdx.x;
    int ji = njobs - 1;
#pragma unroll
    for (int t = 1; t < 3; t++)
        if (t < njobs && linear < jobs.j[t].ctaStart) { ji = t - 1; break; }
    const GemmJob& J = jobs.j[ji];
    int local = linear - J.ctaStart;
    int bx = local % J.nx, by = local / J.nx;

    const float* A = J.A; int lda = J.lda;
    float* C = J.C; int ldc = J.ldc;
    int K = J.K;
    int row0 = by * 128, col0 = bx * 128;

    const float* Bsrc;
    int ldb;
    if (col0 < J.n0) { Bsrc = J.B0 + col0; ldb = J.ldb0; }
    else             { Bsrc = J.B1 + (col0 - J.n0); ldb = J.ldb1; }

    int tid = threadIdx.x;
    int warp = tid >> 5, lane = tid & 31;
    int g = lane >> 2, tg = lane & 3;
    int wm = warp >> 2, wn = warp & 3;

    uint32_t as_addr = (uint32_t)__cvta_generic_to_shared(As);
    uint32_t bs_addr = (uint32_t)__cvta_generic_to_shared(Bs);

    int ar0 = row0 + (tid >> 2);
    int ar1 = row0 + 64 + (tid >> 2);
    if (J.rowIdx) { ar0 = J.rowIdx[ar0]; ar1 = J.rowIdx[ar1]; }
    const float* Ag0 = A + (size_t)ar0 * lda + (tid & 3) * 4;
    const float* Ag1 = A + (size_t)ar1 * lda + (tid & 3) * 4;
    const float* Bg0 = Bsrc + (size_t)(tid >> 5) * ldb + (tid & 31) * 4;
    const float* Bg1 = Bsrc + (size_t)(8 + (tid >> 5)) * ldb + (tid & 31) * 4;
    uint32_t offA0 = (((tid >> 2)) * 20 + (tid & 3) * 4) * 4;
    uint32_t offA1 = (((tid >> 2) + 64) * 20 + (tid & 3) * 4) * 4;
    uint32_t offB0 = ((tid >> 5) * 136 + (tid & 31) * 4) * 4;
    uint32_t offB1 = ((8 + (tid >> 5)) * 136 + (tid & 31) * 4) * 4;

    float d[4][4][4];
#pragma unroll
    for (int mi = 0; mi < 4; mi++)
#pragma unroll
        for (int ni = 0; ni < 4; ni++)
#pragma unroll
            for (int r = 0; r < 4; r++) d[mi][ni][r] = 0.f;

    int nk = K / 16;

    {
        cp16(as_addr + offA0, Ag0);
        cp16(as_addr + offA1, Ag1);
        cp16(bs_addr + offB0, Bg0);
        cp16(bs_addr + offB1, Bg1);
        CP_COMMIT();
    }
    if (nk > 1) {
        uint32_t ab = as_addr + G2_A * 4, bb = bs_addr + G2_B * 4;
        cp16(ab + offA0, Ag0 + 16);
        cp16(ab + offA1, Ag1 + 16);
        cp16(bb + offB0, Bg0 + (size_t)16 * ldb);
        cp16(bb + offB1, Bg1 + (size_t)16 * ldb);
        CP_COMMIT();
    }

    for (int kt = 0; kt < nk; kt++) {
        if (kt + 1 < nk) { asm volatile("cp.async.wait_group 1;"); }
        else             { asm volatile("cp.async.wait_group 0;"); }
        __syncthreads();

        if (kt + 2 < nk) {
            int s = (kt + 2) % 3;
            int k0 = (kt + 2) * 16;
            uint32_t ab = as_addr + s * G2_A * 4, bb = bs_addr + s * G2_B * 4;
            cp16(ab + offA0, Ag0 + k0);
            cp16(ab + offA1, Ag1 + k0);
            cp16(bb + offB0, Bg0 + (size_t)k0 * ldb);
            cp16(bb + offB1, Bg1 + (size_t)k0 * ldb);
            CP_COMMIT();
        }

        const float* Ac = As + (kt % 3) * G2_A;
        const float* Bc = Bs + (kt % 3) * G2_B;

#pragma unroll
        for (int ks = 0; ks < 16; ks += 8) {
            uint32_t bf[4][2];
#pragma unroll
            for (int ni = 0; ni < 4; ni++) {
                int c = wn * 32 + ni * 8 + g;
                bf[ni][0] = f2tf(Bc[(ks + tg) * 136 + c]);
                bf[ni][1] = f2tf(Bc[(ks + tg + 4) * 136 + c]);
            }
#pragma unroll
            for (int mi = 0; mi < 4; mi++) {
                int r = wm * 64 + mi * 16;
                uint32_t af[4];
                af[0] = __float_as_uint(Ac[(r + g) * 20 + ks + tg]);
                af[1] = __float_as_uint(Ac[(r + 8 + g) * 20 + ks + tg]);
                af[2] = __float_as_uint(Ac[(r + g) * 20 + ks + tg + 4]);
                af[3] = __float_as_uint(Ac[(r + 8 + g) * 20 + ks + tg + 4]);
#pragma unroll
                for (int ni = 0; ni < 4; ni++) {
                    mma_tf32(d[mi][ni], af, bf[ni]);
                }
            }
        }
    }

    if (J.rnd) {
#pragma unroll
        for (int mi = 0; mi < 4; mi++)
#pragma unroll
            for (int ni = 0; ni < 4; ni++)
#pragma unroll
                for (int r = 0; r < 4; r++) d[mi][ni][r] = to_tf32(d[mi][ni][r]);
    }
#pragma unroll
    for (int mi = 0; mi < 4; mi++) {
#pragma unroll
        for (int ni = 0; ni < 4; ni++) {
            int r = row0 + wm * 64 + mi * 16 + g;
            int c = col0 + wn * 32 + ni * 8 + 2 * tg;
            *(float2*)(C + (size_t)r * ldc + c) = make_float2(d[mi][ni][0], d[mi][ni][1]);
            *(float2*)(C + (size_t)(r + 8) * ldc + c) = make_float2(d[mi][ni][2], d[mi][ni][3]);
        }
    }
}

// ---------------- fused prep: scores+xtf | xmean | pack_wc1 ----------------
__global__ void prep_kernel(const float* __restrict__ x, const float* __restrict__ w_imp,
                            float* __restrict__ scores, float* __restrict__ xtf,
                            float* __restrict__ xmean,
                            const float* __restrict__ w_cq, const float* __restrict__ w_ckv,
                            const float* __restrict__ w_krope, float* __restrict__ wc1) {
    int blk = blockIdx.x, tid = threadIdx.x;
    if (blk < 2048) {
        __shared__ float s8[8];
        int row = blk;
        float s = 0.f;
        for (int c = tid; c < CC; c += 256) {
            float xv = x[row * CC + c];
            xtf[row * CC + c] = to_tf32(xv);   // rounded copy for all GEMM A-sides
            s += xv * w_imp[c];
        }
#pragma unroll
        for (int o = 16; o > 0; o >>= 1) s += __shfl_xor_sync(0xffffffffu, s, o);
        if ((tid & 31) == 0) s8[tid >> 5] = s;
        __syncthreads();
        if (tid == 0) {
            float t = 0.f;
#pragma unroll
            for (int i = 0; i < 8; i++) t += s8[i];
            scores[row] = t;
        }
    } else if (blk < 2056) {
        int i = blk - 2048;
        int b = i >> 2;
        int c = (i & 3) * 256 + tid;
        float s = 0.f;
        for (int t = 0; t < TT; t++) s += x[(b * TT + t) * CC + c];
        xmean[b * CC + c] = s * (1.f / (float)TT);
    } else {
        int k = blk - 2056;
        float v;
        if (tid < 96) v = w_cq[k * 96 + tid];
        else if (tid < 128) v = w_ckv[k * 32 + (tid - 96)];
        else if (tid < 192) v = w_krope[k * 64 + (tid - 128)];
        else v = 0.f;
        wc1[k * 256 + tid] = v;
    }
}

// ---------------- fused topk + gate (topk emits GLOBAL row ids) ----------------
__global__ void topk_gate_kernel(const float* __restrict__ scores, int* __restrict__ idxout,
                                 const float* __restrict__ xmean, const float* __restrict__ wg,
                                 float* __restrict__ gate) {
    int blk = blockIdx.x, tid = threadIdx.x;
    if (blk < 2) {
        __shared__ float sv[1024];
        __shared__ int si[1024];
        __shared__ int ti[256];
        int b = blk;
        sv[tid] = scores[b * TT + tid];
        si[tid] = tid;
        __syncthreads();
        for (int k = 2; k <= 1024; k <<= 1) {
            for (int j = k >> 1; j > 0; j >>= 1) {
                int ixj = tid ^ j;
                if (ixj > tid) {
                    bool desc = ((tid & k) == 0);
                    float va = sv[tid], vb = sv[ixj];
                    int ia = si[tid], ib = si[ixj];
                    bool agtb = (va > vb) || (va == vb && ia < ib);
                    if (desc ? !agtb : agtb) {
                        sv[tid] = vb; sv[ixj] = va;
                        si[tid] = ib; si[ixj] = ia;
                    }
                }
                __syncthreads();
            }
        }
        if (tid < 256) ti[tid] = si[tid];
        __syncthreads();
        for (int k = 2; k <= 256; k <<= 1) {
            for (int j = k >> 1; j > 0; j >>= 1) {
                int ixj = tid ^ j;
                if (tid < 256 && ixj > tid) {
                    bool asc = ((tid & k) == 0);
                    int ia = ti[tid], ib = ti[ixj];
                    if (asc ? (ia > ib) : (ia < ib)) { ti[tid] = ib; ti[ixj] = ia; }
                }
                __syncthreads();
            }
        }
        if (tid < 256) idxout[b * KEEP_ + tid] = b * TT + ti[tid];
    } else {
        int b = blk - 2;
        __shared__ float sg[3];
        int w = tid >> 5, lane = tid & 31;
        if (w < 3) {
            float s = 0.f;
            for (int c = lane; c < CC; c += 32) s += xmean[b * CC + c] * wg[c * 3 + w];
#pragma unroll
            for (int o = 16; o > 0; o >>= 1) s += __shfl_xor_sync(0xffffffffu, s, o);
            if (lane == 0) sg[w] = s;
        }
        __syncthreads();
        if (tid == 0) {
            float m = fmaxf(sg[0], fmaxf(sg[1], sg[2]));
            float e0 = expf(sg[0] - m), e1 = expf(sg[1] - m), e2 = expf(sg[2] - m);
            float inv = 1.f / (e0 + e1 + e2);
            gate[b * 4 + 0] = e0 * inv;
            gate[b * 4 + 1] = e1 * inv;
            gate[b * 4 + 2] = e2 * inv;
        }
    }
}

// ---------------- RMS norm on f0 (writes tf32-rounded) ----------------
__global__ void rms2_kernel(float* __restrict__ f0,
                            const float* __restrict__ gq, const float* __restrict__ gkv) {
    int row = blockIdx.x, tid = threadIdx.x;   // 128 threads
    float* dd = f0 + row * 256;
    __shared__ float s4[4];
    float v = (tid < 96) ? dd[tid] : 0.f;
    float sq = v * v;
#pragma unroll
    for (int o = 16; o > 0; o >>= 1) sq += __shfl_xor_sync(0xffffffffu, sq, o);
    if ((tid & 31) == 0) s4[tid >> 5] = sq;
    __syncthreads();
    float tot = s4[0] + s4[1] + s4[2] + s4[3];
    float sc = rsqrtf(tot / 96.f + 1e-6f);
    if (tid < 96) dd[tid] = to_tf32(v * sc * gq[tid]);
    __syncthreads();
    if (tid < 32) {
        float v2 = dd[96 + tid];
        float sq2 = v2 * v2;
#pragma unroll
        for (int o = 16; o > 0; o >>= 1) sq2 += __shfl_xor_sync(0xffffffffu, sq2, o);
        float sc2 = rsqrtf(sq2 / 32.f + 1e-6f);
        dd[96 + tid] = to_tf32(v2 * sc2 * gkv[tid]);
    }
}

// ---------------- fused assembles: Q + K only (V read in-place by attn) --------------
__global__ void assemble_all_kernel(const float* __restrict__ qout,
                                    const float* __restrict__ kvout,
                                    const float* __restrict__ f0,
                                    const float* __restrict__ selkv,
                                    const float* __restrict__ winout,
                                    float* __restrict__ Q,
                                    float* __restrict__ K1,
                                    float* __restrict__ KSb,
                                    float* __restrict__ KWb) {
    int blk = blockIdx.x;
    int j = threadIdx.x;
    int h = j >> 5, d = j & 31;
    float f = expf(-LOG1E4_OVER_32 * (float)d);

    if (blk < 2048) {
        int row = blk;
        int b = row >> 10, t = row & 1023;
        int qb = (((b * HH + h) * TT) + t) * DQK;
        Q[qb + d] = qout[row * 1536 + j];   // already tf32 (gemm rnd)
        float x1 = qout[row * 1536 + 512 + h * RD + d];
        float x2 = qout[row * 1536 + 512 + h * RD + RP + d];
        float sn, cs;
        sincosf((float)t * f, &sn, &cs);
        Q[qb + NOPE_ + d] = to_tf32(x1 * cs - x2 * sn);
        Q[qb + NOPE_ + RP + d] = to_tf32(x1 * sn + x2 * cs);
    } else if (blk < 4096) {
        int row = blk - 2048;
        int b = row >> 10, t = row & 1023;
        int kb = (((b * HH + h) * TT) + t) * DQK;
        K1[kb + d] = kvout[row * 1024 + j];   // already tf32
        float x1 = f0[row * 256 + 128 + d] * 0.0625f;
        float x2 = f0[row * 256 + 128 + RP + d] * 0.0625f;
        float sn, cs;
        sincosf((float)t * f, &sn, &cs);
        K1[kb + NOPE_ + d] = to_tf32(x1 * cs - x2 * sn);
        K1[kb + NOPE_ + RP + d] = to_tf32(x1 * sn + x2 * cs);
    } else {
        const float* raw;
        float* K;
        int row, S;
        if (blk < 4608) { row = blk - 4096; S = KEEP_; raw = selkv; K = KSb; }
        else            { row = blk - 4608; S = TT;    raw = winout; K = KWb; }
        int b = row / S, pos = row % S;
        size_t base = (size_t)row * 2048;
        float nope = raw[base + h * DQK + d];
        float x1 = raw[base + h * DQK + NOPE_ + d];
        float x2 = raw[base + h * DQK + NOPE_ + RP + d];
        float sn, cs;
        sincosf((float)pos * f, &sn, &cs);
        int kb = (((b * HH + h) * S) + pos) * DQK;
        K[kb + d] = nope;   // already tf32
        K[kb + NOPE_ + d] = to_tf32(x1 * cs - x2 * sn);
        K[kb + NOPE_ + RP + d] = to_tf32(x1 * sn + x2 * cs);
    }
}

// ---------------- adds ----------------
__global__ void attadd3_kernel(float* __restrict__ a0, const float* __restrict__ a1,
                               const float* __restrict__ a2) {
    int i = (blockIdx.x * 256 + threadIdx.x) * 4;
    float4 v0 = *(float4*)(a0 + i);
    float4 v1 = *(const float4*)(a1 + i);
    float4 v2 = *(const float4*)(a2 + i);
    // tf32-round (moves proj's A-side rounding here — bit-identical to consume-rounding)
    v0.x = to_tf32(v0.x + v1.x + v2.x);
    v0.y = to_tf32(v0.y + v1.y + v2.y);
    v0.z = to_tf32(v0.z + v1.z + v2.z);
    v0.w = to_tf32(v0.w + v1.w + v2.w);
    *(float4*)(a0 + i) = v0;
}

__global__ void outadd_kernel(float* __restrict__ o, const float* __restrict__ pa,
                              const float* __restrict__ pb) {
    int i = (blockIdx.x * 256 + threadIdx.x) * 4;
    float4 va = *(const float4*)(pa + i);
    float4 vb = *(const float4*)(pb + i);
    va.x += vb.x; va.y += vb.y; va.z += vb.z; va.w += vb.w;
    *(float4*)(o + i) = va;
}

// ---------------- pipelined tf32 MMA flash attention, 3-way branch split -------------
// All inputs tf32-pre-rounded (Q/K by assemble, V by gemm rnd epilogue) — zero cvts.
constexpr int QS_STR = 100;
constexpr int KS_STR = 100;
constexpr int VS_STR = 40;
constexpr int PS_STR = 68;
constexpr int KBUF = 64 * KS_STR;
constexpr int VBUF = 64 * VS_STR;
constexpr int ASM_QS = 0;
constexpr int ASM_KS = 128 * QS_STR;
constexpr int ASM_VS = ASM_KS + 2 * KBUF;
constexpr int ASM_PS = ASM_VS + 2 * VBUF;
constexpr int ATTN_SMEM = (ASM_PS + 8 * 16 * PS_STR) * 4;

__global__ void __launch_bounds__(256)
attn_mma(const float* __restrict__ Q,
         const float* __restrict__ K1, const float* __restrict__ KS,
         const float* __restrict__ KW,
         const float* __restrict__ kvout, const float* __restrict__ selkv,
         const float* __restrict__ winout,
         const float* __restrict__ gate,
         float* __restrict__ att0, float* __restrict__ att1, float* __restrict__ att2) {
    extern __shared__ float sm[];
    float* Qs = sm + ASM_QS;

    int tid = threadIdx.x;
    int w = tid >> 5, lane = tid & 31;
    int g = lane >> 2, tg = lane & 3;
    float* Ps = sm + ASM_PS + w * 16 * PS_STR;

    int xid = blockIdx.x;
    int part = xid % 3;
    int tile = 7 - (xid / 3);
    int h = blockIdx.y, b = blockIdx.z;
    int q0 = tile * 128;
    int bh = b * HH + h;
    int rowg = q0 + 16 * w + g;

    int br = (part == 0) ? 0 : ((part == 1) ? 2 : 1);
    float* outp = (part == 0) ? att0 : ((part == 1) ? att1 : att2);
    bool causal = (br != 1);
    int nchunk = (br == 1) ? 4 : 2 * (tile + 1);

    const float* Kp = (br == 0) ? K1 + bh * TT * DQK
                    : (br == 1) ? KS + bh * KEEP_ * DQK
                                : KW + bh * TT * DQK;
    const float* Vp;
    int vld;
    if (br == 0)      { Vp = kvout + (size_t)(b * TT) * 1024 + 512 + h * VD;    vld = 1024; }
    else if (br == 1) { Vp = selkv + (size_t)(b * KEEP_) * 2048 + 1536 + h * VD; vld = 2048; }
    else              { Vp = winout + (size_t)(b * TT) * 2048 + 1536 + h * VD;   vld = 2048; }

    uint32_t smem_u32 = (uint32_t)__cvta_generic_to_shared(sm);

    const float* Qp = Q + (bh * TT + q0) * DQK;
    for (int i = tid; i < 128 * 24; i += 256) {
        int q = i / 24, dq = i % 24;
        float4 v = *(const float4*)(Qp + q * DQK + dq * 4);
        *(float4*)&Qs[q * QS_STR + dq * 4] = v;
    }

    auto stage = [&](int buf, int k0) {
        uint32_t kaddr = smem_u32 + (ASM_KS + buf * KBUF) * 4;
        uint32_t vaddr = smem_u32 + (ASM_VS + buf * VBUF) * 4;
#pragma unroll
        for (int it = 0; it < 6; it++) {
            int i = tid + it * 256;
            int key = i / 24, dq = i % 24;
            cp16(kaddr + (key * KS_STR + dq * 4) * 4, Kp + (k0 + key) * DQK + dq * 4);
        }
#pragma unroll
        for (int it = 0; it < 2; it++) {
            int i = tid + it * 256;
            int key = i >> 3, dq = i & 7;
            cp16(vaddr + (key * VS_STR + dq * 4) * 4, Vp + (size_t)(k0 + key) * vld + dq * 4);
        }
        CP_COMMIT();
    };

    stage(0, 0);
    int buf = 0;

    __syncthreads();
    uint32_t Qf[12][4];
    {
        const float* q0p = &Qs[(16 * w + g) * QS_STR];
        const float* q1p = q0p + 8 * QS_STR;
#pragma unroll
        for (int ks = 0; ks < 12; ks++) {
            Qf[ks][0] = __float_as_uint(q0p[8 * ks + tg]);
            Qf[ks][1] = __float_as_uint(q1p[8 * ks + tg]);
            Qf[ks][2] = __float_as_uint(q0p[8 * ks + tg + 4]);
            Qf[ks][3] = __float_as_uint(q1p[8 * ks + tg + 4]);
        }
    }

    float m0 = -1e30f, m1 = -1e30f, l0 = 0.f, l1 = 0.f;
    float acc[4][4];
#pragma unroll
    for (int nv = 0; nv < 4; nv++)
#pragma unroll
        for (int r = 0; r < 4; r++) acc[nv][r] = 0.f;

    for (int c = 0; c < nchunk; c++) {
        int k0 = c * 64;

        __syncthreads();
        if (c + 1 < nchunk) {
            stage(buf ^ 1, (c + 1) * 64);
            asm volatile("cp.async.wait_group 1;");
        } else {
            asm volatile("cp.async.wait_group 0;");
        }
        __syncthreads();

        const float* Kc = sm + ASM_KS + buf * KBUF;
        const float* Vc = sm + ASM_VS + buf * VBUF;

        float s[8][4];
#pragma unroll
        for (int ni = 0; ni < 8; ni++)
#pragma unroll
            for (int r = 0; r < 4; r++) s[ni][r] = 0.f;

#pragma unroll
        for (int ks = 0; ks < 12; ks++) {
            int kb = ks * 8;
#pragma unroll
            for (int ni = 0; ni < 8; ni++) {
                uint32_t Bf[2];
                Bf[0] = __float_as_uint(Kc[(8 * ni + g) * KS_STR + kb + tg]);
                Bf[1] = __float_as_uint(Kc[(8 * ni + g) * KS_STR + kb + tg + 4]);
                mma_tf32(s[ni], Qf[ks], Bf);
            }
        }

        if (causal && (k0 + 64 > q0)) {
#pragma unroll
            for (int ni = 0; ni < 8; ni++) {
                int key = k0 + 8 * ni + 2 * tg;
                if (key > rowg)         s[ni][0] = -1e30f;
                if (key + 1 > rowg)     s[ni][1] = -1e30f;
                if (key > rowg + 8)     s[ni][2] = -1e30f;
                if (key + 1 > rowg + 8) s[ni][3] = -1e30f;
            }
        }

        float cm0 = -1e30f, cm1 = -1e30f;
#pragma unroll
        for (int ni = 0; ni < 8; ni++) {
            cm0 = fmaxf(cm0, fmaxf(s[ni][0], s[ni][1]));
            cm1 = fmaxf(cm1, fmaxf(s[ni][2], s[ni][3]));
        }
        cm0 = fmaxf(cm0, __shfl_xor_sync(0xffffffffu, cm0, 1));
        cm0 = fmaxf(cm0, __shfl_xor_sync(0xffffffffu, cm0, 2));
        cm1 = fmaxf(cm1, __shfl_xor_sync(0xffffffffu, cm1, 1));
        cm1 = fmaxf(cm1, __shfl_xor_sync(0xffffffffu, cm1, 2));

        float nm0 = fmaxf(m0, cm0), nm1 = fmaxf(m1, cm1);
        float al0 = __expf((m0 - nm0) * ATTN_SCALE);
        float al1 = __expf((m1 - nm1) * ATTN_SCALE);
        m0 = nm0; m1 = nm1;

        float sum0 = 0.f, sum1 = 0.f;
#pragma unroll
        for (int ni = 0; ni < 8; ni++) {
            s[ni][0] = __expf((s[ni][0] - m0) * ATTN_SCALE);
            s[ni][1] = __expf((s[ni][1] - m0) * ATTN_SCALE);
            s[ni][2] = __expf((s[ni][2] - m1) * ATTN_SCALE);
            s[ni][3] = __expf((s[ni][3] - m1) * ATTN_SCALE);
            sum0 += s[ni][0] + s[ni][1];
            sum1 += s[ni][2] + s[ni][3];
        }
        sum0 += __shfl_xor_sync(0xffffffffu, sum0, 1);
        sum0 += __shfl_xor_sync(0xffffffffu, sum0, 2);
        sum1 += __shfl_xor_sync(0xffffffffu, sum1, 1);
        sum1 += __shfl_xor_sync(0xffffffffu, sum1, 2);
        l0 = l0 * al0 + sum0;
        l1 = l1 * al1 + sum1;

#pragma unroll
        for (int nv = 0; nv < 4; nv++) {
            acc[nv][0] *= al0; acc[nv][1] *= al0;
            acc[nv][2] *= al1; acc[nv][3] *= al1;
        }

        __syncwarp();
#pragma unroll
        for (int ni = 0; ni < 8; ni++) {
            *(float2*)&Ps[g * PS_STR + 8 * ni + 2 * tg] =
                make_float2(to_tf32(s[ni][0]), to_tf32(s[ni][1]));
            *(float2*)&Ps[(g + 8) * PS_STR + 8 * ni + 2 * tg] =
                make_float2(to_tf32(s[ni][2]), to_tf32(s[ni][3]));
        }
        __syncwarp();

#pragma unroll
        for (int ks = 0; ks < 8; ks++) {
            int kb = ks * 8;
            uint32_t Af[4];
            Af[0] = __float_as_uint(Ps[g * PS_STR + kb + tg]);
            Af[1] = __float_as_uint(Ps[(g + 8) * PS_STR + kb + tg]);
            Af[2] = __float_as_uint(Ps[g * PS_STR + kb + tg + 4]);
            Af[3] = __float_as_uint(Ps[(g + 8) * PS_STR + kb + tg + 4]);
#pragma unroll
            for (int nv = 0; nv < 4; nv++) {
                uint32_t Bf[2];
                Bf[0] = __float_as_uint(Vc[(kb + tg) * VS_STR + 8 * nv + g]);
                Bf[1] = __float_as_uint(Vc[(kb + tg + 4) * VS_STR + 8 * nv + g]);
                mma_tf32(acc[nv], Af, Bf);
            }
        }
        buf ^= 1;
    }

    float gb = gate[b * 4 + br];
    float inv0 = gb / l0, inv1 = gb / l1;
#pragma unroll
    for (int nv = 0; nv < 4; nv++) {
        int col = h * VD + 8 * nv + 2 * tg;
        *(float2*)(outp + (b * TT + rowg) * (HH * VD) + col) =
            make_float2(acc[nv][0] * inv0, acc[nv][1] * inv0);
        *(float2*)(outp + (b * TT + rowg + 8) * (HH * VD) + col) =
            make_float2(acc[nv][2] * inv1, acc[nv][3] * inv1);
    }
}

// ---------------- launcher ----------------
extern "C" void kernel_launch(void* const* d_in, const int* in_sizes, int n_in,
                              void* d_out, int out_size) {
    const float* x         = (const float*)d_in[0];
    const float* w_cq      = (const float*)d_in[1];
    const float* g_qnorm   = (const float*)d_in[2];
    const float* w_dq_nope = (const float*)d_in[3];
    const float* w_dq_rope = (const float*)d_in[4];
    const float* w_ckv     = (const float*)d_in[5];
    const float* g_kvnorm  = (const float*)d_in[6];
    const float* w_dk_nope = (const float*)d_in[7];
    const float* w_dv      = (const float*)d_in[8];
    const float* w_krope   = (const float*)d_in[9];
    const float* w_imp     = (const float*)d_in[10];
    const float* w_selk    = (const float*)d_in[11];
    const float* w_selv    = (const float*)d_in[12];
    const float* w_wink    = (const float*)d_in[13];
    const float* w_winv    = (const float*)d_in[14];
    const float* w_gate    = (const float*)d_in[15];
    const float* w_proj    = (const float*)d_in[16];
    float* out = (float*)d_out;

    float* base = nullptr;
    cudaGetSymbolAddress((void**)&base, g_scratch);

    float* wc1    = base + OFF_WC1;
    float* xtf    = base + OFF_XTF;
    float* f0     = base + OFF_F0;
    float* qout   = base + OFF_QOUT;
    float* kvout  = base + OFF_KVOUT;
    float* winout = base + OFF_WINOUT;
    float* selkv  = base + OFF_SELKV;
    float* xmean  = base + OFF_XMEAN;
    float* gate   = base + OFF_GATE;
    float* scores = base + OFF_SCORES;
    int*   idx    = (int*)(base + OFF_IDX);
    float* Qb     = base + OFF_Q;
    float* K1b    = base + OFF_K1;
    float* KWb    = base + OFF_KW;
    float* KSb    = base + OFF_KS;
    float* att0   = base + OFF_ATTN;
    float* att1   = base + OFF_ATTN2;
    float* att2   = base + OFF_ATTN3;
    float* projA  = base + OFF_PROJA;
    float* projB  = base + OFF_PROJB;

    const int M = BB * TT;  // 2048

    cudaFuncSetAttribute(gemm_multi, cudaFuncAttributeMaxDynamicSharedMemorySize, G2_SMEM);
    cudaFuncSetAttribute(attn_mma, cudaFuncAttributeMaxDynamicSharedMemorySize, ATTN_SMEM);

    // 1) prep: scores+xtf | xmean | pack wc1
    prep_kernel<<<3080, 256>>>(x, w_imp, scores, xtf, xmean, w_cq, w_ckv, w_krope, wc1);

    // 2) topk + gate (global row ids; gather fused into selkv GEMM)
    topk_gate_kernel<<<4, 1024>>>(scores, idx, xmean, w_gate, gate);

    // 3) mega GEMM 1: winout | f0 | selkv — A = pre-rounded xtf, outputs tf32-rounded
    {
        GemmJobs jobs;
        jobs.j[0] = {xtf, CC, w_wink, 1536, 1536, w_winv, 512,
                     winout, 2048, CC, 0, 16, nullptr, 1};
        jobs.j[1] = {xtf, CC, wc1, 256, 256, wc1, 256,
                     f0, 256, CC, 256, 2, nullptr, 1};
        jobs.j[2] = {xtf, CC, w_selk, 1536, 1536, w_selv, 512,
                     selkv, 2048, CC, 288, 16, idx, 1};
        gemm_multi<<<352, 256, G2_SMEM>>>(jobs, 3);
    }

    // 4) rms on f0 (writes tf32-rounded)
    rms2_kernel<<<M, 128>>>(f0, g_qnorm, g_kvnorm);

    // 5) mega GEMM 2: qout | kvout — A = f0 (pre-rounded), outputs tf32-rounded
    {
        GemmJobs jobs;
        jobs.j[0] = {f0, 256, w_dq_nope, 512, 512, w_dq_rope, 1024,
                     qout, 1536, 96, 0, 12, nullptr, 1};
        jobs.j[1] = {f0 + 96, 256, w_dk_nope, 512, 512, w_dv, 512,
                     kvout, 1024, 32, 192, 8, nullptr, 1};
        jobs.j[2] = jobs.j[1];
        gemm_multi<<<320, 256, G2_SMEM>>>(jobs, 2);
    }

    // 6) assembles: Q + K only (V consumed in place by attention)
    assemble_all_kernel<<<6656, 512>>>(qout, kvout, f0, selkv, winout,
                                       Qb, K1b, KSb, KWb);

    // 7) attention, 3-way branch split (768 CTAs, heavy tiles first)
    attn_mma<<<dim3(24, HH, BB), 256, ATTN_SMEM>>>(Qb, K1b, KSb, KWb,
                                                   kvout, selkv, winout,
                                                   gate, att0, att1, att2);

    // 7b) att0 = round(att0+att1+att2)  (proj A-side rounding moved here)
    attadd3_kernel<<<(M * HH * VD) / 1024, 256>>>(att0, att1, att2);

    // 8) output projection, split-K halves (256 CTAs, one wave); final C NOT rounded
    {
        GemmJobs jobs;
        jobs.j[0] = {att0, HH * VD, w_proj, CC, CC, w_proj, CC,
                     projA, CC, 256, 0, 8, nullptr, 0};
        jobs.j[1] = {att0 + 256, HH * VD, w_proj + 256 * CC, CC, CC, w_proj + 256 * CC, CC,
                     projB, CC, 256, 128, 8, nullptr, 0};
        jobs.j[2] = jobs.j[1];
        gemm_multi<<<256, 256, G2_SMEM>>>(jobs, 2);
    }

    // 8b) out = projA + projB
    outadd_kernel<<<(M * CC) / 1024, 256>>>(out, projA, projB);
}

// round 15
// speedup vs baseline: 13.4853x; 1.0199x over previous
#include <cuda_runtime.h>
#include <math.h>
#include <stdint.h>

// ---------------- problem constants ----------------
#define BB 2
#define TT 1024
#define CC 1024
#define HH 16
#define VD 32
#define NOPE_ 32
#define RP 32
#define RD 64
#define DQK 96
#define KEEP_ 256
#define QL 96
#define KVL 32

#define LOG1E4_OVER_32 0.28782313662425572f   // ln(10000)/32
#define ATTN_SCALE 0.10206207261596577f       // 1/sqrt(96)

// ---------------- rounded-weight region offsets (floats, within WTF) ----------------
constexpr int WTF_WINK = 0;                      // 1024*1536
constexpr int WTF_WINV = WTF_WINK + 1024*1536;   // 1024*512
constexpr int WTF_SELK = WTF_WINV + 1024*512;    // 1024*1536
constexpr int WTF_SELV = WTF_SELK + 1024*1536;   // 1024*512
constexpr int WTF_PROJ = WTF_SELV + 1024*512;    // 512*1024
constexpr int WTF_DQN  = WTF_PROJ + 512*1024;    // 96*512
constexpr int WTF_DQR  = WTF_DQN  + 96*512;      // 96*1024
constexpr int WTF_DKN  = WTF_DQR  + 96*1024;     // 32*512
constexpr int WTF_DV   = WTF_DKN  + 32*512;      // 32*512
constexpr int WTF_TOTAL = WTF_DV + 32*512;       // 4,898,816 floats
constexpr int WTF_BLOCKS = WTF_TOTAL / 1024;     // 4784

// ---------------- scratch ----------------
constexpr int OFF_WC1     = 0;                           // [1024][256]
constexpr int OFF_WTF     = OFF_WC1     + 1024*256;      // rounded weights
constexpr int OFF_XTF     = OFF_WTF     + WTF_TOTAL;     // [2048][1024]
constexpr int OFF_F0      = OFF_XTF     + 2048*1024;     // [2048][256]
constexpr int OFF_QOUT    = OFF_F0      + 2048*256;      // [2048][1536]
constexpr int OFF_KVOUT   = OFF_QOUT    + 2048*1536;     // [2048][1024] knope|v1
constexpr int OFF_WINOUT  = OFF_KVOUT   + 2048*1024;     // [2048][2048] kw|vw
constexpr int OFF_SELKV   = OFF_WINOUT  + 2048*2048;     // [512][2048]  ks|vs
constexpr int OFF_XMEAN   = OFF_SELKV   + 512*2048;
constexpr int OFF_GATE    = OFF_XMEAN   + BB*CC;
constexpr int OFF_SCORES  = OFF_GATE    + 8;
constexpr int OFF_IDX     = OFF_SCORES  + BB*TT;
constexpr int OFF_Q       = OFF_IDX     + BB*KEEP_;
constexpr int OFF_K1      = OFF_Q       + BB*HH*TT*DQK;
constexpr int OFF_KW      = OFF_K1      + BB*HH*TT*DQK;
constexpr int OFF_KS      = OFF_KW      + BB*HH*TT*DQK;
constexpr int OFF_ATTN    = OFF_KS      + BB*HH*KEEP_*DQK;
constexpr int OFF_ATTN2   = OFF_ATTN    + BB*TT*HH*VD;
constexpr int OFF_ATTN3   = OFF_ATTN2   + BB*TT*HH*VD;
constexpr int OFF_PROJA   = OFF_ATTN3   + BB*TT*HH*VD;
constexpr int OFF_PROJB   = OFF_PROJA   + 2048*1024;
constexpr int SCRATCH_TOTAL = OFF_PROJB + 2048*1024;

__device__ __align__(256) float g_scratch[SCRATCH_TOTAL];

// ---------------- tf32 helpers ----------------
__device__ __forceinline__ float to_tf32(float v) {
    uint32_t u;
    asm("cvt.rna.tf32.f32 %0, %1;" : "=r"(u) : "f"(v));
    return __uint_as_float(u);
}

__device__ __forceinline__ void mma_tf32(float* d, const uint32_t* a, const uint32_t* b) {
    asm volatile(
        "mma.sync.aligned.m16n8k8.row.col.f32.tf32.tf32.f32 "
        "{%0,%1,%2,%3}, {%4,%5,%6,%7}, {%8,%9}, {%0,%1,%2,%3};\n"
        : "+f"(d[0]), "+f"(d[1]), "+f"(d[2]), "+f"(d[3])
        : "r"(a[0]), "r"(a[1]), "r"(a[2]), "r"(a[3]), "r"(b[0]), "r"(b[1]));
}

__device__ __forceinline__ void cp16(uint32_t dst, const float* src) {
    asm volatile("cp.async.cg.shared.global [%0], [%1], 16;" :: "r"(dst), "l"(src));
}
#define CP_COMMIT() asm volatile("cp.async.commit_group;")

// ---------------- multi-GEMM job table ----------------
struct GemmJob {
    const float* A; int lda;     // A tf32-pre-rounded
    const float* B0; int ldb0; int n0;   // B tf32-pre-rounded
    const float* B1; int ldb1;
    float* C; int ldc;
    int K;
    int ctaStart;
    int nx;
    const int* rowIdx;
    int rnd;             // 1 = write C tf32-rounded
};
struct GemmJobs { GemmJob j[3]; };

constexpr int G2_A = 128 * 20;
constexpr int G2_B = 16 * 136;
constexpr int G2_SMEM = 3 * (G2_A + G2_B) * 4;   // 56832 B

__global__ void __launch_bounds__(256, 2)
gemm_multi(GemmJobs jobs, int njobs) {
    extern __shared__ float sm2[];
    float* As = sm2;
    float* Bs = sm2 + 3 * G2_A;

    int linear = blockIdx.x;
    int ji = njobs - 1;
#pragma unroll
    for (int t = 1; t < 3; t++)
        if (t < njobs && linear < jobs.j[t].ctaStart) { ji = t - 1; break; }
    const GemmJob& J = jobs.j[ji];
    int local = linear - J.ctaStart;
    int bx = local % J.nx, by = local / J.nx;

    const float* A = J.A; int lda = J.lda;
    float* C = J.C; int ldc = J.ldc;
    int K = J.K;
    int row0 = by * 128, col0 = bx * 128;

    const float* Bsrc;
    int ldb;
    if (col0 < J.n0) { Bsrc = J.B0 + col0; ldb = J.ldb0; }
    else             { Bsrc = J.B1 + (col0 - J.n0); ldb = J.ldb1; }

    int tid = threadIdx.x;
    int warp = tid >> 5, lane = tid & 31;
    int g = lane >> 2, tg = lane & 3;
    int wm = warp >> 2, wn = warp & 3;

    uint32_t as_addr = (uint32_t)__cvta_generic_to_shared(As);
    uint32_t bs_addr = (uint32_t)__cvta_generic_to_shared(Bs);

    int ar0 = row0 + (tid >> 2);
    int ar1 = row0 + 64 + (tid >> 2);
    if (J.rowIdx) { ar0 = J.rowIdx[ar0]; ar1 = J.rowIdx[ar1]; }
    const float* Ag0 = A + (size_t)ar0 * lda + (tid & 3) * 4;
    const float* Ag1 = A + (size_t)ar1 * lda + (tid & 3) * 4;
    const float* Bg0 = Bsrc + (size_t)(tid >> 5) * ldb + (tid & 31) * 4;
    const float* Bg1 = Bsrc + (size_t)(8 + (tid >> 5)) * ldb + (tid & 31) * 4;
    uint32_t offA0 = (((tid >> 2)) * 20 + (tid & 3) * 4) * 4;
    uint32_t offA1 = (((tid >> 2) + 64) * 20 + (tid & 3) * 4) * 4;
    uint32_t offB0 = ((tid >> 5) * 136 + (tid & 31) * 4) * 4;
    uint32_t offB1 = ((8 + (tid >> 5)) * 136 + (tid & 31) * 4) * 4;

    float d[4][4][4];
#pragma unroll
    for (int mi = 0; mi < 4; mi++)
#pragma unroll
        for (int ni = 0; ni < 4; ni++)
#pragma unroll
            for (int r = 0; r < 4; r++) d[mi][ni][r] = 0.f;

    int nk = K / 16;

    {
        cp16(as_addr + offA0, Ag0);
        cp16(as_addr + offA1, Ag1);
        cp16(bs_addr + offB0, Bg0);
        cp16(bs_addr + offB1, Bg1);
        CP_COMMIT();
    }
    if (nk > 1) {
        uint32_t ab = as_addr + G2_A * 4, bb = bs_addr + G2_B * 4;
        cp16(ab + offA0, Ag0 + 16);
        cp16(ab + offA1, Ag1 + 16);
        cp16(bb + offB0, Bg0 + (size_t)16 * ldb);
        cp16(bb + offB1, Bg1 + (size_t)16 * ldb);
        CP_COMMIT();
    }

    for (int kt = 0; kt < nk; kt++) {
        if (kt + 1 < nk) { asm volatile("cp.async.wait_group 1;"); }
        else             { asm volatile("cp.async.wait_group 0;"); }
        __syncthreads();

        if (kt + 2 < nk) {
            int s = (kt + 2) % 3;
            int k0 = (kt + 2) * 16;
            uint32_t ab = as_addr + s * G2_A * 4, bb = bs_addr + s * G2_B * 4;
            cp16(ab + offA0, Ag0 + k0);
            cp16(ab + offA1, Ag1 + k0);
            cp16(bb + offB0, Bg0 + (size_t)k0 * ldb);
            cp16(bb + offB1, Bg1 + (size_t)k0 * ldb);
            CP_COMMIT();
        }

        const float* Ac = As + (kt % 3) * G2_A;
        const float* Bc = Bs + (kt % 3) * G2_B;

#pragma unroll
        for (int ks = 0; ks < 16; ks += 8) {
            uint32_t bf[4][2];
#pragma unroll
            for (int ni = 0; ni < 4; ni++) {
                int c = wn * 32 + ni * 8 + g;
                bf[ni][0] = __float_as_uint(Bc[(ks + tg) * 136 + c]);
                bf[ni][1] = __float_as_uint(Bc[(ks + tg + 4) * 136 + c]);
            }
#pragma unroll
            for (int mi = 0; mi < 4; mi++) {
                int r = wm * 64 + mi * 16;
                uint32_t af[4];
                af[0] = __float_as_uint(Ac[(r + g) * 20 + ks + tg]);
                af[1] = __float_as_uint(Ac[(r + 8 + g) * 20 + ks + tg]);
                af[2] = __float_as_uint(Ac[(r + g) * 20 + ks + tg + 4]);
                af[3] = __float_as_uint(Ac[(r + 8 + g) * 20 + ks + tg + 4]);
#pragma unroll
                for (int ni = 0; ni < 4; ni++) {
                    mma_tf32(d[mi][ni], af, bf[ni]);
                }
            }
        }
    }

    if (J.rnd) {
#pragma unroll
        for (int mi = 0; mi < 4; mi++)
#pragma unroll
            for (int ni = 0; ni < 4; ni++)
#pragma unroll
                for (int r = 0; r < 4; r++) d[mi][ni][r] = to_tf32(d[mi][ni][r]);
    }
#pragma unroll
    for (int mi = 0; mi < 4; mi++) {
#pragma unroll
        for (int ni = 0; ni < 4; ni++) {
            int r = row0 + wm * 64 + mi * 16 + g;
            int c = col0 + wn * 32 + ni * 8 + 2 * tg;
            *(float2*)(C + (size_t)r * ldc + c) = make_float2(d[mi][ni][0], d[mi][ni][1]);
            *(float2*)(C + (size_t)(r + 8) * ldc + c) = make_float2(d[mi][ni][2], d[mi][ni][3]);
        }
    }
}

// ---------------- fused prep: scores+xtf | xmean | pack_wc1 | round weights ----------
__global__ void prep_kernel(const float* __restrict__ x, const float* __restrict__ w_imp,
                            float* __restrict__ scores, float* __restrict__ xtf,
                            float* __restrict__ xmean,
                            const float* __restrict__ w_cq, const float* __restrict__ w_ckv,
                            const float* __restrict__ w_krope, float* __restrict__ wc1,
                            const float* __restrict__ w_wink, const float* __restrict__ w_winv,
                            const float* __restrict__ w_selk, const float* __restrict__ w_selv,
                            const float* __restrict__ w_proj,
                            const float* __restrict__ w_dqn, const float* __restrict__ w_dqr,
                            const float* __restrict__ w_dkn, const float* __restrict__ w_dv,
                            float* __restrict__ wtf) {
    int blk = blockIdx.x, tid = threadIdx.x;
    if (blk < 2048) {
        __shared__ float s8[8];
        int row = blk;
        float s = 0.f;
        for (int c = tid; c < CC; c += 256) {
            float xv = x[row * CC + c];
            xtf[row * CC + c] = to_tf32(xv);
            s += xv * w_imp[c];
        }
#pragma unroll
        for (int o = 16; o > 0; o >>= 1) s += __shfl_xor_sync(0xffffffffu, s, o);
        if ((tid & 31) == 0) s8[tid >> 5] = s;
        __syncthreads();
        if (tid == 0) {
            float t = 0.f;
#pragma unroll
            for (int i = 0; i < 8; i++) t += s8[i];
            scores[row] = t;
        }
    } else if (blk < 2056) {
        int i = blk - 2048;
        int b = i >> 2;
        int c = (i & 3) * 256 + tid;
        float s = 0.f;
        for (int t = 0; t < TT; t++) s += x[(b * TT + t) * CC + c];
        xmean[b * CC + c] = s * (1.f / (float)TT);
    } else if (blk < 3080) {
        int k = blk - 2056;
        float v;
        if (tid < 96) v = w_cq[k * 96 + tid];
        else if (tid < 128) v = w_ckv[k * 32 + (tid - 96)];
        else if (tid < 192) v = w_krope[k * 64 + (tid - 128)];
        else v = 0.f;
        wc1[k * 256 + tid] = to_tf32(v);
    } else {
        // round weights: each block handles 1024 consecutive floats of WTF
        int off = (blk - 3080) * 1024 + tid * 4;
        const float* src;
        int rel;
        if (off < WTF_WINV)      { src = w_wink; rel = off - WTF_WINK; }
        else if (off < WTF_SELK) { src = w_winv; rel = off - WTF_WINV; }
        else if (off < WTF_SELV) { src = w_selk; rel = off - WTF_SELK; }
        else if (off < WTF_PROJ) { src = w_selv; rel = off - WTF_SELV; }
        else if (off < WTF_DQN)  { src = w_proj; rel = off - WTF_PROJ; }
        else if (off < WTF_DQR)  { src = w_dqn;  rel = off - WTF_DQN; }
        else if (off < WTF_DKN)  { src = w_dqr;  rel = off - WTF_DQR; }
        else if (off < WTF_DV)   { src = w_dkn;  rel = off - WTF_DKN; }
        else                     { src = w_dv;   rel = off - WTF_DV; }
        float4 v = *(const float4*)(src + rel);
        v.x = to_tf32(v.x); v.y = to_tf32(v.y);
        v.z = to_tf32(v.z); v.w = to_tf32(v.w);
        *(float4*)(wtf + off) = v;
    }
}

// ---------------- fused topk + gate ----------------
__global__ void topk_gate_kernel(const float* __restrict__ scores, int* __restrict__ idxout,
                                 const float* __restrict__ xmean, const float* __restrict__ wg,
                                 float* __restrict__ gate) {
    int blk = blockIdx.x, tid = threadIdx.x;
    if (blk < 2) {
        __shared__ float sv[1024];
        __shared__ int si[1024];
        __shared__ int ti[256];
        int b = blk;
        sv[tid] = scores[b * TT + tid];
        si[tid] = tid;
        __syncthreads();
        for (int k = 2; k <= 1024; k <<= 1) {
            for (int j = k >> 1; j > 0; j >>= 1) {
                int ixj = tid ^ j;
                if (ixj > tid) {
                    bool desc = ((tid & k) == 0);
                    float va = sv[tid], vb = sv[ixj];
                    int ia = si[tid], ib = si[ixj];
                    bool agtb = (va > vb) || (va == vb && ia < ib);
                    if (desc ? !agtb : agtb) {
                        sv[tid] = vb; sv[ixj] = va;
                        si[tid] = ib; si[ixj] = ia;
                    }
                }
                __syncthreads();
            }
        }
        if (tid < 256) ti[tid] = si[tid];
        __syncthreads();
        for (int k = 2; k <= 256; k <<= 1) {
            for (int j = k >> 1; j > 0; j >>= 1) {
                int ixj = tid ^ j;
                if (tid < 256 && ixj > tid) {
                    bool asc = ((tid & k) == 0);
                    int ia = ti[tid], ib = ti[ixj];
                    if (asc ? (ia > ib) : (ia < ib)) { ti[tid] = ib; ti[ixj] = ia; }
                }
                __syncthreads();
            }
        }
        if (tid < 256) idxout[b * KEEP_ + tid] = b * TT + ti[tid];
    } else {
        int b = blk - 2;
        __shared__ float sg[3];
        int w = tid >> 5, lane = tid & 31;
        if (w < 3) {
            float s = 0.f;
            for (int c = lane; c < CC; c += 32) s += xmean[b * CC + c] * wg[c * 3 + w];
#pragma unroll
            for (int o = 16; o > 0; o >>= 1) s += __shfl_xor_sync(0xffffffffu, s, o);
            if (lane == 0) sg[w] = s;
        }
        __syncthreads();
        if (tid == 0) {
            float m = fmaxf(sg[0], fmaxf(sg[1], sg[2]));
            float e0 = expf(sg[0] - m), e1 = expf(sg[1] - m), e2 = expf(sg[2] - m);
            float inv = 1.f / (e0 + e1 + e2);
            gate[b * 4 + 0] = e0 * inv;
            gate[b * 4 + 1] = e1 * inv;
            gate[b * 4 + 2] = e2 * inv;
        }
    }
}

// ---------------- RMS norm on f0 (writes tf32-rounded) ----------------
__global__ void rms2_kernel(float* __restrict__ f0,
                            const float* __restrict__ gq, const float* __restrict__ gkv) {
    int row = blockIdx.x, tid = threadIdx.x;
    float* dd = f0 + row * 256;
    __shared__ float s4[4];
    float v = (tid < 96) ? dd[tid] : 0.f;
    float sq = v * v;
#pragma unroll
    for (int o = 16; o > 0; o >>= 1) sq += __shfl_xor_sync(0xffffffffu, sq, o);
    if ((tid & 31) == 0) s4[tid >> 5] = sq;
    __syncthreads();
    float tot = s4[0] + s4[1] + s4[2] + s4[3];
    float sc = rsqrtf(tot / 96.f + 1e-6f);
    if (tid < 96) dd[tid] = to_tf32(v * sc * gq[tid]);
    __syncthreads();
    if (tid < 32) {
        float v2 = dd[96 + tid];
        float sq2 = v2 * v2;
#pragma unroll
        for (int o = 16; o > 0; o >>= 1) sq2 += __shfl_xor_sync(0xffffffffu, sq2, o);
        float sc2 = rsqrtf(sq2 / 32.f + 1e-6f);
        dd[96 + tid] = to_tf32(v2 * sc2 * gkv[tid]);
    }
}

// ---------------- fused assembles: Q + K only ----------------
__global__ void assemble_all_kernel(const float* __restrict__ qout,
                                    const float* __restrict__ kvout,
                                    const float* __restrict__ f0,
                                    const float* __restrict__ selkv,
                                    const float* __restrict__ winout,
                                    float* __restrict__ Q,
                                    float* __restrict__ K1,
                                    float* __restrict__ KSb,
                                    float* __restrict__ KWb) {
    int blk = blockIdx.x;
    int j = threadIdx.x;
    int h = j >> 5, d = j & 31;
    float f = expf(-LOG1E4_OVER_32 * (float)d);

    if (blk < 2048) {
        int row = blk;
        int b = row >> 10, t = row & 1023;
        int qb = (((b * HH + h) * TT) + t) * DQK;
        Q[qb + d] = qout[row * 1536 + j];
        float x1 = qout[row * 1536 + 512 + h * RD + d];
        float x2 = qout[row * 1536 + 512 + h * RD + RP + d];
        float sn, cs;
        sincosf((float)t * f, &sn, &cs);
        Q[qb + NOPE_ + d] = to_tf32(x1 * cs - x2 * sn);
        Q[qb + NOPE_ + RP + d] = to_tf32(x1 * sn + x2 * cs);
    } else if (blk < 4096) {
        int row = blk - 2048;
        int b = row >> 10, t = row & 1023;
        int kb = (((b * HH + h) * TT) + t) * DQK;
        K1[kb + d] = kvout[row * 1024 + j];
        float x1 = f0[row * 256 + 128 + d] * 0.0625f;
        float x2 = f0[row * 256 + 128 + RP + d] * 0.0625f;
        float sn, cs;
        sincosf((float)t * f, &sn, &cs);
        K1[kb + NOPE_ + d] = to_tf32(x1 * cs - x2 * sn);
        K1[kb + NOPE_ + RP + d] = to_tf32(x1 * sn + x2 * cs);
    } else {
        const float* raw;
        float* K;
        int row, S;
        if (blk < 4608) { row = blk - 4096; S = KEEP_; raw = selkv; K = KSb; }
        else            { row = blk - 4608; S = TT;    raw = winout; K = KWb; }
        int b = row / S, pos = row % S;
        size_t base = (size_t)row * 2048;
        float nope = raw[base + h * DQK + d];
        float x1 = raw[base + h * DQK + NOPE_ + d];
        float x2 = raw[base + h * DQK + NOPE_ + RP + d];
        float sn, cs;
        sincosf((float)pos * f, &sn, &cs);
        int kb = (((b * HH + h) * S) + pos) * DQK;
        K[kb + d] = nope;
        K[kb + NOPE_ + d] = to_tf32(x1 * cs - x2 * sn);
        K[kb + NOPE_ + RP + d] = to_tf32(x1 * sn + x2 * cs);
    }
}

// ---------------- adds ----------------
__global__ void attadd3_kernel(float* __restrict__ a0, const float* __restrict__ a1,
                               const float* __restrict__ a2) {
    int i = (blockIdx.x * 256 + threadIdx.x) * 4;
    float4 v0 = *(float4*)(a0 + i);
    float4 v1 = *(const float4*)(a1 + i);
    float4 v2 = *(const float4*)(a2 + i);
    v0.x = to_tf32(v0.x + v1.x + v2.x);
    v0.y = to_tf32(v0.y + v1.y + v2.y);
    v0.z = to_tf32(v0.z + v1.z + v2.z);
    v0.w = to_tf32(v0.w + v1.w + v2.w);
    *(float4*)(a0 + i) = v0;
}

__global__ void outadd_kernel(float* __restrict__ o, const float* __restrict__ pa,
                              const float* __restrict__ pb) {
    int i = (blockIdx.x * 256 + threadIdx.x) * 4;
    float4 va = *(const float4*)(pa + i);
    float4 vb = *(const float4*)(pb + i);
    va.x += vb.x; va.y += vb.y; va.z += vb.z; va.w += vb.w;
    *(float4*)(o + i) = va;
}

// ---------------- pipelined tf32 MMA flash attention, 3-way split, 2 CTA/SM ----------
// Qs smem is dead after the register preload — K double-buffer overlays it.
// smem: phase1 Qs[128][100] @0 | main: K[2][64][100] @0, V[2][64][40] @12800, Ps @17920
constexpr int QS_STR = 100;
constexpr int KS_STR = 100;
constexpr int VS_STR = 40;
constexpr int PS_STR = 68;
constexpr int KBUF = 64 * KS_STR;
constexpr int VBUF = 64 * VS_STR;
constexpr int ASM_KS = 0;                    // overlays Qs
constexpr int ASM_VS = 2 * KBUF;             // 12800
constexpr int ASM_PS = ASM_VS + 2 * VBUF;    // 17920
constexpr int ATTN_SMEM = (ASM_PS + 8 * 16 * PS_STR) * 4;   // 106496 B

__global__ void __launch_bounds__(256, 2)
attn_mma(const float* __restrict__ Q,
         const float* __restrict__ K1, const float* __restrict__ KS,
         const float* __restrict__ KW,
         const float* __restrict__ kvout, const float* __restrict__ selkv,
         const float* __restrict__ winout,
         const float* __restrict__ gate,
         float* __restrict__ att0, float* __restrict__ att1, float* __restrict__ att2) {
    extern __shared__ float sm[];
    float* Qs = sm;                 // phase-1 only

    int tid = threadIdx.x;
    int w = tid >> 5, lane = tid & 31;
    int g = lane >> 2, tg = lane & 3;
    float* Ps = sm + ASM_PS + w * 16 * PS_STR;

    int xid = blockIdx.x;
    int part = xid % 3;
    int tile = 7 - (xid / 3);
    int h = blockIdx.y, b = blockIdx.z;
    int q0 = tile * 128;
    int bh = b * HH + h;
    int rowg = q0 + 16 * w + g;

    int br = (part == 0) ? 0 : ((part == 1) ? 2 : 1);
    float* outp = (part == 0) ? att0 : ((part == 1) ? att1 : att2);
    bool causal = (br != 1);
    int nchunk = (br == 1) ? 4 : 2 * (tile + 1);

    const float* Kp = (br == 0) ? K1 + bh * TT * DQK
                    : (br == 1) ? KS + bh * KEEP_ * DQK
                                : KW + bh * TT * DQK;
    const float* Vp;
    int vld;
    if (br == 0)      { Vp = kvout + (size_t)(b * TT) * 1024 + 512 + h * VD;    vld = 1024; }
    else if (br == 1) { Vp = selkv + (size_t)(b * KEEP_) * 2048 + 1536 + h * VD; vld = 2048; }
    else              { Vp = winout + (size_t)(b * TT) * 2048 + 1536 + h * VD;   vld = 2048; }

    uint32_t smem_u32 = (uint32_t)__cvta_generic_to_shared(sm);

    // ---- phase 1: stage Q, preload register fragments, release smem ----
    const float* Qp = Q + (bh * TT + q0) * DQK;
    for (int i = tid; i < 128 * 24; i += 256) {
        int q = i / 24, dq = i % 24;
        float4 v = *(const float4*)(Qp + q * DQK + dq * 4);
        *(float4*)&Qs[q * QS_STR + dq * 4] = v;
    }
    __syncthreads();
    uint32_t Qf[12][4];
    {
        const float* q0p = &Qs[(16 * w + g) * QS_STR];
        const float* q1p = q0p + 8 * QS_STR;
#pragma unroll
        for (int ks = 0; ks < 12; ks++) {
            Qf[ks][0] = __float_as_uint(q0p[8 * ks + tg]);
            Qf[ks][1] = __float_as_uint(q1p[8 * ks + tg]);
            Qf[ks][2] = __float_as_uint(q0p[8 * ks + tg + 4]);
            Qf[ks][3] = __float_as_uint(q1p[8 * ks + tg + 4]);
        }
    }
    __syncthreads();   // all warps done with Qs before K staging overwrites it

    // ---- main phase ----
    auto stage = [&](int buf, int k0) {
        uint32_t kaddr = smem_u32 + (ASM_KS + buf * KBUF) * 4;
        uint32_t vaddr = smem_u32 + (ASM_VS + buf * VBUF) * 4;
#pragma unroll
        for (int it = 0; it < 6; it++) {
            int i = tid + it * 256;
            int key = i / 24, dq = i % 24;
            cp16(kaddr + (key * KS_STR + dq * 4) * 4, Kp + (k0 + key) * DQK + dq * 4);
        }
#pragma unroll
        for (int it = 0; it < 2; it++) {
            int i = tid + it * 256;
            int key = i >> 3, dq = i & 7;
            cp16(vaddr + (key * VS_STR + dq * 4) * 4, Vp + (size_t)(k0 + key) * vld + dq * 4);
        }
        CP_COMMIT();
    };

    stage(0, 0);
    int buf = 0;

    float m0 = -1e30f, m1 = -1e30f, l0 = 0.f, l1 = 0.f;
    float acc[4][4];
#pragma unroll
    for (int nv = 0; nv < 4; nv++)
#pragma unroll
        for (int r = 0; r < 4; r++) acc[nv][r] = 0.f;

    for (int c = 0; c < nchunk; c++) {
        int k0 = c * 64;

        __syncthreads();
        if (c + 1 < nchunk) {
            stage(buf ^ 1, (c + 1) * 64);
            asm volatile("cp.async.wait_group 1;");
        } else {
            asm volatile("cp.async.wait_group 0;");
        }
        __syncthreads();

        const float* Kc = sm + ASM_KS + buf * KBUF;
        const float* Vc = sm + ASM_VS + buf * VBUF;

        float s[8][4];
#pragma unroll
        for (int ni = 0; ni < 8; ni++)
#pragma unroll
            for (int r = 0; r < 4; r++) s[ni][r] = 0.f;

#pragma unroll
        for (int ks = 0; ks < 12; ks++) {
            int kb = ks * 8;
#pragma unroll
            for (int ni = 0; ni < 8; ni++) {
                uint32_t Bf[2];
                Bf[0] = __float_as_uint(Kc[(8 * ni + g) * KS_STR + kb + tg]);
                Bf[1] = __float_as_uint(Kc[(8 * ni + g) * KS_STR + kb + tg + 4]);
                mma_tf32(s[ni], Qf[ks], Bf);
            }
        }

        if (causal && (k0 + 64 > q0)) {
#pragma unroll
            for (int ni = 0; ni < 8; ni++) {
                int key = k0 + 8 * ni + 2 * tg;
                if (key > rowg)         s[ni][0] = -1e30f;
                if (key + 1 > rowg)     s[ni][1] = -1e30f;
                if (key > rowg + 8)     s[ni][2] = -1e30f;
                if (key + 1 > rowg + 8) s[ni][3] = -1e30f;
            }
        }

        float cm0 = -1e30f, cm1 = -1e30f;
#pragma unroll
        for (int ni = 0; ni < 8; ni++) {
            cm0 = fmaxf(cm0, fmaxf(s[ni][0], s[ni][1]));
            cm1 = fmaxf(cm1, fmaxf(s[ni][2], s[ni][3]));
        }
        cm0 = fmaxf(cm0, __shfl_xor_sync(0xffffffffu, cm0, 1));
        cm0 = fmaxf(cm0, __shfl_xor_sync(0xffffffffu, cm0, 2));
        cm1 = fmaxf(cm1, __shfl_xor_sync(0xffffffffu, cm1, 1));
        cm1 = fmaxf(cm1, __shfl_xor_sync(0xffffffffu, cm1, 2));

        float nm0 = fmaxf(m0, cm0), nm1 = fmaxf(m1, cm1);
        float al0 = __expf((m0 - nm0) * ATTN_SCALE);
        float al1 = __expf((m1 - nm1) * ATTN_SCALE);
        m0 = nm0; m1 = nm1;

        float sum0 = 0.f, sum1 = 0.f;
#pragma unroll
        for (int ni = 0; ni < 8; ni++) {
            s[ni][0] = __expf((s[ni][0] - m0) * ATTN_SCALE);
            s[ni][1] = __expf((s[ni][1] - m0) * ATTN_SCALE);
            s[ni][2] = __expf((s[ni][2] - m1) * ATTN_SCALE);
            s[ni][3] = __expf((s[ni][3] - m1) * ATTN_SCALE);
            sum0 += s[ni][0] + s[ni][1];
            sum1 += s[ni][2] + s[ni][3];
        }
        sum0 += __shfl_xor_sync(0xffffffffu, sum0, 1);
        sum0 += __shfl_xor_sync(0xffffffffu, sum0, 2);
        sum1 += __shfl_xor_sync(0xffffffffu, sum1, 1);
        sum1 += __shfl_xor_sync(0xffffffffu, sum1, 2);
        l0 = l0 * al0 + sum0;
        l1 = l1 * al1 + sum1;

#pragma unroll
        for (int nv = 0; nv < 4; nv++) {
            acc[nv][0] *= al0; acc[nv][1] *= al0;
            acc[nv][2] *= al1; acc[nv][3] *= al1;
        }

        __syncwarp();
#pragma unroll
        for (int ni = 0; ni < 8; ni++) {
            *(float2*)&Ps[g * PS_STR + 8 * ni + 2 * tg] =
                make_float2(to_tf32(s[ni][0]), to_tf32(s[ni][1]));
            *(float2*)&Ps[(g + 8) * PS_STR + 8 * ni + 2 * tg] =
                make_float2(to_tf32(s[ni][2]), to_tf32(s[ni][3]));
        }
        __syncwarp();

#pragma unroll
        for (int ks = 0; ks < 8; ks++) {
            int kb = ks * 8;
            uint32_t Af[4];
            Af[0] = __float_as_uint(Ps[g * PS_STR + kb + tg]);
            Af[1] = __float_as_uint(Ps[(g + 8) * PS_STR + kb + tg]);
            Af[2] = __float_as_uint(Ps[g * PS_STR + kb + tg + 4]);
            Af[3] = __float_as_uint(Ps[(g + 8) * PS_STR + kb + tg + 4]);
#pragma unroll
            for (int nv = 0; nv < 4; nv++) {
                uint32_t Bf[2];
                Bf[0] = __float_as_uint(Vc[(kb + tg) * VS_STR + 8 * nv + g]);
                Bf[1] = __float_as_uint(Vc[(kb + tg + 4) * VS_STR + 8 * nv + g]);
                mma_tf32(acc[nv], Af, Bf);
            }
        }
        buf ^= 1;
    }

    float gb = gate[b * 4 + br];
    float inv0 = gb / l0, inv1 = gb / l1;
#pragma unroll
    for (int nv = 0; nv < 4; nv++) {
        int col = h * VD + 8 * nv + 2 * tg;
        *(float2*)(outp + (b * TT + rowg) * (HH * VD) + col) =
            make_float2(acc[nv][0] * inv0, acc[nv][1] * inv0);
        *(float2*)(outp + (b * TT + rowg + 8) * (HH * VD) + col) =
            make_float2(acc[nv][2] * inv1, acc[nv][3] * inv1);
    }
}

// ---------------- launcher ----------------
extern "C" void kernel_launch(void* const* d_in, const int* in_sizes, int n_in,
                              void* d_out, int out_size) {
    const float* x         = (const float*)d_in[0];
    const float* w_cq      = (const float*)d_in[1];
    const float* g_qnorm   = (const float*)d_in[2];
    const float* w_dq_nope = (const float*)d_in[3];
    const float* w_dq_rope = (const float*)d_in[4];
    const float* w_ckv     = (const float*)d_in[5];
    const float* g_kvnorm  = (const float*)d_in[6];
    const float* w_dk_nope = (const float*)d_in[7];
    const float* w_dv      = (const float*)d_in[8];
    const float* w_krope   = (const float*)d_in[9];
    const float* w_imp     = (const float*)d_in[10];
    const float* w_selk    = (const float*)d_in[11];
    const float* w_selv    = (const float*)d_in[12];
    const float* w_wink    = (const float*)d_in[13];
    const float* w_winv    = (const float*)d_in[14];
    const float* w_gate    = (const float*)d_in[15];
    const float* w_proj    = (const float*)d_in[16];
    float* out = (float*)d_out;

    float* base = nullptr;
    cudaGetSymbolAddress((void**)&base, g_scratch);

    float* wc1    = base + OFF_WC1;
    float* wtf    = base + OFF_WTF;
    float* xtf    = base + OFF_XTF;
    float* f0     = base + OFF_F0;
    float* qout   = base + OFF_QOUT;
    float* kvout  = base + OFF_KVOUT;
    float* winout = base + OFF_WINOUT;
    float* selkv  = base + OFF_SELKV;
    float* xmean  = base + OFF_XMEAN;
    float* gate   = base + OFF_GATE;
    float* scores = base + OFF_SCORES;
    int*   idx    = (int*)(base + OFF_IDX);
    float* Qb     = base + OFF_Q;
    float* K1b    = base + OFF_K1;
    float* KWb    = base + OFF_KW;
    float* KSb    = base + OFF_KS;
    float* att0   = base + OFF_ATTN;
    float* att1   = base + OFF_ATTN2;
    float* att2   = base + OFF_ATTN3;
    float* projA  = base + OFF_PROJA;
    float* projB  = base + OFF_PROJB;

    const int M = BB * TT;  // 2048

    cudaFuncSetAttribute(gemm_multi, cudaFuncAttributeMaxDynamicSharedMemorySize, G2_SMEM);
    cudaFuncSetAttribute(attn_mma, cudaFuncAttributeMaxDynamicSharedMemorySize, ATTN_SMEM);

    // 1) prep: scores+xtf | xmean | pack wc1 | round all weights
    prep_kernel<<<3080 + WTF_BLOCKS, 256>>>(x, w_imp, scores, xtf, xmean,
                                            w_cq, w_ckv, w_krope, wc1,
                                            w_wink, w_winv, w_selk, w_selv, w_proj,
                                            w_dq_nope, w_dq_rope, w_dk_nope, w_dv, wtf);

    // 2) topk + gate
    topk_gate_kernel<<<4, 1024>>>(scores, idx, xmean, w_gate, gate);

    // 3) mega GEMM 1: winout | f0 | selkv (all operands pre-rounded)
    {
        GemmJobs jobs;
        jobs.j[0] = {xtf, CC, wtf + WTF_WINK, 1536, 1536, wtf + WTF_WINV, 512,
                     winout, 2048, CC, 0, 16, nullptr, 1};
        jobs.j[1] = {xtf, CC, wc1, 256, 256, wc1, 256,
                     f0, 256, CC, 256, 2, nullptr, 1};
        jobs.j[2] = {xtf, CC, wtf + WTF_SELK, 1536, 1536, wtf + WTF_SELV, 512,
                     selkv, 2048, CC, 288, 16, idx, 1};
        gemm_multi<<<352, 256, G2_SMEM>>>(jobs, 3);
    }

    // 4) rms on f0
    rms2_kernel<<<M, 128>>>(f0, g_qnorm, g_kvnorm);

    // 5) mega GEMM 2: qout | kvout
    {
        GemmJobs jobs;
        jobs.j[0] = {f0, 256, wtf + WTF_DQN, 512, 512, wtf + WTF_DQR, 1024,
                     qout, 1536, 96, 0, 12, nullptr, 1};
        jobs.j[1] = {f0 + 96, 256, wtf + WTF_DKN, 512, 512, wtf + WTF_DV, 512,
                     kvout, 1024, 32, 192, 8, nullptr, 1};
        jobs.j[2] = jobs.j[1];
        gemm_multi<<<320, 256, G2_SMEM>>>(jobs, 2);
    }

    // 6) assembles: Q + K only
    assemble_all_kernel<<<6656, 512>>>(qout, kvout, f0, selkv, winout,
                                       Qb, K1b, KSb, KWb);

    // 7) attention, 3-way branch split, 2 CTA/SM
    attn_mma<<<dim3(24, HH, BB), 256, ATTN_SMEM>>>(Qb, K1b, KSb, KWb,
                                                   kvout, selkv, winout,
                                                   gate, att0, att1, att2);

    // 7b) att0 = round(att0+att1+att2)
    attadd3_kernel<<<(M * HH * VD) / 1024, 256>>>(att0, att1, att2);

    // 8) output projection, split-K halves
    {
        GemmJobs jobs;
        jobs.j[0] = {att0, HH * VD, wtf + WTF_PROJ, CC, CC, wtf + WTF_PROJ, CC,
                     projA, CC, 256, 0, 8, nullptr, 0};
        jobs.j[1] = {att0 + 256, HH * VD, wtf + WTF_PROJ + 256 * CC, CC, CC,
                     wtf + WTF_PROJ + 256 * CC, CC,
                     projB, CC, 256, 128, 8, nullptr, 0};
        jobs.j[2] = jobs.j[1];
        gemm_multi<<<256, 256, G2_SMEM>>>(jobs, 2);
    }

    // 8b) out = projA + projB
    outadd_kernel<<<(M * CC) / 1024, 256>>>(out, projA, projB);
}